// round 1
// baseline (speedup 1.0000x reference)
#include <cuda_runtime.h>
#include <math.h>

#define NSER 448
#define LSEQ 512
#define TTOK 68
#define DMOD 768
#define NTOK (NSER*TTOK)       // 30464
#define PNUM 64
#define POOLN 1000
#define PREDL 96
#define NLAYER 6

// ---------------- scratch (device globals; no allocations) ----------------
__device__ float g_xn  [NSER*LSEQ];
__device__ float g_mean[NSER];
__device__ float g_std [NSER];
__device__ float g_dec [NSER*3*LSEQ];
__device__ float g_tok [NSER*PNUM*48];
__device__ float g_h   [(size_t)NTOK*DMOD];
__device__ float g_a   [(size_t)NTOK*DMOD];
__device__ float g_qkv [(size_t)NTOK*3*DMOD];
__device__ float g_ob  [(size_t)NTOK*DMOD];
__device__ float g_mlp [(size_t)NTOK*4*DMOD];
__device__ float g_xq  [NSER*DMOD];
__device__ float g_keyn[POOLN*DMOD];
__device__ float g_sim [NSER*POOLN];
__device__ float g_ogem[NSER*3*PREDL];
__device__ float g_rsim;

__device__ __forceinline__ float gelu_tanh(float x){
    float c = 0.7978845608028654f;
    float t = tanhf(c*(x + 0.044715f*x*x*x));
    return 0.5f*x*(1.f+t);
}

// ---------------- RevIN stats + normalize ----------------
__global__ void norm_k(const float* __restrict__ x){
    int n = blockIdx.x, b = n/7, m = n%7, tid = threadIdx.x;
    __shared__ float xs[LSEQ];
    __shared__ float red[256];
    for (int l = tid; l < LSEQ; l += 256) xs[l] = x[((size_t)b*LSEQ + l)*7 + m];
    __syncthreads();
    float s = xs[tid] + xs[tid+256];
    red[tid] = s; __syncthreads();
    for (int o = 128; o; o >>= 1){ if (tid < o) red[tid] += red[tid+o]; __syncthreads(); }
    float mu = red[0] * (1.f/LSEQ);
    __syncthreads();
    float d0 = xs[tid]-mu, d1 = xs[tid+256]-mu;
    red[tid] = d0*d0 + d1*d1; __syncthreads();
    for (int o = 128; o; o >>= 1){ if (tid < o) red[tid] += red[tid+o]; __syncthreads(); }
    float sd = sqrtf(red[0]*(1.f/LSEQ) + 1e-5f);
    if (tid == 0){ g_mean[n] = mu; g_std[n] = sd; }
    float inv = 1.f/sd;
    g_xn[n*LSEQ + tid]       = d0*inv;
    g_xn[n*LSEQ + 256 + tid] = d1*inv;
}

// ---------------- trend / seasonal / residual decomposition ----------------
__global__ void dec_k(){
    int n = blockIdx.x, tid = threadIdx.x;
    __shared__ float xs[LSEQ];
    __shared__ float valid[489];
    __shared__ float det[LSEQ];
    __shared__ float ph[24];
    for (int l = tid; l < LSEQ; l += 256) xs[l] = g_xn[n*LSEQ + l];
    if (tid < 24) ph[tid] = 0.f;
    __syncthreads();
    for (int i = tid; i < 489; i += 256){
        float s = 0.f;
        #pragma unroll
        for (int k = 0; k < 24; k++) s += xs[i+k];
        valid[i] = s * (1.f/24.f);
    }
    __syncthreads();
    for (int l = tid; l < LSEQ; l += 256){
        int vi = l - 12; vi = vi < 0 ? 0 : (vi > 488 ? 488 : vi);
        float tr = valid[vi];
        float dt = xs[l] - tr;
        det[l] = dt;
        atomicAdd(&ph[l % 24], dt);
        g_dec[((size_t)n*3 + 0)*LSEQ + l] = tr;
    }
    __syncthreads();
    for (int l = tid; l < LSEQ; l += 256){
        int p = l % 24;
        float cnt = (p < 8) ? 22.f : 21.f;     // 512 = 21*24 + 8
        float se = ph[p] / cnt;
        g_dec[((size_t)n*3 + 1)*LSEQ + l] = se;
        g_dec[((size_t)n*3 + 2)*LSEQ + l] = det[l] - se;
    }
}

// ---------------- patch extraction ----------------
__global__ void patch_k(){
    int n = blockIdx.x, tid = threadIdx.x;
    for (int e = tid; e < PNUM*48; e += 256){
        int p = e/48, rem = e%48, c = rem/16, j = rem%16;
        int l = p*8 + j; if (l > LSEQ-1) l = LSEQ-1;   // right-pad with last value
        g_tok[(size_t)n*PNUM*48 + e] = g_dec[((size_t)n*3 + c)*LSEQ + l];
    }
}

// ---------------- generic tiled SGEMM ----------------
// C[M,N] = A[M,K] @ B + bias  (B is (K,N), or (N,K) if TRANSB)
// ACT: 0 none, 1 gelu.  RESID: C += result.  REMAP: out row r -> (r/64)*68+4+(r%64) (emb into h)
// Requirements: M%64==0, K%16==0, N%4==0.
template<bool TRANSB, int ACT, bool RESID, bool REMAP>
__global__ void gemm_k(const float* __restrict__ A, const float* __restrict__ B,
                       const float* __restrict__ bias, float* __restrict__ C,
                       int M, int N, int K){
    __shared__ float As[16][68];
    __shared__ float Bs[16][68];
    int tid = threadIdx.x;
    int tx = tid & 15, ty = tid >> 4;
    int row0 = blockIdx.y * 64, col0 = blockIdx.x * 64;
    float acc[4][4] = {};
    for (int k0 = 0; k0 < K; k0 += 16){
        {   // A tile 64x16, stored transposed
            int r  = tid >> 2;
            int c4 = (tid & 3) * 4;
            float4 v = *reinterpret_cast<const float4*>(&A[(size_t)(row0 + r)*K + k0 + c4]);
            As[c4+0][r] = v.x; As[c4+1][r] = v.y; As[c4+2][r] = v.z; As[c4+3][r] = v.w;
        }
        if (!TRANSB){
            int kk = tid >> 4;
            int c4 = (tid & 15) * 4;
            int col = col0 + c4;
            float4 v = make_float4(0.f,0.f,0.f,0.f);
            if (col < N) v = *reinterpret_cast<const float4*>(&B[(size_t)(k0+kk)*N + col]);
            Bs[kk][c4+0] = v.x; Bs[kk][c4+1] = v.y; Bs[kk][c4+2] = v.z; Bs[kk][c4+3] = v.w;
        } else {
            int nn = tid >> 2;
            int c4 = (tid & 3) * 4;
            int col = col0 + nn;
            float4 v = make_float4(0.f,0.f,0.f,0.f);
            if (col < N) v = *reinterpret_cast<const float4*>(&B[(size_t)col*K + k0 + c4]);
            Bs[c4+0][nn] = v.x; Bs[c4+1][nn] = v.y; Bs[c4+2][nn] = v.z; Bs[c4+3][nn] = v.w;
        }
        __syncthreads();
        #pragma unroll
        for (int kk = 0; kk < 16; kk++){
            float a[4], b[4];
            #pragma unroll
            for (int i = 0; i < 4; i++) a[i] = As[kk][ty*4+i];
            #pragma unroll
            for (int j = 0; j < 4; j++) b[j] = Bs[kk][tx*4+j];
            #pragma unroll
            for (int i = 0; i < 4; i++)
                #pragma unroll
                for (int j = 0; j < 4; j++) acc[i][j] = fmaf(a[i], b[j], acc[i][j]);
        }
        __syncthreads();
    }
    #pragma unroll
    for (int i = 0; i < 4; i++){
        int r = row0 + ty*4 + i;
        size_t orow = REMAP ? (size_t)((r >> 6)*TTOK + 4 + (r & 63)) : (size_t)r;
        #pragma unroll
        for (int j = 0; j < 4; j++){
            int col = col0 + tx*4 + j;
            if (col < N){
                float v = acc[i][j];
                if (bias) v += bias[col];
                if (ACT == 1) v = gelu_tanh(v);
                size_t idx = orow*(size_t)N + col;
                if (RESID) C[idx] += v; else C[idx] = v;
            }
        }
    }
}

// ---------------- l2-normalize prompt keys ----------------
__global__ void keynorm_k(const float* __restrict__ pk){
    int r = blockIdx.x, tid = threadIdx.x;
    __shared__ float red[256];
    float v0 = pk[(size_t)r*DMOD + tid], v1 = pk[(size_t)r*DMOD + 256 + tid], v2 = pk[(size_t)r*DMOD + 512 + tid];
    red[tid] = v0*v0 + v1*v1 + v2*v2; __syncthreads();
    for (int o = 128; o; o >>= 1){ if (tid < o) red[tid] += red[tid+o]; __syncthreads(); }
    float inv = rsqrtf(fmaxf(red[0], 1e-12f));
    g_keyn[(size_t)r*DMOD + tid]       = v0*inv;
    g_keyn[(size_t)r*DMOD + 256 + tid] = v1*inv;
    g_keyn[(size_t)r*DMOD + 512 + tid] = v2*inv;
}

// ---------------- xq = l2n(mean over patches of emb) ----------------
__global__ void xq_k(){
    int n = blockIdx.x, tid = threadIdx.x;
    __shared__ float xs[DMOD];
    __shared__ float red[256];
    float ss = 0.f;
    for (int d = tid; d < DMOD; d += 256){
        float s = 0.f;
        for (int p = 0; p < PNUM; p++) s += g_h[((size_t)n*TTOK + 4 + p)*DMOD + d];
        s *= (1.f/PNUM);
        xs[d] = s; ss += s*s;
    }
    red[tid] = ss; __syncthreads();
    for (int o = 128; o; o >>= 1){ if (tid < o) red[tid] += red[tid+o]; __syncthreads(); }
    float inv = rsqrtf(fmaxf(red[0], 1e-12f));
    for (int d = tid; d < DMOD; d += 256) g_xq[(size_t)n*DMOD + d] = xs[d]*inv;
}

// ---------------- top-k (k=4) + write prompts into h + reduce_sim ----------------
__global__ void topk_k(){
    int n = blockIdx.x, tid = threadIdx.x;
    __shared__ float bv[256];
    __shared__ int   bi[256];
    __shared__ int   chosen[4];
    float rs = 0.f;
    for (int r = 0; r < 4; r++){
        float best = -1e30f; int besti = 1 << 30;
        for (int j = tid; j < POOLN; j += 256){
            bool skip = false;
            for (int c = 0; c < r; c++) if (chosen[c] == j) skip = true;
            float v = g_sim[(size_t)n*POOLN + j];
            if (!skip && (v > best || (v == best && j < besti))){ best = v; besti = j; }
        }
        bv[tid] = best; bi[tid] = besti; __syncthreads();
        for (int o = 128; o; o >>= 1){
            if (tid < o){
                if (bv[tid+o] > bv[tid] || (bv[tid+o] == bv[tid] && bi[tid+o] < bi[tid])){
                    bv[tid] = bv[tid+o]; bi[tid] = bi[tid+o];
                }
            }
            __syncthreads();
        }
        if (tid == 0){ chosen[r] = bi[0]; rs += bv[0]; }
        __syncthreads();
    }
    for (int e = tid; e < 4*DMOD; e += 256){
        int k = e / DMOD, d = e % DMOD;
        g_h[((size_t)n*TTOK + k)*DMOD + d] = g_keyn[(size_t)chosen[k]*DMOD + d];
    }
    if (tid == 0) atomicAdd(&g_rsim, rs);
}

__global__ void zero_k(){ g_rsim = 0.f; }

// ---------------- add positional embedding ----------------
__global__ void wpe_k(const float* __restrict__ wpe){
    size_t i = (size_t)blockIdx.x*blockDim.x + threadIdx.x;
    if (i < (size_t)NTOK*DMOD){
        int tok = (int)(i / DMOD);
        int t = tok % TTOK;
        int d = (int)(i % DMOD);
        g_h[i] += wpe[(size_t)t*DMOD + d];
    }
}

// ---------------- layernorm (768, 256 threads) ----------------
__global__ void ln_k(const float* __restrict__ x, const float* __restrict__ g,
                     const float* __restrict__ b, float* __restrict__ y){
    int t = blockIdx.x, tid = threadIdx.x;
    const float* xr = x + (size_t)t*DMOD;
    __shared__ float red[256];
    float v0 = xr[tid], v1 = xr[tid+256], v2 = xr[tid+512];
    red[tid] = v0+v1+v2; __syncthreads();
    for (int o = 128; o; o >>= 1){ if (tid < o) red[tid] += red[tid+o]; __syncthreads(); }
    float mu = red[0] * (1.f/DMOD);
    __syncthreads();
    float d0 = v0-mu, d1 = v1-mu, d2 = v2-mu;
    red[tid] = d0*d0 + d1*d1 + d2*d2; __syncthreads();
    for (int o = 128; o; o >>= 1){ if (tid < o) red[tid] += red[tid+o]; __syncthreads(); }
    float inv = rsqrtf(red[0]*(1.f/DMOD) + 1e-5f);
    float* yr = y + (size_t)t*DMOD;
    yr[tid]     = d0*inv*g[tid]     + b[tid];
    yr[tid+256] = d1*inv*g[tid+256] + b[tid+256];
    yr[tid+512] = d2*inv*g[tid+512] + b[tid+512];
}

// ---------------- attention: one block per (series, head) ----------------
__global__ void attn_k(){
    int blk = blockIdx.x;
    int n = blk / 12, head = blk % 12;
    __shared__ float ks[TTOK][65];
    __shared__ float vs[TTOK][65];
    __shared__ float qrow[8][64];
    __shared__ float pb[8][TTOK];
    int tid = threadIdx.x, lane = tid & 31, w = tid >> 5;
    const size_t base = (size_t)n*TTOK*3*DMOD;
    for (int e = tid; e < TTOK*64; e += 256){
        int t = e >> 6, d = e & 63;
        ks[t][d] = g_qkv[base + (size_t)t*3*DMOD + DMOD   + head*64 + d];
        vs[t][d] = g_qkv[base + (size_t)t*3*DMOD + 2*DMOD + head*64 + d];
    }
    __syncthreads();
    for (int i = w; i < TTOK; i += 8){
        qrow[w][lane]    = g_qkv[base + (size_t)i*3*DMOD + head*64 + lane];
        qrow[w][lane+32] = g_qkv[base + (size_t)i*3*DMOD + head*64 + 32 + lane];
        __syncwarp();
        float lmax = -1e30f;
        for (int j = lane; j <= i; j += 32){
            float s = 0.f;
            #pragma unroll 16
            for (int d = 0; d < 64; d++) s = fmaf(qrow[w][d], ks[j][d], s);
            s *= 0.125f;
            pb[w][j] = s;
            lmax = fmaxf(lmax, s);
        }
        for (int o = 16; o; o >>= 1) lmax = fmaxf(lmax, __shfl_xor_sync(0xffffffffu, lmax, o));
        float lsum = 0.f;
        for (int j = lane; j <= i; j += 32){
            float p = expf(pb[w][j] - lmax);
            pb[w][j] = p;
            lsum += p;
        }
        for (int o = 16; o; o >>= 1) lsum += __shfl_xor_sync(0xffffffffu, lsum, o);
        float inv = 1.f/lsum;
        __syncwarp();
        #pragma unroll
        for (int du = 0; du < 2; du++){
            int d = lane + du*32;
            float o = 0.f;
            for (int j = 0; j <= i; j++) o = fmaf(pb[w][j], vs[j][d], o);
            g_ob[((size_t)n*TTOK + i)*DMOD + head*64 + d] = o*inv;
        }
        __syncwarp();
    }
}

// ---------------- denormalize + combine channels ----------------
__global__ void final_k(float* __restrict__ out){
    int n = blockIdx.x, b = n/7, m = n%7;
    for (int t = threadIdx.x; t < PREDL; t += blockDim.x){
        float v = g_ogem[(size_t)(n*3+0)*PREDL + t]
                + g_ogem[(size_t)(n*3+1)*PREDL + t]
                + g_ogem[(size_t)(n*3+2)*PREDL + t];
        out[(size_t)b*PREDL*7 + (size_t)t*7 + m] = v*g_std[n] + g_mean[n];
    }
}

__global__ void rsim_k(float* __restrict__ out, int out_size){
    if (out_size > 64*PREDL*7) out[64*PREDL*7] = g_rsim * (1.f/NSER);
}

// ---------------- host ----------------
template <typename T, size_t S>
static float* symaddr(T (&arr)[S]){ void* p = nullptr; cudaGetSymbolAddress(&p, arr); return (float*)p; }

extern "C" void kernel_launch(void* const* d_in, const int* in_sizes, int n_in,
                              void* d_out, int out_size){
    // itr may or may not be materialized as an input; detect by size of slot 1
    int s = (n_in >= 2 && in_sizes[1] == 1) ? 1 : 0;
    const float* x    = (const float*)d_in[0];
    const float* in_w = (const float*)d_in[1+s];
    const float* in_b = (const float*)d_in[2+s];
    const float* pk   = (const float*)d_in[3+s];
    const float* wpe  = (const float*)d_in[4+s];
    const float* ln1g = (const float*)d_in[5+s];
    const float* ln1b = (const float*)d_in[6+s];
    const float* qkvw = (const float*)d_in[7+s];
    const float* qkvb = (const float*)d_in[8+s];
    const float* aw   = (const float*)d_in[9+s];
    const float* ab   = (const float*)d_in[10+s];
    const float* ln2g = (const float*)d_in[11+s];
    const float* ln2b = (const float*)d_in[12+s];
    const float* fcw  = (const float*)d_in[13+s];
    const float* fcb  = (const float*)d_in[14+s];
    const float* pw   = (const float*)d_in[15+s];
    const float* pbb  = (const float*)d_in[16+s];
    const float* lnfg = (const float*)d_in[17+s];
    const float* lnfb = (const float*)d_in[18+s];
    const float* outw = (const float*)d_in[19+s];
    const float* outb = (const float*)d_in[20+s];
    float* out = (float*)d_out;

    float* p_h    = symaddr(g_h);
    float* p_a    = symaddr(g_a);
    float* p_qkv  = symaddr(g_qkv);
    float* p_ob   = symaddr(g_ob);
    float* p_mlp  = symaddr(g_mlp);
    float* p_tok  = symaddr(g_tok);
    float* p_xq   = symaddr(g_xq);
    float* p_keyn = symaddr(g_keyn);
    float* p_sim  = symaddr(g_sim);
    float* p_og   = symaddr(g_ogem);

    zero_k<<<1,1>>>();
    norm_k<<<NSER,256>>>(x);
    dec_k<<<NSER,256>>>();
    patch_k<<<NSER,256>>>();

    // patch embedding -> h rows 4..67 per series (REMAP)
    gemm_k<false,0,false,true><<<dim3(DMOD/64, NSER*PNUM/64),256>>>(p_tok, in_w, in_b, p_h, NSER*PNUM, DMOD, 48);

    keynorm_k<<<POOLN,256>>>(pk);
    xq_k<<<NSER,256>>>();
    gemm_k<true,0,false,false><<<dim3((POOLN+63)/64, NSER/64),256>>>(p_xq, p_keyn, (const float*)nullptr, p_sim, NSER, POOLN, DMOD);
    topk_k<<<NSER,256>>>();
    wpe_k<<<(unsigned)(((size_t)NTOK*DMOD + 255)/256),256>>>(wpe);

    for (int L = 0; L < NLAYER; L++){
        ln_k<<<NTOK,256>>>(p_h, ln1g + (size_t)L*DMOD, ln1b + (size_t)L*DMOD, p_a);
        gemm_k<false,0,false,false><<<dim3(3*DMOD/64, NTOK/64),256>>>(p_a, qkvw + (size_t)L*DMOD*3*DMOD, qkvb + (size_t)L*3*DMOD, p_qkv, NTOK, 3*DMOD, DMOD);
        attn_k<<<NSER*12,256>>>();
        gemm_k<false,0,true,false><<<dim3(DMOD/64, NTOK/64),256>>>(p_ob, aw + (size_t)L*DMOD*DMOD, ab + (size_t)L*DMOD, p_h, NTOK, DMOD, DMOD);
        ln_k<<<NTOK,256>>>(p_h, ln2g + (size_t)L*DMOD, ln2b + (size_t)L*DMOD, p_a);
        gemm_k<false,1,false,false><<<dim3(4*DMOD/64, NTOK/64),256>>>(p_a, fcw + (size_t)L*DMOD*4*DMOD, fcb + (size_t)L*4*DMOD, p_mlp, NTOK, 4*DMOD, DMOD);
        gemm_k<false,0,true,false><<<dim3(DMOD/64, NTOK/64),256>>>(p_mlp, pw + (size_t)L*4*DMOD*DMOD, pbb + (size_t)L*DMOD, p_h, NTOK, DMOD, 4*DMOD);
    }

    ln_k<<<NTOK,256>>>(p_h, lnfg, lnfb, p_a);
    // output head: rows = 448*3 = 1344, K = 68*256 = 17408, N = 96
    gemm_k<false,0,false,false><<<dim3((PREDL+63)/64, NSER*3/64),256>>>(p_a, outw, outb, p_og, NSER*3, PREDL, TTOK*DMOD/3);
    final_k<<<NSER,96>>>(out);
    rsim_k<<<1,1>>>(out, out_size);
}

// round 2
// speedup vs baseline: 3.0647x; 3.0647x over previous
#include <cuda_runtime.h>
#include <math.h>

#define NSER 448
#define LSEQ 512
#define TTOK 68
#define DMOD 768
#define NTOK (NSER*TTOK)       // 30464
#define PNUM 64
#define POOLN 1000
#define PREDL 96
#define NLAYER 6

// ---------------- scratch (device globals; no allocations) ----------------
__device__ float g_xn  [NSER*LSEQ];
__device__ float g_mean[NSER];
__device__ float g_std [NSER];
__device__ float g_dec [NSER*3*LSEQ];
__device__ float g_tok [NSER*PNUM*48];
__device__ float g_h   [(size_t)NTOK*DMOD];
__device__ float g_a   [(size_t)NTOK*DMOD];
__device__ float g_qkv [(size_t)NTOK*3*DMOD];
__device__ float g_ob  [(size_t)NTOK*DMOD];
__device__ float g_mlp [(size_t)NTOK*4*DMOD];
__device__ float g_xq  [NSER*DMOD];
__device__ float g_keyn[POOLN*DMOD];
__device__ float g_sim [NSER*POOLN];
__device__ float g_ogem[NSER*3*PREDL];
__device__ float g_rsim;

__device__ __forceinline__ float gelu_tanh(float x){
    float c = 0.7978845608028654f;
    float t = tanhf(c*(x + 0.044715f*x*x*x));
    return 0.5f*x*(1.f+t);
}

__device__ __forceinline__ unsigned f2tf(float x){
    unsigned r; asm("cvt.rna.tf32.f32 %0, %1;" : "=r"(r) : "f"(x)); return r;
}

__device__ __forceinline__ void mma8(float* c, const unsigned* a, const unsigned* b){
    asm volatile("mma.sync.aligned.m16n8k8.row.col.f32.tf32.tf32.f32 "
        "{%0,%1,%2,%3}, {%4,%5,%6,%7}, {%8,%9}, {%0,%1,%2,%3};"
        : "+f"(c[0]),"+f"(c[1]),"+f"(c[2]),"+f"(c[3])
        : "r"(a[0]),"r"(a[1]),"r"(a[2]),"r"(a[3]), "r"(b[0]),"r"(b[1]));
}

// ---------------- RevIN stats + normalize ----------------
__global__ void norm_k(const float* __restrict__ x){
    int n = blockIdx.x, b = n/7, m = n%7, tid = threadIdx.x;
    __shared__ float xs[LSEQ];
    __shared__ float red[256];
    for (int l = tid; l < LSEQ; l += 256) xs[l] = x[((size_t)b*LSEQ + l)*7 + m];
    __syncthreads();
    float s = xs[tid] + xs[tid+256];
    red[tid] = s; __syncthreads();
    for (int o = 128; o; o >>= 1){ if (tid < o) red[tid] += red[tid+o]; __syncthreads(); }
    float mu = red[0] * (1.f/LSEQ);
    __syncthreads();
    float d0 = xs[tid]-mu, d1 = xs[tid+256]-mu;
    red[tid] = d0*d0 + d1*d1; __syncthreads();
    for (int o = 128; o; o >>= 1){ if (tid < o) red[tid] += red[tid+o]; __syncthreads(); }
    float sd = sqrtf(red[0]*(1.f/LSEQ) + 1e-5f);
    if (tid == 0){ g_mean[n] = mu; g_std[n] = sd; }
    float inv = 1.f/sd;
    g_xn[n*LSEQ + tid]       = d0*inv;
    g_xn[n*LSEQ + 256 + tid] = d1*inv;
}

// ---------------- trend / seasonal / residual decomposition ----------------
__global__ void dec_k(){
    int n = blockIdx.x, tid = threadIdx.x;
    __shared__ float xs[LSEQ];
    __shared__ float valid[489];
    __shared__ float det[LSEQ];
    __shared__ float ph[24];
    for (int l = tid; l < LSEQ; l += 256) xs[l] = g_xn[n*LSEQ + l];
    if (tid < 24) ph[tid] = 0.f;
    __syncthreads();
    for (int i = tid; i < 489; i += 256){
        float s = 0.f;
        #pragma unroll
        for (int k = 0; k < 24; k++) s += xs[i+k];
        valid[i] = s * (1.f/24.f);
    }
    __syncthreads();
    for (int l = tid; l < LSEQ; l += 256){
        int vi = l - 12; vi = vi < 0 ? 0 : (vi > 488 ? 488 : vi);
        float tr = valid[vi];
        float dt = xs[l] - tr;
        det[l] = dt;
        atomicAdd(&ph[l % 24], dt);
        g_dec[((size_t)n*3 + 0)*LSEQ + l] = tr;
    }
    __syncthreads();
    for (int l = tid; l < LSEQ; l += 256){
        int p = l % 24;
        float cnt = (p < 8) ? 22.f : 21.f;     // 512 = 21*24 + 8
        float se = ph[p] / cnt;
        g_dec[((size_t)n*3 + 1)*LSEQ + l] = se;
        g_dec[((size_t)n*3 + 2)*LSEQ + l] = det[l] - se;
    }
}

// ---------------- patch extraction ----------------
__global__ void patch_k(){
    int n = blockIdx.x, tid = threadIdx.x;
    for (int e = tid; e < PNUM*48; e += 256){
        int p = e/48, rem = e%48, c = rem/16, j = rem%16;
        int l = p*8 + j; if (l > LSEQ-1) l = LSEQ-1;
        g_tok[(size_t)n*PNUM*48 + e] = g_dec[((size_t)n*3 + c)*LSEQ + l];
    }
}

// ---------------- generic fp32 SIMT GEMM (small/precision-critical paths) --
template<bool TRANSB, int ACT, bool RESID, bool REMAP>
__global__ void gemm_k(const float* __restrict__ A, const float* __restrict__ B,
                       const float* __restrict__ bias, float* __restrict__ C,
                       int M, int N, int K){
    __shared__ float As[16][68];
    __shared__ float Bs[16][68];
    int tid = threadIdx.x;
    int tx = tid & 15, ty = tid >> 4;
    int row0 = blockIdx.y * 64, col0 = blockIdx.x * 64;
    float acc[4][4] = {};
    for (int k0 = 0; k0 < K; k0 += 16){
        {
            int r  = tid >> 2;
            int c4 = (tid & 3) * 4;
            float4 v = *reinterpret_cast<const float4*>(&A[(size_t)(row0 + r)*K + k0 + c4]);
            As[c4+0][r] = v.x; As[c4+1][r] = v.y; As[c4+2][r] = v.z; As[c4+3][r] = v.w;
        }
        if (!TRANSB){
            int kk = tid >> 4;
            int c4 = (tid & 15) * 4;
            int col = col0 + c4;
            float4 v = make_float4(0.f,0.f,0.f,0.f);
            if (col < N) v = *reinterpret_cast<const float4*>(&B[(size_t)(k0+kk)*N + col]);
            Bs[kk][c4+0] = v.x; Bs[kk][c4+1] = v.y; Bs[kk][c4+2] = v.z; Bs[kk][c4+3] = v.w;
        } else {
            int nn = tid >> 2;
            int c4 = (tid & 3) * 4;
            int col = col0 + nn;
            float4 v = make_float4(0.f,0.f,0.f,0.f);
            if (col < N) v = *reinterpret_cast<const float4*>(&B[(size_t)col*K + k0 + c4]);
            Bs[c4+0][nn] = v.x; Bs[c4+1][nn] = v.y; Bs[c4+2][nn] = v.z; Bs[c4+3][nn] = v.w;
        }
        __syncthreads();
        #pragma unroll
        for (int kk = 0; kk < 16; kk++){
            float a[4], b[4];
            #pragma unroll
            for (int i = 0; i < 4; i++) a[i] = As[kk][ty*4+i];
            #pragma unroll
            for (int j = 0; j < 4; j++) b[j] = Bs[kk][tx*4+j];
            #pragma unroll
            for (int i = 0; i < 4; i++)
                #pragma unroll
                for (int j = 0; j < 4; j++) acc[i][j] = fmaf(a[i], b[j], acc[i][j]);
        }
        __syncthreads();
    }
    #pragma unroll
    for (int i = 0; i < 4; i++){
        int r = row0 + ty*4 + i;
        size_t orow = REMAP ? (size_t)((r >> 6)*TTOK + 4 + (r & 63)) : (size_t)r;
        #pragma unroll
        for (int j = 0; j < 4; j++){
            int col = col0 + tx*4 + j;
            if (col < N){
                float v = acc[i][j];
                if (bias) v += bias[col];
                if (ACT == 1) v = gelu_tanh(v);
                size_t idx = orow*(size_t)N + col;
                if (RESID) C[idx] += v; else C[idx] = v;
            }
        }
    }
}

// ---------------- tf32 tensor-core GEMM: C[M,N] = A[M,K]@B[K,N] (+bias,act,resid)
// 128x128 block tile, K-tile 32, 8 warps (2x4), warp tile 64x32. K%32==0 required.
template<int ACT, bool RESID>
__global__ __launch_bounds__(256, 2) void tgemm_k(
        const float* __restrict__ A, const float* __restrict__ B,
        const float* __restrict__ bias, float* __restrict__ C,
        int M, int N, int K){
    __shared__ unsigned As[128][36];   // [m][k], pad 36 -> conflict-free frag loads
    __shared__ unsigned Bs[32][136];   // [k][n], pad 136
    int tid = threadIdx.x;
    int warp = tid >> 5, lane = tid & 31;
    int wm = warp >> 2, wn = warp & 3;     // warps: 2 (m) x 4 (n)
    int g = lane >> 2, tg = lane & 3;
    int row0 = blockIdx.y * 128, col0 = blockIdx.x * 128;

    float acc[4][4][4];
    #pragma unroll
    for (int i=0;i<4;i++) for (int j=0;j<4;j++) for (int q=0;q<4;q++) acc[i][j][q]=0.f;

    float4 pa[4], pb[4];

    // prefetch helpers: 1024 float4 per tile / 256 threads = 4 each
    #define LOAD_A(k0) { \
        _Pragma("unroll") \
        for (int i=0;i<4;i++){ \
            int idx = tid + i*256; int r = idx>>3, ch=(idx&7)<<2; \
            int grow = row0 + r; \
            float4 v = make_float4(0.f,0.f,0.f,0.f); \
            if (grow < M) v = *reinterpret_cast<const float4*>(&A[(size_t)grow*K + (k0) + ch]); \
            pa[i]=v; } }
    #define LOAD_B(k0) { \
        _Pragma("unroll") \
        for (int i=0;i<4;i++){ \
            int idx = tid + i*256; int kk = idx>>5, c4=(idx&31)<<2; \
            int gcol = col0 + c4; \
            float4 v = make_float4(0.f,0.f,0.f,0.f); \
            if (gcol < N) v = *reinterpret_cast<const float4*>(&B[(size_t)((k0)+kk)*N + gcol]); \
            pb[i]=v; } }
    #define STORE_AB() { \
        _Pragma("unroll") \
        for (int i=0;i<4;i++){ \
            int idx = tid + i*256; int r = idx>>3, ch=(idx&7)<<2; \
            As[r][ch]=f2tf(pa[i].x); As[r][ch+1]=f2tf(pa[i].y); \
            As[r][ch+2]=f2tf(pa[i].z); As[r][ch+3]=f2tf(pa[i].w); } \
        _Pragma("unroll") \
        for (int i=0;i<4;i++){ \
            int idx = tid + i*256; int kk = idx>>5, c4=(idx&31)<<2; \
            Bs[kk][c4]=f2tf(pb[i].x); Bs[kk][c4+1]=f2tf(pb[i].y); \
            Bs[kk][c4+2]=f2tf(pb[i].z); Bs[kk][c4+3]=f2tf(pb[i].w); } }

    LOAD_A(0); LOAD_B(0);
    STORE_AB();
    __syncthreads();

    int ntiles = K >> 5;
    for (int kt = 0; kt < ntiles; kt++){
        if (kt + 1 < ntiles){ LOAD_A((kt+1)*32); LOAD_B((kt+1)*32); }
        #pragma unroll
        for (int ks = 0; ks < 32; ks += 8){
            unsigned af[4][4], bf[4][2];
            #pragma unroll
            for (int mt = 0; mt < 4; mt++){
                int r = wm*64 + mt*16 + g;
                af[mt][0] = As[r][ks+tg];
                af[mt][1] = As[r+8][ks+tg];
                af[mt][2] = As[r][ks+tg+4];
                af[mt][3] = As[r+8][ks+tg+4];
            }
            #pragma unroll
            for (int nt = 0; nt < 4; nt++){
                int c = wn*32 + nt*8 + g;
                bf[nt][0] = Bs[ks+tg][c];
                bf[nt][1] = Bs[ks+tg+4][c];
            }
            #pragma unroll
            for (int mt = 0; mt < 4; mt++)
                #pragma unroll
                for (int nt = 0; nt < 4; nt++)
                    mma8(acc[mt][nt], af[mt], bf[nt]);
        }
        __syncthreads();
        if (kt + 1 < ntiles){ STORE_AB(); __syncthreads(); }
    }

    #pragma unroll
    for (int mt = 0; mt < 4; mt++){
        int rbase = row0 + wm*64 + mt*16;
        #pragma unroll
        for (int nt = 0; nt < 4; nt++){
            int cbase = col0 + wn*32 + nt*8 + tg*2;
            #pragma unroll
            for (int half = 0; half < 2; half++){
                int rr = rbase + g + half*8;
                if (rr < M){
                    #pragma unroll
                    for (int jj = 0; jj < 2; jj++){
                        int cc = cbase + jj;
                        if (cc < N){
                            float v = acc[mt][nt][half*2+jj];
                            if (bias) v += bias[cc];
                            if (ACT == 1) v = gelu_tanh(v);
                            size_t idx = (size_t)rr*N + cc;
                            if (RESID) C[idx] += v; else C[idx] = v;
                        }
                    }
                }
            }
        }
    }
    #undef LOAD_A
    #undef LOAD_B
    #undef STORE_AB
}

// ---------------- l2-normalize prompt keys ----------------
__global__ void keynorm_k(const float* __restrict__ pk){
    int r = blockIdx.x, tid = threadIdx.x;
    __shared__ float red[256];
    float v0 = pk[(size_t)r*DMOD + tid], v1 = pk[(size_t)r*DMOD + 256 + tid], v2 = pk[(size_t)r*DMOD + 512 + tid];
    red[tid] = v0*v0 + v1*v1 + v2*v2; __syncthreads();
    for (int o = 128; o; o >>= 1){ if (tid < o) red[tid] += red[tid+o]; __syncthreads(); }
    float inv = rsqrtf(fmaxf(red[0], 1e-12f));
    g_keyn[(size_t)r*DMOD + tid]       = v0*inv;
    g_keyn[(size_t)r*DMOD + 256 + tid] = v1*inv;
    g_keyn[(size_t)r*DMOD + 512 + tid] = v2*inv;
}

// ---------------- xq = l2n(mean over patches of emb) ----------------
__global__ void xq_k(){
    int n = blockIdx.x, tid = threadIdx.x;
    __shared__ float xs[DMOD];
    __shared__ float red[256];
    float ss = 0.f;
    for (int d = tid; d < DMOD; d += 256){
        float s = 0.f;
        for (int p = 0; p < PNUM; p++) s += g_h[((size_t)n*TTOK + 4 + p)*DMOD + d];
        s *= (1.f/PNUM);
        xs[d] = s; ss += s*s;
    }
    red[tid] = ss; __syncthreads();
    for (int o = 128; o; o >>= 1){ if (tid < o) red[tid] += red[tid+o]; __syncthreads(); }
    float inv = rsqrtf(fmaxf(red[0], 1e-12f));
    for (int d = tid; d < DMOD; d += 256) g_xq[(size_t)n*DMOD + d] = xs[d]*inv;
}

// ---------------- top-k (k=4) + write prompts into h + reduce_sim ----------------
__global__ void topk_k(){
    int n = blockIdx.x, tid = threadIdx.x;
    __shared__ float bv[256];
    __shared__ int   bi[256];
    __shared__ int   chosen[4];
    float rs = 0.f;
    for (int r = 0; r < 4; r++){
        float best = -1e30f; int besti = 1 << 30;
        for (int j = tid; j < POOLN; j += 256){
            bool skip = false;
            for (int c = 0; c < r; c++) if (chosen[c] == j) skip = true;
            float v = g_sim[(size_t)n*POOLN + j];
            if (!skip && (v > best || (v == best && j < besti))){ best = v; besti = j; }
        }
        bv[tid] = best; bi[tid] = besti; __syncthreads();
        for (int o = 128; o; o >>= 1){
            if (tid < o){
                if (bv[tid+o] > bv[tid] || (bv[tid+o] == bv[tid] && bi[tid+o] < bi[tid])){
                    bv[tid] = bv[tid+o]; bi[tid] = bi[tid+o];
                }
            }
            __syncthreads();
        }
        if (tid == 0){ chosen[r] = bi[0]; rs += bv[0]; }
        __syncthreads();
    }
    for (int e = tid; e < 4*DMOD; e += 256){
        int k = e / DMOD, d = e % DMOD;
        g_h[((size_t)n*TTOK + k)*DMOD + d] = g_keyn[(size_t)chosen[k]*DMOD + d];
    }
    if (tid == 0) atomicAdd(&g_rsim, rs);
}

__global__ void zero_k(){ g_rsim = 0.f; }

// ---------------- add positional embedding ----------------
__global__ void wpe_k(const float* __restrict__ wpe){
    size_t i = (size_t)blockIdx.x*blockDim.x + threadIdx.x;
    if (i < (size_t)NTOK*DMOD){
        int tok = (int)(i / DMOD);
        int t = tok % TTOK;
        int d = (int)(i % DMOD);
        g_h[i] += wpe[(size_t)t*DMOD + d];
    }
}

// ---------------- layernorm ----------------
__global__ void ln_k(const float* __restrict__ x, const float* __restrict__ g,
                     const float* __restrict__ b, float* __restrict__ y){
    int t = blockIdx.x, tid = threadIdx.x;
    const float* xr = x + (size_t)t*DMOD;
    __shared__ float red[256];
    float v0 = xr[tid], v1 = xr[tid+256], v2 = xr[tid+512];
    red[tid] = v0+v1+v2; __syncthreads();
    for (int o = 128; o; o >>= 1){ if (tid < o) red[tid] += red[tid+o]; __syncthreads(); }
    float mu = red[0] * (1.f/DMOD);
    __syncthreads();
    float d0 = v0-mu, d1 = v1-mu, d2 = v2-mu;
    red[tid] = d0*d0 + d1*d1 + d2*d2; __syncthreads();
    for (int o = 128; o; o >>= 1){ if (tid < o) red[tid] += red[tid+o]; __syncthreads(); }
    float inv = rsqrtf(red[0]*(1.f/DMOD) + 1e-5f);
    float* yr = y + (size_t)t*DMOD;
    yr[tid]     = d0*inv*g[tid]     + b[tid];
    yr[tid+256] = d1*inv*g[tid+256] + b[tid+256];
    yr[tid+512] = d2*inv*g[tid+512] + b[tid+512];
}

// ---------------- attention: one block per (series, head) ----------------
__global__ void attn_k(){
    int blk = blockIdx.x;
    int n = blk / 12, head = blk % 12;
    __shared__ float ks[TTOK][65];
    __shared__ float vs[TTOK][65];
    __shared__ float qrow[8][64];
    __shared__ float pb[8][TTOK];
    int tid = threadIdx.x, lane = tid & 31, w = tid >> 5;
    const size_t base = (size_t)n*TTOK*3*DMOD;
    for (int e = tid; e < TTOK*64; e += 256){
        int t = e >> 6, d = e & 63;
        ks[t][d] = g_qkv[base + (size_t)t*3*DMOD + DMOD   + head*64 + d];
        vs[t][d] = g_qkv[base + (size_t)t*3*DMOD + 2*DMOD + head*64 + d];
    }
    __syncthreads();
    for (int i = w; i < TTOK; i += 8){
        qrow[w][lane]    = g_qkv[base + (size_t)i*3*DMOD + head*64 + lane];
        qrow[w][lane+32] = g_qkv[base + (size_t)i*3*DMOD + head*64 + 32 + lane];
        __syncwarp();
        float lmax = -1e30f;
        for (int j = lane; j <= i; j += 32){
            float s = 0.f;
            #pragma unroll 16
            for (int d = 0; d < 64; d++) s = fmaf(qrow[w][d], ks[j][d], s);
            s *= 0.125f;
            pb[w][j] = s;
            lmax = fmaxf(lmax, s);
        }
        for (int o = 16; o; o >>= 1) lmax = fmaxf(lmax, __shfl_xor_sync(0xffffffffu, lmax, o));
        float lsum = 0.f;
        for (int j = lane; j <= i; j += 32){
            float p = expf(pb[w][j] - lmax);
            pb[w][j] = p;
            lsum += p;
        }
        for (int o = 16; o; o >>= 1) lsum += __shfl_xor_sync(0xffffffffu, lsum, o);
        float inv = 1.f/lsum;
        __syncwarp();
        #pragma unroll
        for (int du = 0; du < 2; du++){
            int d = lane + du*32;
            float o = 0.f;
            for (int j = 0; j <= i; j++) o = fmaf(pb[w][j], vs[j][d], o);
            g_ob[((size_t)n*TTOK + i)*DMOD + head*64 + d] = o*inv;
        }
        __syncwarp();
    }
}

// ---------------- denormalize + combine channels ----------------
__global__ void final_k(float* __restrict__ out){
    int n = blockIdx.x, b = n/7, m = n%7;
    for (int t = threadIdx.x; t < PREDL; t += blockDim.x){
        float v = g_ogem[(size_t)(n*3+0)*PREDL + t]
                + g_ogem[(size_t)(n*3+1)*PREDL + t]
                + g_ogem[(size_t)(n*3+2)*PREDL + t];
        out[(size_t)b*PREDL*7 + (size_t)t*7 + m] = v*g_std[n] + g_mean[n];
    }
}

__global__ void rsim_k(float* __restrict__ out, int out_size){
    if (out_size > 64*PREDL*7) out[64*PREDL*7] = g_rsim * (1.f/NSER);
}

// ---------------- host ----------------
template <typename T, size_t S>
static float* symaddr(T (&arr)[S]){ void* p = nullptr; cudaGetSymbolAddress(&p, arr); return (float*)p; }

extern "C" void kernel_launch(void* const* d_in, const int* in_sizes, int n_in,
                              void* d_out, int out_size){
    int s = (n_in >= 2 && in_sizes[1] == 1) ? 1 : 0;
    const float* x    = (const float*)d_in[0];
    const float* in_w = (const float*)d_in[1+s];
    const float* in_b = (const float*)d_in[2+s];
    const float* pk   = (const float*)d_in[3+s];
    const float* wpe  = (const float*)d_in[4+s];
    const float* ln1g = (const float*)d_in[5+s];
    const float* ln1b = (const float*)d_in[6+s];
    const float* qkvw = (const float*)d_in[7+s];
    const float* qkvb = (const float*)d_in[8+s];
    const float* aw   = (const float*)d_in[9+s];
    const float* ab   = (const float*)d_in[10+s];
    const float* ln2g = (const float*)d_in[11+s];
    const float* ln2b = (const float*)d_in[12+s];
    const float* fcw  = (const float*)d_in[13+s];
    const float* fcb  = (const float*)d_in[14+s];
    const float* pw   = (const float*)d_in[15+s];
    const float* pbb  = (const float*)d_in[16+s];
    const float* lnfg = (const float*)d_in[17+s];
    const float* lnfb = (const float*)d_in[18+s];
    const float* outw = (const float*)d_in[19+s];
    const float* outb = (const float*)d_in[20+s];
    float* out = (float*)d_out;

    float* p_h    = symaddr(g_h);
    float* p_a    = symaddr(g_a);
    float* p_qkv  = symaddr(g_qkv);
    float* p_ob   = symaddr(g_ob);
    float* p_mlp  = symaddr(g_mlp);
    float* p_tok  = symaddr(g_tok);
    float* p_xq   = symaddr(g_xq);
    float* p_keyn = symaddr(g_keyn);
    float* p_sim  = symaddr(g_sim);
    float* p_og   = symaddr(g_ogem);

    zero_k<<<1,1>>>();
    norm_k<<<NSER,256>>>(x);
    dec_k<<<NSER,256>>>();
    patch_k<<<NSER,256>>>();

    // patch embedding (fp32 exact: feeds top-k selection) -> h rows 4..67 (REMAP)
    gemm_k<false,0,false,true><<<dim3(DMOD/64, NSER*PNUM/64),256>>>(p_tok, in_w, in_b, p_h, NSER*PNUM, DMOD, 48);

    keynorm_k<<<POOLN,256>>>(pk);
    xq_k<<<NSER,256>>>();
    gemm_k<true,0,false,false><<<dim3((POOLN+63)/64, NSER/64),256>>>(p_xq, p_keyn, (const float*)nullptr, p_sim, NSER, POOLN, DMOD);
    topk_k<<<NSER,256>>>();
    wpe_k<<<(unsigned)(((size_t)NTOK*DMOD + 255)/256),256>>>(wpe);

    const int MB = NTOK/128;   // 238
    for (int L = 0; L < NLAYER; L++){
        ln_k<<<NTOK,256>>>(p_h, ln1g + (size_t)L*DMOD, ln1b + (size_t)L*DMOD, p_a);
        tgemm_k<0,false><<<dim3(3*DMOD/128, MB),256>>>(p_a, qkvw + (size_t)L*DMOD*3*DMOD, qkvb + (size_t)L*3*DMOD, p_qkv, NTOK, 3*DMOD, DMOD);
        attn_k<<<NSER*12,256>>>();
        tgemm_k<0,true ><<<dim3(DMOD/128, MB),256>>>(p_ob, aw + (size_t)L*DMOD*DMOD, ab + (size_t)L*DMOD, p_h, NTOK, DMOD, DMOD);
        ln_k<<<NTOK,256>>>(p_h, ln2g + (size_t)L*DMOD, ln2b + (size_t)L*DMOD, p_a);
        tgemm_k<1,false><<<dim3(4*DMOD/128, MB),256>>>(p_a, fcw + (size_t)L*DMOD*4*DMOD, fcb + (size_t)L*4*DMOD, p_mlp, NTOK, 4*DMOD, DMOD);
        tgemm_k<0,true ><<<dim3(DMOD/128, MB),256>>>(p_mlp, pw + (size_t)L*4*DMOD*DMOD, pbb + (size_t)L*DMOD, p_h, NTOK, DMOD, 4*DMOD);
    }

    ln_k<<<NTOK,256>>>(p_h, lnfg, lnfb, p_a);
    // output head: M=1344, N=96, K=17408 (K%32==0)
    tgemm_k<0,false><<<dim3(1, (NSER*3+127)/128),256>>>(p_a, outw, outb, p_og, NSER*3, PREDL, TTOK*DMOD/3);
    final_k<<<NSER,96>>>(out);
    rsim_k<<<1,1>>>(out, out_size);
}

// round 3
// speedup vs baseline: 3.4467x; 1.1246x over previous
#include <cuda_runtime.h>
#include <math.h>

#define NSER 448
#define LSEQ 512
#define TTOK 68
#define DMOD 768
#define NTOK (NSER*TTOK)       // 30464
#define PNUM 64
#define POOLN 1000
#define PREDL 96
#define NLAYER 6
#define SPLITZ 16

// ---------------- scratch (device globals; no allocations) ----------------
__device__ float g_xn  [NSER*LSEQ];
__device__ float g_mean[NSER];
__device__ float g_std [NSER];
__device__ float g_dec [NSER*3*LSEQ];
__device__ float g_tok [NSER*PNUM*48];
__device__ float g_h   [(size_t)NTOK*DMOD];
__device__ float g_a   [(size_t)NTOK*DMOD];
__device__ float g_qkv [(size_t)NTOK*3*DMOD];
__device__ float g_ob  [(size_t)NTOK*DMOD];
__device__ float g_mlp [(size_t)NTOK*4*DMOD];
__device__ float g_xq  [NSER*DMOD];
__device__ float g_keyn[POOLN*DMOD];
__device__ float g_sim [NSER*POOLN];
__device__ float g_osp [(size_t)SPLITZ*NSER*3*PREDL];
__device__ float g_rsim;

__device__ __forceinline__ float gelu_tanh(float x){
    float c = 0.7978845608028654f;
    float t = tanhf(c*(x + 0.044715f*x*x*x));
    return 0.5f*x*(1.f+t);
}

__device__ __forceinline__ unsigned f2tf(float x){
    unsigned r; asm("cvt.rna.tf32.f32 %0, %1;" : "=r"(r) : "f"(x)); return r;
}

__device__ __forceinline__ void mma8(float* c, const unsigned* a, const unsigned* b){
    asm volatile("mma.sync.aligned.m16n8k8.row.col.f32.tf32.tf32.f32 "
        "{%0,%1,%2,%3}, {%4,%5,%6,%7}, {%8,%9}, {%0,%1,%2,%3};"
        : "+f"(c[0]),"+f"(c[1]),"+f"(c[2]),"+f"(c[3])
        : "r"(a[0]),"r"(a[1]),"r"(a[2]),"r"(a[3]), "r"(b[0]),"r"(b[1]));
}

__device__ __forceinline__ void cpasync16(float* dst, const float* src, bool pred){
    unsigned sa = (unsigned)__cvta_generic_to_shared(dst);
    int sz = pred ? 16 : 0;
    asm volatile("cp.async.cg.shared.global [%0], [%1], 16, %2;" :: "r"(sa), "l"(src), "r"(sz));
}
__device__ __forceinline__ void cp_commit(){ asm volatile("cp.async.commit_group;"); }
template<int N> __device__ __forceinline__ void cp_wait(){ asm volatile("cp.async.wait_group %0;"::"n"(N)); }

// ---------------- RevIN stats + normalize ----------------
__global__ void norm_k(const float* __restrict__ x){
    int n = blockIdx.x, b = n/7, m = n%7, tid = threadIdx.x;
    __shared__ float xs[LSEQ];
    __shared__ float red[256];
    for (int l = tid; l < LSEQ; l += 256) xs[l] = x[((size_t)b*LSEQ + l)*7 + m];
    __syncthreads();
    float s = xs[tid] + xs[tid+256];
    red[tid] = s; __syncthreads();
    for (int o = 128; o; o >>= 1){ if (tid < o) red[tid] += red[tid+o]; __syncthreads(); }
    float mu = red[0] * (1.f/LSEQ);
    __syncthreads();
    float d0 = xs[tid]-mu, d1 = xs[tid+256]-mu;
    red[tid] = d0*d0 + d1*d1; __syncthreads();
    for (int o = 128; o; o >>= 1){ if (tid < o) red[tid] += red[tid+o]; __syncthreads(); }
    float sd = sqrtf(red[0]*(1.f/LSEQ) + 1e-5f);
    if (tid == 0){ g_mean[n] = mu; g_std[n] = sd; }
    float inv = 1.f/sd;
    g_xn[n*LSEQ + tid]       = d0*inv;
    g_xn[n*LSEQ + 256 + tid] = d1*inv;
}

// ---------------- decomposition ----------------
__global__ void dec_k(){
    int n = blockIdx.x, tid = threadIdx.x;
    __shared__ float xs[LSEQ];
    __shared__ float valid[489];
    __shared__ float det[LSEQ];
    __shared__ float ph[24];
    for (int l = tid; l < LSEQ; l += 256) xs[l] = g_xn[n*LSEQ + l];
    if (tid < 24) ph[tid] = 0.f;
    __syncthreads();
    for (int i = tid; i < 489; i += 256){
        float s = 0.f;
        #pragma unroll
        for (int k = 0; k < 24; k++) s += xs[i+k];
        valid[i] = s * (1.f/24.f);
    }
    __syncthreads();
    for (int l = tid; l < LSEQ; l += 256){
        int vi = l - 12; vi = vi < 0 ? 0 : (vi > 488 ? 488 : vi);
        float tr = valid[vi];
        float dt = xs[l] - tr;
        det[l] = dt;
        atomicAdd(&ph[l % 24], dt);
        g_dec[((size_t)n*3 + 0)*LSEQ + l] = tr;
    }
    __syncthreads();
    for (int l = tid; l < LSEQ; l += 256){
        int p = l % 24;
        float cnt = (p < 8) ? 22.f : 21.f;
        float se = ph[p] / cnt;
        g_dec[((size_t)n*3 + 1)*LSEQ + l] = se;
        g_dec[((size_t)n*3 + 2)*LSEQ + l] = det[l] - se;
    }
}

// ---------------- patch extraction ----------------
__global__ void patch_k(){
    int n = blockIdx.x, tid = threadIdx.x;
    for (int e = tid; e < PNUM*48; e += 256){
        int p = e/48, rem = e%48, c = rem/16, j = rem%16;
        int l = p*8 + j; if (l > LSEQ-1) l = LSEQ-1;
        g_tok[(size_t)n*PNUM*48 + e] = g_dec[((size_t)n*3 + c)*LSEQ + l];
    }
}

// ---------------- generic fp32 SIMT GEMM (precision-critical small paths) --
template<bool TRANSB, int ACT, bool RESID, bool REMAP>
__global__ void gemm_k(const float* __restrict__ A, const float* __restrict__ B,
                       const float* __restrict__ bias, float* __restrict__ C,
                       int M, int N, int K){
    __shared__ float As[16][68];
    __shared__ float Bs[16][68];
    int tid = threadIdx.x;
    int tx = tid & 15, ty = tid >> 4;
    int row0 = blockIdx.y * 64, col0 = blockIdx.x * 64;
    float acc[4][4] = {};
    for (int k0 = 0; k0 < K; k0 += 16){
        {
            int r  = tid >> 2;
            int c4 = (tid & 3) * 4;
            float4 v = *reinterpret_cast<const float4*>(&A[(size_t)(row0 + r)*K + k0 + c4]);
            As[c4+0][r] = v.x; As[c4+1][r] = v.y; As[c4+2][r] = v.z; As[c4+3][r] = v.w;
        }
        if (!TRANSB){
            int kk = tid >> 4;
            int c4 = (tid & 15) * 4;
            int col = col0 + c4;
            float4 v = make_float4(0.f,0.f,0.f,0.f);
            if (col < N) v = *reinterpret_cast<const float4*>(&B[(size_t)(k0+kk)*N + col]);
            Bs[kk][c4+0] = v.x; Bs[kk][c4+1] = v.y; Bs[kk][c4+2] = v.z; Bs[kk][c4+3] = v.w;
        } else {
            int nn = tid >> 2;
            int c4 = (tid & 3) * 4;
            int col = col0 + nn;
            float4 v = make_float4(0.f,0.f,0.f,0.f);
            if (col < N) v = *reinterpret_cast<const float4*>(&B[(size_t)col*K + k0 + c4]);
            Bs[c4+0][nn] = v.x; Bs[c4+1][nn] = v.y; Bs[c4+2][nn] = v.z; Bs[c4+3][nn] = v.w;
        }
        __syncthreads();
        #pragma unroll
        for (int kk = 0; kk < 16; kk++){
            float a[4], b[4];
            #pragma unroll
            for (int i = 0; i < 4; i++) a[i] = As[kk][ty*4+i];
            #pragma unroll
            for (int j = 0; j < 4; j++) b[j] = Bs[kk][tx*4+j];
            #pragma unroll
            for (int i = 0; i < 4; i++)
                #pragma unroll
                for (int j = 0; j < 4; j++) acc[i][j] = fmaf(a[i], b[j], acc[i][j]);
        }
        __syncthreads();
    }
    #pragma unroll
    for (int i = 0; i < 4; i++){
        int r = row0 + ty*4 + i;
        size_t orow = REMAP ? (size_t)((r >> 6)*TTOK + 4 + (r & 63)) : (size_t)r;
        #pragma unroll
        for (int j = 0; j < 4; j++){
            int col = col0 + tx*4 + j;
            if (col < N){
                float v = acc[i][j];
                if (bias) v += bias[col];
                if (ACT == 1) v = gelu_tanh(v);
                size_t idx = orow*(size_t)N + col;
                if (RESID) C[idx] += v; else C[idx] = v;
            }
        }
    }
}

// ---------------- tf32 tensor-core GEMM, cp.async 3-stage pipeline --------
// C[M,N] = A[M,K]@B[K,N]. 128x128 tile, K-tile 32, 8 warps (2x4).
// SPLITK: grid.z chunks, each writes C + z*M*N (no bias/resid there).
#define AS_ST 36
#define BS_ST 136
#define A_STAGE (128*AS_ST)      // 4608 floats
#define B_STAGE (32*BS_ST)       // 4352 floats
#define SM_FLOATS (3*(A_STAGE+B_STAGE))   // 26880 -> 107520 bytes

template<int ACT, bool RESID, bool SPLITK>
__global__ __launch_bounds__(256, 2) void tgemm_k(
        const float* __restrict__ A, const float* __restrict__ B,
        const float* __restrict__ bias, float* __restrict__ C,
        int M, int N, int K){
    extern __shared__ float sm[];
    float* smA = sm;                       // 3 stages of [128][36]
    float* smB = sm + 3*A_STAGE;           // 3 stages of [32][136]
    int tid = threadIdx.x;
    int warp = tid >> 5, lane = tid & 31;
    int wm = warp >> 2, wn = warp & 3;
    int g = lane >> 2, tg = lane & 3;
    int row0 = blockIdx.y * 128, col0 = blockIdx.x * 128;

    int Kc   = SPLITK ? (K / gridDim.z) : K;
    int kbeg = SPLITK ? blockIdx.z * Kc : 0;
    int nt   = Kc >> 5;

    float acc[4][4][4];
    #pragma unroll
    for (int i=0;i<4;i++) for (int j=0;j<4;j++) for (int q=0;q<4;q++) acc[i][j][q]=0.f;

    // per-thread copy coordinates (4 chunks of 16B for A, 4 for B)
    #define ISSUE_TILE(T, S) { \
        int k0 = kbeg + (T)*32; \
        float* as = smA + (S)*A_STAGE; \
        float* bs = smB + (S)*B_STAGE; \
        _Pragma("unroll") \
        for (int i=0;i<4;i++){ \
            int idx = tid + i*256; int r = idx>>3; int ch=(idx&7)<<2; \
            int grow = row0 + r; bool p = grow < M; int gr = p ? grow : (M-1); \
            cpasync16(&as[r*AS_ST + ch], &A[(size_t)gr*K + k0 + ch], p); \
        } \
        _Pragma("unroll") \
        for (int i=0;i<4;i++){ \
            int idx = tid + i*256; int kk = idx>>5; int c4=(idx&31)<<2; \
            int gcol = col0 + c4; bool p = gcol < N; int gc = p ? gcol : 0; \
            cpasync16(&bs[kk*BS_ST + c4], &B[(size_t)(k0+kk)*N + gc], p); \
        } \
        cp_commit(); }

    ISSUE_TILE(0, 0);
    ISSUE_TILE(1, 1);

    int stage = 0;
    for (int kt = 0; kt < nt; kt++){
        if (kt == nt-1) cp_wait<0>(); else cp_wait<1>();
        __syncthreads();
        if (kt + 2 < nt){
            int s2 = stage + 2; if (s2 >= 3) s2 -= 3;
            ISSUE_TILE(kt+2, s2);
        }
        const float* as = smA + stage*A_STAGE;
        const float* bs = smB + stage*B_STAGE;
        #pragma unroll
        for (int ks = 0; ks < 32; ks += 8){
            unsigned af[4][4], bf[4][2];
            #pragma unroll
            for (int mt = 0; mt < 4; mt++){
                int r = wm*64 + mt*16 + g;
                af[mt][0] = f2tf(as[r*AS_ST + ks+tg]);
                af[mt][1] = f2tf(as[(r+8)*AS_ST + ks+tg]);
                af[mt][2] = f2tf(as[r*AS_ST + ks+tg+4]);
                af[mt][3] = f2tf(as[(r+8)*AS_ST + ks+tg+4]);
            }
            #pragma unroll
            for (int nt2 = 0; nt2 < 4; nt2++){
                int c = wn*32 + nt2*8 + g;
                bf[nt2][0] = f2tf(bs[(ks+tg)*BS_ST + c]);
                bf[nt2][1] = f2tf(bs[(ks+tg+4)*BS_ST + c]);
            }
            #pragma unroll
            for (int mt = 0; mt < 4; mt++)
                #pragma unroll
                for (int nt2 = 0; nt2 < 4; nt2++)
                    mma8(acc[mt][nt2], af[mt], bf[nt2]);
        }
        stage++; if (stage >= 3) stage -= 3;
    }
    #undef ISSUE_TILE

    float* Cout = SPLITK ? (C + (size_t)blockIdx.z*M*N) : C;
    #pragma unroll
    for (int mt = 0; mt < 4; mt++){
        int rbase = row0 + wm*64 + mt*16;
        #pragma unroll
        for (int nt2 = 0; nt2 < 4; nt2++){
            int cbase = col0 + wn*32 + nt2*8 + tg*2;
            #pragma unroll
            for (int half = 0; half < 2; half++){
                int rr = rbase + g + half*8;
                if (rr < M){
                    #pragma unroll
                    for (int jj = 0; jj < 2; jj++){
                        int cc = cbase + jj;
                        if (cc < N){
                            float v = acc[mt][nt2][half*2+jj];
                            if (!SPLITK){
                                if (bias) v += bias[cc];
                                if (ACT == 1) v = gelu_tanh(v);
                            }
                            size_t idx = (size_t)rr*N + cc;
                            if (RESID) Cout[idx] += v; else Cout[idx] = v;
                        }
                    }
                }
            }
        }
    }
}

// ---------------- l2-normalize prompt keys ----------------
__global__ void keynorm_k(const float* __restrict__ pk){
    int r = blockIdx.x, tid = threadIdx.x;
    __shared__ float red[256];
    float v0 = pk[(size_t)r*DMOD + tid], v1 = pk[(size_t)r*DMOD + 256 + tid], v2 = pk[(size_t)r*DMOD + 512 + tid];
    red[tid] = v0*v0 + v1*v1 + v2*v2; __syncthreads();
    for (int o = 128; o; o >>= 1){ if (tid < o) red[tid] += red[tid+o]; __syncthreads(); }
    float inv = rsqrtf(fmaxf(red[0], 1e-12f));
    g_keyn[(size_t)r*DMOD + tid]       = v0*inv;
    g_keyn[(size_t)r*DMOD + 256 + tid] = v1*inv;
    g_keyn[(size_t)r*DMOD + 512 + tid] = v2*inv;
}

// ---------------- xq ----------------
__global__ void xq_k(){
    int n = blockIdx.x, tid = threadIdx.x;
    __shared__ float xs[DMOD];
    __shared__ float red[256];
    float ss = 0.f;
    for (int d = tid; d < DMOD; d += 256){
        float s = 0.f;
        for (int p = 0; p < PNUM; p++) s += g_h[((size_t)n*TTOK + 4 + p)*DMOD + d];
        s *= (1.f/PNUM);
        xs[d] = s; ss += s*s;
    }
    red[tid] = ss; __syncthreads();
    for (int o = 128; o; o >>= 1){ if (tid < o) red[tid] += red[tid+o]; __syncthreads(); }
    float inv = rsqrtf(fmaxf(red[0], 1e-12f));
    for (int d = tid; d < DMOD; d += 256) g_xq[(size_t)n*DMOD + d] = xs[d]*inv;
}

// ---------------- top-k ----------------
__global__ void topk_k(){
    int n = blockIdx.x, tid = threadIdx.x;
    __shared__ float bv[256];
    __shared__ int   bi[256];
    __shared__ int   chosen[4];
    float rs = 0.f;
    for (int r = 0; r < 4; r++){
        float best = -1e30f; int besti = 1 << 30;
        for (int j = tid; j < POOLN; j += 256){
            bool skip = false;
            for (int c = 0; c < r; c++) if (chosen[c] == j) skip = true;
            float v = g_sim[(size_t)n*POOLN + j];
            if (!skip && (v > best || (v == best && j < besti))){ best = v; besti = j; }
        }
        bv[tid] = best; bi[tid] = besti; __syncthreads();
        for (int o = 128; o; o >>= 1){
            if (tid < o){
                if (bv[tid+o] > bv[tid] || (bv[tid+o] == bv[tid] && bi[tid+o] < bi[tid])){
                    bv[tid] = bv[tid+o]; bi[tid] = bi[tid+o];
                }
            }
            __syncthreads();
        }
        if (tid == 0){ chosen[r] = bi[0]; rs += bv[0]; }
        __syncthreads();
    }
    for (int e = tid; e < 4*DMOD; e += 256){
        int k = e / DMOD, d = e % DMOD;
        g_h[((size_t)n*TTOK + k)*DMOD + d] = g_keyn[(size_t)chosen[k]*DMOD + d];
    }
    if (tid == 0) atomicAdd(&g_rsim, rs);
}

__global__ void zero_k(){ g_rsim = 0.f; }

// ---------------- add positional embedding ----------------
__global__ void wpe_k(const float* __restrict__ wpe){
    size_t i = (size_t)blockIdx.x*blockDim.x + threadIdx.x;
    if (i < (size_t)NTOK*DMOD){
        int tok = (int)(i / DMOD);
        int t = tok % TTOK;
        int d = (int)(i % DMOD);
        g_h[i] += wpe[(size_t)t*DMOD + d];
    }
}

// ---------------- layernorm: warp per row, float4 ----------------
__global__ void ln_k(const float* __restrict__ x, const float* __restrict__ g,
                     const float* __restrict__ b, float* __restrict__ y){
    int row  = blockIdx.x*8 + (threadIdx.x >> 5);
    int lane = threadIdx.x & 31;
    const float4* xr = reinterpret_cast<const float4*>(x + (size_t)row*DMOD);
    const float4* g4 = reinterpret_cast<const float4*>(g);
    const float4* b4 = reinterpret_cast<const float4*>(b);
    float4 v[6];
    float s = 0.f, sq = 0.f;
    #pragma unroll
    for (int i = 0; i < 6; i++){
        v[i] = xr[lane + i*32];
        s  += v[i].x + v[i].y + v[i].z + v[i].w;
        sq += v[i].x*v[i].x + v[i].y*v[i].y + v[i].z*v[i].z + v[i].w*v[i].w;
    }
    #pragma unroll
    for (int o = 16; o; o >>= 1){
        s  += __shfl_xor_sync(0xffffffffu, s,  o);
        sq += __shfl_xor_sync(0xffffffffu, sq, o);
    }
    float mu  = s * (1.f/DMOD);
    float var = sq * (1.f/DMOD) - mu*mu;
    float inv = rsqrtf(var + 1e-5f);
    float4* yr = reinterpret_cast<float4*>(y + (size_t)row*DMOD);
    #pragma unroll
    for (int i = 0; i < 6; i++){
        float4 gg = g4[lane + i*32], bb = b4[lane + i*32], o;
        o.x = (v[i].x-mu)*inv*gg.x + bb.x;
        o.y = (v[i].y-mu)*inv*gg.y + bb.y;
        o.z = (v[i].z-mu)*inv*gg.z + bb.z;
        o.w = (v[i].w-mu)*inv*gg.w + bb.w;
        yr[lane + i*32] = o;
    }
}

// ---------------- attention ----------------
__global__ void attn_k(){
    int blk = blockIdx.x;
    int n = blk / 12, head = blk % 12;
    __shared__ float ks[TTOK][65];
    __shared__ float vs[TTOK][65];
    __shared__ float qrow[8][64];
    __shared__ float pb[8][TTOK];
    int tid = threadIdx.x, lane = tid & 31, w = tid >> 5;
    const size_t base = (size_t)n*TTOK*3*DMOD;
    for (int e = tid; e < TTOK*64; e += 256){
        int t = e >> 6, d = e & 63;
        ks[t][d] = g_qkv[base + (size_t)t*3*DMOD + DMOD   + head*64 + d];
        vs[t][d] = g_qkv[base + (size_t)t*3*DMOD + 2*DMOD + head*64 + d];
    }
    __syncthreads();
    for (int i = w; i < TTOK; i += 8){
        qrow[w][lane]    = g_qkv[base + (size_t)i*3*DMOD + head*64 + lane];
        qrow[w][lane+32] = g_qkv[base + (size_t)i*3*DMOD + head*64 + 32 + lane];
        __syncwarp();
        float lmax = -1e30f;
        for (int j = lane; j <= i; j += 32){
            float s = 0.f;
            #pragma unroll 16
            for (int d = 0; d < 64; d++) s = fmaf(qrow[w][d], ks[j][d], s);
            s *= 0.125f;
            pb[w][j] = s;
            lmax = fmaxf(lmax, s);
        }
        for (int o = 16; o; o >>= 1) lmax = fmaxf(lmax, __shfl_xor_sync(0xffffffffu, lmax, o));
        float lsum = 0.f;
        for (int j = lane; j <= i; j += 32){
            float p = expf(pb[w][j] - lmax);
            pb[w][j] = p;
            lsum += p;
        }
        for (int o = 16; o; o >>= 1) lsum += __shfl_xor_sync(0xffffffffu, lsum, o);
        float inv = 1.f/lsum;
        __syncwarp();
        #pragma unroll
        for (int du = 0; du < 2; du++){
            int d = lane + du*32;
            float o = 0.f;
            for (int j = 0; j <= i; j++) o = fmaf(pb[w][j], vs[j][d], o);
            g_ob[((size_t)n*TTOK + i)*DMOD + head*64 + d] = o*inv;
        }
        __syncwarp();
    }
}

// ---------------- final: sum split-K chunks + channels, denormalize -------
__global__ void final_k(const float* __restrict__ outb, float* __restrict__ out){
    int n = blockIdx.x, b = n/7, m = n%7;
    for (int t = threadIdx.x; t < PREDL; t += blockDim.x){
        float v = 3.f*outb[t];
        #pragma unroll
        for (int z = 0; z < SPLITZ; z++){
            const float* p = g_osp + (size_t)z*NSER*3*PREDL;
            v += p[(size_t)(n*3+0)*PREDL + t]
               + p[(size_t)(n*3+1)*PREDL + t]
               + p[(size_t)(n*3+2)*PREDL + t];
        }
        out[(size_t)b*PREDL*7 + (size_t)t*7 + m] = v*g_std[n] + g_mean[n];
    }
}

__global__ void rsim_k(float* __restrict__ out, int out_size){
    if (out_size > 64*PREDL*7) out[64*PREDL*7] = g_rsim * (1.f/NSER);
}

// ---------------- host ----------------
template <typename T, size_t S>
static float* symaddr(T (&arr)[S]){ void* p = nullptr; cudaGetSymbolAddress(&p, arr); return (float*)p; }

extern "C" void kernel_launch(void* const* d_in, const int* in_sizes, int n_in,
                              void* d_out, int out_size){
    int s = (n_in >= 2 && in_sizes[1] == 1) ? 1 : 0;
    const float* x    = (const float*)d_in[0];
    const float* in_w = (const float*)d_in[1+s];
    const float* in_b = (const float*)d_in[2+s];
    const float* pk   = (const float*)d_in[3+s];
    const float* wpe  = (const float*)d_in[4+s];
    const float* ln1g = (const float*)d_in[5+s];
    const float* ln1b = (const float*)d_in[6+s];
    const float* qkvw = (const float*)d_in[7+s];
    const float* qkvb = (const float*)d_in[8+s];
    const float* aw   = (const float*)d_in[9+s];
    const float* ab   = (const float*)d_in[10+s];
    const float* ln2g = (const float*)d_in[11+s];
    const float* ln2b = (const float*)d_in[12+s];
    const float* fcw  = (const float*)d_in[13+s];
    const float* fcb  = (const float*)d_in[14+s];
    const float* pw   = (const float*)d_in[15+s];
    const float* pbb  = (const float*)d_in[16+s];
    const float* lnfg = (const float*)d_in[17+s];
    const float* lnfb = (const float*)d_in[18+s];
    const float* outw = (const float*)d_in[19+s];
    const float* outb = (const float*)d_in[20+s];
    float* out = (float*)d_out;

    float* p_h    = symaddr(g_h);
    float* p_a    = symaddr(g_a);
    float* p_qkv  = symaddr(g_qkv);
    float* p_ob   = symaddr(g_ob);
    float* p_mlp  = symaddr(g_mlp);
    float* p_tok  = symaddr(g_tok);
    float* p_xq   = symaddr(g_xq);
    float* p_keyn = symaddr(g_keyn);
    float* p_sim  = symaddr(g_sim);
    float* p_osp  = symaddr(g_osp);

    const int SMB = SM_FLOATS*4;
    static bool attr_done = false;
    if (!attr_done){
        cudaFuncSetAttribute(tgemm_k<0,false,false>, cudaFuncAttributeMaxDynamicSharedMemorySize, SMB);
        cudaFuncSetAttribute(tgemm_k<0,true ,false>, cudaFuncAttributeMaxDynamicSharedMemorySize, SMB);
        cudaFuncSetAttribute(tgemm_k<1,false,false>, cudaFuncAttributeMaxDynamicSharedMemorySize, SMB);
        cudaFuncSetAttribute(tgemm_k<0,false,true >, cudaFuncAttributeMaxDynamicSharedMemorySize, SMB);
        attr_done = true;
    }

    zero_k<<<1,1>>>();
    norm_k<<<NSER,256>>>(x);
    dec_k<<<NSER,256>>>();
    patch_k<<<NSER,256>>>();

    // patch embedding (fp32 exact: feeds top-k) -> h rows 4..67 (REMAP)
    gemm_k<false,0,false,true><<<dim3(DMOD/64, NSER*PNUM/64),256>>>(p_tok, in_w, in_b, p_h, NSER*PNUM, DMOD, 48);

    keynorm_k<<<POOLN,256>>>(pk);
    xq_k<<<NSER,256>>>();
    gemm_k<true,0,false,false><<<dim3((POOLN+63)/64, NSER/64),256>>>(p_xq, p_keyn, (const float*)nullptr, p_sim, NSER, POOLN, DMOD);
    topk_k<<<NSER,256>>>();
    wpe_k<<<(unsigned)(((size_t)NTOK*DMOD + 255)/256),256>>>(wpe);

    const int MB = NTOK/128;   // 238
    for (int L = 0; L < NLAYER; L++){
        ln_k<<<NTOK/8,256>>>(p_h, ln1g + (size_t)L*DMOD, ln1b + (size_t)L*DMOD, p_a);
        tgemm_k<0,false,false><<<dim3(3*DMOD/128, MB),256,SMB>>>(p_a, qkvw + (size_t)L*DMOD*3*DMOD, qkvb + (size_t)L*3*DMOD, p_qkv, NTOK, 3*DMOD, DMOD);
        attn_k<<<NSER*12,256>>>();
        tgemm_k<0,true ,false><<<dim3(DMOD/128, MB),256,SMB>>>(p_ob, aw + (size_t)L*DMOD*DMOD, ab + (size_t)L*DMOD, p_h, NTOK, DMOD, DMOD);
        ln_k<<<NTOK/8,256>>>(p_h, ln2g + (size_t)L*DMOD, ln2b + (size_t)L*DMOD, p_a);
        tgemm_k<1,false,false><<<dim3(4*DMOD/128, MB),256,SMB>>>(p_a, fcw + (size_t)L*DMOD*4*DMOD, fcb + (size_t)L*4*DMOD, p_mlp, NTOK, 4*DMOD, DMOD);
        tgemm_k<0,true ,false><<<dim3(DMOD/128, MB),256,SMB>>>(p_mlp, pw + (size_t)L*4*DMOD*DMOD, pbb + (size_t)L*DMOD, p_h, NTOK, DMOD, 4*DMOD);
    }

    ln_k<<<NTOK/8,256>>>(p_h, lnfg, lnfb, p_a);
    // output head: M=1344, N=96, K=17408, split-K 16 (chunk 1088)
    tgemm_k<0,false,true><<<dim3(1, (NSER*3+127)/128, SPLITZ),256,SMB>>>(p_a, outw, (const float*)nullptr, p_osp, NSER*3, PREDL, TTOK*DMOD/3);
    final_k<<<NSER,96>>>(outb, out);
    rsim_k<<<1,1>>>(out, out_size);
}

// round 5
// speedup vs baseline: 5.7449x; 1.6668x over previous
#include <cuda_runtime.h>
#include <cuda_fp16.h>
#include <math.h>
#include <stdint.h>

#define NSER 448
#define LSEQ 512
#define TTOK 68
#define DMOD 768
#define NTOK (NSER*TTOK)       // 30464
#define PNUM 64
#define POOLN 1000
#define PREDL 96
#define NLAYER 6
#define SPLITZ 16

// ---------------- scratch (device globals; no allocations) ----------------
__device__ float  g_xn  [NSER*LSEQ];
__device__ float  g_mean[NSER];
__device__ float  g_std [NSER];
__device__ float  g_dec [NSER*3*LSEQ];
__device__ float  g_tok [NSER*PNUM*48];
__device__ float  g_h   [(size_t)NTOK*DMOD];
__device__ __half g_a   [(size_t)NTOK*DMOD];     // LN outputs (half, GEMM A)
__device__ float  g_af  [(size_t)NTOK*DMOD];     // final LN output (fp32, head)
__device__ float  g_qkv [(size_t)NTOK*3*DMOD];   // fp32: attention reads exact
__device__ __half g_ob  [(size_t)NTOK*DMOD];
__device__ __half g_mlp [(size_t)NTOK*4*DMOD];
__device__ float  g_xq  [NSER*DMOD];
__device__ float  g_keyn[POOLN*DMOD];
__device__ float  g_sim [NSER*POOLN];
__device__ float  g_osp [(size_t)SPLITZ*NSER*3*PREDL];
__device__ float  g_rsim;
// transposed half weights per layer: qkvT, awT, fcT, pwT
#define WL 7077888u
__device__ __half g_wT  [(size_t)NLAYER*WL];

__device__ __forceinline__ float gelu_tanh(float x){
    float c = 0.7978845608028654f;
    float t = tanhf(c*(x + 0.044715f*x*x*x));
    return 0.5f*x*(1.f+t);
}

__device__ __forceinline__ unsigned f2tf(float x){
    unsigned r; asm("cvt.rna.tf32.f32 %0, %1;" : "=r"(r) : "f"(x)); return r;
}

__device__ __forceinline__ void mma8(float* c, const unsigned* a, const unsigned* b){
    asm volatile("mma.sync.aligned.m16n8k8.row.col.f32.tf32.tf32.f32 "
        "{%0,%1,%2,%3}, {%4,%5,%6,%7}, {%8,%9}, {%0,%1,%2,%3};"
        : "+f"(c[0]),"+f"(c[1]),"+f"(c[2]),"+f"(c[3])
        : "r"(a[0]),"r"(a[1]),"r"(a[2]),"r"(a[3]), "r"(b[0]),"r"(b[1]));
}

__device__ __forceinline__ void mma16(float* c, const unsigned* a, const unsigned* b){
    asm volatile("mma.sync.aligned.m16n8k16.row.col.f32.f16.f16.f32 "
        "{%0,%1,%2,%3}, {%4,%5,%6,%7}, {%8,%9}, {%0,%1,%2,%3};"
        : "+f"(c[0]),"+f"(c[1]),"+f"(c[2]),"+f"(c[3])
        : "r"(a[0]),"r"(a[1]),"r"(a[2]),"r"(a[3]), "r"(b[0]),"r"(b[1]));
}

__device__ __forceinline__ void cpasyncF(float* dst, const float* src, bool pred){
    unsigned sa = (unsigned)__cvta_generic_to_shared(dst);
    int sz = pred ? 16 : 0;
    asm volatile("cp.async.cg.shared.global [%0], [%1], 16, %2;" :: "r"(sa), "l"(src), "r"(sz));
}
__device__ __forceinline__ void cpasyncH(__half* dst, const __half* src){
    unsigned sa = (unsigned)__cvta_generic_to_shared(dst);
    asm volatile("cp.async.cg.shared.global [%0], [%1], 16;" :: "r"(sa), "l"(src));
}
__device__ __forceinline__ void cp_commit(){ asm volatile("cp.async.commit_group;"); }
template<int N> __device__ __forceinline__ void cp_wait(){ asm volatile("cp.async.wait_group %0;"::"n"(N)); }

// ---------------- RevIN stats + normalize ----------------
__global__ void norm_k(const float* __restrict__ x){
    int n = blockIdx.x, b = n/7, m = n%7, tid = threadIdx.x;
    __shared__ float xs[LSEQ];
    __shared__ float red[256];
    for (int l = tid; l < LSEQ; l += 256) xs[l] = x[((size_t)b*LSEQ + l)*7 + m];
    __syncthreads();
    float s = xs[tid] + xs[tid+256];
    red[tid] = s; __syncthreads();
    for (int o = 128; o; o >>= 1){ if (tid < o) red[tid] += red[tid+o]; __syncthreads(); }
    float mu = red[0] * (1.f/LSEQ);
    __syncthreads();
    float d0 = xs[tid]-mu, d1 = xs[tid+256]-mu;
    red[tid] = d0*d0 + d1*d1; __syncthreads();
    for (int o = 128; o; o >>= 1){ if (tid < o) red[tid] += red[tid+o]; __syncthreads(); }
    float sd = sqrtf(red[0]*(1.f/LSEQ) + 1e-5f);
    if (tid == 0){ g_mean[n] = mu; g_std[n] = sd; }
    float inv = 1.f/sd;
    g_xn[n*LSEQ + tid]       = d0*inv;
    g_xn[n*LSEQ + 256 + tid] = d1*inv;
}

// ---------------- decomposition ----------------
__global__ void dec_k(){
    int n = blockIdx.x, tid = threadIdx.x;
    __shared__ float xs[LSEQ];
    __shared__ float valid[489];
    __shared__ float det[LSEQ];
    __shared__ float ph[24];
    for (int l = tid; l < LSEQ; l += 256) xs[l] = g_xn[n*LSEQ + l];
    if (tid < 24) ph[tid] = 0.f;
    __syncthreads();
    for (int i = tid; i < 489; i += 256){
        float s = 0.f;
        #pragma unroll
        for (int k = 0; k < 24; k++) s += xs[i+k];
        valid[i] = s * (1.f/24.f);
    }
    __syncthreads();
    for (int l = tid; l < LSEQ; l += 256){
        int vi = l - 12; vi = vi < 0 ? 0 : (vi > 488 ? 488 : vi);
        float tr = valid[vi];
        float dt = xs[l] - tr;
        det[l] = dt;
        atomicAdd(&ph[l % 24], dt);
        g_dec[((size_t)n*3 + 0)*LSEQ + l] = tr;
    }
    __syncthreads();
    for (int l = tid; l < LSEQ; l += 256){
        int p = l % 24;
        float cnt = (p < 8) ? 22.f : 21.f;
        float se = ph[p] / cnt;
        g_dec[((size_t)n*3 + 1)*LSEQ + l] = se;
        g_dec[((size_t)n*3 + 2)*LSEQ + l] = det[l] - se;
    }
}

// ---------------- patch extraction ----------------
__global__ void patch_k(){
    int n = blockIdx.x, tid = threadIdx.x;
    for (int e = tid; e < PNUM*48; e += 256){
        int p = e/48, rem = e%48, c = rem/16, j = rem%16;
        int l = p*8 + j; if (l > LSEQ-1) l = LSEQ-1;
        g_tok[(size_t)n*PNUM*48 + e] = g_dec[((size_t)n*3 + c)*LSEQ + l];
    }
}

// ---------------- weight transpose to half: W[K,N] -> WT[N,K] -------------
__global__ void transp_k(const float* __restrict__ W, __half* __restrict__ WT, int K, int N){
    __shared__ float t[32][33];
    int bx = blockIdx.x*32, by = blockIdx.y*32;
    int x = threadIdx.x, y = threadIdx.y;   // 32 x 8
    #pragma unroll
    for (int i = 0; i < 4; i++){
        int r = by + y*4 + i;
        t[y*4+i][x] = W[(size_t)r*N + bx + x];
    }
    __syncthreads();
    #pragma unroll
    for (int i = 0; i < 4; i++){
        int rn = bx + y*4 + i;
        WT[(size_t)rn*K + by + x] = __float2half(t[x][y*4+i]);
    }
}

// ---------------- generic fp32 SIMT GEMM (precision-critical small paths) --
template<bool TRANSB, int ACT, bool RESID, bool REMAP>
__global__ void gemm_k(const float* __restrict__ A, const float* __restrict__ B,
                       const float* __restrict__ bias, float* __restrict__ C,
                       int M, int N, int K){
    __shared__ float As[16][68];
    __shared__ float Bs[16][68];
    int tid = threadIdx.x;
    int tx = tid & 15, ty = tid >> 4;
    int row0 = blockIdx.y * 64, col0 = blockIdx.x * 64;
    float acc[4][4] = {};
    for (int k0 = 0; k0 < K; k0 += 16){
        {
            int r  = tid >> 2;
            int c4 = (tid & 3) * 4;
            float4 v = *reinterpret_cast<const float4*>(&A[(size_t)(row0 + r)*K + k0 + c4]);
            As[c4+0][r] = v.x; As[c4+1][r] = v.y; As[c4+2][r] = v.z; As[c4+3][r] = v.w;
        }
        if (!TRANSB){
            int kk = tid >> 4;
            int c4 = (tid & 15) * 4;
            int col = col0 + c4;
            float4 v = make_float4(0.f,0.f,0.f,0.f);
            if (col < N) v = *reinterpret_cast<const float4*>(&B[(size_t)(k0+kk)*N + col]);
            Bs[kk][c4+0] = v.x; Bs[kk][c4+1] = v.y; Bs[kk][c4+2] = v.z; Bs[kk][c4+3] = v.w;
        } else {
            int nn = tid >> 2;
            int c4 = (tid & 3) * 4;
            int col = col0 + nn;
            float4 v = make_float4(0.f,0.f,0.f,0.f);
            if (col < N) v = *reinterpret_cast<const float4*>(&B[(size_t)col*K + k0 + c4]);
            Bs[c4+0][nn] = v.x; Bs[c4+1][nn] = v.y; Bs[c4+2][nn] = v.z; Bs[c4+3][nn] = v.w;
        }
        __syncthreads();
        #pragma unroll
        for (int kk = 0; kk < 16; kk++){
            float a[4], b[4];
            #pragma unroll
            for (int i = 0; i < 4; i++) a[i] = As[kk][ty*4+i];
            #pragma unroll
            for (int j = 0; j < 4; j++) b[j] = Bs[kk][tx*4+j];
            #pragma unroll
            for (int i = 0; i < 4; i++)
                #pragma unroll
                for (int j = 0; j < 4; j++) acc[i][j] = fmaf(a[i], b[j], acc[i][j]);
        }
        __syncthreads();
    }
    #pragma unroll
    for (int i = 0; i < 4; i++){
        int r = row0 + ty*4 + i;
        size_t orow = REMAP ? (size_t)((r >> 6)*TTOK + 4 + (r & 63)) : (size_t)r;
        #pragma unroll
        for (int j = 0; j < 4; j++){
            int col = col0 + tx*4 + j;
            if (col < N){
                float v = acc[i][j];
                if (bias) v += bias[col];
                if (ACT == 1) v = gelu_tanh(v);
                size_t idx = orow*(size_t)N + col;
                if (RESID) C[idx] += v; else C[idx] = v;
            }
        }
    }
}

// ================= fp16 tensor-core GEMM ==================================
// C[M,N] = A[M,K] @ BT[N,K]^T (+bias, ACT, RESID). A,BT half K-major.
// 128x128 CTA tile, K-tile 32 (2 x k16 mma), 8 warps 2x4, 3-stage cp.async.
// Requires M%128==0, N%128==0, K%32==0.
#define HST 40                  // halves per smem row (32 data + 8 pad), 80B
#define H_STAGE (128*HST)       // 5120 halves = 10KB per matrix per stage
#define H_SMEMB (6*H_STAGE*2)   // 61440 bytes

template<int ACT, bool RESID, bool HOUT>
__global__ __launch_bounds__(256, 2) void hgemm_k(
        const __half* __restrict__ A, const __half* __restrict__ BT,
        const float* __restrict__ bias, void* __restrict__ Cv,
        int M, int N, int K){
    extern __shared__ __half hsm[];
    __half* smA = hsm;                  // 3 stages
    __half* smB = hsm + 3*H_STAGE;      // 3 stages
    int tid = threadIdx.x;
    int warp = tid >> 5, lane = tid & 31;
    int wm = warp >> 2, wn = warp & 3;
    int g = lane >> 2, tg = lane & 3;
    int row0 = blockIdx.y * 128, col0 = blockIdx.x * 128;

    float acc[4][4][4];
    #pragma unroll
    for (int i=0;i<4;i++) for (int j=0;j<4;j++) for (int q=0;q<4;q++) acc[i][j][q]=0.f;

    #define ISSUE_H(T, S) { \
        __half* as = smA + (S)*H_STAGE; \
        __half* bs = smB + (S)*H_STAGE; \
        const __half* Ab = A + (size_t)row0*K + (T)*32; \
        const __half* Bb = BT + (size_t)col0*K + (T)*32; \
        _Pragma("unroll") \
        for (int i=0;i<2;i++){ \
            int idx = tid + i*256; int r = idx>>2, ch = idx&3; \
            cpasyncH(&as[r*HST + ch*8], &Ab[(size_t)r*K + ch*8]); \
        } \
        _Pragma("unroll") \
        for (int i=0;i<2;i++){ \
            int idx = tid + i*256; int r = idx>>2, ch = idx&3; \
            cpasyncH(&bs[r*HST + ch*8], &Bb[(size_t)r*K + ch*8]); \
        } \
        cp_commit(); }

    int nt = K >> 5;
    ISSUE_H(0, 0);
    ISSUE_H(1, 1);

    int stage = 0;
    for (int kt = 0; kt < nt; kt++){
        if (kt == nt-1) cp_wait<0>(); else cp_wait<1>();
        __syncthreads();
        if (kt + 2 < nt){
            int s2 = stage + 2; if (s2 >= 3) s2 -= 3;
            ISSUE_H(kt+2, s2);
        }
        const __half* as = smA + stage*H_STAGE;
        const __half* bs = smB + stage*H_STAGE;
        #pragma unroll
        for (int ks = 0; ks < 32; ks += 16){
            unsigned af[4][4], bf[4][2];
            #pragma unroll
            for (int mt = 0; mt < 4; mt++){
                int r = wm*64 + mt*16 + g;
                int base = r*HST + ks + 2*tg;
                af[mt][0] = *reinterpret_cast<const unsigned*>(&as[base]);
                af[mt][1] = *reinterpret_cast<const unsigned*>(&as[base + 8*HST]);
                af[mt][2] = *reinterpret_cast<const unsigned*>(&as[base + 8]);
                af[mt][3] = *reinterpret_cast<const unsigned*>(&as[base + 8*HST + 8]);
            }
            #pragma unroll
            for (int nt2 = 0; nt2 < 4; nt2++){
                int rn = wn*32 + nt2*8 + g;
                int base = rn*HST + ks + 2*tg;
                bf[nt2][0] = *reinterpret_cast<const unsigned*>(&bs[base]);
                bf[nt2][1] = *reinterpret_cast<const unsigned*>(&bs[base + 8]);
            }
            #pragma unroll
            for (int mt = 0; mt < 4; mt++)
                #pragma unroll
                for (int nt2 = 0; nt2 < 4; nt2++)
                    mma16(acc[mt][nt2], af[mt], bf[nt2]);
        }
        stage++; if (stage >= 3) stage -= 3;
    }
    #undef ISSUE_H

    // epilogue: c0,c1 at (row g, cols 2tg..2tg+1), c2,c3 at (row g+8)
    #pragma unroll
    for (int mt = 0; mt < 4; mt++){
        int rbase = row0 + wm*64 + mt*16;
        #pragma unroll
        for (int nt2 = 0; nt2 < 4; nt2++){
            int cbase = col0 + wn*32 + nt2*8 + tg*2;
            float b0 = bias[cbase], b1 = bias[cbase+1];
            #pragma unroll
            for (int hh = 0; hh < 2; hh++){
                int rr = rbase + g + hh*8;
                float v0 = acc[mt][nt2][hh*2]   + b0;
                float v1 = acc[mt][nt2][hh*2+1] + b1;
                if (ACT == 1){ v0 = gelu_tanh(v0); v1 = gelu_tanh(v1); }
                size_t gi = (size_t)rr*N + cbase;
                if (HOUT){
                    __half2* p = reinterpret_cast<__half2*>(reinterpret_cast<__half*>(Cv) + gi);
                    *p = __floats2half2_rn(v0, v1);
                } else {
                    float* C = reinterpret_cast<float*>(Cv);
                    if (RESID){
                        float2 c = *reinterpret_cast<float2*>(&C[gi]);
                        c.x += v0; c.y += v1;
                        *reinterpret_cast<float2*>(&C[gi]) = c;
                    } else {
                        *reinterpret_cast<float2*>(&C[gi]) = make_float2(v0, v1);
                    }
                }
            }
        }
    }
}

// ---------------- legacy tf32 tensor GEMM (output head, split-K) ----------
#define AS_ST 36
#define BS_ST 136
#define A_STAGE (128*AS_ST)
#define B_STAGE (32*BS_ST)
#define SM_FLOATS (3*(A_STAGE+B_STAGE))

__global__ __launch_bounds__(256, 2) void headgemm_k(
        const float* __restrict__ A, const float* __restrict__ B,
        float* __restrict__ C, int M, int N, int K){
    extern __shared__ float sm[];
    float* smA = sm;
    float* smB = sm + 3*A_STAGE;
    int tid = threadIdx.x;
    int warp = tid >> 5, lane = tid & 31;
    int wm = warp >> 2, wn = warp & 3;
    int g = lane >> 2, tg = lane & 3;
    int row0 = blockIdx.y * 128, col0 = blockIdx.x * 128;

    int Kc   = K / gridDim.z;
    int kbeg = blockIdx.z * Kc;
    int nt   = Kc >> 5;

    float acc[4][4][4];
    #pragma unroll
    for (int i=0;i<4;i++) for (int j=0;j<4;j++) for (int q=0;q<4;q++) acc[i][j][q]=0.f;

    #define ISSUE_T(T, S) { \
        int k0 = kbeg + (T)*32; \
        float* as = smA + (S)*A_STAGE; \
        float* bs = smB + (S)*B_STAGE; \
        _Pragma("unroll") \
        for (int i=0;i<4;i++){ \
            int idx = tid + i*256; int r = idx>>3; int ch=(idx&7)<<2; \
            int grow = row0 + r; bool p = grow < M; int gr = p ? grow : (M-1); \
            cpasyncF(&as[r*AS_ST + ch], &A[(size_t)gr*K + k0 + ch], p); \
        } \
        _Pragma("unroll") \
        for (int i=0;i<4;i++){ \
            int idx = tid + i*256; int kk = idx>>5; int c4=(idx&31)<<2; \
            int gcol = col0 + c4; bool p = gcol < N; int gc = p ? gcol : 0; \
            cpasyncF(&bs[kk*BS_ST + c4], &B[(size_t)(k0+kk)*N + gc], p); \
        } \
        cp_commit(); }

    ISSUE_T(0, 0);
    ISSUE_T(1, 1);

    int stage = 0;
    for (int kt = 0; kt < nt; kt++){
        if (kt == nt-1) cp_wait<0>(); else cp_wait<1>();
        __syncthreads();
        if (kt + 2 < nt){
            int s2 = stage + 2; if (s2 >= 3) s2 -= 3;
            ISSUE_T(kt+2, s2);
        }
        const float* as = smA + stage*A_STAGE;
        const float* bs = smB + stage*B_STAGE;
        #pragma unroll
        for (int ks = 0; ks < 32; ks += 8){
            unsigned af[4][4], bf[4][2];
            #pragma unroll
            for (int mt = 0; mt < 4; mt++){
                int r = wm*64 + mt*16 + g;
                af[mt][0] = f2tf(as[r*AS_ST + ks+tg]);
                af[mt][1] = f2tf(as[(r+8)*AS_ST + ks+tg]);
                af[mt][2] = f2tf(as[r*AS_ST + ks+tg+4]);
                af[mt][3] = f2tf(as[(r+8)*AS_ST + ks+tg+4]);
            }
            #pragma unroll
            for (int nt2 = 0; nt2 < 4; nt2++){
                int c = wn*32 + nt2*8 + g;
                bf[nt2][0] = f2tf(bs[(ks+tg)*BS_ST + c]);
                bf[nt2][1] = f2tf(bs[(ks+tg+4)*BS_ST + c]);
            }
            #pragma unroll
            for (int mt = 0; mt < 4; mt++)
                #pragma unroll
                for (int nt2 = 0; nt2 < 4; nt2++)
                    mma8(acc[mt][nt2], af[mt], bf[nt2]);
        }
        stage++; if (stage >= 3) stage -= 3;
        __syncthreads();
    }
    #undef ISSUE_T

    float* Cout = C + (size_t)blockIdx.z*M*N;
    #pragma unroll
    for (int mt = 0; mt < 4; mt++){
        int rbase = row0 + wm*64 + mt*16;
        #pragma unroll
        for (int nt2 = 0; nt2 < 4; nt2++){
            int cbase = col0 + wn*32 + nt2*8 + tg*2;
            #pragma unroll
            for (int half2_ = 0; half2_ < 2; half2_++){
                int rr = rbase + g + half2_*8;
                if (rr < M){
                    #pragma unroll
                    for (int jj = 0; jj < 2; jj++){
                        int cc = cbase + jj;
                        if (cc < N) Cout[(size_t)rr*N + cc] = acc[mt][nt2][half2_*2+jj];
                    }
                }
            }
        }
    }
}

// ---------------- l2-normalize prompt keys ----------------
__global__ void keynorm_k(const float* __restrict__ pk){
    int r = blockIdx.x, tid = threadIdx.x;
    __shared__ float red[256];
    float v0 = pk[(size_t)r*DMOD + tid], v1 = pk[(size_t)r*DMOD + 256 + tid], v2 = pk[(size_t)r*DMOD + 512 + tid];
    red[tid] = v0*v0 + v1*v1 + v2*v2; __syncthreads();
    for (int o = 128; o; o >>= 1){ if (tid < o) red[tid] += red[tid+o]; __syncthreads(); }
    float inv = rsqrtf(fmaxf(red[0], 1e-12f));
    g_keyn[(size_t)r*DMOD + tid]       = v0*inv;
    g_keyn[(size_t)r*DMOD + 256 + tid] = v1*inv;
    g_keyn[(size_t)r*DMOD + 512 + tid] = v2*inv;
}

// ---------------- xq ----------------
__global__ void xq_k(){
    int n = blockIdx.x, tid = threadIdx.x;
    __shared__ float xs[DMOD];
    __shared__ float red[256];
    float ss = 0.f;
    for (int d = tid; d < DMOD; d += 256){
        float s = 0.f;
        for (int p = 0; p < PNUM; p++) s += g_h[((size_t)n*TTOK + 4 + p)*DMOD + d];
        s *= (1.f/PNUM);
        xs[d] = s; ss += s*s;
    }
    red[tid] = ss; __syncthreads();
    for (int o = 128; o; o >>= 1){ if (tid < o) red[tid] += red[tid+o]; __syncthreads(); }
    float inv = rsqrtf(fmaxf(red[0], 1e-12f));
    for (int d = tid; d < DMOD; d += 256) g_xq[(size_t)n*DMOD + d] = xs[d]*inv;
}

// ---------------- top-k ----------------
__global__ void topk_k(){
    int n = blockIdx.x, tid = threadIdx.x;
    __shared__ float bv[256];
    __shared__ int   bi[256];
    __shared__ int   chosen[4];
    float rs = 0.f;
    for (int r = 0; r < 4; r++){
        float best = -1e30f; int besti = 1 << 30;
        for (int j = tid; j < POOLN; j += 256){
            bool skip = false;
            for (int c = 0; c < r; c++) if (chosen[c] == j) skip = true;
            float v = g_sim[(size_t)n*POOLN + j];
            if (!skip && (v > best || (v == best && j < besti))){ best = v; besti = j; }
        }
        bv[tid] = best; bi[tid] = besti; __syncthreads();
        for (int o = 128; o; o >>= 1){
            if (tid < o){
                if (bv[tid+o] > bv[tid] || (bv[tid+o] == bv[tid] && bi[tid+o] < bi[tid])){
                    bv[tid] = bv[tid+o]; bi[tid] = bi[tid+o];
                }
            }
            __syncthreads();
        }
        if (tid == 0){ chosen[r] = bi[0]; rs += bv[0]; }
        __syncthreads();
    }
    for (int e = tid; e < 4*DMOD; e += 256){
        int k = e / DMOD, d = e % DMOD;
        g_h[((size_t)n*TTOK + k)*DMOD + d] = g_keyn[(size_t)chosen[k]*DMOD + d];
    }
    if (tid == 0) atomicAdd(&g_rsim, rs);
}

__global__ void zero_k(){ g_rsim = 0.f; }

// ---------------- add positional embedding ----------------
__global__ void wpe_k(const float* __restrict__ wpe){
    size_t i = (size_t)blockIdx.x*blockDim.x + threadIdx.x;
    if (i < (size_t)NTOK*DMOD){
        int tok = (int)(i / DMOD);
        int t = tok % TTOK;
        int d = (int)(i % DMOD);
        g_h[i] += wpe[(size_t)t*DMOD + d];
    }
}

// ---------------- layernorm: warp per row; half or float out --------------
template<bool HOUT>
__global__ void ln_k(const float* __restrict__ x, const float* __restrict__ g,
                     const float* __restrict__ b, void* __restrict__ yv){
    int row  = blockIdx.x*8 + (threadIdx.x >> 5);
    int lane = threadIdx.x & 31;
    const float4* xr = reinterpret_cast<const float4*>(x + (size_t)row*DMOD);
    const float4* g4 = reinterpret_cast<const float4*>(g);
    const float4* b4 = reinterpret_cast<const float4*>(b);
    float4 v[6];
    float s = 0.f, sq = 0.f;
    #pragma unroll
    for (int i = 0; i < 6; i++){
        v[i] = xr[lane + i*32];
        s  += v[i].x + v[i].y + v[i].z + v[i].w;
        sq += v[i].x*v[i].x + v[i].y*v[i].y + v[i].z*v[i].z + v[i].w*v[i].w;
    }
    #pragma unroll
    for (int o = 16; o; o >>= 1){
        s  += __shfl_xor_sync(0xffffffffu, s,  o);
        sq += __shfl_xor_sync(0xffffffffu, sq, o);
    }
    float mu  = s * (1.f/DMOD);
    float var = sq * (1.f/DMOD) - mu*mu;
    float inv = rsqrtf(var + 1e-5f);
    #pragma unroll
    for (int i = 0; i < 6; i++){
        float4 gg = g4[lane + i*32], bb = b4[lane + i*32], o;
        o.x = (v[i].x-mu)*inv*gg.x + bb.x;
        o.y = (v[i].y-mu)*inv*gg.y + bb.y;
        o.z = (v[i].z-mu)*inv*gg.z + bb.z;
        o.w = (v[i].w-mu)*inv*gg.w + bb.w;
        if (HOUT){
            __half2* yr = reinterpret_cast<__half2*>(reinterpret_cast<__half*>(yv) + (size_t)row*DMOD);
            yr[2*(lane+i*32)]   = __floats2half2_rn(o.x, o.y);
            yr[2*(lane+i*32)+1] = __floats2half2_rn(o.z, o.w);
        } else {
            float4* yr = reinterpret_cast<float4*>(reinterpret_cast<float*>(yv) + (size_t)row*DMOD);
            yr[lane + i*32] = o;
        }
    }
}

// ---------------- attention: qkv fp32 in, half out ----------------
__global__ void attn_k(){
    int blk = blockIdx.x;
    int n = blk / 12, head = blk % 12;
    __shared__ float ks[TTOK][65];
    __shared__ float vs[TTOK][65];
    __shared__ float qrow[8][64];
    __shared__ float pb[8][TTOK];
    int tid = threadIdx.x, lane = tid & 31, w = tid >> 5;
    const size_t base = (size_t)n*TTOK*3*DMOD;
    for (int e = tid; e < TTOK*64; e += 256){
        int t = e >> 6, d = e & 63;
        ks[t][d] = g_qkv[base + (size_t)t*3*DMOD + DMOD   + head*64 + d];
        vs[t][d] = g_qkv[base + (size_t)t*3*DMOD + 2*DMOD + head*64 + d];
    }
    __syncthreads();
    for (int i = w; i < TTOK; i += 8){
        qrow[w][lane]    = g_qkv[base + (size_t)i*3*DMOD + head*64 + lane];
        qrow[w][lane+32] = g_qkv[base + (size_t)i*3*DMOD + head*64 + 32 + lane];
        __syncwarp();
        float lmax = -1e30f;
        for (int j = lane; j <= i; j += 32){
            float s = 0.f;
            #pragma unroll 16
            for (int d = 0; d < 64; d++) s = fmaf(qrow[w][d], ks[j][d], s);
            s *= 0.125f;
            pb[w][j] = s;
            lmax = fmaxf(lmax, s);
        }
        for (int o = 16; o; o >>= 1) lmax = fmaxf(lmax, __shfl_xor_sync(0xffffffffu, lmax, o));
        float lsum = 0.f;
        for (int j = lane; j <= i; j += 32){
            float p = expf(pb[w][j] - lmax);
            pb[w][j] = p;
            lsum += p;
        }
        for (int o = 16; o; o >>= 1) lsum += __shfl_xor_sync(0xffffffffu, lsum, o);
        float inv = 1.f/lsum;
        __syncwarp();
        #pragma unroll
        for (int du = 0; du < 2; du++){
            int d = lane + du*32;
            float o = 0.f;
            for (int j = 0; j <= i; j++) o = fmaf(pb[w][j], vs[j][d], o);
            g_ob[((size_t)n*TTOK + i)*DMOD + head*64 + d] = __float2half(o*inv);
        }
        __syncwarp();
    }
}

// ---------------- final: sum split-K chunks + channels, denormalize -------
__global__ void final_k(const float* __restrict__ outb, float* __restrict__ out){
    int n = blockIdx.x, b = n/7, m = n%7;
    for (int t = threadIdx.x; t < PREDL; t += blockDim.x){
        float v = 3.f*outb[t];
        #pragma unroll
        for (int z = 0; z < SPLITZ; z++){
            const float* p = g_osp + (size_t)z*NSER*3*PREDL;
            v += p[(size_t)(n*3+0)*PREDL + t]
               + p[(size_t)(n*3+1)*PREDL + t]
               + p[(size_t)(n*3+2)*PREDL + t];
        }
        out[(size_t)b*PREDL*7 + (size_t)t*7 + m] = v*g_std[n] + g_mean[n];
    }
}

__global__ void rsim_k(float* __restrict__ out, int out_size){
    if (out_size > 64*PREDL*7) out[64*PREDL*7] = g_rsim * (1.f/NSER);
}

// ---------------- host ----------------
template <typename T, size_t S>
static void* symaddr(T (&arr)[S]){ void* p = nullptr; cudaGetSymbolAddress(&p, arr); return p; }

extern "C" void kernel_launch(void* const* d_in, const int* in_sizes, int n_in,
                              void* d_out, int out_size){
    int s = (n_in >= 2 && in_sizes[1] == 1) ? 1 : 0;
    const float* x    = (const float*)d_in[0];
    const float* in_w = (const float*)d_in[1+s];
    const float* in_b = (const float*)d_in[2+s];
    const float* pk   = (const float*)d_in[3+s];
    const float* wpe  = (const float*)d_in[4+s];
    const float* ln1g = (const float*)d_in[5+s];
    const float* ln1b = (const float*)d_in[6+s];
    const float* qkvw = (const float*)d_in[7+s];
    const float* qkvb = (const float*)d_in[8+s];
    const float* aw   = (const float*)d_in[9+s];
    const float* ab   = (const float*)d_in[10+s];
    const float* ln2g = (const float*)d_in[11+s];
    const float* ln2b = (const float*)d_in[12+s];
    const float* fcw  = (const float*)d_in[13+s];
    const float* fcb  = (const float*)d_in[14+s];
    const float* pw   = (const float*)d_in[15+s];
    const float* pbb  = (const float*)d_in[16+s];
    const float* lnfg = (const float*)d_in[17+s];
    const float* lnfb = (const float*)d_in[18+s];
    const float* outw = (const float*)d_in[19+s];
    const float* outb = (const float*)d_in[20+s];
    float* out = (float*)d_out;

    float*  p_h    = (float*) symaddr(g_h);
    __half* p_a    = (__half*)symaddr(g_a);
    float*  p_af   = (float*) symaddr(g_af);
    float*  p_qkv  = (float*) symaddr(g_qkv);
    __half* p_ob   = (__half*)symaddr(g_ob);
    __half* p_mlp  = (__half*)symaddr(g_mlp);
    float*  p_tok  = (float*) symaddr(g_tok);
    float*  p_xq   = (float*) symaddr(g_xq);
    float*  p_keyn = (float*) symaddr(g_keyn);
    float*  p_sim  = (float*) symaddr(g_sim);
    float*  p_osp  = (float*) symaddr(g_osp);
    __half* p_wT   = (__half*)symaddr(g_wT);

    const int SMB = SM_FLOATS*4;
    static bool attr_done = false;
    if (!attr_done){
        cudaFuncSetAttribute(headgemm_k, cudaFuncAttributeMaxDynamicSharedMemorySize, SMB);
        cudaFuncSetAttribute(hgemm_k<0,false,false>, cudaFuncAttributeMaxDynamicSharedMemorySize, H_SMEMB);
        cudaFuncSetAttribute(hgemm_k<0,true ,false>, cudaFuncAttributeMaxDynamicSharedMemorySize, H_SMEMB);
        cudaFuncSetAttribute(hgemm_k<1,false,true >, cudaFuncAttributeMaxDynamicSharedMemorySize, H_SMEMB);
        attr_done = true;
    }

    zero_k<<<1,1>>>();
    norm_k<<<NSER,256>>>(x);
    dec_k<<<NSER,256>>>();
    patch_k<<<NSER,256>>>();

    // transpose weights to half [N,K]
    for (int L = 0; L < NLAYER; L++){
        __half* qkvT = p_wT + (size_t)L*WL;
        __half* awT  = qkvT + 1769472;
        __half* fcT  = awT  + 589824;
        __half* pwT  = fcT  + 2359296;
        transp_k<<<dim3(2304/32, 768/32), dim3(32,8)>>>(qkvw + (size_t)L*DMOD*3*DMOD, qkvT, 768, 2304);
        transp_k<<<dim3( 768/32, 768/32), dim3(32,8)>>>(aw   + (size_t)L*DMOD*DMOD,   awT,  768, 768);
        transp_k<<<dim3(3072/32, 768/32), dim3(32,8)>>>(fcw  + (size_t)L*DMOD*4*DMOD, fcT,  768, 3072);
        transp_k<<<dim3( 768/32,3072/32), dim3(32,8)>>>(pw   + (size_t)L*4*DMOD*DMOD, pwT, 3072, 768);
    }

    // patch embedding (fp32 exact: feeds top-k) -> h rows 4..67 (REMAP)
    gemm_k<false,0,false,true><<<dim3(DMOD/64, NSER*PNUM/64),256>>>(p_tok, in_w, in_b, p_h, NSER*PNUM, DMOD, 48);

    keynorm_k<<<POOLN,256>>>(pk);
    xq_k<<<NSER,256>>>();
    gemm_k<true,0,false,false><<<dim3((POOLN+63)/64, NSER/64),256>>>(p_xq, p_keyn, (const float*)nullptr, p_sim, NSER, POOLN, DMOD);
    topk_k<<<NSER,256>>>();
    wpe_k<<<(unsigned)(((size_t)NTOK*DMOD + 255)/256),256>>>(wpe);

    const int MB = NTOK/128;   // 238
    for (int L = 0; L < NLAYER; L++){
        __half* qkvT = p_wT + (size_t)L*WL;
        __half* awT  = qkvT + 1769472;
        __half* fcT  = awT  + 589824;
        __half* pwT  = fcT  + 2359296;
        ln_k<true><<<NTOK/8,256>>>(p_h, ln1g + (size_t)L*DMOD, ln1b + (size_t)L*DMOD, p_a);
        hgemm_k<0,false,false><<<dim3(3*DMOD/128, MB),256,H_SMEMB>>>(p_a, qkvT, qkvb + (size_t)L*3*DMOD, p_qkv, NTOK, 3*DMOD, DMOD);
        attn_k<<<NSER*12,256>>>();
        hgemm_k<0,true ,false><<<dim3(DMOD/128, MB),256,H_SMEMB>>>(p_ob, awT, ab + (size_t)L*DMOD, p_h, NTOK, DMOD, DMOD);
        ln_k<true><<<NTOK/8,256>>>(p_h, ln2g + (size_t)L*DMOD, ln2b + (size_t)L*DMOD, p_a);
        hgemm_k<1,false,true ><<<dim3(4*DMOD/128, MB),256,H_SMEMB>>>(p_a, fcT, fcb + (size_t)L*4*DMOD, p_mlp, NTOK, 4*DMOD, DMOD);
        hgemm_k<0,true ,false><<<dim3(DMOD/128, MB),256,H_SMEMB>>>(p_mlp, pwT, pbb + (size_t)L*DMOD, p_h, NTOK, DMOD, 3072);
    }

    ln_k<false><<<NTOK/8,256>>>(p_h, lnfg, lnfb, p_af);
    // output head: M=1344, N=96, K=17408, split-K 16 (chunk 1088)
    headgemm_k<<<dim3(1, (NSER*3+127)/128, SPLITZ),256,SMB>>>(p_af, outw, p_osp, NSER*3, PREDL, TTOK*DMOD/3);
    final_k<<<NSER,96>>>(outb, out);
    rsim_k<<<1,1>>>(out, out_size);
}

// round 6
// speedup vs baseline: 6.4764x; 1.1273x over previous
#include <cuda_runtime.h>
#include <cuda_fp16.h>
#include <math.h>
#include <stdint.h>

#define NSER 448
#define LSEQ 512
#define TTOK 68
#define DMOD 768
#define NTOK (NSER*TTOK)       // 30464
#define PNUM 64
#define POOLN 1000
#define PREDL 96
#define NLAYER 6
#define SPLITZ 16

// ---------------- scratch (device globals; no allocations) ----------------
__device__ float  g_xn  [NSER*LSEQ];
__device__ float  g_mean[NSER];
__device__ float  g_std [NSER];
__device__ float  g_dec [NSER*3*LSEQ];
__device__ float  g_tok [NSER*PNUM*48];
__device__ float  g_h   [(size_t)NTOK*DMOD];
__device__ __half g_a   [(size_t)NTOK*DMOD];     // LN outputs (half, GEMM A)
__device__ float  g_af  [(size_t)NTOK*DMOD];     // final LN output (fp32, head)
__device__ __half g_qkvh[(size_t)NTOK*3*DMOD];   // half qkv
__device__ __half g_ob  [(size_t)NTOK*DMOD];
__device__ __half g_mlp [(size_t)NTOK*4*DMOD];
__device__ float  g_xq  [NSER*DMOD];
__device__ float  g_keyn[POOLN*DMOD];
__device__ float  g_sim [NSER*POOLN];
__device__ float  g_osp [(size_t)SPLITZ*NSER*3*PREDL];
__device__ float  g_rsim;
// transposed half weights per layer: qkvT, awT, fcT, pwT
#define WL 7077888u
__device__ __half g_wT  [(size_t)NLAYER*WL];

__device__ __forceinline__ float gelu_tanh(float x){
    float c = 0.7978845608028654f;
    float t = tanhf(c*(x + 0.044715f*x*x*x));
    return 0.5f*x*(1.f+t);
}

__device__ __forceinline__ unsigned f2tf(float x){
    unsigned r; asm("cvt.rna.tf32.f32 %0, %1;" : "=r"(r) : "f"(x)); return r;
}

__device__ __forceinline__ void mma8(float* c, const unsigned* a, const unsigned* b){
    asm volatile("mma.sync.aligned.m16n8k8.row.col.f32.tf32.tf32.f32 "
        "{%0,%1,%2,%3}, {%4,%5,%6,%7}, {%8,%9}, {%0,%1,%2,%3};"
        : "+f"(c[0]),"+f"(c[1]),"+f"(c[2]),"+f"(c[3])
        : "r"(a[0]),"r"(a[1]),"r"(a[2]),"r"(a[3]), "r"(b[0]),"r"(b[1]));
}

__device__ __forceinline__ void mma16(float* c, const unsigned* a, const unsigned* b){
    asm volatile("mma.sync.aligned.m16n8k16.row.col.f32.f16.f16.f32 "
        "{%0,%1,%2,%3}, {%4,%5,%6,%7}, {%8,%9}, {%0,%1,%2,%3};"
        : "+f"(c[0]),"+f"(c[1]),"+f"(c[2]),"+f"(c[3])
        : "r"(a[0]),"r"(a[1]),"r"(a[2]),"r"(a[3]), "r"(b[0]),"r"(b[1]));
}

__device__ __forceinline__ void cpasyncF(float* dst, const float* src, bool pred){
    unsigned sa = (unsigned)__cvta_generic_to_shared(dst);
    int sz = pred ? 16 : 0;
    asm volatile("cp.async.cg.shared.global [%0], [%1], 16, %2;" :: "r"(sa), "l"(src), "r"(sz));
}
__device__ __forceinline__ void cpasyncH(__half* dst, const __half* src){
    unsigned sa = (unsigned)__cvta_generic_to_shared(dst);
    asm volatile("cp.async.cg.shared.global [%0], [%1], 16;" :: "r"(sa), "l"(src));
}
__device__ __forceinline__ void cp_commit(){ asm volatile("cp.async.commit_group;"); }
template<int N> __device__ __forceinline__ void cp_wait(){ asm volatile("cp.async.wait_group %0;"::"n"(N)); }

__device__ __forceinline__ unsigned packh2(float a, float b){
    __half2 h = __floats2half2_rn(a, b);
    return *reinterpret_cast<unsigned*>(&h);
}

// ---------------- RevIN stats + normalize ----------------
__global__ void norm_k(const float* __restrict__ x){
    int n = blockIdx.x, b = n/7, m = n%7, tid = threadIdx.x;
    __shared__ float xs[LSEQ];
    __shared__ float red[256];
    for (int l = tid; l < LSEQ; l += 256) xs[l] = x[((size_t)b*LSEQ + l)*7 + m];
    __syncthreads();
    float s = xs[tid] + xs[tid+256];
    red[tid] = s; __syncthreads();
    for (int o = 128; o; o >>= 1){ if (tid < o) red[tid] += red[tid+o]; __syncthreads(); }
    float mu = red[0] * (1.f/LSEQ);
    __syncthreads();
    float d0 = xs[tid]-mu, d1 = xs[tid+256]-mu;
    red[tid] = d0*d0 + d1*d1; __syncthreads();
    for (int o = 128; o; o >>= 1){ if (tid < o) red[tid] += red[tid+o]; __syncthreads(); }
    float sd = sqrtf(red[0]*(1.f/LSEQ) + 1e-5f);
    if (tid == 0){ g_mean[n] = mu; g_std[n] = sd; }
    float inv = 1.f/sd;
    g_xn[n*LSEQ + tid]       = d0*inv;
    g_xn[n*LSEQ + 256 + tid] = d1*inv;
}

// ---------------- decomposition ----------------
__global__ void dec_k(){
    int n = blockIdx.x, tid = threadIdx.x;
    __shared__ float xs[LSEQ];
    __shared__ float valid[489];
    __shared__ float det[LSEQ];
    __shared__ float ph[24];
    for (int l = tid; l < LSEQ; l += 256) xs[l] = g_xn[n*LSEQ + l];
    if (tid < 24) ph[tid] = 0.f;
    __syncthreads();
    for (int i = tid; i < 489; i += 256){
        float s = 0.f;
        #pragma unroll
        for (int k = 0; k < 24; k++) s += xs[i+k];
        valid[i] = s * (1.f/24.f);
    }
    __syncthreads();
    for (int l = tid; l < LSEQ; l += 256){
        int vi = l - 12; vi = vi < 0 ? 0 : (vi > 488 ? 488 : vi);
        float tr = valid[vi];
        float dt = xs[l] - tr;
        det[l] = dt;
        atomicAdd(&ph[l % 24], dt);
        g_dec[((size_t)n*3 + 0)*LSEQ + l] = tr;
    }
    __syncthreads();
    for (int l = tid; l < LSEQ; l += 256){
        int p = l % 24;
        float cnt = (p < 8) ? 22.f : 21.f;
        float se = ph[p] / cnt;
        g_dec[((size_t)n*3 + 1)*LSEQ + l] = se;
        g_dec[((size_t)n*3 + 2)*LSEQ + l] = det[l] - se;
    }
}

// ---------------- patch extraction ----------------
__global__ void patch_k(){
    int n = blockIdx.x, tid = threadIdx.x;
    for (int e = tid; e < PNUM*48; e += 256){
        int p = e/48, rem = e%48, c = rem/16, j = rem%16;
        int l = p*8 + j; if (l > LSEQ-1) l = LSEQ-1;
        g_tok[(size_t)n*PNUM*48 + e] = g_dec[((size_t)n*3 + c)*LSEQ + l];
    }
}

// ---------------- weight transpose to half: W[K,N] -> WT[N,K] -------------
__global__ void transp_k(const float* __restrict__ W, __half* __restrict__ WT, int K, int N){
    __shared__ float t[32][33];
    int bx = blockIdx.x*32, by = blockIdx.y*32;
    int x = threadIdx.x, y = threadIdx.y;   // 32 x 8
    #pragma unroll
    for (int i = 0; i < 4; i++){
        int r = by + y*4 + i;
        t[y*4+i][x] = W[(size_t)r*N + bx + x];
    }
    __syncthreads();
    #pragma unroll
    for (int i = 0; i < 4; i++){
        int rn = bx + y*4 + i;
        WT[(size_t)rn*K + by + x] = __float2half(t[x][y*4+i]);
    }
}

// ---------------- generic fp32 SIMT GEMM (precision-critical small paths) --
template<bool TRANSB, int ACT, bool RESID, bool REMAP>
__global__ void gemm_k(const float* __restrict__ A, const float* __restrict__ B,
                       const float* __restrict__ bias, float* __restrict__ C,
                       int M, int N, int K){
    __shared__ float As[16][68];
    __shared__ float Bs[16][68];
    int tid = threadIdx.x;
    int tx = tid & 15, ty = tid >> 4;
    int row0 = blockIdx.y * 64, col0 = blockIdx.x * 64;
    float acc[4][4] = {};
    for (int k0 = 0; k0 < K; k0 += 16){
        {
            int r  = tid >> 2;
            int c4 = (tid & 3) * 4;
            float4 v = *reinterpret_cast<const float4*>(&A[(size_t)(row0 + r)*K + k0 + c4]);
            As[c4+0][r] = v.x; As[c4+1][r] = v.y; As[c4+2][r] = v.z; As[c4+3][r] = v.w;
        }
        if (!TRANSB){
            int kk = tid >> 4;
            int c4 = (tid & 15) * 4;
            int col = col0 + c4;
            float4 v = make_float4(0.f,0.f,0.f,0.f);
            if (col < N) v = *reinterpret_cast<const float4*>(&B[(size_t)(k0+kk)*N + col]);
            Bs[kk][c4+0] = v.x; Bs[kk][c4+1] = v.y; Bs[kk][c4+2] = v.z; Bs[kk][c4+3] = v.w;
        } else {
            int nn = tid >> 2;
            int c4 = (tid & 3) * 4;
            int col = col0 + nn;
            float4 v = make_float4(0.f,0.f,0.f,0.f);
            if (col < N) v = *reinterpret_cast<const float4*>(&B[(size_t)col*K + k0 + c4]);
            Bs[c4+0][nn] = v.x; Bs[c4+1][nn] = v.y; Bs[c4+2][nn] = v.z; Bs[c4+3][nn] = v.w;
        }
        __syncthreads();
        #pragma unroll
        for (int kk = 0; kk < 16; kk++){
            float a[4], b[4];
            #pragma unroll
            for (int i = 0; i < 4; i++) a[i] = As[kk][ty*4+i];
            #pragma unroll
            for (int j = 0; j < 4; j++) b[j] = Bs[kk][tx*4+j];
            #pragma unroll
            for (int i = 0; i < 4; i++)
                #pragma unroll
                for (int j = 0; j < 4; j++) acc[i][j] = fmaf(a[i], b[j], acc[i][j]);
        }
        __syncthreads();
    }
    #pragma unroll
    for (int i = 0; i < 4; i++){
        int r = row0 + ty*4 + i;
        size_t orow = REMAP ? (size_t)((r >> 6)*TTOK + 4 + (r & 63)) : (size_t)r;
        #pragma unroll
        for (int j = 0; j < 4; j++){
            int col = col0 + tx*4 + j;
            if (col < N){
                float v = acc[i][j];
                if (bias) v += bias[col];
                if (ACT == 1) v = gelu_tanh(v);
                size_t idx = orow*(size_t)N + col;
                if (RESID) C[idx] += v; else C[idx] = v;
            }
        }
    }
}

// ================= fp16 tensor-core GEMM ==================================
#define HST 40
#define H_STAGE (128*HST)
#define H_SMEMB (6*H_STAGE*2)

template<int ACT, bool RESID, bool HOUT>
__global__ __launch_bounds__(256, 2) void hgemm_k(
        const __half* __restrict__ A, const __half* __restrict__ BT,
        const float* __restrict__ bias, void* __restrict__ Cv,
        int M, int N, int K){
    extern __shared__ __half hsm[];
    __half* smA = hsm;
    __half* smB = hsm + 3*H_STAGE;
    int tid = threadIdx.x;
    int warp = tid >> 5, lane = tid & 31;
    int wm = warp >> 2, wn = warp & 3;
    int g = lane >> 2, tg = lane & 3;
    int row0 = blockIdx.y * 128, col0 = blockIdx.x * 128;

    float acc[4][4][4];
    #pragma unroll
    for (int i=0;i<4;i++) for (int j=0;j<4;j++) for (int q=0;q<4;q++) acc[i][j][q]=0.f;

    #define ISSUE_H(T, S) { \
        __half* as = smA + (S)*H_STAGE; \
        __half* bs = smB + (S)*H_STAGE; \
        const __half* Ab = A + (size_t)row0*K + (T)*32; \
        const __half* Bb = BT + (size_t)col0*K + (T)*32; \
        _Pragma("unroll") \
        for (int i=0;i<2;i++){ \
            int idx = tid + i*256; int r = idx>>2, ch = idx&3; \
            cpasyncH(&as[r*HST + ch*8], &Ab[(size_t)r*K + ch*8]); \
        } \
        _Pragma("unroll") \
        for (int i=0;i<2;i++){ \
            int idx = tid + i*256; int r = idx>>2, ch = idx&3; \
            cpasyncH(&bs[r*HST + ch*8], &Bb[(size_t)r*K + ch*8]); \
        } \
        cp_commit(); }

    int nt = K >> 5;
    ISSUE_H(0, 0);
    ISSUE_H(1, 1);

    int stage = 0;
    for (int kt = 0; kt < nt; kt++){
        if (kt == nt-1) cp_wait<0>(); else cp_wait<1>();
        __syncthreads();
        if (kt + 2 < nt){
            int s2 = stage + 2; if (s2 >= 3) s2 -= 3;
            ISSUE_H(kt+2, s2);
        }
        const __half* as = smA + stage*H_STAGE;
        const __half* bs = smB + stage*H_STAGE;
        #pragma unroll
        for (int ks = 0; ks < 32; ks += 16){
            unsigned af[4][4], bf[4][2];
            #pragma unroll
            for (int mt = 0; mt < 4; mt++){
                int r = wm*64 + mt*16 + g;
                int base = r*HST + ks + 2*tg;
                af[mt][0] = *reinterpret_cast<const unsigned*>(&as[base]);
                af[mt][1] = *reinterpret_cast<const unsigned*>(&as[base + 8*HST]);
                af[mt][2] = *reinterpret_cast<const unsigned*>(&as[base + 8]);
                af[mt][3] = *reinterpret_cast<const unsigned*>(&as[base + 8*HST + 8]);
            }
            #pragma unroll
            for (int nt2 = 0; nt2 < 4; nt2++){
                int rn = wn*32 + nt2*8 + g;
                int base = rn*HST + ks + 2*tg;
                bf[nt2][0] = *reinterpret_cast<const unsigned*>(&bs[base]);
                bf[nt2][1] = *reinterpret_cast<const unsigned*>(&bs[base + 8]);
            }
            #pragma unroll
            for (int mt = 0; mt < 4; mt++)
                #pragma unroll
                for (int nt2 = 0; nt2 < 4; nt2++)
                    mma16(acc[mt][nt2], af[mt], bf[nt2]);
        }
        stage++; if (stage >= 3) stage -= 3;
    }
    #undef ISSUE_H

    #pragma unroll
    for (int mt = 0; mt < 4; mt++){
        int rbase = row0 + wm*64 + mt*16;
        #pragma unroll
        for (int nt2 = 0; nt2 < 4; nt2++){
            int cbase = col0 + wn*32 + nt2*8 + tg*2;
            float b0 = bias[cbase], b1 = bias[cbase+1];
            #pragma unroll
            for (int hh = 0; hh < 2; hh++){
                int rr = rbase + g + hh*8;
                float v0 = acc[mt][nt2][hh*2]   + b0;
                float v1 = acc[mt][nt2][hh*2+1] + b1;
                if (ACT == 1){ v0 = gelu_tanh(v0); v1 = gelu_tanh(v1); }
                size_t gi = (size_t)rr*N + cbase;
                if (HOUT){
                    __half2* p = reinterpret_cast<__half2*>(reinterpret_cast<__half*>(Cv) + gi);
                    *p = __floats2half2_rn(v0, v1);
                } else {
                    float* C = reinterpret_cast<float*>(Cv);
                    if (RESID){
                        float2 c = *reinterpret_cast<float2*>(&C[gi]);
                        c.x += v0; c.y += v1;
                        *reinterpret_cast<float2*>(&C[gi]) = c;
                    } else {
                        *reinterpret_cast<float2*>(&C[gi]) = make_float2(v0, v1);
                    }
                }
            }
        }
    }
}

// ---------------- legacy tf32 tensor GEMM (output head, split-K) ----------
#define AS_ST 36
#define BS_ST 136
#define A_STAGE (128*AS_ST)
#define B_STAGE (32*BS_ST)
#define SM_FLOATS (3*(A_STAGE+B_STAGE))

__global__ __launch_bounds__(256, 2) void headgemm_k(
        const float* __restrict__ A, const float* __restrict__ B,
        float* __restrict__ C, int M, int N, int K){
    extern __shared__ float sm[];
    float* smA = sm;
    float* smB = sm + 3*A_STAGE;
    int tid = threadIdx.x;
    int warp = tid >> 5, lane = tid & 31;
    int wm = warp >> 2, wn = warp & 3;
    int g = lane >> 2, tg = lane & 3;
    int row0 = blockIdx.y * 128, col0 = blockIdx.x * 128;

    int Kc   = K / gridDim.z;
    int kbeg = blockIdx.z * Kc;
    int nt   = Kc >> 5;

    float acc[4][4][4];
    #pragma unroll
    for (int i=0;i<4;i++) for (int j=0;j<4;j++) for (int q=0;q<4;q++) acc[i][j][q]=0.f;

    #define ISSUE_T(T, S) { \
        int k0 = kbeg + (T)*32; \
        float* as = smA + (S)*A_STAGE; \
        float* bs = smB + (S)*B_STAGE; \
        _Pragma("unroll") \
        for (int i=0;i<4;i++){ \
            int idx = tid + i*256; int r = idx>>3; int ch=(idx&7)<<2; \
            int grow = row0 + r; bool p = grow < M; int gr = p ? grow : (M-1); \
            cpasyncF(&as[r*AS_ST + ch], &A[(size_t)gr*K + k0 + ch], p); \
        } \
        _Pragma("unroll") \
        for (int i=0;i<4;i++){ \
            int idx = tid + i*256; int kk = idx>>5; int c4=(idx&31)<<2; \
            int gcol = col0 + c4; bool p = gcol < N; int gc = p ? gcol : 0; \
            cpasyncF(&bs[kk*BS_ST + c4], &B[(size_t)(k0+kk)*N + gc], p); \
        } \
        cp_commit(); }

    ISSUE_T(0, 0);
    ISSUE_T(1, 1);

    int stage = 0;
    for (int kt = 0; kt < nt; kt++){
        if (kt == nt-1) cp_wait<0>(); else cp_wait<1>();
        __syncthreads();
        if (kt + 2 < nt){
            int s2 = stage + 2; if (s2 >= 3) s2 -= 3;
            ISSUE_T(kt+2, s2);
        }
        const float* as = smA + stage*A_STAGE;
        const float* bs = smB + stage*B_STAGE;
        #pragma unroll
        for (int ks = 0; ks < 32; ks += 8){
            unsigned af[4][4], bf[4][2];
            #pragma unroll
            for (int mt = 0; mt < 4; mt++){
                int r = wm*64 + mt*16 + g;
                af[mt][0] = f2tf(as[r*AS_ST + ks+tg]);
                af[mt][1] = f2tf(as[(r+8)*AS_ST + ks+tg]);
                af[mt][2] = f2tf(as[r*AS_ST + ks+tg+4]);
                af[mt][3] = f2tf(as[(r+8)*AS_ST + ks+tg+4]);
            }
            #pragma unroll
            for (int nt2 = 0; nt2 < 4; nt2++){
                int c = wn*32 + nt2*8 + g;
                bf[nt2][0] = f2tf(bs[(ks+tg)*BS_ST + c]);
                bf[nt2][1] = f2tf(bs[(ks+tg+4)*BS_ST + c]);
            }
            #pragma unroll
            for (int mt = 0; mt < 4; mt++)
                #pragma unroll
                for (int nt2 = 0; nt2 < 4; nt2++)
                    mma8(acc[mt][nt2], af[mt], bf[nt2]);
        }
        stage++; if (stage >= 3) stage -= 3;
        __syncthreads();
    }
    #undef ISSUE_T

    float* Cout = C + (size_t)blockIdx.z*M*N;
    #pragma unroll
    for (int mt = 0; mt < 4; mt++){
        int rbase = row0 + wm*64 + mt*16;
        #pragma unroll
        for (int nt2 = 0; nt2 < 4; nt2++){
            int cbase = col0 + wn*32 + nt2*8 + tg*2;
            #pragma unroll
            for (int half2_ = 0; half2_ < 2; half2_++){
                int rr = rbase + g + half2_*8;
                if (rr < M){
                    #pragma unroll
                    for (int jj = 0; jj < 2; jj++){
                        int cc = cbase + jj;
                        if (cc < N) Cout[(size_t)rr*N + cc] = acc[mt][nt2][half2_*2+jj];
                    }
                }
            }
        }
    }
}

// ---------------- l2-normalize prompt keys ----------------
__global__ void keynorm_k(const float* __restrict__ pk){
    int r = blockIdx.x, tid = threadIdx.x;
    __shared__ float red[256];
    float v0 = pk[(size_t)r*DMOD + tid], v1 = pk[(size_t)r*DMOD + 256 + tid], v2 = pk[(size_t)r*DMOD + 512 + tid];
    red[tid] = v0*v0 + v1*v1 + v2*v2; __syncthreads();
    for (int o = 128; o; o >>= 1){ if (tid < o) red[tid] += red[tid+o]; __syncthreads(); }
    float inv = rsqrtf(fmaxf(red[0], 1e-12f));
    g_keyn[(size_t)r*DMOD + tid]       = v0*inv;
    g_keyn[(size_t)r*DMOD + 256 + tid] = v1*inv;
    g_keyn[(size_t)r*DMOD + 512 + tid] = v2*inv;
}

// ---------------- xq ----------------
__global__ void xq_k(){
    int n = blockIdx.x, tid = threadIdx.x;
    __shared__ float xs[DMOD];
    __shared__ float red[256];
    float ss = 0.f;
    for (int d = tid; d < DMOD; d += 256){
        float s = 0.f;
        for (int p = 0; p < PNUM; p++) s += g_h[((size_t)n*TTOK + 4 + p)*DMOD + d];
        s *= (1.f/PNUM);
        xs[d] = s; ss += s*s;
    }
    red[tid] = ss; __syncthreads();
    for (int o = 128; o; o >>= 1){ if (tid < o) red[tid] += red[tid+o]; __syncthreads(); }
    float inv = rsqrtf(fmaxf(red[0], 1e-12f));
    for (int d = tid; d < DMOD; d += 256) g_xq[(size_t)n*DMOD + d] = xs[d]*inv;
}

// ---------------- top-k ----------------
__global__ void topk_k(){
    int n = blockIdx.x, tid = threadIdx.x;
    __shared__ float bv[256];
    __shared__ int   bi[256];
    __shared__ int   chosen[4];
    float rs = 0.f;
    for (int r = 0; r < 4; r++){
        float best = -1e30f; int besti = 1 << 30;
        for (int j = tid; j < POOLN; j += 256){
            bool skip = false;
            for (int c = 0; c < r; c++) if (chosen[c] == j) skip = true;
            float v = g_sim[(size_t)n*POOLN + j];
            if (!skip && (v > best || (v == best && j < besti))){ best = v; besti = j; }
        }
        bv[tid] = best; bi[tid] = besti; __syncthreads();
        for (int o = 128; o; o >>= 1){
            if (tid < o){
                if (bv[tid+o] > bv[tid] || (bv[tid+o] == bv[tid] && bi[tid+o] < bi[tid])){
                    bv[tid] = bv[tid+o]; bi[tid] = bi[tid+o];
                }
            }
            __syncthreads();
        }
        if (tid == 0){ chosen[r] = bi[0]; rs += bv[0]; }
        __syncthreads();
    }
    for (int e = tid; e < 4*DMOD; e += 256){
        int k = e / DMOD, d = e % DMOD;
        g_h[((size_t)n*TTOK + k)*DMOD + d] = g_keyn[(size_t)chosen[k]*DMOD + d];
    }
    if (tid == 0) atomicAdd(&g_rsim, rs);
}

__global__ void zero_k(){ g_rsim = 0.f; }

// ---------------- add positional embedding ----------------
__global__ void wpe_k(const float* __restrict__ wpe){
    size_t i = (size_t)blockIdx.x*blockDim.x + threadIdx.x;
    if (i < (size_t)NTOK*DMOD){
        int tok = (int)(i / DMOD);
        int t = tok % TTOK;
        int d = (int)(i % DMOD);
        g_h[i] += wpe[(size_t)t*DMOD + d];
    }
}

// ---------------- layernorm: warp per row; half or float out --------------
template<bool HOUT>
__global__ void ln_k(const float* __restrict__ x, const float* __restrict__ g,
                     const float* __restrict__ b, void* __restrict__ yv){
    int row  = blockIdx.x*8 + (threadIdx.x >> 5);
    int lane = threadIdx.x & 31;
    const float4* xr = reinterpret_cast<const float4*>(x + (size_t)row*DMOD);
    const float4* g4 = reinterpret_cast<const float4*>(g);
    const float4* b4 = reinterpret_cast<const float4*>(b);
    float4 v[6];
    float s = 0.f, sq = 0.f;
    #pragma unroll
    for (int i = 0; i < 6; i++){
        v[i] = xr[lane + i*32];
        s  += v[i].x + v[i].y + v[i].z + v[i].w;
        sq += v[i].x*v[i].x + v[i].y*v[i].y + v[i].z*v[i].z + v[i].w*v[i].w;
    }
    #pragma unroll
    for (int o = 16; o; o >>= 1){
        s  += __shfl_xor_sync(0xffffffffu, s,  o);
        sq += __shfl_xor_sync(0xffffffffu, sq, o);
    }
    float mu  = s * (1.f/DMOD);
    float var = sq * (1.f/DMOD) - mu*mu;
    float inv = rsqrtf(var + 1e-5f);
    #pragma unroll
    for (int i = 0; i < 6; i++){
        float4 gg = g4[lane + i*32], bb = b4[lane + i*32], o;
        o.x = (v[i].x-mu)*inv*gg.x + bb.x;
        o.y = (v[i].y-mu)*inv*gg.y + bb.y;
        o.z = (v[i].z-mu)*inv*gg.z + bb.z;
        o.w = (v[i].w-mu)*inv*gg.w + bb.w;
        if (HOUT){
            __half2* yr = reinterpret_cast<__half2*>(reinterpret_cast<__half*>(yv) + (size_t)row*DMOD);
            yr[2*(lane+i*32)]   = __floats2half2_rn(o.x, o.y);
            yr[2*(lane+i*32)+1] = __floats2half2_rn(o.z, o.w);
        } else {
            float4* yr = reinterpret_cast<float4*>(reinterpret_cast<float*>(yv) + (size_t)row*DMOD);
            yr[lane + i*32] = o;
        }
    }
}

// ---------------- attention: fp16 mma flash, block per (series, head) -----
// T padded to 80 (5 slabs x 16 rows, warp per slab), head dim 64.
#define QKS 72      // halves stride for qs/ks rows
#define VTS 88      // halves stride for vt rows (d-major)
__global__ __launch_bounds__(160) void attn_k(){
    int blk = blockIdx.x;
    int n = blk / 12, head = blk % 12;
    __shared__ __half qs[80*QKS];
    __shared__ __half ks[80*QKS];
    __shared__ __half vt[64*VTS];
    int tid = threadIdx.x, w = tid >> 5, lane = tid & 31;
    int g = lane >> 2, tg = lane & 3;

    // zero smem (covers pads)
    for (int i = tid; i < 80*QKS/2; i += 160){
        reinterpret_cast<float*>(qs)[i] = 0.f;
        reinterpret_cast<float*>(ks)[i] = 0.f;
    }
    for (int i = tid; i < 64*VTS/2; i += 160) reinterpret_cast<float*>(vt)[i] = 0.f;
    __syncthreads();

    const __half* qkv = g_qkvh + (size_t)n*TTOK*3*DMOD + head*64;
    for (int idx = tid; idx < TTOK*32; idx += 160){
        int t = idx >> 5, c = (idx & 31)*2;
        __half2 q2 = *reinterpret_cast<const __half2*>(qkv + (size_t)t*3*DMOD + c);
        __half2 k2 = *reinterpret_cast<const __half2*>(qkv + (size_t)t*3*DMOD + DMOD + c);
        __half2 v2 = *reinterpret_cast<const __half2*>(qkv + (size_t)t*3*DMOD + 2*DMOD + c);
        *reinterpret_cast<__half2*>(qs + t*QKS + c) = q2;
        *reinterpret_cast<__half2*>(ks + t*QKS + c) = k2;
        vt[c*VTS + t]     = __low2half(v2);
        vt[(c+1)*VTS + t] = __high2half(v2);
    }
    __syncthreads();

    int rb = w*16 + g;
    // S = Q K^T : 10 n-tiles of 8 keys, 4 k-chunks of 16 dims
    float sacc[10][4];
    #pragma unroll
    for (int i = 0; i < 10; i++) for (int j = 0; j < 4; j++) sacc[i][j] = 0.f;
    #pragma unroll
    for (int kc = 0; kc < 4; kc++){
        unsigned af[4];
        int base = rb*QKS + kc*16 + 2*tg;
        af[0] = *reinterpret_cast<const unsigned*>(&qs[base]);
        af[1] = *reinterpret_cast<const unsigned*>(&qs[base + 8*QKS]);
        af[2] = *reinterpret_cast<const unsigned*>(&qs[base + 8]);
        af[3] = *reinterpret_cast<const unsigned*>(&qs[base + 8*QKS + 8]);
        #pragma unroll
        for (int nt = 0; nt < 10; nt++){
            unsigned bf[2];
            int bb = (nt*8 + g)*QKS + kc*16 + 2*tg;
            bf[0] = *reinterpret_cast<const unsigned*>(&ks[bb]);
            bf[1] = *reinterpret_cast<const unsigned*>(&ks[bb + 8]);
            mma16(sacc[nt], af, bf);
        }
    }
    // scale + causal mask + softmax (rows R = rb + 8*hh; quad reduce over tg)
    float inv_[2];
    #pragma unroll
    for (int hh = 0; hh < 2; hh++){
        int R = rb + hh*8;
        float mx = -1e30f;
        #pragma unroll
        for (int nt = 0; nt < 10; nt++)
            #pragma unroll
            for (int jj = 0; jj < 2; jj++){
                int Cn = nt*8 + 2*tg + jj;
                float sv = sacc[nt][hh*2+jj] * 0.125f;
                sv = (Cn <= R) ? sv : -1e9f;
                sacc[nt][hh*2+jj] = sv;
                mx = fmaxf(mx, sv);
            }
        mx = fmaxf(mx, __shfl_xor_sync(0xffffffffu, mx, 1));
        mx = fmaxf(mx, __shfl_xor_sync(0xffffffffu, mx, 2));
        float sm = 0.f;
        #pragma unroll
        for (int nt = 0; nt < 10; nt++)
            #pragma unroll
            for (int jj = 0; jj < 2; jj++){
                float p = expf(sacc[nt][hh*2+jj] - mx);
                sacc[nt][hh*2+jj] = p;
                sm += p;
            }
        sm += __shfl_xor_sync(0xffffffffu, sm, 1);
        sm += __shfl_xor_sync(0xffffffffu, sm, 2);
        inv_[hh] = 1.f/sm;
    }
    // O = P V : 8 n-tiles of 8 dims, 5 k-chunks of 16 keys
    float oacc[8][4];
    #pragma unroll
    for (int i = 0; i < 8; i++) for (int j = 0; j < 4; j++) oacc[i][j] = 0.f;
    #pragma unroll
    for (int kc = 0; kc < 5; kc++){
        unsigned af[4];
        af[0] = packh2(sacc[2*kc][0],   sacc[2*kc][1]);
        af[1] = packh2(sacc[2*kc][2],   sacc[2*kc][3]);
        af[2] = packh2(sacc[2*kc+1][0], sacc[2*kc+1][1]);
        af[3] = packh2(sacc[2*kc+1][2], sacc[2*kc+1][3]);
        #pragma unroll
        for (int nt = 0; nt < 8; nt++){
            unsigned bf[2];
            int bb = (nt*8 + g)*VTS + kc*16 + 2*tg;
            bf[0] = *reinterpret_cast<const unsigned*>(&vt[bb]);
            bf[1] = *reinterpret_cast<const unsigned*>(&vt[bb + 8]);
            mma16(oacc[nt], af, bf);
        }
    }
    // write out (normalize by row sum)
    __half* ob = g_ob + (size_t)n*TTOK*DMOD + head*64;
    #pragma unroll
    for (int hh = 0; hh < 2; hh++){
        int R = rb + hh*8;
        if (R < TTOK){
            #pragma unroll
            for (int nt = 0; nt < 8; nt++){
                __half2 hv = __floats2half2_rn(oacc[nt][hh*2]*inv_[hh], oacc[nt][hh*2+1]*inv_[hh]);
                *reinterpret_cast<__half2*>(ob + (size_t)R*DMOD + nt*8 + 2*tg) = hv;
            }
        }
    }
}

// ---------------- final: sum split-K chunks + channels, denormalize -------
__global__ void final_k(const float* __restrict__ outb, float* __restrict__ out){
    int n = blockIdx.x, b = n/7, m = n%7;
    for (int t = threadIdx.x; t < PREDL; t += blockDim.x){
        float v = 3.f*outb[t];
        #pragma unroll
        for (int z = 0; z < SPLITZ; z++){
            const float* p = g_osp + (size_t)z*NSER*3*PREDL;
            v += p[(size_t)(n*3+0)*PREDL + t]
               + p[(size_t)(n*3+1)*PREDL + t]
               + p[(size_t)(n*3+2)*PREDL + t];
        }
        out[(size_t)b*PREDL*7 + (size_t)t*7 + m] = v*g_std[n] + g_mean[n];
    }
}

__global__ void rsim_k(float* __restrict__ out, int out_size){
    if (out_size > 64*PREDL*7) out[64*PREDL*7] = g_rsim * (1.f/NSER);
}

// ---------------- host ----------------
template <typename T, size_t S>
static void* symaddr(T (&arr)[S]){ void* p = nullptr; cudaGetSymbolAddress(&p, arr); return p; }

extern "C" void kernel_launch(void* const* d_in, const int* in_sizes, int n_in,
                              void* d_out, int out_size){
    int s = (n_in >= 2 && in_sizes[1] == 1) ? 1 : 0;
    const float* x    = (const float*)d_in[0];
    const float* in_w = (const float*)d_in[1+s];
    const float* in_b = (const float*)d_in[2+s];
    const float* pk   = (const float*)d_in[3+s];
    const float* wpe  = (const float*)d_in[4+s];
    const float* ln1g = (const float*)d_in[5+s];
    const float* ln1b = (const float*)d_in[6+s];
    const float* qkvw = (const float*)d_in[7+s];
    const float* qkvb = (const float*)d_in[8+s];
    const float* aw   = (const float*)d_in[9+s];
    const float* ab   = (const float*)d_in[10+s];
    const float* ln2g = (const float*)d_in[11+s];
    const float* ln2b = (const float*)d_in[12+s];
    const float* fcw  = (const float*)d_in[13+s];
    const float* fcb  = (const float*)d_in[14+s];
    const float* pw   = (const float*)d_in[15+s];
    const float* pbb  = (const float*)d_in[16+s];
    const float* lnfg = (const float*)d_in[17+s];
    const float* lnfb = (const float*)d_in[18+s];
    const float* outw = (const float*)d_in[19+s];
    const float* outb = (const float*)d_in[20+s];
    float* out = (float*)d_out;

    float*  p_h    = (float*) symaddr(g_h);
    __half* p_a    = (__half*)symaddr(g_a);
    float*  p_af   = (float*) symaddr(g_af);
    __half* p_qkv  = (__half*)symaddr(g_qkvh);
    __half* p_ob   = (__half*)symaddr(g_ob);
    __half* p_mlp  = (__half*)symaddr(g_mlp);
    float*  p_tok  = (float*) symaddr(g_tok);
    float*  p_xq   = (float*) symaddr(g_xq);
    float*  p_keyn = (float*) symaddr(g_keyn);
    float*  p_sim  = (float*) symaddr(g_sim);
    float*  p_osp  = (float*) symaddr(g_osp);
    __half* p_wT   = (__half*)symaddr(g_wT);

    const int SMB = SM_FLOATS*4;
    static bool attr_done = false;
    if (!attr_done){
        cudaFuncSetAttribute(headgemm_k, cudaFuncAttributeMaxDynamicSharedMemorySize, SMB);
        cudaFuncSetAttribute(hgemm_k<0,false,false>, cudaFuncAttributeMaxDynamicSharedMemorySize, H_SMEMB);
        cudaFuncSetAttribute(hgemm_k<0,true ,false>, cudaFuncAttributeMaxDynamicSharedMemorySize, H_SMEMB);
        cudaFuncSetAttribute(hgemm_k<1,false,true >, cudaFuncAttributeMaxDynamicSharedMemorySize, H_SMEMB);
        cudaFuncSetAttribute(hgemm_k<0,false,true >, cudaFuncAttributeMaxDynamicSharedMemorySize, H_SMEMB);
        attr_done = true;
    }

    zero_k<<<1,1>>>();
    norm_k<<<NSER,256>>>(x);
    dec_k<<<NSER,256>>>();
    patch_k<<<NSER,256>>>();

    for (int L = 0; L < NLAYER; L++){
        __half* qkvT = p_wT + (size_t)L*WL;
        __half* awT  = qkvT + 1769472;
        __half* fcT  = awT  + 589824;
        __half* pwT  = fcT  + 2359296;
        transp_k<<<dim3(2304/32, 768/32), dim3(32,8)>>>(qkvw + (size_t)L*DMOD*3*DMOD, qkvT, 768, 2304);
        transp_k<<<dim3( 768/32, 768/32), dim3(32,8)>>>(aw   + (size_t)L*DMOD*DMOD,   awT,  768, 768);
        transp_k<<<dim3(3072/32, 768/32), dim3(32,8)>>>(fcw  + (size_t)L*DMOD*4*DMOD, fcT,  768, 3072);
        transp_k<<<dim3( 768/32,3072/32), dim3(32,8)>>>(pw   + (size_t)L*4*DMOD*DMOD, pwT, 3072, 768);
    }

    // patch embedding (fp32 exact: feeds top-k) -> h rows 4..67 (REMAP)
    gemm_k<false,0,false,true><<<dim3(DMOD/64, NSER*PNUM/64),256>>>(p_tok, in_w, in_b, p_h, NSER*PNUM, DMOD, 48);

    keynorm_k<<<POOLN,256>>>(pk);
    xq_k<<<NSER,256>>>();
    gemm_k<true,0,false,false><<<dim3((POOLN+63)/64, NSER/64),256>>>(p_xq, p_keyn, (const float*)nullptr, p_sim, NSER, POOLN, DMOD);
    topk_k<<<NSER,256>>>();
    wpe_k<<<(unsigned)(((size_t)NTOK*DMOD + 255)/256),256>>>(wpe);

    const int MB = NTOK/128;   // 238
    for (int L = 0; L < NLAYER; L++){
        __half* qkvT = p_wT + (size_t)L*WL;
        __half* awT  = qkvT + 1769472;
        __half* fcT  = awT  + 589824;
        __half* pwT  = fcT  + 2359296;
        ln_k<true><<<NTOK/8,256>>>(p_h, ln1g + (size_t)L*DMOD, ln1b + (size_t)L*DMOD, p_a);
        hgemm_k<0,false,true ><<<dim3(3*DMOD/128, MB),256,H_SMEMB>>>(p_a, qkvT, qkvb + (size_t)L*3*DMOD, p_qkv, NTOK, 3*DMOD, DMOD);
        attn_k<<<NSER*12,160>>>();
        hgemm_k<0,true ,false><<<dim3(DMOD/128, MB),256,H_SMEMB>>>(p_ob, awT, ab + (size_t)L*DMOD, p_h, NTOK, DMOD, DMOD);
        ln_k<true><<<NTOK/8,256>>>(p_h, ln2g + (size_t)L*DMOD, ln2b + (size_t)L*DMOD, p_a);
        hgemm_k<1,false,true ><<<dim3(4*DMOD/128, MB),256,H_SMEMB>>>(p_a, fcT, fcb + (size_t)L*4*DMOD, p_mlp, NTOK, 4*DMOD, DMOD);
        hgemm_k<0,true ,false><<<dim3(DMOD/128, MB),256,H_SMEMB>>>(p_mlp, pwT, pbb + (size_t)L*DMOD, p_h, NTOK, DMOD, 3072);
    }

    ln_k<false><<<NTOK/8,256>>>(p_h, lnfg, lnfb, p_af);
    // output head: M=1344, N=96, K=17408, split-K 16 (chunk 1088)
    headgemm_k<<<dim3(1, (NSER*3+127)/128, SPLITZ),256,SMB>>>(p_af, outw, p_osp, NSER*3, PREDL, TTOK*DMOD/3);
    final_k<<<NSER,96>>>(outb, out);
    rsim_k<<<1,1>>>(out, out_size);
}

// round 7
// speedup vs baseline: 6.9939x; 1.0799x over previous
#include <cuda_runtime.h>
#include <cuda_fp16.h>
#include <math.h>
#include <stdint.h>

#define NSER 448
#define LSEQ 512
#define TTOK 68
#define DMOD 768
#define NTOK (NSER*TTOK)       // 30464
#define PNUM 64
#define POOLN 1000
#define PREDL 96
#define NLAYER 6
#define SPLITZ 16

// ---------------- scratch (device globals; no allocations) ----------------
__device__ float  g_xn  [NSER*LSEQ];
__device__ float  g_mean[NSER];
__device__ float  g_std [NSER];
__device__ float  g_dec [NSER*3*LSEQ];
__device__ float  g_tok [NSER*PNUM*48];
__device__ float  g_h   [(size_t)NTOK*DMOD];
__device__ __half g_a   [(size_t)NTOK*DMOD];
__device__ float  g_af  [(size_t)NTOK*DMOD];
__device__ __half g_qkvh[(size_t)NTOK*3*DMOD];
__device__ __half g_ob  [(size_t)NTOK*DMOD];
__device__ __half g_mlp [(size_t)NTOK*4*DMOD];
__device__ float  g_xq  [NSER*DMOD];
__device__ float  g_keyn[POOLN*DMOD];
__device__ float  g_sim [NSER*POOLN];
__device__ float  g_osp [(size_t)SPLITZ*NSER*3*PREDL];
__device__ float  g_rsim;
#define WL 7077888u
__device__ __half g_wT  [(size_t)NLAYER*WL];

__device__ __forceinline__ float gelu_tanh(float x){
    float c = 0.7978845608028654f;
    float t = tanhf(c*(x + 0.044715f*x*x*x));
    return 0.5f*x*(1.f+t);
}

__device__ __forceinline__ unsigned f2tf(float x){
    unsigned r; asm("cvt.rna.tf32.f32 %0, %1;" : "=r"(r) : "f"(x)); return r;
}

__device__ __forceinline__ void mma8(float* c, const unsigned* a, const unsigned* b){
    asm volatile("mma.sync.aligned.m16n8k8.row.col.f32.tf32.tf32.f32 "
        "{%0,%1,%2,%3}, {%4,%5,%6,%7}, {%8,%9}, {%0,%1,%2,%3};"
        : "+f"(c[0]),"+f"(c[1]),"+f"(c[2]),"+f"(c[3])
        : "r"(a[0]),"r"(a[1]),"r"(a[2]),"r"(a[3]), "r"(b[0]),"r"(b[1]));
}

__device__ __forceinline__ void mma16(float* c, const unsigned* a, const unsigned* b){
    asm volatile("mma.sync.aligned.m16n8k16.row.col.f32.f16.f16.f32 "
        "{%0,%1,%2,%3}, {%4,%5,%6,%7}, {%8,%9}, {%0,%1,%2,%3};"
        : "+f"(c[0]),"+f"(c[1]),"+f"(c[2]),"+f"(c[3])
        : "r"(a[0]),"r"(a[1]),"r"(a[2]),"r"(a[3]), "r"(b[0]),"r"(b[1]));
}

__device__ __forceinline__ void ldsm4(unsigned &r0, unsigned &r1, unsigned &r2, unsigned &r3, uint32_t addr){
    asm volatile("ldmatrix.sync.aligned.m8n8.x4.shared.b16 {%0,%1,%2,%3}, [%4];"
        : "=r"(r0),"=r"(r1),"=r"(r2),"=r"(r3) : "r"(addr));
}

__device__ __forceinline__ void cpasyncF(float* dst, const float* src, bool pred){
    unsigned sa = (unsigned)__cvta_generic_to_shared(dst);
    int sz = pred ? 16 : 0;
    asm volatile("cp.async.cg.shared.global [%0], [%1], 16, %2;" :: "r"(sa), "l"(src), "r"(sz));
}
__device__ __forceinline__ void cpasyncH(__half* dst, const __half* src){
    unsigned sa = (unsigned)__cvta_generic_to_shared(dst);
    asm volatile("cp.async.cg.shared.global [%0], [%1], 16;" :: "r"(sa), "l"(src));
}
__device__ __forceinline__ void cp_commit(){ asm volatile("cp.async.commit_group;"); }
template<int N> __device__ __forceinline__ void cp_wait(){ asm volatile("cp.async.wait_group %0;"::"n"(N)); }

__device__ __forceinline__ unsigned packh2(float a, float b){
    __half2 h = __floats2half2_rn(a, b);
    return *reinterpret_cast<unsigned*>(&h);
}

// ---------------- RevIN stats + normalize ----------------
__global__ void norm_k(const float* __restrict__ x){
    int n = blockIdx.x, b = n/7, m = n%7, tid = threadIdx.x;
    __shared__ float xs[LSEQ];
    __shared__ float red[256];
    for (int l = tid; l < LSEQ; l += 256) xs[l] = x[((size_t)b*LSEQ + l)*7 + m];
    __syncthreads();
    float s = xs[tid] + xs[tid+256];
    red[tid] = s; __syncthreads();
    for (int o = 128; o; o >>= 1){ if (tid < o) red[tid] += red[tid+o]; __syncthreads(); }
    float mu = red[0] * (1.f/LSEQ);
    __syncthreads();
    float d0 = xs[tid]-mu, d1 = xs[tid+256]-mu;
    red[tid] = d0*d0 + d1*d1; __syncthreads();
    for (int o = 128; o; o >>= 1){ if (tid < o) red[tid] += red[tid+o]; __syncthreads(); }
    float sd = sqrtf(red[0]*(1.f/LSEQ) + 1e-5f);
    if (tid == 0){ g_mean[n] = mu; g_std[n] = sd; }
    float inv = 1.f/sd;
    g_xn[n*LSEQ + tid]       = d0*inv;
    g_xn[n*LSEQ + 256 + tid] = d1*inv;
}

// ---------------- decomposition ----------------
__global__ void dec_k(){
    int n = blockIdx.x, tid = threadIdx.x;
    __shared__ float xs[LSEQ];
    __shared__ float valid[489];
    __shared__ float det[LSEQ];
    __shared__ float ph[24];
    for (int l = tid; l < LSEQ; l += 256) xs[l] = g_xn[n*LSEQ + l];
    if (tid < 24) ph[tid] = 0.f;
    __syncthreads();
    for (int i = tid; i < 489; i += 256){
        float s = 0.f;
        #pragma unroll
        for (int k = 0; k < 24; k++) s += xs[i+k];
        valid[i] = s * (1.f/24.f);
    }
    __syncthreads();
    for (int l = tid; l < LSEQ; l += 256){
        int vi = l - 12; vi = vi < 0 ? 0 : (vi > 488 ? 488 : vi);
        float tr = valid[vi];
        float dt = xs[l] - tr;
        det[l] = dt;
        atomicAdd(&ph[l % 24], dt);
        g_dec[((size_t)n*3 + 0)*LSEQ + l] = tr;
    }
    __syncthreads();
    for (int l = tid; l < LSEQ; l += 256){
        int p = l % 24;
        float cnt = (p < 8) ? 22.f : 21.f;
        float se = ph[p] / cnt;
        g_dec[((size_t)n*3 + 1)*LSEQ + l] = se;
        g_dec[((size_t)n*3 + 2)*LSEQ + l] = det[l] - se;
    }
}

// ---------------- patch extraction ----------------
__global__ void patch_k(){
    int n = blockIdx.x, tid = threadIdx.x;
    for (int e = tid; e < PNUM*48; e += 256){
        int p = e/48, rem = e%48, c = rem/16, j = rem%16;
        int l = p*8 + j; if (l > LSEQ-1) l = LSEQ-1;
        g_tok[(size_t)n*PNUM*48 + e] = g_dec[((size_t)n*3 + c)*LSEQ + l];
    }
}

// ---------------- weight transpose to half: W[K,N] -> WT[N,K] -------------
__global__ void transp_k(const float* __restrict__ W, __half* __restrict__ WT, int K, int N){
    __shared__ float t[32][33];
    int bx = blockIdx.x*32, by = blockIdx.y*32;
    int x = threadIdx.x, y = threadIdx.y;   // 32 x 8
    #pragma unroll
    for (int i = 0; i < 4; i++){
        int r = by + y*4 + i;
        t[y*4+i][x] = W[(size_t)r*N + bx + x];
    }
    __syncthreads();
    #pragma unroll
    for (int i = 0; i < 4; i++){
        int rn = bx + y*4 + i;
        WT[(size_t)rn*K + by + x] = __float2half(t[x][y*4+i]);
    }
}

// ---------------- generic fp32 SIMT GEMM (precision-critical small paths) --
template<bool TRANSB, int ACT, bool RESID, bool REMAP>
__global__ void gemm_k(const float* __restrict__ A, const float* __restrict__ B,
                       const float* __restrict__ bias, float* __restrict__ C,
                       int M, int N, int K){
    __shared__ float As[16][68];
    __shared__ float Bs[16][68];
    int tid = threadIdx.x;
    int tx = tid & 15, ty = tid >> 4;
    int row0 = blockIdx.y * 64, col0 = blockIdx.x * 64;
    float acc[4][4] = {};
    for (int k0 = 0; k0 < K; k0 += 16){
        {
            int r  = tid >> 2;
            int c4 = (tid & 3) * 4;
            float4 v = *reinterpret_cast<const float4*>(&A[(size_t)(row0 + r)*K + k0 + c4]);
            As[c4+0][r] = v.x; As[c4+1][r] = v.y; As[c4+2][r] = v.z; As[c4+3][r] = v.w;
        }
        if (!TRANSB){
            int kk = tid >> 4;
            int c4 = (tid & 15) * 4;
            int col = col0 + c4;
            float4 v = make_float4(0.f,0.f,0.f,0.f);
            if (col < N) v = *reinterpret_cast<const float4*>(&B[(size_t)(k0+kk)*N + col]);
            Bs[kk][c4+0] = v.x; Bs[kk][c4+1] = v.y; Bs[kk][c4+2] = v.z; Bs[kk][c4+3] = v.w;
        } else {
            int nn = tid >> 2;
            int c4 = (tid & 3) * 4;
            int col = col0 + nn;
            float4 v = make_float4(0.f,0.f,0.f,0.f);
            if (col < N) v = *reinterpret_cast<const float4*>(&B[(size_t)col*K + k0 + c4]);
            Bs[c4+0][nn] = v.x; Bs[c4+1][nn] = v.y; Bs[c4+2][nn] = v.z; Bs[c4+3][nn] = v.w;
        }
        __syncthreads();
        #pragma unroll
        for (int kk = 0; kk < 16; kk++){
            float a[4], b[4];
            #pragma unroll
            for (int i = 0; i < 4; i++) a[i] = As[kk][ty*4+i];
            #pragma unroll
            for (int j = 0; j < 4; j++) b[j] = Bs[kk][tx*4+j];
            #pragma unroll
            for (int i = 0; i < 4; i++)
                #pragma unroll
                for (int j = 0; j < 4; j++) acc[i][j] = fmaf(a[i], b[j], acc[i][j]);
        }
        __syncthreads();
    }
    #pragma unroll
    for (int i = 0; i < 4; i++){
        int r = row0 + ty*4 + i;
        size_t orow = REMAP ? (size_t)((r >> 6)*TTOK + 4 + (r & 63)) : (size_t)r;
        #pragma unroll
        for (int j = 0; j < 4; j++){
            int col = col0 + tx*4 + j;
            if (col < N){
                float v = acc[i][j];
                if (bias) v += bias[col];
                if (ACT == 1) v = gelu_tanh(v);
                size_t idx = orow*(size_t)N + col;
                if (RESID) C[idx] += v; else C[idx] = v;
            }
        }
    }
}

// ================= fp16 tensor-core GEMM (ldmatrix fragments) =============
#define HST 40
#define H_STAGE (128*HST)
#define H_SMEMB (6*H_STAGE*2)

template<int ACT, bool RESID, bool HOUT>
__global__ __launch_bounds__(256, 2) void hgemm_k(
        const __half* __restrict__ A, const __half* __restrict__ BT,
        const float* __restrict__ bias, void* __restrict__ Cv,
        int M, int N, int K){
    extern __shared__ __half hsm[];
    __half* smA = hsm;
    __half* smB = hsm + 3*H_STAGE;
    int tid = threadIdx.x;
    int warp = tid >> 5, lane = tid & 31;
    int wm = warp >> 2, wn = warp & 3;
    int g = lane >> 2, tg = lane & 3;
    int row0 = blockIdx.y * 128, col0 = blockIdx.x * 128;

    float acc[4][4][4];
    #pragma unroll
    for (int i=0;i<4;i++) for (int j=0;j<4;j++) for (int q=0;q<4;q++) acc[i][j][q]=0.f;

    // ldmatrix base offsets (bytes, within a stage)
    uint32_t smA_u = (uint32_t)__cvta_generic_to_shared(smA);
    uint32_t smB_u = (uint32_t)__cvta_generic_to_shared(smB);
    uint32_t aoff = (uint32_t)(((wm*64 + (lane & 15))*HST + ((lane >> 4)*8)) * 2);
    int brlo = lane & 7, b8 = ((lane >> 4) & 1)*8, bc8 = ((lane >> 3) & 1)*8;
    uint32_t boff0 = (uint32_t)(((wn*32 +  0 + b8 + brlo)*HST + bc8) * 2);
    uint32_t boff1 = (uint32_t)(((wn*32 + 16 + b8 + brlo)*HST + bc8) * 2);

    #define ISSUE_H(T, S) { \
        __half* as = smA + (S)*H_STAGE; \
        __half* bs = smB + (S)*H_STAGE; \
        const __half* Ab = A + (size_t)row0*K + (T)*32; \
        const __half* Bb = BT + (size_t)col0*K + (T)*32; \
        _Pragma("unroll") \
        for (int i=0;i<2;i++){ \
            int idx = tid + i*256; int r = idx>>2, ch = idx&3; \
            cpasyncH(&as[r*HST + ch*8], &Ab[(size_t)r*K + ch*8]); \
        } \
        _Pragma("unroll") \
        for (int i=0;i<2;i++){ \
            int idx = tid + i*256; int r = idx>>2, ch = idx&3; \
            cpasyncH(&bs[r*HST + ch*8], &Bb[(size_t)r*K + ch*8]); \
        } \
        cp_commit(); }

    int nt = K >> 5;
    ISSUE_H(0, 0);
    ISSUE_H(1, 1);

    int stage = 0;
    for (int kt = 0; kt < nt; kt++){
        if (kt == nt-1) cp_wait<0>(); else cp_wait<1>();
        __syncthreads();
        if (kt + 2 < nt){
            int s2 = stage + 2; if (s2 >= 3) s2 -= 3;
            ISSUE_H(kt+2, s2);
        }
        uint32_t stb = (uint32_t)(stage*H_STAGE*2);
        #pragma unroll
        for (int ks = 0; ks < 32; ks += 16){
            unsigned af[4][4], bf[4][2];
            #pragma unroll
            for (int mt = 0; mt < 4; mt++)
                ldsm4(af[mt][0], af[mt][1], af[mt][2], af[mt][3],
                      smA_u + stb + aoff + (uint32_t)((mt*16*HST + ks)*2));
            ldsm4(bf[0][0], bf[0][1], bf[1][0], bf[1][1], smB_u + stb + boff0 + (uint32_t)(ks*2));
            ldsm4(bf[2][0], bf[2][1], bf[3][0], bf[3][1], smB_u + stb + boff1 + (uint32_t)(ks*2));
            #pragma unroll
            for (int mt = 0; mt < 4; mt++)
                #pragma unroll
                for (int nt2 = 0; nt2 < 4; nt2++)
                    mma16(acc[mt][nt2], af[mt], bf[nt2]);
        }
        stage++; if (stage >= 3) stage -= 3;
    }
    #undef ISSUE_H

    #pragma unroll
    for (int mt = 0; mt < 4; mt++){
        int rbase = row0 + wm*64 + mt*16;
        #pragma unroll
        for (int nt2 = 0; nt2 < 4; nt2++){
            int cbase = col0 + wn*32 + nt2*8 + tg*2;
            float b0 = bias[cbase], b1 = bias[cbase+1];
            #pragma unroll
            for (int hh = 0; hh < 2; hh++){
                int rr = rbase + g + hh*8;
                float v0 = acc[mt][nt2][hh*2]   + b0;
                float v1 = acc[mt][nt2][hh*2+1] + b1;
                if (ACT == 1){ v0 = gelu_tanh(v0); v1 = gelu_tanh(v1); }
                size_t gi = (size_t)rr*N + cbase;
                if (HOUT){
                    __half2* p = reinterpret_cast<__half2*>(reinterpret_cast<__half*>(Cv) + gi);
                    *p = __floats2half2_rn(v0, v1);
                } else {
                    float* C = reinterpret_cast<float*>(Cv);
                    if (RESID){
                        float2 c = *reinterpret_cast<float2*>(&C[gi]);
                        c.x += v0; c.y += v1;
                        *reinterpret_cast<float2*>(&C[gi]) = c;
                    } else {
                        *reinterpret_cast<float2*>(&C[gi]) = make_float2(v0, v1);
                    }
                }
            }
        }
    }
}

// ---------------- legacy tf32 tensor GEMM (output head, split-K) ----------
#define AS_ST 36
#define BS_ST 136
#define A_STAGE (128*AS_ST)
#define B_STAGE (32*BS_ST)
#define SM_FLOATS (3*(A_STAGE+B_STAGE))

__global__ __launch_bounds__(256, 2) void headgemm_k(
        const float* __restrict__ A, const float* __restrict__ B,
        float* __restrict__ C, int M, int N, int K){
    extern __shared__ float sm[];
    float* smA = sm;
    float* smB = sm + 3*A_STAGE;
    int tid = threadIdx.x;
    int warp = tid >> 5, lane = tid & 31;
    int wm = warp >> 2, wn = warp & 3;
    int g = lane >> 2, tg = lane & 3;
    int row0 = blockIdx.y * 128, col0 = blockIdx.x * 128;

    int Kc   = K / gridDim.z;
    int kbeg = blockIdx.z * Kc;
    int nt   = Kc >> 5;

    float acc[4][4][4];
    #pragma unroll
    for (int i=0;i<4;i++) for (int j=0;j<4;j++) for (int q=0;q<4;q++) acc[i][j][q]=0.f;

    #define ISSUE_T(T, S) { \
        int k0 = kbeg + (T)*32; \
        float* as = smA + (S)*A_STAGE; \
        float* bs = smB + (S)*B_STAGE; \
        _Pragma("unroll") \
        for (int i=0;i<4;i++){ \
            int idx = tid + i*256; int r = idx>>3; int ch=(idx&7)<<2; \
            int grow = row0 + r; bool p = grow < M; int gr = p ? grow : (M-1); \
            cpasyncF(&as[r*AS_ST + ch], &A[(size_t)gr*K + k0 + ch], p); \
        } \
        _Pragma("unroll") \
        for (int i=0;i<4;i++){ \
            int idx = tid + i*256; int kk = idx>>5; int c4=(idx&31)<<2; \
            int gcol = col0 + c4; bool p = gcol < N; int gc = p ? gcol : 0; \
            cpasyncF(&bs[kk*BS_ST + c4], &B[(size_t)(k0+kk)*N + gc], p); \
        } \
        cp_commit(); }

    ISSUE_T(0, 0);
    ISSUE_T(1, 1);

    int stage = 0;
    for (int kt = 0; kt < nt; kt++){
        if (kt == nt-1) cp_wait<0>(); else cp_wait<1>();
        __syncthreads();
        if (kt + 2 < nt){
            int s2 = stage + 2; if (s2 >= 3) s2 -= 3;
            ISSUE_T(kt+2, s2);
        }
        const float* as = smA + stage*A_STAGE;
        const float* bs = smB + stage*B_STAGE;
        #pragma unroll
        for (int ks = 0; ks < 32; ks += 8){
            unsigned af[4][4], bf[4][2];
            #pragma unroll
            for (int mt = 0; mt < 4; mt++){
                int r = wm*64 + mt*16 + g;
                af[mt][0] = f2tf(as[r*AS_ST + ks+tg]);
                af[mt][1] = f2tf(as[(r+8)*AS_ST + ks+tg]);
                af[mt][2] = f2tf(as[r*AS_ST + ks+tg+4]);
                af[mt][3] = f2tf(as[(r+8)*AS_ST + ks+tg+4]);
            }
            #pragma unroll
            for (int nt2 = 0; nt2 < 4; nt2++){
                int c = wn*32 + nt2*8 + g;
                bf[nt2][0] = f2tf(bs[(ks+tg)*BS_ST + c]);
                bf[nt2][1] = f2tf(bs[(ks+tg+4)*BS_ST + c]);
            }
            #pragma unroll
            for (int mt = 0; mt < 4; mt++)
                #pragma unroll
                for (int nt2 = 0; nt2 < 4; nt2++)
                    mma8(acc[mt][nt2], af[mt], bf[nt2]);
        }
        stage++; if (stage >= 3) stage -= 3;
        __syncthreads();
    }
    #undef ISSUE_T

    float* Cout = C + (size_t)blockIdx.z*M*N;
    #pragma unroll
    for (int mt = 0; mt < 4; mt++){
        int rbase = row0 + wm*64 + mt*16;
        #pragma unroll
        for (int nt2 = 0; nt2 < 4; nt2++){
            int cbase = col0 + wn*32 + nt2*8 + tg*2;
            #pragma unroll
            for (int half2_ = 0; half2_ < 2; half2_++){
                int rr = rbase + g + half2_*8;
                if (rr < M){
                    #pragma unroll
                    for (int jj = 0; jj < 2; jj++){
                        int cc = cbase + jj;
                        if (cc < N) Cout[(size_t)rr*N + cc] = acc[mt][nt2][half2_*2+jj];
                    }
                }
            }
        }
    }
}

// ---------------- l2-normalize prompt keys ----------------
__global__ void keynorm_k(const float* __restrict__ pk){
    int r = blockIdx.x, tid = threadIdx.x;
    __shared__ float red[256];
    float v0 = pk[(size_t)r*DMOD + tid], v1 = pk[(size_t)r*DMOD + 256 + tid], v2 = pk[(size_t)r*DMOD + 512 + tid];
    red[tid] = v0*v0 + v1*v1 + v2*v2; __syncthreads();
    for (int o = 128; o; o >>= 1){ if (tid < o) red[tid] += red[tid+o]; __syncthreads(); }
    float inv = rsqrtf(fmaxf(red[0], 1e-12f));
    g_keyn[(size_t)r*DMOD + tid]       = v0*inv;
    g_keyn[(size_t)r*DMOD + 256 + tid] = v1*inv;
    g_keyn[(size_t)r*DMOD + 512 + tid] = v2*inv;
}

// ---------------- xq ----------------
__global__ void xq_k(){
    int n = blockIdx.x, tid = threadIdx.x;
    __shared__ float xs[DMOD];
    __shared__ float red[256];
    float ss = 0.f;
    for (int d = tid; d < DMOD; d += 256){
        float s = 0.f;
        for (int p = 0; p < PNUM; p++) s += g_h[((size_t)n*TTOK + 4 + p)*DMOD + d];
        s *= (1.f/PNUM);
        xs[d] = s; ss += s*s;
    }
    red[tid] = ss; __syncthreads();
    for (int o = 128; o; o >>= 1){ if (tid < o) red[tid] += red[tid+o]; __syncthreads(); }
    float inv = rsqrtf(fmaxf(red[0], 1e-12f));
    for (int d = tid; d < DMOD; d += 256) g_xq[(size_t)n*DMOD + d] = xs[d]*inv;
}

// ---------------- top-k ----------------
__global__ void topk_k(){
    int n = blockIdx.x, tid = threadIdx.x;
    __shared__ float bv[256];
    __shared__ int   bi[256];
    __shared__ int   chosen[4];
    float rs = 0.f;
    for (int r = 0; r < 4; r++){
        float best = -1e30f; int besti = 1 << 30;
        for (int j = tid; j < POOLN; j += 256){
            bool skip = false;
            for (int c = 0; c < r; c++) if (chosen[c] == j) skip = true;
            float v = g_sim[(size_t)n*POOLN + j];
            if (!skip && (v > best || (v == best && j < besti))){ best = v; besti = j; }
        }
        bv[tid] = best; bi[tid] = besti; __syncthreads();
        for (int o = 128; o; o >>= 1){
            if (tid < o){
                if (bv[tid+o] > bv[tid] || (bv[tid+o] == bv[tid] && bi[tid+o] < bi[tid])){
                    bv[tid] = bv[tid+o]; bi[tid] = bi[tid+o];
                }
            }
            __syncthreads();
        }
        if (tid == 0){ chosen[r] = bi[0]; rs += bv[0]; }
        __syncthreads();
    }
    for (int e = tid; e < 4*DMOD; e += 256){
        int k = e / DMOD, d = e % DMOD;
        g_h[((size_t)n*TTOK + k)*DMOD + d] = g_keyn[(size_t)chosen[k]*DMOD + d];
    }
    if (tid == 0) atomicAdd(&g_rsim, rs);
}

__global__ void zero_k(){ g_rsim = 0.f; }

// ---------------- add positional embedding ----------------
__global__ void wpe_k(const float* __restrict__ wpe){
    size_t i = (size_t)blockIdx.x*blockDim.x + threadIdx.x;
    if (i < (size_t)NTOK*DMOD){
        int tok = (int)(i / DMOD);
        int t = tok % TTOK;
        int d = (int)(i % DMOD);
        g_h[i] += wpe[(size_t)t*DMOD + d];
    }
}

// ---------------- layernorm: warp per row; half or float out --------------
template<bool HOUT>
__global__ void ln_k(const float* __restrict__ x, const float* __restrict__ g,
                     const float* __restrict__ b, void* __restrict__ yv){
    int row  = blockIdx.x*8 + (threadIdx.x >> 5);
    int lane = threadIdx.x & 31;
    const float4* xr = reinterpret_cast<const float4*>(x + (size_t)row*DMOD);
    const float4* g4 = reinterpret_cast<const float4*>(g);
    const float4* b4 = reinterpret_cast<const float4*>(b);
    float4 v[6];
    float s = 0.f, sq = 0.f;
    #pragma unroll
    for (int i = 0; i < 6; i++){
        v[i] = xr[lane + i*32];
        s  += v[i].x + v[i].y + v[i].z + v[i].w;
        sq += v[i].x*v[i].x + v[i].y*v[i].y + v[i].z*v[i].z + v[i].w*v[i].w;
    }
    #pragma unroll
    for (int o = 16; o; o >>= 1){
        s  += __shfl_xor_sync(0xffffffffu, s,  o);
        sq += __shfl_xor_sync(0xffffffffu, sq, o);
    }
    float mu  = s * (1.f/DMOD);
    float var = sq * (1.f/DMOD) - mu*mu;
    float inv = rsqrtf(var + 1e-5f);
    #pragma unroll
    for (int i = 0; i < 6; i++){
        float4 gg = g4[lane + i*32], bb = b4[lane + i*32], o;
        o.x = (v[i].x-mu)*inv*gg.x + bb.x;
        o.y = (v[i].y-mu)*inv*gg.y + bb.y;
        o.z = (v[i].z-mu)*inv*gg.z + bb.z;
        o.w = (v[i].w-mu)*inv*gg.w + bb.w;
        if (HOUT){
            __half2* yr = reinterpret_cast<__half2*>(reinterpret_cast<__half*>(yv) + (size_t)row*DMOD);
            yr[2*(lane+i*32)]   = __floats2half2_rn(o.x, o.y);
            yr[2*(lane+i*32)+1] = __floats2half2_rn(o.z, o.w);
        } else {
            float4* yr = reinterpret_cast<float4*>(reinterpret_cast<float*>(yv) + (size_t)row*DMOD);
            yr[lane + i*32] = o;
        }
    }
}

// ---------------- attention: fp16 mma flash, block per (series, head) -----
#define QKS 72
#define VTS 88
__global__ __launch_bounds__(160) void attn_k(){
    int blk = blockIdx.x;
    int n = blk / 12, head = blk % 12;
    __shared__ __half qs[80*QKS];
    __shared__ __half ks[80*QKS];
    __shared__ __half vt[64*VTS];
    int tid = threadIdx.x, w = tid >> 5, lane = tid & 31;
    int g = lane >> 2, tg = lane & 3;

    // fill qs/ks/vt; zero only vt key-columns 68..79 (masked-P NaN guard)
    const __half* qkv = g_qkvh + (size_t)n*TTOK*3*DMOD + head*64;
    for (int idx = tid; idx < TTOK*32; idx += 160){
        int t = idx >> 5, c = (idx & 31)*2;
        __half2 q2 = *reinterpret_cast<const __half2*>(qkv + (size_t)t*3*DMOD + c);
        __half2 k2 = *reinterpret_cast<const __half2*>(qkv + (size_t)t*3*DMOD + DMOD + c);
        __half2 v2 = *reinterpret_cast<const __half2*>(qkv + (size_t)t*3*DMOD + 2*DMOD + c);
        *reinterpret_cast<__half2*>(qs + t*QKS + c) = q2;
        *reinterpret_cast<__half2*>(ks + t*QKS + c) = k2;
        vt[c*VTS + t]     = __low2half(v2);
        vt[(c+1)*VTS + t] = __high2half(v2);
    }
    for (int idx = tid; idx < 64*12; idx += 160){
        int d = idx / 12, t = 68 + idx % 12;
        vt[d*VTS + t] = __float2half(0.f);
    }
    __syncthreads();

    int rb = w*16 + g;
    float sacc[10][4];
    #pragma unroll
    for (int i = 0; i < 10; i++) for (int j = 0; j < 4; j++) sacc[i][j] = 0.f;
    #pragma unroll
    for (int kc = 0; kc < 4; kc++){
        unsigned af[4];
        int base = rb*QKS + kc*16 + 2*tg;
        af[0] = *reinterpret_cast<const unsigned*>(&qs[base]);
        af[1] = *reinterpret_cast<const unsigned*>(&qs[base + 8*QKS]);
        af[2] = *reinterpret_cast<const unsigned*>(&qs[base + 8]);
        af[3] = *reinterpret_cast<const unsigned*>(&qs[base + 8*QKS + 8]);
        #pragma unroll
        for (int nt = 0; nt < 10; nt++){
            unsigned bf[2];
            int bb = (nt*8 + g)*QKS + kc*16 + 2*tg;
            bf[0] = *reinterpret_cast<const unsigned*>(&ks[bb]);
            bf[1] = *reinterpret_cast<const unsigned*>(&ks[bb + 8]);
            mma16(sacc[nt], af, bf);
        }
    }
    float inv_[2];
    #pragma unroll
    for (int hh = 0; hh < 2; hh++){
        int R = rb + hh*8;
        float mx = -1e30f;
        #pragma unroll
        for (int nt = 0; nt < 10; nt++)
            #pragma unroll
            for (int jj = 0; jj < 2; jj++){
                int Cn = nt*8 + 2*tg + jj;
                float sv = sacc[nt][hh*2+jj] * 0.125f;
                sv = (Cn <= R) ? sv : -1e9f;
                sacc[nt][hh*2+jj] = sv;
                mx = fmaxf(mx, sv);
            }
        mx = fmaxf(mx, __shfl_xor_sync(0xffffffffu, mx, 1));
        mx = fmaxf(mx, __shfl_xor_sync(0xffffffffu, mx, 2));
        float sm = 0.f;
        #pragma unroll
        for (int nt = 0; nt < 10; nt++)
            #pragma unroll
            for (int jj = 0; jj < 2; jj++){
                float p = expf(sacc[nt][hh*2+jj] - mx);
                sacc[nt][hh*2+jj] = p;
                sm += p;
            }
        sm += __shfl_xor_sync(0xffffffffu, sm, 1);
        sm += __shfl_xor_sync(0xffffffffu, sm, 2);
        inv_[hh] = 1.f/sm;
    }
    float oacc[8][4];
    #pragma unroll
    for (int i = 0; i < 8; i++) for (int j = 0; j < 4; j++) oacc[i][j] = 0.f;
    #pragma unroll
    for (int kc = 0; kc < 5; kc++){
        unsigned af[4];
        af[0] = packh2(sacc[2*kc][0],   sacc[2*kc][1]);
        af[1] = packh2(sacc[2*kc][2],   sacc[2*kc][3]);
        af[2] = packh2(sacc[2*kc+1][0], sacc[2*kc+1][1]);
        af[3] = packh2(sacc[2*kc+1][2], sacc[2*kc+1][3]);
        #pragma unroll
        for (int nt = 0; nt < 8; nt++){
            unsigned bf[2];
            int bb = (nt*8 + g)*VTS + kc*16 + 2*tg;
            bf[0] = *reinterpret_cast<const unsigned*>(&vt[bb]);
            bf[1] = *reinterpret_cast<const unsigned*>(&vt[bb + 8]);
            mma16(oacc[nt], af, bf);
        }
    }
    __half* ob = g_ob + (size_t)n*TTOK*DMOD + head*64;
    #pragma unroll
    for (int hh = 0; hh < 2; hh++){
        int R = rb + hh*8;
        if (R < TTOK){
            #pragma unroll
            for (int nt = 0; nt < 8; nt++){
                __half2 hv = __floats2half2_rn(oacc[nt][hh*2]*inv_[hh], oacc[nt][hh*2+1]*inv_[hh]);
                *reinterpret_cast<__half2*>(ob + (size_t)R*DMOD + nt*8 + 2*tg) = hv;
            }
        }
    }
}

// ---------------- final: sum split-K chunks + channels, denormalize -------
__global__ void final_k(const float* __restrict__ outb, float* __restrict__ out){
    int n = blockIdx.x, b = n/7, m = n%7;
    for (int t = threadIdx.x; t < PREDL; t += blockDim.x){
        float v = 3.f*outb[t];
        #pragma unroll
        for (int z = 0; z < SPLITZ; z++){
            const float* p = g_osp + (size_t)z*NSER*3*PREDL;
            v += p[(size_t)(n*3+0)*PREDL + t]
               + p[(size_t)(n*3+1)*PREDL + t]
               + p[(size_t)(n*3+2)*PREDL + t];
        }
        out[(size_t)b*PREDL*7 + (size_t)t*7 + m] = v*g_std[n] + g_mean[n];
    }
}

__global__ void rsim_k(float* __restrict__ out, int out_size){
    if (out_size > 64*PREDL*7) out[64*PREDL*7] = g_rsim * (1.f/NSER);
}

// ---------------- host ----------------
template <typename T, size_t S>
static void* symaddr(T (&arr)[S]){ void* p = nullptr; cudaGetSymbolAddress(&p, arr); return p; }

extern "C" void kernel_launch(void* const* d_in, const int* in_sizes, int n_in,
                              void* d_out, int out_size){
    int s = (n_in >= 2 && in_sizes[1] == 1) ? 1 : 0;
    const float* x    = (const float*)d_in[0];
    const float* in_w = (const float*)d_in[1+s];
    const float* in_b = (const float*)d_in[2+s];
    const float* pk   = (const float*)d_in[3+s];
    const float* wpe  = (const float*)d_in[4+s];
    const float* ln1g = (const float*)d_in[5+s];
    const float* ln1b = (const float*)d_in[6+s];
    const float* qkvw = (const float*)d_in[7+s];
    const float* qkvb = (const float*)d_in[8+s];
    const float* aw   = (const float*)d_in[9+s];
    const float* ab   = (const float*)d_in[10+s];
    const float* ln2g = (const float*)d_in[11+s];
    const float* ln2b = (const float*)d_in[12+s];
    const float* fcw  = (const float*)d_in[13+s];
    const float* fcb  = (const float*)d_in[14+s];
    const float* pw   = (const float*)d_in[15+s];
    const float* pbb  = (const float*)d_in[16+s];
    const float* lnfg = (const float*)d_in[17+s];
    const float* lnfb = (const float*)d_in[18+s];
    const float* outw = (const float*)d_in[19+s];
    const float* outb = (const float*)d_in[20+s];
    float* out = (float*)d_out;

    float*  p_h    = (float*) symaddr(g_h);
    __half* p_a    = (__half*)symaddr(g_a);
    float*  p_af   = (float*) symaddr(g_af);
    __half* p_qkv  = (__half*)symaddr(g_qkvh);
    __half* p_ob   = (__half*)symaddr(g_ob);
    __half* p_mlp  = (__half*)symaddr(g_mlp);
    float*  p_tok  = (float*) symaddr(g_tok);
    float*  p_xq   = (float*) symaddr(g_xq);
    float*  p_keyn = (float*) symaddr(g_keyn);
    float*  p_sim  = (float*) symaddr(g_sim);
    float*  p_osp  = (float*) symaddr(g_osp);
    __half* p_wT   = (__half*)symaddr(g_wT);

    const int SMB = SM_FLOATS*4;
    static cudaStream_t s2 = nullptr;
    static cudaEvent_t evA = nullptr, evB = nullptr;
    if (!s2){
        cudaFuncSetAttribute(headgemm_k, cudaFuncAttributeMaxDynamicSharedMemorySize, SMB);
        cudaFuncSetAttribute(hgemm_k<0,false,false>, cudaFuncAttributeMaxDynamicSharedMemorySize, H_SMEMB);
        cudaFuncSetAttribute(hgemm_k<0,true ,false>, cudaFuncAttributeMaxDynamicSharedMemorySize, H_SMEMB);
        cudaFuncSetAttribute(hgemm_k<1,false,true >, cudaFuncAttributeMaxDynamicSharedMemorySize, H_SMEMB);
        cudaFuncSetAttribute(hgemm_k<0,false,true >, cudaFuncAttributeMaxDynamicSharedMemorySize, H_SMEMB);
        cudaStreamCreateWithFlags(&s2, cudaStreamNonBlocking);
        cudaEventCreateWithFlags(&evA, cudaEventDisableTiming);
        cudaEventCreateWithFlags(&evB, cudaEventDisableTiming);
    }

    zero_k<<<1,1>>>();

    // fork: weight transposes on s2, preamble on main stream
    cudaEventRecord(evA, 0);
    cudaStreamWaitEvent(s2, evA, 0);
    for (int L = 0; L < NLAYER; L++){
        __half* qkvT = p_wT + (size_t)L*WL;
        __half* awT  = qkvT + 1769472;
        __half* fcT  = awT  + 589824;
        __half* pwT  = fcT  + 2359296;
        transp_k<<<dim3(2304/32, 768/32), dim3(32,8), 0, s2>>>(qkvw + (size_t)L*DMOD*3*DMOD, qkvT, 768, 2304);
        transp_k<<<dim3( 768/32, 768/32), dim3(32,8), 0, s2>>>(aw   + (size_t)L*DMOD*DMOD,   awT,  768, 768);
        transp_k<<<dim3(3072/32, 768/32), dim3(32,8), 0, s2>>>(fcw  + (size_t)L*DMOD*4*DMOD, fcT,  768, 3072);
        transp_k<<<dim3( 768/32,3072/32), dim3(32,8), 0, s2>>>(pw   + (size_t)L*4*DMOD*DMOD, pwT, 3072, 768);
    }
    cudaEventRecord(evB, s2);

    norm_k<<<NSER,256>>>(x);
    dec_k<<<NSER,256>>>();
    patch_k<<<NSER,256>>>();
    gemm_k<false,0,false,true><<<dim3(DMOD/64, NSER*PNUM/64),256>>>(p_tok, in_w, in_b, p_h, NSER*PNUM, DMOD, 48);
    keynorm_k<<<POOLN,256>>>(pk);
    xq_k<<<NSER,256>>>();
    gemm_k<true,0,false,false><<<dim3((POOLN+63)/64, NSER/64),256>>>(p_xq, p_keyn, (const float*)nullptr, p_sim, NSER, POOLN, DMOD);
    topk_k<<<NSER,256>>>();
    wpe_k<<<(unsigned)(((size_t)NTOK*DMOD + 255)/256),256>>>(wpe);

    // join: transposed weights ready before layer loop
    cudaStreamWaitEvent(0, evB, 0);

    const int MB = NTOK/128;   // 238
    for (int L = 0; L < NLAYER; L++){
        __half* qkvT = p_wT + (size_t)L*WL;
        __half* awT  = qkvT + 1769472;
        __half* fcT  = awT  + 589824;
        __half* pwT  = fcT  + 2359296;
        ln_k<true><<<NTOK/8,256>>>(p_h, ln1g + (size_t)L*DMOD, ln1b + (size_t)L*DMOD, p_a);
        hgemm_k<0,false,true ><<<dim3(3*DMOD/128, MB),256,H_SMEMB>>>(p_a, qkvT, qkvb + (size_t)L*3*DMOD, p_qkv, NTOK, 3*DMOD, DMOD);
        attn_k<<<NSER*12,160>>>();
        hgemm_k<0,true ,false><<<dim3(DMOD/128, MB),256,H_SMEMB>>>(p_ob, awT, ab + (size_t)L*DMOD, p_h, NTOK, DMOD, DMOD);
        ln_k<true><<<NTOK/8,256>>>(p_h, ln2g + (size_t)L*DMOD, ln2b + (size_t)L*DMOD, p_a);
        hgemm_k<1,false,true ><<<dim3(4*DMOD/128, MB),256,H_SMEMB>>>(p_a, fcT, fcb + (size_t)L*4*DMOD, p_mlp, NTOK, 4*DMOD, DMOD);
        hgemm_k<0,true ,false><<<dim3(DMOD/128, MB),256,H_SMEMB>>>(p_mlp, pwT, pbb + (size_t)L*DMOD, p_h, NTOK, DMOD, 3072);
    }

    ln_k<false><<<NTOK/8,256>>>(p_h, lnfg, lnfb, p_af);
    headgemm_k<<<dim3(1, (NSER*3+127)/128, SPLITZ),256,SMB>>>(p_af, outw, p_osp, NSER*3, PREDL, TTOK*DMOD/3);
    final_k<<<NSER,96>>>(outb, out);
    rsim_k<<<1,1>>>(out, out_size);
}

// round 8
// speedup vs baseline: 7.0213x; 1.0039x over previous
#include <cuda_runtime.h>
#include <cuda_fp16.h>
#include <math.h>
#include <stdint.h>

#define NSER 448
#define LSEQ 512
#define TTOK 68
#define DMOD 768
#define NTOK (NSER*TTOK)       // 30464
#define PNUM 64
#define POOLN 1000
#define PREDL 96
#define NLAYER 6
#define SPLITZ 32

// ---------------- scratch (device globals; no allocations) ----------------
__device__ float  g_mean[NSER];
__device__ float  g_std [NSER];
__device__ float  g_tok [NSER*PNUM*48];
__device__ float  g_h   [(size_t)NTOK*DMOD];
__device__ __half g_a   [(size_t)NTOK*DMOD];
__device__ float  g_af  [(size_t)NTOK*DMOD];
__device__ __half g_qkvh[(size_t)NTOK*3*DMOD];
__device__ __half g_ob  [(size_t)NTOK*DMOD];
__device__ __half g_mlp [(size_t)NTOK*4*DMOD];
__device__ float  g_xq  [NSER*DMOD];
__device__ float  g_keyn[POOLN*DMOD];
__device__ float  g_sim [NSER*POOLN];
__device__ float  g_osp [(size_t)SPLITZ*NSER*3*PREDL];
__device__ float  g_rsim;
#define WL 7077888u
__device__ __half g_wT  [(size_t)NLAYER*WL];

__device__ __forceinline__ float gelu_tanh(float x){
    float c = 0.7978845608028654f;
    float t = tanhf(c*(x + 0.044715f*x*x*x));
    return 0.5f*x*(1.f+t);
}

__device__ __forceinline__ unsigned f2tf(float x){
    unsigned r; asm("cvt.rna.tf32.f32 %0, %1;" : "=r"(r) : "f"(x)); return r;
}

__device__ __forceinline__ void mma8(float* c, const unsigned* a, const unsigned* b){
    asm volatile("mma.sync.aligned.m16n8k8.row.col.f32.tf32.tf32.f32 "
        "{%0,%1,%2,%3}, {%4,%5,%6,%7}, {%8,%9}, {%0,%1,%2,%3};"
        : "+f"(c[0]),"+f"(c[1]),"+f"(c[2]),"+f"(c[3])
        : "r"(a[0]),"r"(a[1]),"r"(a[2]),"r"(a[3]), "r"(b[0]),"r"(b[1]));
}

__device__ __forceinline__ void mma16(float* c, const unsigned* a, const unsigned* b){
    asm volatile("mma.sync.aligned.m16n8k16.row.col.f32.f16.f16.f32 "
        "{%0,%1,%2,%3}, {%4,%5,%6,%7}, {%8,%9}, {%0,%1,%2,%3};"
        : "+f"(c[0]),"+f"(c[1]),"+f"(c[2]),"+f"(c[3])
        : "r"(a[0]),"r"(a[1]),"r"(a[2]),"r"(a[3]), "r"(b[0]),"r"(b[1]));
}

__device__ __forceinline__ void ldsm4(unsigned &r0, unsigned &r1, unsigned &r2, unsigned &r3, uint32_t addr){
    asm volatile("ldmatrix.sync.aligned.m8n8.x4.shared.b16 {%0,%1,%2,%3}, [%4];"
        : "=r"(r0),"=r"(r1),"=r"(r2),"=r"(r3) : "r"(addr));
}

__device__ __forceinline__ void cpasyncF(float* dst, const float* src, bool pred){
    unsigned sa = (unsigned)__cvta_generic_to_shared(dst);
    int sz = pred ? 16 : 0;
    asm volatile("cp.async.cg.shared.global [%0], [%1], 16, %2;" :: "r"(sa), "l"(src), "r"(sz));
}
__device__ __forceinline__ void cpasyncH(__half* dst, const __half* src){
    unsigned sa = (unsigned)__cvta_generic_to_shared(dst);
    asm volatile("cp.async.cg.shared.global [%0], [%1], 16;" :: "r"(sa), "l"(src));
}
__device__ __forceinline__ void cp_commit(){ asm volatile("cp.async.commit_group;"); }
template<int N> __device__ __forceinline__ void cp_wait(){ asm volatile("cp.async.wait_group %0;"::"n"(N)); }

__device__ __forceinline__ unsigned packh2(float a, float b){
    __half2 h = __floats2half2_rn(a, b);
    return *reinterpret_cast<unsigned*>(&h);
}

// ---------------- fused preamble: RevIN + decompose + patch + zero --------
__global__ void prep_k(const float* __restrict__ x){
    int n = blockIdx.x, b = n/7, m = n%7, tid = threadIdx.x;
    __shared__ float xs[LSEQ];
    __shared__ float valid[489];
    __shared__ float det[LSEQ];
    __shared__ float ph[24];
    __shared__ float red[256];
    if (n == 0 && tid == 0) g_rsim = 0.f;
    for (int l = tid; l < LSEQ; l += 256) xs[l] = x[((size_t)b*LSEQ + l)*7 + m];
    if (tid < 24) ph[tid] = 0.f;
    __syncthreads();
    float s = xs[tid] + xs[tid+256];
    red[tid] = s; __syncthreads();
    for (int o = 128; o; o >>= 1){ if (tid < o) red[tid] += red[tid+o]; __syncthreads(); }
    float mu = red[0] * (1.f/LSEQ);
    __syncthreads();
    float d0 = xs[tid]-mu, d1 = xs[tid+256]-mu;
    red[tid] = d0*d0 + d1*d1; __syncthreads();
    for (int o = 128; o; o >>= 1){ if (tid < o) red[tid] += red[tid+o]; __syncthreads(); }
    float sd = sqrtf(red[0]*(1.f/LSEQ) + 1e-5f);
    if (tid == 0){ g_mean[n] = mu; g_std[n] = sd; }
    float inv = 1.f/sd;
    xs[tid]       = d0*inv;
    xs[tid + 256] = d1*inv;
    __syncthreads();
    for (int i = tid; i < 489; i += 256){
        float ss = 0.f;
        #pragma unroll
        for (int k = 0; k < 24; k++) ss += xs[i+k];
        valid[i] = ss * (1.f/24.f);
    }
    __syncthreads();
    for (int l = tid; l < LSEQ; l += 256){
        int vi = l - 12; vi = vi < 0 ? 0 : (vi > 488 ? 488 : vi);
        float dt = xs[l] - valid[vi];
        det[l] = dt;
        atomicAdd(&ph[l % 24], dt);
    }
    __syncthreads();
    // patch extraction straight to g_tok
    for (int e = tid; e < PNUM*48; e += 256){
        int p = e/48, rem = e%48, c = rem/16, j = rem%16;
        int l = p*8 + j; if (l > LSEQ-1) l = LSEQ-1;
        float v;
        if (c == 0){
            int vi = l - 12; vi = vi < 0 ? 0 : (vi > 488 ? 488 : vi);
            v = valid[vi];
        } else {
            int pp = l % 24;
            float cnt = (pp < 8) ? 22.f : 21.f;
            float se = ph[pp] / cnt;
            v = (c == 1) ? se : (det[l] - se);
        }
        g_tok[(size_t)n*PNUM*48 + e] = v;
    }
}

// ---------------- weight transpose to half: W[K,N] -> WT[N,K] -------------
__global__ void transp_k(const float* __restrict__ W, __half* __restrict__ WT, int K, int N){
    __shared__ float t[32][33];
    int bx = blockIdx.x*32, by = blockIdx.y*32;
    int x = threadIdx.x, y = threadIdx.y;   // 32 x 8
    #pragma unroll
    for (int i = 0; i < 4; i++){
        int r = by + y*4 + i;
        t[y*4+i][x] = W[(size_t)r*N + bx + x];
    }
    __syncthreads();
    #pragma unroll
    for (int i = 0; i < 4; i++){
        int rn = bx + y*4 + i;
        WT[(size_t)rn*K + by + x] = __float2half(t[x][y*4+i]);
    }
}

// ---------------- generic fp32 SIMT GEMM (precision-critical small paths) --
template<bool TRANSB, int ACT, bool RESID, bool REMAP>
__global__ void gemm_k(const float* __restrict__ A, const float* __restrict__ B,
                       const float* __restrict__ bias, float* __restrict__ C,
                       int M, int N, int K){
    __shared__ float As[16][68];
    __shared__ float Bs[16][68];
    int tid = threadIdx.x;
    int tx = tid & 15, ty = tid >> 4;
    int row0 = blockIdx.y * 64, col0 = blockIdx.x * 64;
    float acc[4][4] = {};
    for (int k0 = 0; k0 < K; k0 += 16){
        {
            int r  = tid >> 2;
            int c4 = (tid & 3) * 4;
            float4 v = *reinterpret_cast<const float4*>(&A[(size_t)(row0 + r)*K + k0 + c4]);
            As[c4+0][r] = v.x; As[c4+1][r] = v.y; As[c4+2][r] = v.z; As[c4+3][r] = v.w;
        }
        if (!TRANSB){
            int kk = tid >> 4;
            int c4 = (tid & 15) * 4;
            int col = col0 + c4;
            float4 v = make_float4(0.f,0.f,0.f,0.f);
            if (col < N) v = *reinterpret_cast<const float4*>(&B[(size_t)(k0+kk)*N + col]);
            Bs[kk][c4+0] = v.x; Bs[kk][c4+1] = v.y; Bs[kk][c4+2] = v.z; Bs[kk][c4+3] = v.w;
        } else {
            int nn = tid >> 2;
            int c4 = (tid & 3) * 4;
            int col = col0 + nn;
            float4 v = make_float4(0.f,0.f,0.f,0.f);
            if (col < N) v = *reinterpret_cast<const float4*>(&B[(size_t)col*K + k0 + c4]);
            Bs[c4+0][nn] = v.x; Bs[c4+1][nn] = v.y; Bs[c4+2][nn] = v.z; Bs[c4+3][nn] = v.w;
        }
        __syncthreads();
        #pragma unroll
        for (int kk = 0; kk < 16; kk++){
            float a[4], b[4];
            #pragma unroll
            for (int i = 0; i < 4; i++) a[i] = As[kk][ty*4+i];
            #pragma unroll
            for (int j = 0; j < 4; j++) b[j] = Bs[kk][tx*4+j];
            #pragma unroll
            for (int i = 0; i < 4; i++)
                #pragma unroll
                for (int j = 0; j < 4; j++) acc[i][j] = fmaf(a[i], b[j], acc[i][j]);
        }
        __syncthreads();
    }
    #pragma unroll
    for (int i = 0; i < 4; i++){
        int r = row0 + ty*4 + i;
        size_t orow = REMAP ? (size_t)((r >> 6)*TTOK + 4 + (r & 63)) : (size_t)r;
        #pragma unroll
        for (int j = 0; j < 4; j++){
            int col = col0 + tx*4 + j;
            if (col < N){
                float v = acc[i][j];
                if (bias) v += bias[col];
                if (ACT == 1) v = gelu_tanh(v);
                size_t idx = orow*(size_t)N + col;
                if (RESID) C[idx] += v; else C[idx] = v;
            }
        }
    }
}

// ================= fp16 tensor-core GEMM (ldmatrix fragments) =============
#define HST 40
#define H_STAGE (128*HST)
#define H_SMEMB (6*H_STAGE*2)

template<int ACT, bool RESID, bool HOUT>
__global__ __launch_bounds__(256, 2) void hgemm_k(
        const __half* __restrict__ A, const __half* __restrict__ BT,
        const float* __restrict__ bias, void* __restrict__ Cv,
        int M, int N, int K){
    extern __shared__ __half hsm[];
    __half* smA = hsm;
    __half* smB = hsm + 3*H_STAGE;
    int tid = threadIdx.x;
    int warp = tid >> 5, lane = tid & 31;
    int wm = warp >> 2, wn = warp & 3;
    int g = lane >> 2, tg = lane & 3;
    int row0 = blockIdx.y * 128, col0 = blockIdx.x * 128;

    float acc[4][4][4];
    #pragma unroll
    for (int i=0;i<4;i++) for (int j=0;j<4;j++) for (int q=0;q<4;q++) acc[i][j][q]=0.f;

    uint32_t smA_u = (uint32_t)__cvta_generic_to_shared(smA);
    uint32_t smB_u = (uint32_t)__cvta_generic_to_shared(smB);
    uint32_t aoff = (uint32_t)(((wm*64 + (lane & 15))*HST + ((lane >> 4)*8)) * 2);
    int brlo = lane & 7, b8 = ((lane >> 4) & 1)*8, bc8 = ((lane >> 3) & 1)*8;
    uint32_t boff0 = (uint32_t)(((wn*32 +  0 + b8 + brlo)*HST + bc8) * 2);
    uint32_t boff1 = (uint32_t)(((wn*32 + 16 + b8 + brlo)*HST + bc8) * 2);

    #define ISSUE_H(T, S) { \
        __half* as = smA + (S)*H_STAGE; \
        __half* bs = smB + (S)*H_STAGE; \
        const __half* Ab = A + (size_t)row0*K + (T)*32; \
        const __half* Bb = BT + (size_t)col0*K + (T)*32; \
        _Pragma("unroll") \
        for (int i=0;i<2;i++){ \
            int idx = tid + i*256; int r = idx>>2, ch = idx&3; \
            cpasyncH(&as[r*HST + ch*8], &Ab[(size_t)r*K + ch*8]); \
        } \
        _Pragma("unroll") \
        for (int i=0;i<2;i++){ \
            int idx = tid + i*256; int r = idx>>2, ch = idx&3; \
            cpasyncH(&bs[r*HST + ch*8], &Bb[(size_t)r*K + ch*8]); \
        } \
        cp_commit(); }

    int nt = K >> 5;
    ISSUE_H(0, 0);
    ISSUE_H(1, 1);

    int stage = 0;
    for (int kt = 0; kt < nt; kt++){
        if (kt == nt-1) cp_wait<0>(); else cp_wait<1>();
        __syncthreads();
        if (kt + 2 < nt){
            int s2 = stage + 2; if (s2 >= 3) s2 -= 3;
            ISSUE_H(kt+2, s2);
        }
        uint32_t stb = (uint32_t)(stage*H_STAGE*2);
        #pragma unroll
        for (int ks = 0; ks < 32; ks += 16){
            unsigned af[4][4], bf[4][2];
            #pragma unroll
            for (int mt = 0; mt < 4; mt++)
                ldsm4(af[mt][0], af[mt][1], af[mt][2], af[mt][3],
                      smA_u + stb + aoff + (uint32_t)((mt*16*HST + ks)*2));
            ldsm4(bf[0][0], bf[0][1], bf[1][0], bf[1][1], smB_u + stb + boff0 + (uint32_t)(ks*2));
            ldsm4(bf[2][0], bf[2][1], bf[3][0], bf[3][1], smB_u + stb + boff1 + (uint32_t)(ks*2));
            #pragma unroll
            for (int mt = 0; mt < 4; mt++)
                #pragma unroll
                for (int nt2 = 0; nt2 < 4; nt2++)
                    mma16(acc[mt][nt2], af[mt], bf[nt2]);
        }
        stage++; if (stage >= 3) stage -= 3;
    }
    #undef ISSUE_H

    #pragma unroll
    for (int mt = 0; mt < 4; mt++){
        int rbase = row0 + wm*64 + mt*16;
        #pragma unroll
        for (int nt2 = 0; nt2 < 4; nt2++){
            int cbase = col0 + wn*32 + nt2*8 + tg*2;
            float b0 = bias[cbase], b1 = bias[cbase+1];
            #pragma unroll
            for (int hh = 0; hh < 2; hh++){
                int rr = rbase + g + hh*8;
                float v0 = acc[mt][nt2][hh*2]   + b0;
                float v1 = acc[mt][nt2][hh*2+1] + b1;
                if (ACT == 1){ v0 = gelu_tanh(v0); v1 = gelu_tanh(v1); }
                size_t gi = (size_t)rr*N + cbase;
                if (HOUT){
                    __half2* p = reinterpret_cast<__half2*>(reinterpret_cast<__half*>(Cv) + gi);
                    *p = __floats2half2_rn(v0, v1);
                } else {
                    float* C = reinterpret_cast<float*>(Cv);
                    if (RESID){
                        float2 c = *reinterpret_cast<float2*>(&C[gi]);
                        c.x += v0; c.y += v1;
                        *reinterpret_cast<float2*>(&C[gi]) = c;
                    } else {
                        *reinterpret_cast<float2*>(&C[gi]) = make_float2(v0, v1);
                    }
                }
            }
        }
    }
}

// ---------------- legacy tf32 tensor GEMM (output head, split-K) ----------
#define AS_ST 36
#define BS_ST 136
#define A_STAGE (128*AS_ST)
#define B_STAGE (32*BS_ST)
#define SM_FLOATS (3*(A_STAGE+B_STAGE))

__global__ __launch_bounds__(256, 2) void headgemm_k(
        const float* __restrict__ A, const float* __restrict__ B,
        float* __restrict__ C, int M, int N, int K){
    extern __shared__ float sm[];
    float* smA = sm;
    float* smB = sm + 3*A_STAGE;
    int tid = threadIdx.x;
    int warp = tid >> 5, lane = tid & 31;
    int wm = warp >> 2, wn = warp & 3;
    int g = lane >> 2, tg = lane & 3;
    int row0 = blockIdx.y * 128, col0 = blockIdx.x * 128;

    int Kc   = K / gridDim.z;
    int kbeg = blockIdx.z * Kc;
    int nt   = Kc >> 5;

    float acc[4][4][4];
    #pragma unroll
    for (int i=0;i<4;i++) for (int j=0;j<4;j++) for (int q=0;q<4;q++) acc[i][j][q]=0.f;

    #define ISSUE_T(T, S) { \
        int k0 = kbeg + (T)*32; \
        float* as = smA + (S)*A_STAGE; \
        float* bs = smB + (S)*B_STAGE; \
        _Pragma("unroll") \
        for (int i=0;i<4;i++){ \
            int idx = tid + i*256; int r = idx>>3; int ch=(idx&7)<<2; \
            int grow = row0 + r; bool p = grow < M; int gr = p ? grow : (M-1); \
            cpasyncF(&as[r*AS_ST + ch], &A[(size_t)gr*K + k0 + ch], p); \
        } \
        _Pragma("unroll") \
        for (int i=0;i<4;i++){ \
            int idx = tid + i*256; int kk = idx>>5; int c4=(idx&31)<<2; \
            int gcol = col0 + c4; bool p = gcol < N; int gc = p ? gcol : 0; \
            cpasyncF(&bs[kk*BS_ST + c4], &B[(size_t)(k0+kk)*N + gc], p); \
        } \
        cp_commit(); }

    ISSUE_T(0, 0);
    ISSUE_T(1, 1);

    int stage = 0;
    for (int kt = 0; kt < nt; kt++){
        if (kt == nt-1) cp_wait<0>(); else cp_wait<1>();
        __syncthreads();
        if (kt + 2 < nt){
            int s2 = stage + 2; if (s2 >= 3) s2 -= 3;
            ISSUE_T(kt+2, s2);
        }
        const float* as = smA + stage*A_STAGE;
        const float* bs = smB + stage*B_STAGE;
        #pragma unroll
        for (int ks = 0; ks < 32; ks += 8){
            unsigned af[4][4], bf[4][2];
            #pragma unroll
            for (int mt = 0; mt < 4; mt++){
                int r = wm*64 + mt*16 + g;
                af[mt][0] = f2tf(as[r*AS_ST + ks+tg]);
                af[mt][1] = f2tf(as[(r+8)*AS_ST + ks+tg]);
                af[mt][2] = f2tf(as[r*AS_ST + ks+tg+4]);
                af[mt][3] = f2tf(as[(r+8)*AS_ST + ks+tg+4]);
            }
            #pragma unroll
            for (int nt2 = 0; nt2 < 4; nt2++){
                int c = wn*32 + nt2*8 + g;
                bf[nt2][0] = f2tf(bs[(ks+tg)*BS_ST + c]);
                bf[nt2][1] = f2tf(bs[(ks+tg+4)*BS_ST + c]);
            }
            #pragma unroll
            for (int mt = 0; mt < 4; mt++)
                #pragma unroll
                for (int nt2 = 0; nt2 < 4; nt2++)
                    mma8(acc[mt][nt2], af[mt], bf[nt2]);
        }
        stage++; if (stage >= 3) stage -= 3;
        __syncthreads();
    }
    #undef ISSUE_T

    float* Cout = C + (size_t)blockIdx.z*M*N;
    #pragma unroll
    for (int mt = 0; mt < 4; mt++){
        int rbase = row0 + wm*64 + mt*16;
        #pragma unroll
        for (int nt2 = 0; nt2 < 4; nt2++){
            int cbase = col0 + wn*32 + nt2*8 + tg*2;
            #pragma unroll
            for (int half2_ = 0; half2_ < 2; half2_++){
                int rr = rbase + g + half2_*8;
                if (rr < M){
                    #pragma unroll
                    for (int jj = 0; jj < 2; jj++){
                        int cc = cbase + jj;
                        if (cc < N) Cout[(size_t)rr*N + cc] = acc[mt][nt2][half2_*2+jj];
                    }
                }
            }
        }
    }
}

// ---------------- l2-normalize prompt keys ----------------
__global__ void keynorm_k(const float* __restrict__ pk){
    int r = blockIdx.x, tid = threadIdx.x;
    __shared__ float red[256];
    float v0 = pk[(size_t)r*DMOD + tid], v1 = pk[(size_t)r*DMOD + 256 + tid], v2 = pk[(size_t)r*DMOD + 512 + tid];
    red[tid] = v0*v0 + v1*v1 + v2*v2; __syncthreads();
    for (int o = 128; o; o >>= 1){ if (tid < o) red[tid] += red[tid+o]; __syncthreads(); }
    float inv = rsqrtf(fmaxf(red[0], 1e-12f));
    g_keyn[(size_t)r*DMOD + tid]       = v0*inv;
    g_keyn[(size_t)r*DMOD + 256 + tid] = v1*inv;
    g_keyn[(size_t)r*DMOD + 512 + tid] = v2*inv;
}

// ---------------- xq ----------------
__global__ void xq_k(){
    int n = blockIdx.x, tid = threadIdx.x;
    __shared__ float xs[DMOD];
    __shared__ float red[256];
    float ss = 0.f;
    for (int d = tid; d < DMOD; d += 256){
        float s = 0.f;
        for (int p = 0; p < PNUM; p++) s += g_h[((size_t)n*TTOK + 4 + p)*DMOD + d];
        s *= (1.f/PNUM);
        xs[d] = s; ss += s*s;
    }
    red[tid] = ss; __syncthreads();
    for (int o = 128; o; o >>= 1){ if (tid < o) red[tid] += red[tid+o]; __syncthreads(); }
    float inv = rsqrtf(fmaxf(red[0], 1e-12f));
    for (int d = tid; d < DMOD; d += 256) g_xq[(size_t)n*DMOD + d] = xs[d]*inv;
}

// ---------------- top-k ----------------
__global__ void topk_k(){
    int n = blockIdx.x, tid = threadIdx.x;
    __shared__ float bv[256];
    __shared__ int   bi[256];
    __shared__ int   chosen[4];
    float rs = 0.f;
    for (int r = 0; r < 4; r++){
        float best = -1e30f; int besti = 1 << 30;
        for (int j = tid; j < POOLN; j += 256){
            bool skip = false;
            for (int c = 0; c < r; c++) if (chosen[c] == j) skip = true;
            float v = g_sim[(size_t)n*POOLN + j];
            if (!skip && (v > best || (v == best && j < besti))){ best = v; besti = j; }
        }
        bv[tid] = best; bi[tid] = besti; __syncthreads();
        for (int o = 128; o; o >>= 1){
            if (tid < o){
                if (bv[tid+o] > bv[tid] || (bv[tid+o] == bv[tid] && bi[tid+o] < bi[tid])){
                    bv[tid] = bv[tid+o]; bi[tid] = bi[tid+o];
                }
            }
            __syncthreads();
        }
        if (tid == 0){ chosen[r] = bi[0]; rs += bv[0]; }
        __syncthreads();
    }
    for (int e = tid; e < 4*DMOD; e += 256){
        int k = e / DMOD, d = e % DMOD;
        g_h[((size_t)n*TTOK + k)*DMOD + d] = g_keyn[(size_t)chosen[k]*DMOD + d];
    }
    if (tid == 0) atomicAdd(&g_rsim, rs);
}

// ---------------- add positional embedding ----------------
__global__ void wpe_k(const float* __restrict__ wpe){
    size_t i = (size_t)blockIdx.x*blockDim.x + threadIdx.x;
    if (i < (size_t)NTOK*DMOD){
        int tok = (int)(i / DMOD);
        int t = tok % TTOK;
        int d = (int)(i % DMOD);
        g_h[i] += wpe[(size_t)t*DMOD + d];
    }
}

// ---------------- layernorm: warp per row; half or float out --------------
template<bool HOUT>
__global__ void ln_k(const float* __restrict__ x, const float* __restrict__ g,
                     const float* __restrict__ b, void* __restrict__ yv){
    int row  = blockIdx.x*8 + (threadIdx.x >> 5);
    int lane = threadIdx.x & 31;
    const float4* xr = reinterpret_cast<const float4*>(x + (size_t)row*DMOD);
    const float4* g4 = reinterpret_cast<const float4*>(g);
    const float4* b4 = reinterpret_cast<const float4*>(b);
    float4 v[6];
    float s = 0.f, sq = 0.f;
    #pragma unroll
    for (int i = 0; i < 6; i++){
        v[i] = xr[lane + i*32];
        s  += v[i].x + v[i].y + v[i].z + v[i].w;
        sq += v[i].x*v[i].x + v[i].y*v[i].y + v[i].z*v[i].z + v[i].w*v[i].w;
    }
    #pragma unroll
    for (int o = 16; o; o >>= 1){
        s  += __shfl_xor_sync(0xffffffffu, s,  o);
        sq += __shfl_xor_sync(0xffffffffu, sq, o);
    }
    float mu  = s * (1.f/DMOD);
    float var = sq * (1.f/DMOD) - mu*mu;
    float inv = rsqrtf(var + 1e-5f);
    #pragma unroll
    for (int i = 0; i < 6; i++){
        float4 gg = g4[lane + i*32], bb = b4[lane + i*32], o;
        o.x = (v[i].x-mu)*inv*gg.x + bb.x;
        o.y = (v[i].y-mu)*inv*gg.y + bb.y;
        o.z = (v[i].z-mu)*inv*gg.z + bb.z;
        o.w = (v[i].w-mu)*inv*gg.w + bb.w;
        if (HOUT){
            __half2* yr = reinterpret_cast<__half2*>(reinterpret_cast<__half*>(yv) + (size_t)row*DMOD);
            yr[2*(lane+i*32)]   = __floats2half2_rn(o.x, o.y);
            yr[2*(lane+i*32)+1] = __floats2half2_rn(o.z, o.w);
        } else {
            float4* yr = reinterpret_cast<float4*>(reinterpret_cast<float*>(yv) + (size_t)row*DMOD);
            yr[lane + i*32] = o;
        }
    }
}

// ---------------- attention: fp16 mma flash, block per (series, head) -----
#define QKS 72
#define VTS 88
__global__ __launch_bounds__(160) void attn_k(){
    int blk = blockIdx.x;
    int n = blk / 12, head = blk % 12;
    __shared__ __half qs[80*QKS];
    __shared__ __half ks[80*QKS];
    __shared__ __half vt[64*VTS];
    int tid = threadIdx.x, w = tid >> 5, lane = tid & 31;
    int g = lane >> 2, tg = lane & 3;

    const __half* qkv = g_qkvh + (size_t)n*TTOK*3*DMOD + head*64;
    for (int idx = tid; idx < TTOK*32; idx += 160){
        int t = idx >> 5, c = (idx & 31)*2;
        __half2 q2 = *reinterpret_cast<const __half2*>(qkv + (size_t)t*3*DMOD + c);
        __half2 k2 = *reinterpret_cast<const __half2*>(qkv + (size_t)t*3*DMOD + DMOD + c);
        __half2 v2 = *reinterpret_cast<const __half2*>(qkv + (size_t)t*3*DMOD + 2*DMOD + c);
        *reinterpret_cast<__half2*>(qs + t*QKS + c) = q2;
        *reinterpret_cast<__half2*>(ks + t*QKS + c) = k2;
        vt[c*VTS + t]     = __low2half(v2);
        vt[(c+1)*VTS + t] = __high2half(v2);
    }
    for (int idx = tid; idx < 64*12; idx += 160){
        int d = idx / 12, t = 68 + idx % 12;
        vt[d*VTS + t] = __float2half(0.f);
    }
    __syncthreads();

    int rb = w*16 + g;
    float sacc[10][4];
    #pragma unroll
    for (int i = 0; i < 10; i++) for (int j = 0; j < 4; j++) sacc[i][j] = 0.f;
    #pragma unroll
    for (int kc = 0; kc < 4; kc++){
        unsigned af[4];
        int base = rb*QKS + kc*16 + 2*tg;
        af[0] = *reinterpret_cast<const unsigned*>(&qs[base]);
        af[1] = *reinterpret_cast<const unsigned*>(&qs[base + 8*QKS]);
        af[2] = *reinterpret_cast<const unsigned*>(&qs[base + 8]);
        af[3] = *reinterpret_cast<const unsigned*>(&qs[base + 8*QKS + 8]);
        #pragma unroll
        for (int nt = 0; nt < 10; nt++){
            unsigned bf[2];
            int bb = (nt*8 + g)*QKS + kc*16 + 2*tg;
            bf[0] = *reinterpret_cast<const unsigned*>(&ks[bb]);
            bf[1] = *reinterpret_cast<const unsigned*>(&ks[bb + 8]);
            mma16(sacc[nt], af, bf);
        }
    }
    float inv_[2];
    #pragma unroll
    for (int hh = 0; hh < 2; hh++){
        int R = rb + hh*8;
        float mx = -1e30f;
        #pragma unroll
        for (int nt = 0; nt < 10; nt++)
            #pragma unroll
            for (int jj = 0; jj < 2; jj++){
                int Cn = nt*8 + 2*tg + jj;
                float sv = sacc[nt][hh*2+jj] * 0.125f;
                sv = (Cn <= R) ? sv : -1e9f;
                sacc[nt][hh*2+jj] = sv;
                mx = fmaxf(mx, sv);
            }
        mx = fmaxf(mx, __shfl_xor_sync(0xffffffffu, mx, 1));
        mx = fmaxf(mx, __shfl_xor_sync(0xffffffffu, mx, 2));
        float sm = 0.f;
        #pragma unroll
        for (int nt = 0; nt < 10; nt++)
            #pragma unroll
            for (int jj = 0; jj < 2; jj++){
                float p = expf(sacc[nt][hh*2+jj] - mx);
                sacc[nt][hh*2+jj] = p;
                sm += p;
            }
        sm += __shfl_xor_sync(0xffffffffu, sm, 1);
        sm += __shfl_xor_sync(0xffffffffu, sm, 2);
        inv_[hh] = 1.f/sm;
    }
    float oacc[8][4];
    #pragma unroll
    for (int i = 0; i < 8; i++) for (int j = 0; j < 4; j++) oacc[i][j] = 0.f;
    #pragma unroll
    for (int kc = 0; kc < 5; kc++){
        unsigned af[4];
        af[0] = packh2(sacc[2*kc][0],   sacc[2*kc][1]);
        af[1] = packh2(sacc[2*kc][2],   sacc[2*kc][3]);
        af[2] = packh2(sacc[2*kc+1][0], sacc[2*kc+1][1]);
        af[3] = packh2(sacc[2*kc+1][2], sacc[2*kc+1][3]);
        #pragma unroll
        for (int nt = 0; nt < 8; nt++){
            unsigned bf[2];
            int bb = (nt*8 + g)*VTS + kc*16 + 2*tg;
            bf[0] = *reinterpret_cast<const unsigned*>(&vt[bb]);
            bf[1] = *reinterpret_cast<const unsigned*>(&vt[bb + 8]);
            mma16(oacc[nt], af, bf);
        }
    }
    __half* ob = g_ob + (size_t)n*TTOK*DMOD + head*64;
    #pragma unroll
    for (int hh = 0; hh < 2; hh++){
        int R = rb + hh*8;
        if (R < TTOK){
            #pragma unroll
            for (int nt = 0; nt < 8; nt++){
                __half2 hv = __floats2half2_rn(oacc[nt][hh*2]*inv_[hh], oacc[nt][hh*2+1]*inv_[hh]);
                *reinterpret_cast<__half2*>(ob + (size_t)R*DMOD + nt*8 + 2*tg) = hv;
            }
        }
    }
}

// ---------------- final: sum split-K chunks + channels, denorm + rsim -----
__global__ void final_k(const float* __restrict__ outb, float* __restrict__ out, int out_size){
    int n = blockIdx.x, b = n/7, m = n%7;
    for (int t = threadIdx.x; t < PREDL; t += blockDim.x){
        float v = 3.f*outb[t];
        #pragma unroll
        for (int z = 0; z < SPLITZ; z++){
            const float* p = g_osp + (size_t)z*NSER*3*PREDL;
            v += p[(size_t)(n*3+0)*PREDL + t]
               + p[(size_t)(n*3+1)*PREDL + t]
               + p[(size_t)(n*3+2)*PREDL + t];
        }
        out[(size_t)b*PREDL*7 + (size_t)t*7 + m] = v*g_std[n] + g_mean[n];
    }
    if (n == 0 && threadIdx.x == 0 && out_size > 64*PREDL*7)
        out[64*PREDL*7] = g_rsim * (1.f/NSER);
}

// ---------------- host ----------------
template <typename T, size_t S>
static void* symaddr(T (&arr)[S]){ void* p = nullptr; cudaGetSymbolAddress(&p, arr); return p; }

extern "C" void kernel_launch(void* const* d_in, const int* in_sizes, int n_in,
                              void* d_out, int out_size){
    int s = (n_in >= 2 && in_sizes[1] == 1) ? 1 : 0;
    const float* x    = (const float*)d_in[0];
    const float* in_w = (const float*)d_in[1+s];
    const float* in_b = (const float*)d_in[2+s];
    const float* pk   = (const float*)d_in[3+s];
    const float* wpe  = (const float*)d_in[4+s];
    const float* ln1g = (const float*)d_in[5+s];
    const float* ln1b = (const float*)d_in[6+s];
    const float* qkvw = (const float*)d_in[7+s];
    const float* qkvb = (const float*)d_in[8+s];
    const float* aw   = (const float*)d_in[9+s];
    const float* ab   = (const float*)d_in[10+s];
    const float* ln2g = (const float*)d_in[11+s];
    const float* ln2b = (const float*)d_in[12+s];
    const float* fcw  = (const float*)d_in[13+s];
    const float* fcb  = (const float*)d_in[14+s];
    const float* pw   = (const float*)d_in[15+s];
    const float* pbb  = (const float*)d_in[16+s];
    const float* lnfg = (const float*)d_in[17+s];
    const float* lnfb = (const float*)d_in[18+s];
    const float* outw = (const float*)d_in[19+s];
    const float* outb = (const float*)d_in[20+s];
    float* out = (float*)d_out;

    float*  p_h    = (float*) symaddr(g_h);
    __half* p_a    = (__half*)symaddr(g_a);
    float*  p_af   = (float*) symaddr(g_af);
    __half* p_qkv  = (__half*)symaddr(g_qkvh);
    __half* p_ob   = (__half*)symaddr(g_ob);
    __half* p_mlp  = (__half*)symaddr(g_mlp);
    float*  p_tok  = (float*) symaddr(g_tok);
    float*  p_xq   = (float*) symaddr(g_xq);
    float*  p_keyn = (float*) symaddr(g_keyn);
    float*  p_sim  = (float*) symaddr(g_sim);
    float*  p_osp  = (float*) symaddr(g_osp);
    __half* p_wT   = (__half*)symaddr(g_wT);

    const int SMB = SM_FLOATS*4;
    static cudaStream_t s2 = nullptr;
    static cudaEvent_t evA = nullptr, evB = nullptr, evK = nullptr;
    if (!s2){
        cudaFuncSetAttribute(headgemm_k, cudaFuncAttributeMaxDynamicSharedMemorySize, SMB);
        cudaFuncSetAttribute(hgemm_k<0,false,false>, cudaFuncAttributeMaxDynamicSharedMemorySize, H_SMEMB);
        cudaFuncSetAttribute(hgemm_k<0,true ,false>, cudaFuncAttributeMaxDynamicSharedMemorySize, H_SMEMB);
        cudaFuncSetAttribute(hgemm_k<1,false,true >, cudaFuncAttributeMaxDynamicSharedMemorySize, H_SMEMB);
        cudaFuncSetAttribute(hgemm_k<0,false,true >, cudaFuncAttributeMaxDynamicSharedMemorySize, H_SMEMB);
        cudaStreamCreateWithFlags(&s2, cudaStreamNonBlocking);
        cudaEventCreateWithFlags(&evA, cudaEventDisableTiming);
        cudaEventCreateWithFlags(&evB, cudaEventDisableTiming);
        cudaEventCreateWithFlags(&evK, cudaEventDisableTiming);
    }

    // fork: weight transposes + keynorm on s2, preamble on main stream
    cudaEventRecord(evA, 0);
    cudaStreamWaitEvent(s2, evA, 0);
    keynorm_k<<<POOLN,256,0,s2>>>(pk);
    cudaEventRecord(evK, s2);
    for (int L = 0; L < NLAYER; L++){
        __half* qkvT = p_wT + (size_t)L*WL;
        __half* awT  = qkvT + 1769472;
        __half* fcT  = awT  + 589824;
        __half* pwT  = fcT  + 2359296;
        transp_k<<<dim3(2304/32, 768/32), dim3(32,8), 0, s2>>>(qkvw + (size_t)L*DMOD*3*DMOD, qkvT, 768, 2304);
        transp_k<<<dim3( 768/32, 768/32), dim3(32,8), 0, s2>>>(aw   + (size_t)L*DMOD*DMOD,   awT,  768, 768);
        transp_k<<<dim3(3072/32, 768/32), dim3(32,8), 0, s2>>>(fcw  + (size_t)L*DMOD*4*DMOD, fcT,  768, 3072);
        transp_k<<<dim3( 768/32,3072/32), dim3(32,8), 0, s2>>>(pw   + (size_t)L*4*DMOD*DMOD, pwT, 3072, 768);
    }
    cudaEventRecord(evB, s2);

    prep_k<<<NSER,256>>>(x);
    gemm_k<false,0,false,true><<<dim3(DMOD/64, NSER*PNUM/64),256>>>(p_tok, in_w, in_b, p_h, NSER*PNUM, DMOD, 48);
    xq_k<<<NSER,256>>>();
    cudaStreamWaitEvent(0, evK, 0);
    gemm_k<true,0,false,false><<<dim3((POOLN+63)/64, NSER/64),256>>>(p_xq, p_keyn, (const float*)nullptr, p_sim, NSER, POOLN, DMOD);
    topk_k<<<NSER,256>>>();
    wpe_k<<<(unsigned)(((size_t)NTOK*DMOD + 255)/256),256>>>(wpe);

    // join: transposed weights ready before layer loop
    cudaStreamWaitEvent(0, evB, 0);

    const int MB = NTOK/128;   // 238
    for (int L = 0; L < NLAYER; L++){
        __half* qkvT = p_wT + (size_t)L*WL;
        __half* awT  = qkvT + 1769472;
        __half* fcT  = awT  + 589824;
        __half* pwT  = fcT  + 2359296;
        ln_k<true><<<NTOK/8,256>>>(p_h, ln1g + (size_t)L*DMOD, ln1b + (size_t)L*DMOD, p_a);
        hgemm_k<0,false,true ><<<dim3(3*DMOD/128, MB),256,H_SMEMB>>>(p_a, qkvT, qkvb + (size_t)L*3*DMOD, p_qkv, NTOK, 3*DMOD, DMOD);
        attn_k<<<NSER*12,160>>>();
        hgemm_k<0,true ,false><<<dim3(DMOD/128, MB),256,H_SMEMB>>>(p_ob, awT, ab + (size_t)L*DMOD, p_h, NTOK, DMOD, DMOD);
        ln_k<true><<<NTOK/8,256>>>(p_h, ln2g + (size_t)L*DMOD, ln2b + (size_t)L*DMOD, p_a);
        hgemm_k<1,false,true ><<<dim3(4*DMOD/128, MB),256,H_SMEMB>>>(p_a, fcT, fcb + (size_t)L*4*DMOD, p_mlp, NTOK, 4*DMOD, DMOD);
        hgemm_k<0,true ,false><<<dim3(DMOD/128, MB),256,H_SMEMB>>>(p_mlp, pwT, pbb + (size_t)L*DMOD, p_h, NTOK, DMOD, 3072);
    }

    ln_k<false><<<NTOK/8,256>>>(p_h, lnfg, lnfb, p_af);
    // output head: M=1344, N=96, K=17408, split-K 32 (chunk 544)
    headgemm_k<<<dim3(1, (NSER*3+127)/128, SPLITZ),256,SMB>>>(p_af, outw, p_osp, NSER*3, PREDL, TTOK*DMOD/3);
    final_k<<<NSER,96>>>(outb, out, out_size);
}

// round 9
// speedup vs baseline: 7.0538x; 1.0046x over previous
#include <cuda_runtime.h>
#include <cuda_fp16.h>
#include <math.h>
#include <stdint.h>

#define NSER 448
#define LSEQ 512
#define TTOK 68
#define DMOD 768
#define NTOK (NSER*TTOK)       // 30464
#define PNUM 64
#define POOLN 1000
#define PREDL 96
#define NLAYER 6
#define SPLITZ 32

// ---------------- scratch (device globals; no allocations) ----------------
__device__ float  g_mean[NSER];
__device__ float  g_std [NSER];
__device__ float  g_tok [NSER*PNUM*48];
__device__ float  g_mtok[NSER*48];
__device__ float  g_h   [(size_t)NTOK*DMOD];
__device__ __half g_a   [(size_t)NTOK*DMOD];
__device__ float  g_af  [(size_t)NTOK*DMOD];
__device__ __half g_qkvh[(size_t)NTOK*3*DMOD];
__device__ __half g_ob  [(size_t)NTOK*DMOD];
__device__ __half g_mlp [(size_t)NTOK*4*DMOD];
__device__ float  g_xq  [NSER*DMOD];
__device__ float  g_keyn[POOLN*DMOD];
__device__ float  g_sim [NSER*POOLN];
__device__ float  g_osp [(size_t)SPLITZ*NSER*3*PREDL];
__device__ float  g_rsim;
#define WL 7077888u
__device__ __half g_wT  [(size_t)NLAYER*WL];

__device__ __forceinline__ float gelu_tanh(float x){
    float c = 0.7978845608028654f;
    float t = tanhf(c*(x + 0.044715f*x*x*x));
    return 0.5f*x*(1.f+t);
}

__device__ __forceinline__ unsigned f2tf(float x){
    unsigned r; asm("cvt.rna.tf32.f32 %0, %1;" : "=r"(r) : "f"(x)); return r;
}

__device__ __forceinline__ void mma8(float* c, const unsigned* a, const unsigned* b){
    asm volatile("mma.sync.aligned.m16n8k8.row.col.f32.tf32.tf32.f32 "
        "{%0,%1,%2,%3}, {%4,%5,%6,%7}, {%8,%9}, {%0,%1,%2,%3};"
        : "+f"(c[0]),"+f"(c[1]),"+f"(c[2]),"+f"(c[3])
        : "r"(a[0]),"r"(a[1]),"r"(a[2]),"r"(a[3]), "r"(b[0]),"r"(b[1]));
}

__device__ __forceinline__ void mma16(float* c, const unsigned* a, const unsigned* b){
    asm volatile("mma.sync.aligned.m16n8k16.row.col.f32.f16.f16.f32 "
        "{%0,%1,%2,%3}, {%4,%5,%6,%7}, {%8,%9}, {%0,%1,%2,%3};"
        : "+f"(c[0]),"+f"(c[1]),"+f"(c[2]),"+f"(c[3])
        : "r"(a[0]),"r"(a[1]),"r"(a[2]),"r"(a[3]), "r"(b[0]),"r"(b[1]));
}

__device__ __forceinline__ void ldsm4(unsigned &r0, unsigned &r1, unsigned &r2, unsigned &r3, uint32_t addr){
    asm volatile("ldmatrix.sync.aligned.m8n8.x4.shared.b16 {%0,%1,%2,%3}, [%4];"
        : "=r"(r0),"=r"(r1),"=r"(r2),"=r"(r3) : "r"(addr));
}

__device__ __forceinline__ void cpasyncF(float* dst, const float* src, bool pred){
    unsigned sa = (unsigned)__cvta_generic_to_shared(dst);
    int sz = pred ? 16 : 0;
    asm volatile("cp.async.cg.shared.global [%0], [%1], 16, %2;" :: "r"(sa), "l"(src), "r"(sz));
}
__device__ __forceinline__ void cpasyncH(__half* dst, const __half* src){
    unsigned sa = (unsigned)__cvta_generic_to_shared(dst);
    asm volatile("cp.async.cg.shared.global [%0], [%1], 16;" :: "r"(sa), "l"(src));
}
__device__ __forceinline__ void cp_commit(){ asm volatile("cp.async.commit_group;"); }
template<int N> __device__ __forceinline__ void cp_wait(){ asm volatile("cp.async.wait_group %0;"::"n"(N)); }

__device__ __forceinline__ unsigned packh2(float a, float b){
    __half2 h = __floats2half2_rn(a, b);
    return *reinterpret_cast<unsigned*>(&h);
}

// ---------------- fused preamble: RevIN + decompose + patch ----------------
__global__ void prep_k(const float* __restrict__ x){
    int n = blockIdx.x, b = n/7, m = n%7, tid = threadIdx.x;
    __shared__ float xs[LSEQ];
    __shared__ float valid[489];
    __shared__ float det[LSEQ];
    __shared__ float ph[24];
    __shared__ float red[256];
    if (n == 0 && tid == 0) g_rsim = 0.f;
    for (int l = tid; l < LSEQ; l += 256) xs[l] = x[((size_t)b*LSEQ + l)*7 + m];
    if (tid < 24) ph[tid] = 0.f;
    __syncthreads();
    float s = xs[tid] + xs[tid+256];
    red[tid] = s; __syncthreads();
    for (int o = 128; o; o >>= 1){ if (tid < o) red[tid] += red[tid+o]; __syncthreads(); }
    float mu = red[0] * (1.f/LSEQ);
    __syncthreads();
    float d0 = xs[tid]-mu, d1 = xs[tid+256]-mu;
    red[tid] = d0*d0 + d1*d1; __syncthreads();
    for (int o = 128; o; o >>= 1){ if (tid < o) red[tid] += red[tid+o]; __syncthreads(); }
    float sd = sqrtf(red[0]*(1.f/LSEQ) + 1e-5f);
    if (tid == 0){ g_mean[n] = mu; g_std[n] = sd; }
    float inv = 1.f/sd;
    xs[tid]       = d0*inv;
    xs[tid + 256] = d1*inv;
    __syncthreads();
    for (int i = tid; i < 489; i += 256){
        float ss = 0.f;
        #pragma unroll
        for (int k = 0; k < 24; k++) ss += xs[i+k];
        valid[i] = ss * (1.f/24.f);
    }
    __syncthreads();
    for (int l = tid; l < LSEQ; l += 256){
        int vi = l - 12; vi = vi < 0 ? 0 : (vi > 488 ? 488 : vi);
        float dt = xs[l] - valid[vi];
        det[l] = dt;
        atomicAdd(&ph[l % 24], dt);
    }
    __syncthreads();
    for (int e = tid; e < PNUM*48; e += 256){
        int p = e/48, rem = e%48, c = rem/16, j = rem%16;
        int l = p*8 + j; if (l > LSEQ-1) l = LSEQ-1;
        float v;
        if (c == 0){
            int vi = l - 12; vi = vi < 0 ? 0 : (vi > 488 ? 488 : vi);
            v = valid[vi];
        } else {
            int pp = l % 24;
            float cnt = (pp < 8) ? 22.f : 21.f;
            float se = ph[pp] / cnt;
            v = (c == 1) ? se : (det[l] - se);
        }
        g_tok[(size_t)n*PNUM*48 + e] = v;
    }
}

// ---------------- patch-mean: mtok[n,c] = mean_p tok[n,p,c] ---------------
__global__ void meantok_k(){
    int n = blockIdx.x, tid = threadIdx.x;
    if (tid < 48){
        float s = 0.f;
        for (int p = 0; p < PNUM; p++) s += g_tok[(size_t)n*PNUM*48 + p*48 + tid];
        g_mtok[n*48 + tid] = s * (1.f/PNUM);
    }
}

// ---------------- l2-normalize xq rows in place ----------------
__global__ void xqn_k(){
    int n = blockIdx.x, tid = threadIdx.x;
    __shared__ float red[256];
    float v0 = g_xq[(size_t)n*DMOD + tid], v1 = g_xq[(size_t)n*DMOD + 256 + tid], v2 = g_xq[(size_t)n*DMOD + 512 + tid];
    red[tid] = v0*v0 + v1*v1 + v2*v2; __syncthreads();
    for (int o = 128; o; o >>= 1){ if (tid < o) red[tid] += red[tid+o]; __syncthreads(); }
    float inv = rsqrtf(fmaxf(red[0], 1e-12f));
    g_xq[(size_t)n*DMOD + tid]       = v0*inv;
    g_xq[(size_t)n*DMOD + 256 + tid] = v1*inv;
    g_xq[(size_t)n*DMOD + 512 + tid] = v2*inv;
}

// ---------------- weight transpose to half: W[K,N] -> WT[N,K] -------------
__global__ void transp_k(const float* __restrict__ W, __half* __restrict__ WT, int K, int N){
    __shared__ float t[32][33];
    int bx = blockIdx.x*32, by = blockIdx.y*32;
    int x = threadIdx.x, y = threadIdx.y;   // 32 x 8
    #pragma unroll
    for (int i = 0; i < 4; i++){
        int r = by + y*4 + i;
        t[y*4+i][x] = W[(size_t)r*N + bx + x];
    }
    __syncthreads();
    #pragma unroll
    for (int i = 0; i < 4; i++){
        int rn = bx + y*4 + i;
        WT[(size_t)rn*K + by + x] = __float2half(t[x][y*4+i]);
    }
}

// ---------------- generic fp32 SIMT GEMM --------------------------------
// REMAP: out row r -> (r/64)*68+4+(r%64); wadd (if non-null, REMAP only) adds
// wpe[t*DMOD+col] in-register (t = 4 + r%64).
template<bool TRANSB, int ACT, bool RESID, bool REMAP>
__global__ void gemm_k(const float* __restrict__ A, const float* __restrict__ B,
                       const float* __restrict__ bias, float* __restrict__ C,
                       int M, int N, int K, const float* __restrict__ wadd){
    __shared__ float As[16][68];
    __shared__ float Bs[16][68];
    int tid = threadIdx.x;
    int tx = tid & 15, ty = tid >> 4;
    int row0 = blockIdx.y * 64, col0 = blockIdx.x * 64;
    float acc[4][4] = {};
    for (int k0 = 0; k0 < K; k0 += 16){
        {
            int r  = tid >> 2;
            int c4 = (tid & 3) * 4;
            float4 v = *reinterpret_cast<const float4*>(&A[(size_t)(row0 + r)*K + k0 + c4]);
            As[c4+0][r] = v.x; As[c4+1][r] = v.y; As[c4+2][r] = v.z; As[c4+3][r] = v.w;
        }
        if (!TRANSB){
            int kk = tid >> 4;
            int c4 = (tid & 15) * 4;
            int col = col0 + c4;
            float4 v = make_float4(0.f,0.f,0.f,0.f);
            if (col < N) v = *reinterpret_cast<const float4*>(&B[(size_t)(k0+kk)*N + col]);
            Bs[kk][c4+0] = v.x; Bs[kk][c4+1] = v.y; Bs[kk][c4+2] = v.z; Bs[kk][c4+3] = v.w;
        } else {
            int nn = tid >> 2;
            int c4 = (tid & 3) * 4;
            int col = col0 + nn;
            float4 v = make_float4(0.f,0.f,0.f,0.f);
            if (col < N) v = *reinterpret_cast<const float4*>(&B[(size_t)col*K + k0 + c4]);
            Bs[c4+0][nn] = v.x; Bs[c4+1][nn] = v.y; Bs[c4+2][nn] = v.z; Bs[c4+3][nn] = v.w;
        }
        __syncthreads();
        #pragma unroll
        for (int kk = 0; kk < 16; kk++){
            float a[4], b[4];
            #pragma unroll
            for (int i = 0; i < 4; i++) a[i] = As[kk][ty*4+i];
            #pragma unroll
            for (int j = 0; j < 4; j++) b[j] = Bs[kk][tx*4+j];
            #pragma unroll
            for (int i = 0; i < 4; i++)
                #pragma unroll
                for (int j = 0; j < 4; j++) acc[i][j] = fmaf(a[i], b[j], acc[i][j]);
        }
        __syncthreads();
    }
    #pragma unroll
    for (int i = 0; i < 4; i++){
        int r = row0 + ty*4 + i;
        size_t orow = REMAP ? (size_t)((r >> 6)*TTOK + 4 + (r & 63)) : (size_t)r;
        int t = REMAP ? (4 + (r & 63)) : 0;
        #pragma unroll
        for (int j = 0; j < 4; j++){
            int col = col0 + tx*4 + j;
            if (col < N){
                float v = acc[i][j];
                if (bias) v += bias[col];
                if (ACT == 1) v = gelu_tanh(v);
                if (REMAP && wadd) v += wadd[(size_t)t*DMOD + col];
                size_t idx = orow*(size_t)N + col;
                if (RESID) C[idx] += v; else C[idx] = v;
            }
        }
    }
}

// ================= fp16 tensor-core GEMM (ldmatrix fragments) =============
#define HST 40
#define H_STAGE (128*HST)
#define H_SMEMB (6*H_STAGE*2)

template<int ACT, bool RESID, bool HOUT>
__global__ __launch_bounds__(256, 2) void hgemm_k(
        const __half* __restrict__ A, const __half* __restrict__ BT,
        const float* __restrict__ bias, void* __restrict__ Cv,
        int M, int N, int K){
    extern __shared__ __half hsm[];
    __half* smA = hsm;
    __half* smB = hsm + 3*H_STAGE;
    int tid = threadIdx.x;
    int warp = tid >> 5, lane = tid & 31;
    int wm = warp >> 2, wn = warp & 3;
    int g = lane >> 2, tg = lane & 3;
    int row0 = blockIdx.y * 128, col0 = blockIdx.x * 128;

    float acc[4][4][4];
    #pragma unroll
    for (int i=0;i<4;i++) for (int j=0;j<4;j++) for (int q=0;q<4;q++) acc[i][j][q]=0.f;

    uint32_t smA_u = (uint32_t)__cvta_generic_to_shared(smA);
    uint32_t smB_u = (uint32_t)__cvta_generic_to_shared(smB);
    uint32_t aoff = (uint32_t)(((wm*64 + (lane & 15))*HST + ((lane >> 4)*8)) * 2);
    int brlo = lane & 7, b8 = ((lane >> 4) & 1)*8, bc8 = ((lane >> 3) & 1)*8;
    uint32_t boff0 = (uint32_t)(((wn*32 +  0 + b8 + brlo)*HST + bc8) * 2);
    uint32_t boff1 = (uint32_t)(((wn*32 + 16 + b8 + brlo)*HST + bc8) * 2);

    #define ISSUE_H(T, S) { \
        __half* as = smA + (S)*H_STAGE; \
        __half* bs = smB + (S)*H_STAGE; \
        const __half* Ab = A + (size_t)row0*K + (T)*32; \
        const __half* Bb = BT + (size_t)col0*K + (T)*32; \
        _Pragma("unroll") \
        for (int i=0;i<2;i++){ \
            int idx = tid + i*256; int r = idx>>2, ch = idx&3; \
            cpasyncH(&as[r*HST + ch*8], &Ab[(size_t)r*K + ch*8]); \
        } \
        _Pragma("unroll") \
        for (int i=0;i<2;i++){ \
            int idx = tid + i*256; int r = idx>>2, ch = idx&3; \
            cpasyncH(&bs[r*HST + ch*8], &Bb[(size_t)r*K + ch*8]); \
        } \
        cp_commit(); }

    int nt = K >> 5;
    ISSUE_H(0, 0);
    ISSUE_H(1, 1);

    int stage = 0;
    for (int kt = 0; kt < nt; kt++){
        if (kt == nt-1) cp_wait<0>(); else cp_wait<1>();
        __syncthreads();
        if (kt + 2 < nt){
            int s2 = stage + 2; if (s2 >= 3) s2 -= 3;
            ISSUE_H(kt+2, s2);
        }
        uint32_t stb = (uint32_t)(stage*H_STAGE*2);
        #pragma unroll
        for (int ks = 0; ks < 32; ks += 16){
            unsigned af[4][4], bf[4][2];
            #pragma unroll
            for (int mt = 0; mt < 4; mt++)
                ldsm4(af[mt][0], af[mt][1], af[mt][2], af[mt][3],
                      smA_u + stb + aoff + (uint32_t)((mt*16*HST + ks)*2));
            ldsm4(bf[0][0], bf[0][1], bf[1][0], bf[1][1], smB_u + stb + boff0 + (uint32_t)(ks*2));
            ldsm4(bf[2][0], bf[2][1], bf[3][0], bf[3][1], smB_u + stb + boff1 + (uint32_t)(ks*2));
            #pragma unroll
            for (int mt = 0; mt < 4; mt++)
                #pragma unroll
                for (int nt2 = 0; nt2 < 4; nt2++)
                    mma16(acc[mt][nt2], af[mt], bf[nt2]);
        }
        stage++; if (stage >= 3) stage -= 3;
    }
    #undef ISSUE_H

    #pragma unroll
    for (int mt = 0; mt < 4; mt++){
        int rbase = row0 + wm*64 + mt*16;
        #pragma unroll
        for (int nt2 = 0; nt2 < 4; nt2++){
            int cbase = col0 + wn*32 + nt2*8 + tg*2;
            float b0 = bias[cbase], b1 = bias[cbase+1];
            #pragma unroll
            for (int hh = 0; hh < 2; hh++){
                int rr = rbase + g + hh*8;
                float v0 = acc[mt][nt2][hh*2]   + b0;
                float v1 = acc[mt][nt2][hh*2+1] + b1;
                if (ACT == 1){ v0 = gelu_tanh(v0); v1 = gelu_tanh(v1); }
                size_t gi = (size_t)rr*N + cbase;
                if (HOUT){
                    __half2* p = reinterpret_cast<__half2*>(reinterpret_cast<__half*>(Cv) + gi);
                    *p = __floats2half2_rn(v0, v1);
                } else {
                    float* C = reinterpret_cast<float*>(Cv);
                    if (RESID){
                        float2 c = *reinterpret_cast<float2*>(&C[gi]);
                        c.x += v0; c.y += v1;
                        *reinterpret_cast<float2*>(&C[gi]) = c;
                    } else {
                        *reinterpret_cast<float2*>(&C[gi]) = make_float2(v0, v1);
                    }
                }
            }
        }
    }
}

// ---------------- legacy tf32 tensor GEMM (output head, split-K) ----------
#define AS_ST 36
#define BS_ST 136
#define A_STAGE (128*AS_ST)
#define B_STAGE (32*BS_ST)
#define SM_FLOATS (3*(A_STAGE+B_STAGE))

__global__ __launch_bounds__(256, 2) void headgemm_k(
        const float* __restrict__ A, const float* __restrict__ B,
        float* __restrict__ C, int M, int N, int K){
    extern __shared__ float sm[];
    float* smA = sm;
    float* smB = sm + 3*A_STAGE;
    int tid = threadIdx.x;
    int warp = tid >> 5, lane = tid & 31;
    int wm = warp >> 2, wn = warp & 3;
    int g = lane >> 2, tg = lane & 3;
    int row0 = blockIdx.y * 128, col0 = blockIdx.x * 128;

    int Kc   = K / gridDim.z;
    int kbeg = blockIdx.z * Kc;
    int nt   = Kc >> 5;

    float acc[4][4][4];
    #pragma unroll
    for (int i=0;i<4;i++) for (int j=0;j<4;j++) for (int q=0;q<4;q++) acc[i][j][q]=0.f;

    #define ISSUE_T(T, S) { \
        int k0 = kbeg + (T)*32; \
        float* as = smA + (S)*A_STAGE; \
        float* bs = smB + (S)*B_STAGE; \
        _Pragma("unroll") \
        for (int i=0;i<4;i++){ \
            int idx = tid + i*256; int r = idx>>3; int ch=(idx&7)<<2; \
            int grow = row0 + r; bool p = grow < M; int gr = p ? grow : (M-1); \
            cpasyncF(&as[r*AS_ST + ch], &A[(size_t)gr*K + k0 + ch], p); \
        } \
        _Pragma("unroll") \
        for (int i=0;i<4;i++){ \
            int idx = tid + i*256; int kk = idx>>5; int c4=(idx&31)<<2; \
            int gcol = col0 + c4; bool p = gcol < N; int gc = p ? gcol : 0; \
            cpasyncF(&bs[kk*BS_ST + c4], &B[(size_t)(k0+kk)*N + gc], p); \
        } \
        cp_commit(); }

    ISSUE_T(0, 0);
    ISSUE_T(1, 1);

    int stage = 0;
    for (int kt = 0; kt < nt; kt++){
        if (kt == nt-1) cp_wait<0>(); else cp_wait<1>();
        __syncthreads();
        if (kt + 2 < nt){
            int s2 = stage + 2; if (s2 >= 3) s2 -= 3;
            ISSUE_T(kt+2, s2);
        }
        const float* as = smA + stage*A_STAGE;
        const float* bs = smB + stage*B_STAGE;
        #pragma unroll
        for (int ks = 0; ks < 32; ks += 8){
            unsigned af[4][4], bf[4][2];
            #pragma unroll
            for (int mt = 0; mt < 4; mt++){
                int r = wm*64 + mt*16 + g;
                af[mt][0] = f2tf(as[r*AS_ST + ks+tg]);
                af[mt][1] = f2tf(as[(r+8)*AS_ST + ks+tg]);
                af[mt][2] = f2tf(as[r*AS_ST + ks+tg+4]);
                af[mt][3] = f2tf(as[(r+8)*AS_ST + ks+tg+4]);
            }
            #pragma unroll
            for (int nt2 = 0; nt2 < 4; nt2++){
                int c = wn*32 + nt2*8 + g;
                bf[nt2][0] = f2tf(bs[(ks+tg)*BS_ST + c]);
                bf[nt2][1] = f2tf(bs[(ks+tg+4)*BS_ST + c]);
            }
            #pragma unroll
            for (int mt = 0; mt < 4; mt++)
                #pragma unroll
                for (int nt2 = 0; nt2 < 4; nt2++)
                    mma8(acc[mt][nt2], af[mt], bf[nt2]);
        }
        stage++; if (stage >= 3) stage -= 3;
        __syncthreads();
    }
    #undef ISSUE_T

    float* Cout = C + (size_t)blockIdx.z*M*N;
    #pragma unroll
    for (int mt = 0; mt < 4; mt++){
        int rbase = row0 + wm*64 + mt*16;
        #pragma unroll
        for (int nt2 = 0; nt2 < 4; nt2++){
            int cbase = col0 + wn*32 + nt2*8 + tg*2;
            #pragma unroll
            for (int half2_ = 0; half2_ < 2; half2_++){
                int rr = rbase + g + half2_*8;
                if (rr < M){
                    #pragma unroll
                    for (int jj = 0; jj < 2; jj++){
                        int cc = cbase + jj;
                        if (cc < N) Cout[(size_t)rr*N + cc] = acc[mt][nt2][half2_*2+jj];
                    }
                }
            }
        }
    }
}

// ---------------- l2-normalize prompt keys ----------------
__global__ void keynorm_k(const float* __restrict__ pk){
    int r = blockIdx.x, tid = threadIdx.x;
    __shared__ float red[256];
    float v0 = pk[(size_t)r*DMOD + tid], v1 = pk[(size_t)r*DMOD + 256 + tid], v2 = pk[(size_t)r*DMOD + 512 + tid];
    red[tid] = v0*v0 + v1*v1 + v2*v2; __syncthreads();
    for (int o = 128; o; o >>= 1){ if (tid < o) red[tid] += red[tid+o]; __syncthreads(); }
    float inv = rsqrtf(fmaxf(red[0], 1e-12f));
    g_keyn[(size_t)r*DMOD + tid]       = v0*inv;
    g_keyn[(size_t)r*DMOD + 256 + tid] = v1*inv;
    g_keyn[(size_t)r*DMOD + 512 + tid] = v2*inv;
}

// ---------------- top-k (writes prompts + wpe into h rows 0..3) -----------
__global__ void topk_k(const float* __restrict__ wpe){
    int n = blockIdx.x, tid = threadIdx.x;
    __shared__ float bv[256];
    __shared__ int   bi[256];
    __shared__ int   chosen[4];
    float rs = 0.f;
    for (int r = 0; r < 4; r++){
        float best = -1e30f; int besti = 1 << 30;
        for (int j = tid; j < POOLN; j += 256){
            bool skip = false;
            for (int c = 0; c < r; c++) if (chosen[c] == j) skip = true;
            float v = g_sim[(size_t)n*POOLN + j];
            if (!skip && (v > best || (v == best && j < besti))){ best = v; besti = j; }
        }
        bv[tid] = best; bi[tid] = besti; __syncthreads();
        for (int o = 128; o; o >>= 1){
            if (tid < o){
                if (bv[tid+o] > bv[tid] || (bv[tid+o] == bv[tid] && bi[tid+o] < bi[tid])){
                    bv[tid] = bv[tid+o]; bi[tid] = bi[tid+o];
                }
            }
            __syncthreads();
        }
        if (tid == 0){ chosen[r] = bi[0]; rs += bv[0]; }
        __syncthreads();
    }
    for (int e = tid; e < 4*DMOD; e += 256){
        int k = e / DMOD, d = e % DMOD;
        g_h[((size_t)n*TTOK + k)*DMOD + d] = g_keyn[(size_t)chosen[k]*DMOD + d] + wpe[(size_t)k*DMOD + d];
    }
    if (tid == 0) atomicAdd(&g_rsim, rs);
}

// ---------------- layernorm: warp per row; half or float out --------------
template<bool HOUT>
__global__ void ln_k(const float* __restrict__ x, const float* __restrict__ g,
                     const float* __restrict__ b, void* __restrict__ yv){
    int row  = blockIdx.x*8 + (threadIdx.x >> 5);
    int lane = threadIdx.x & 31;
    const float4* xr = reinterpret_cast<const float4*>(x + (size_t)row*DMOD);
    const float4* g4 = reinterpret_cast<const float4*>(g);
    const float4* b4 = reinterpret_cast<const float4*>(b);
    float4 v[6];
    float s = 0.f, sq = 0.f;
    #pragma unroll
    for (int i = 0; i < 6; i++){
        v[i] = xr[lane + i*32];
        s  += v[i].x + v[i].y + v[i].z + v[i].w;
        sq += v[i].x*v[i].x + v[i].y*v[i].y + v[i].z*v[i].z + v[i].w*v[i].w;
    }
    #pragma unroll
    for (int o = 16; o; o >>= 1){
        s  += __shfl_xor_sync(0xffffffffu, s,  o);
        sq += __shfl_xor_sync(0xffffffffu, sq, o);
    }
    float mu  = s * (1.f/DMOD);
    float var = sq * (1.f/DMOD) - mu*mu;
    float inv = rsqrtf(var + 1e-5f);
    #pragma unroll
    for (int i = 0; i < 6; i++){
        float4 gg = g4[lane + i*32], bb = b4[lane + i*32], o;
        o.x = (v[i].x-mu)*inv*gg.x + bb.x;
        o.y = (v[i].y-mu)*inv*gg.y + bb.y;
        o.z = (v[i].z-mu)*inv*gg.z + bb.z;
        o.w = (v[i].w-mu)*inv*gg.w + bb.w;
        if (HOUT){
            __half2* yr = reinterpret_cast<__half2*>(reinterpret_cast<__half*>(yv) + (size_t)row*DMOD);
            yr[2*(lane+i*32)]   = __floats2half2_rn(o.x, o.y);
            yr[2*(lane+i*32)+1] = __floats2half2_rn(o.z, o.w);
        } else {
            float4* yr = reinterpret_cast<float4*>(reinterpret_cast<float*>(yv) + (size_t)row*DMOD);
            yr[lane + i*32] = o;
        }
    }
}

// ---------------- attention: fp16 mma flash, block per (series, head) -----
#define QKS 72
#define VTS 88
__global__ __launch_bounds__(160) void attn_k(){
    int blk = blockIdx.x;
    int n = blk / 12, head = blk % 12;
    __shared__ __half qs[80*QKS];
    __shared__ __half ks[80*QKS];
    __shared__ __half vt[64*VTS];
    int tid = threadIdx.x, w = tid >> 5, lane = tid & 31;
    int g = lane >> 2, tg = lane & 3;

    const __half* qkv = g_qkvh + (size_t)n*TTOK*3*DMOD + head*64;
    for (int idx = tid; idx < TTOK*32; idx += 160){
        int t = idx >> 5, c = (idx & 31)*2;
        __half2 q2 = *reinterpret_cast<const __half2*>(qkv + (size_t)t*3*DMOD + c);
        __half2 k2 = *reinterpret_cast<const __half2*>(qkv + (size_t)t*3*DMOD + DMOD + c);
        __half2 v2 = *reinterpret_cast<const __half2*>(qkv + (size_t)t*3*DMOD + 2*DMOD + c);
        *reinterpret_cast<__half2*>(qs + t*QKS + c) = q2;
        *reinterpret_cast<__half2*>(ks + t*QKS + c) = k2;
        vt[c*VTS + t]     = __low2half(v2);
        vt[(c+1)*VTS + t] = __high2half(v2);
    }
    for (int idx = tid; idx < 64*12; idx += 160){
        int d = idx / 12, t = 68 + idx % 12;
        vt[d*VTS + t] = __float2half(0.f);
    }
    __syncthreads();

    int rb = w*16 + g;
    float sacc[10][4];
    #pragma unroll
    for (int i = 0; i < 10; i++) for (int j = 0; j < 4; j++) sacc[i][j] = 0.f;
    #pragma unroll
    for (int kc = 0; kc < 4; kc++){
        unsigned af[4];
        int base = rb*QKS + kc*16 + 2*tg;
        af[0] = *reinterpret_cast<const unsigned*>(&qs[base]);
        af[1] = *reinterpret_cast<const unsigned*>(&qs[base + 8*QKS]);
        af[2] = *reinterpret_cast<const unsigned*>(&qs[base + 8]);
        af[3] = *reinterpret_cast<const unsigned*>(&qs[base + 8*QKS + 8]);
        #pragma unroll
        for (int nt = 0; nt < 10; nt++){
            unsigned bf[2];
            int bb = (nt*8 + g)*QKS + kc*16 + 2*tg;
            bf[0] = *reinterpret_cast<const unsigned*>(&ks[bb]);
            bf[1] = *reinterpret_cast<const unsigned*>(&ks[bb + 8]);
            mma16(sacc[nt], af, bf);
        }
    }
    float inv_[2];
    #pragma unroll
    for (int hh = 0; hh < 2; hh++){
        int R = rb + hh*8;
        float mx = -1e30f;
        #pragma unroll
        for (int nt = 0; nt < 10; nt++)
            #pragma unroll
            for (int jj = 0; jj < 2; jj++){
                int Cn = nt*8 + 2*tg + jj;
                float sv = sacc[nt][hh*2+jj] * 0.125f;
                sv = (Cn <= R) ? sv : -1e9f;
                sacc[nt][hh*2+jj] = sv;
                mx = fmaxf(mx, sv);
            }
        mx = fmaxf(mx, __shfl_xor_sync(0xffffffffu, mx, 1));
        mx = fmaxf(mx, __shfl_xor_sync(0xffffffffu, mx, 2));
        float sm = 0.f;
        #pragma unroll
        for (int nt = 0; nt < 10; nt++)
            #pragma unroll
            for (int jj = 0; jj < 2; jj++){
                float p = expf(sacc[nt][hh*2+jj] - mx);
                sacc[nt][hh*2+jj] = p;
                sm += p;
            }
        sm += __shfl_xor_sync(0xffffffffu, sm, 1);
        sm += __shfl_xor_sync(0xffffffffu, sm, 2);
        inv_[hh] = 1.f/sm;
    }
    float oacc[8][4];
    #pragma unroll
    for (int i = 0; i < 8; i++) for (int j = 0; j < 4; j++) oacc[i][j] = 0.f;
    #pragma unroll
    for (int kc = 0; kc < 5; kc++){
        unsigned af[4];
        af[0] = packh2(sacc[2*kc][0],   sacc[2*kc][1]);
        af[1] = packh2(sacc[2*kc][2],   sacc[2*kc][3]);
        af[2] = packh2(sacc[2*kc+1][0], sacc[2*kc+1][1]);
        af[3] = packh2(sacc[2*kc+1][2], sacc[2*kc+1][3]);
        #pragma unroll
        for (int nt = 0; nt < 8; nt++){
            unsigned bf[2];
            int bb = (nt*8 + g)*VTS + kc*16 + 2*tg;
            bf[0] = *reinterpret_cast<const unsigned*>(&vt[bb]);
            bf[1] = *reinterpret_cast<const unsigned*>(&vt[bb + 8]);
            mma16(oacc[nt], af, bf);
        }
    }
    __half* ob = g_ob + (size_t)n*TTOK*DMOD + head*64;
    #pragma unroll
    for (int hh = 0; hh < 2; hh++){
        int R = rb + hh*8;
        if (R < TTOK){
            #pragma unroll
            for (int nt = 0; nt < 8; nt++){
                __half2 hv = __floats2half2_rn(oacc[nt][hh*2]*inv_[hh], oacc[nt][hh*2+1]*inv_[hh]);
                *reinterpret_cast<__half2*>(ob + (size_t)R*DMOD + nt*8 + 2*tg) = hv;
            }
        }
    }
}

// ---------------- final: sum split-K chunks + channels, denorm + rsim -----
__global__ void final_k(const float* __restrict__ outb, float* __restrict__ out, int out_size){
    int n = blockIdx.x, b = n/7, m = n%7;
    for (int t = threadIdx.x; t < PREDL; t += blockDim.x){
        float v = 3.f*outb[t];
        #pragma unroll
        for (int z = 0; z < SPLITZ; z++){
            const float* p = g_osp + (size_t)z*NSER*3*PREDL;
            v += p[(size_t)(n*3+0)*PREDL + t]
               + p[(size_t)(n*3+1)*PREDL + t]
               + p[(size_t)(n*3+2)*PREDL + t];
        }
        out[(size_t)b*PREDL*7 + (size_t)t*7 + m] = v*g_std[n] + g_mean[n];
    }
    if (n == 0 && threadIdx.x == 0 && out_size > 64*PREDL*7)
        out[64*PREDL*7] = g_rsim * (1.f/NSER);
}

// ---------------- host ----------------
template <typename T, size_t S>
static void* symaddr(T (&arr)[S]){ void* p = nullptr; cudaGetSymbolAddress(&p, arr); return p; }

extern "C" void kernel_launch(void* const* d_in, const int* in_sizes, int n_in,
                              void* d_out, int out_size){
    int s = (n_in >= 2 && in_sizes[1] == 1) ? 1 : 0;
    const float* x    = (const float*)d_in[0];
    const float* in_w = (const float*)d_in[1+s];
    const float* in_b = (const float*)d_in[2+s];
    const float* pk   = (const float*)d_in[3+s];
    const float* wpe  = (const float*)d_in[4+s];
    const float* ln1g = (const float*)d_in[5+s];
    const float* ln1b = (const float*)d_in[6+s];
    const float* qkvw = (const float*)d_in[7+s];
    const float* qkvb = (const float*)d_in[8+s];
    const float* aw   = (const float*)d_in[9+s];
    const float* ab   = (const float*)d_in[10+s];
    const float* ln2g = (const float*)d_in[11+s];
    const float* ln2b = (const float*)d_in[12+s];
    const float* fcw  = (const float*)d_in[13+s];
    const float* fcb  = (const float*)d_in[14+s];
    const float* pw   = (const float*)d_in[15+s];
    const float* pbb  = (const float*)d_in[16+s];
    const float* lnfg = (const float*)d_in[17+s];
    const float* lnfb = (const float*)d_in[18+s];
    const float* outw = (const float*)d_in[19+s];
    const float* outb = (const float*)d_in[20+s];
    float* out = (float*)d_out;

    float*  p_h    = (float*) symaddr(g_h);
    __half* p_a    = (__half*)symaddr(g_a);
    float*  p_af   = (float*) symaddr(g_af);
    __half* p_qkv  = (__half*)symaddr(g_qkvh);
    __half* p_ob   = (__half*)symaddr(g_ob);
    __half* p_mlp  = (__half*)symaddr(g_mlp);
    float*  p_tok  = (float*) symaddr(g_tok);
    float*  p_mtok = (float*) symaddr(g_mtok);
    float*  p_xq   = (float*) symaddr(g_xq);
    float*  p_keyn = (float*) symaddr(g_keyn);
    float*  p_sim  = (float*) symaddr(g_sim);
    float*  p_osp  = (float*) symaddr(g_osp);
    __half* p_wT   = (__half*)symaddr(g_wT);

    const int SMB = SM_FLOATS*4;
    static cudaStream_t s2 = nullptr, s3 = nullptr;
    static cudaEvent_t evA = nullptr, evB = nullptr, evK = nullptr, evPre = nullptr, evP = nullptr;
    if (!s2){
        cudaFuncSetAttribute(headgemm_k, cudaFuncAttributeMaxDynamicSharedMemorySize, SMB);
        cudaFuncSetAttribute(hgemm_k<0,false,false>, cudaFuncAttributeMaxDynamicSharedMemorySize, H_SMEMB);
        cudaFuncSetAttribute(hgemm_k<0,true ,false>, cudaFuncAttributeMaxDynamicSharedMemorySize, H_SMEMB);
        cudaFuncSetAttribute(hgemm_k<1,false,true >, cudaFuncAttributeMaxDynamicSharedMemorySize, H_SMEMB);
        cudaFuncSetAttribute(hgemm_k<0,false,true >, cudaFuncAttributeMaxDynamicSharedMemorySize, H_SMEMB);
        cudaStreamCreateWithFlags(&s2, cudaStreamNonBlocking);
        cudaStreamCreateWithFlags(&s3, cudaStreamNonBlocking);
        cudaEventCreateWithFlags(&evA, cudaEventDisableTiming);
        cudaEventCreateWithFlags(&evB, cudaEventDisableTiming);
        cudaEventCreateWithFlags(&evK, cudaEventDisableTiming);
        cudaEventCreateWithFlags(&evPre, cudaEventDisableTiming);
        cudaEventCreateWithFlags(&evP, cudaEventDisableTiming);
    }

    // fork: keynorm + weight transposes on s2
    cudaEventRecord(evA, 0);
    cudaStreamWaitEvent(s2, evA, 0);
    keynorm_k<<<POOLN,256,0,s2>>>(pk);
    cudaEventRecord(evK, s2);
    for (int L = 0; L < NLAYER; L++){
        __half* qkvT = p_wT + (size_t)L*WL;
        __half* awT  = qkvT + 1769472;
        __half* fcT  = awT  + 589824;
        __half* pwT  = fcT  + 2359296;
        transp_k<<<dim3(2304/32, 768/32), dim3(32,8), 0, s2>>>(qkvw + (size_t)L*DMOD*3*DMOD, qkvT, 768, 2304);
        transp_k<<<dim3( 768/32, 768/32), dim3(32,8), 0, s2>>>(aw   + (size_t)L*DMOD*DMOD,   awT,  768, 768);
        transp_k<<<dim3(3072/32, 768/32), dim3(32,8), 0, s2>>>(fcw  + (size_t)L*DMOD*4*DMOD, fcT,  768, 3072);
        transp_k<<<dim3( 768/32,3072/32), dim3(32,8), 0, s2>>>(pw   + (size_t)L*4*DMOD*DMOD, pwT, 3072, 768);
    }
    cudaEventRecord(evB, s2);

    // main: prep; then patch-embed GEMM forks to s3 (writes h rows 4..67 + wpe)
    prep_k<<<NSER,256>>>(x);
    cudaEventRecord(evPre, 0);
    cudaStreamWaitEvent(s3, evPre, 0);
    gemm_k<false,0,false,true><<<dim3(DMOD/64, NSER*PNUM/64),256,0,s3>>>(p_tok, in_w, in_b, p_h, NSER*PNUM, DMOD, 48, wpe);
    cudaEventRecord(evP, s3);

    // main: xq via linearity (mean over patches commutes with the embedding)
    meantok_k<<<NSER,64>>>();
    gemm_k<false,0,false,false><<<dim3(DMOD/64, NSER/64),256>>>(p_mtok, in_w, in_b, p_xq, NSER, DMOD, 48, nullptr);
    xqn_k<<<NSER,256>>>();
    cudaStreamWaitEvent(0, evK, 0);
    gemm_k<true,0,false,false><<<dim3((POOLN+63)/64, NSER/64),256>>>(p_xq, p_keyn, (const float*)nullptr, p_sim, NSER, POOLN, DMOD, nullptr);
    topk_k<<<NSER,256>>>(wpe);

    // join: weights + patch-embed ready before layer loop
    cudaStreamWaitEvent(0, evB, 0);
    cudaStreamWaitEvent(0, evP, 0);

    const int MB = NTOK/128;   // 238
    for (int L = 0; L < NLAYER; L++){
        __half* qkvT = p_wT + (size_t)L*WL;
        __half* awT  = qkvT + 1769472;
        __half* fcT  = awT  + 589824;
        __half* pwT  = fcT  + 2359296;
        ln_k<true><<<NTOK/8,256>>>(p_h, ln1g + (size_t)L*DMOD, ln1b + (size_t)L*DMOD, p_a);
        hgemm_k<0,false,true ><<<dim3(3*DMOD/128, MB),256,H_SMEMB>>>(p_a, qkvT, qkvb + (size_t)L*3*DMOD, p_qkv, NTOK, 3*DMOD, DMOD);
        attn_k<<<NSER*12,160>>>();
        hgemm_k<0,true ,false><<<dim3(DMOD/128, MB),256,H_SMEMB>>>(p_ob, awT, ab + (size_t)L*DMOD, p_h, NTOK, DMOD, DMOD);
        ln_k<true><<<NTOK/8,256>>>(p_h, ln2g + (size_t)L*DMOD, ln2b + (size_t)L*DMOD, p_a);
        hgemm_k<1,false,true ><<<dim3(4*DMOD/128, MB),256,H_SMEMB>>>(p_a, fcT, fcb + (size_t)L*4*DMOD, p_mlp, NTOK, 4*DMOD, DMOD);
        hgemm_k<0,true ,false><<<dim3(DMOD/128, MB),256,H_SMEMB>>>(p_mlp, pwT, pbb + (size_t)L*DMOD, p_h, NTOK, DMOD, 3072);
    }

    ln_k<false><<<NTOK/8,256>>>(p_h, lnfg, lnfb, p_af);
    headgemm_k<<<dim3(1, (NSER*3+127)/128, SPLITZ),256,SMB>>>(p_af, outw, p_osp, NSER*3, PREDL, TTOK*DMOD/3);
    final_k<<<NSER,96>>>(outb, out, out_size);
}

// round 10
// speedup vs baseline: 7.0843x; 1.0043x over previous
#include <cuda_runtime.h>
#include <cuda_fp16.h>
#include <math.h>
#include <stdint.h>

#define NSER 448
#define LSEQ 512
#define TTOK 68
#define DMOD 768
#define NTOK (NSER*TTOK)       // 30464
#define PNUM 64
#define POOLN 1000
#define PREDL 96
#define NLAYER 6
#define SPLITZ 32

// ---------------- scratch (device globals; no allocations) ----------------
__device__ float  g_mean[NSER];
__device__ float  g_std [NSER];
__device__ float  g_tok [NSER*PNUM*48];
__device__ float  g_mtok[NSER*48];
__device__ float  g_h   [(size_t)NTOK*DMOD];
__device__ __half g_a   [(size_t)NTOK*DMOD];
__device__ float  g_af  [(size_t)NTOK*DMOD];
__device__ __half g_qkvh[(size_t)NTOK*3*DMOD];
__device__ __half g_ob  [(size_t)NTOK*DMOD];
__device__ __half g_mlp [(size_t)NTOK*4*DMOD];
__device__ float  g_xq  [NSER*DMOD];
__device__ float  g_keyn[POOLN*DMOD];
__device__ float  g_sim [NSER*POOLN];
__device__ float  g_osp [(size_t)SPLITZ*NSER*3*PREDL];
__device__ float  g_rsim;
#define WL 7077888u
__device__ __half g_wT  [(size_t)NLAYER*WL];

__device__ __forceinline__ float gelu_tanh(float x){
    float c = 0.7978845608028654f;
    float t = tanhf(c*(x + 0.044715f*x*x*x));
    return 0.5f*x*(1.f+t);
}

__device__ __forceinline__ unsigned f2tf(float x){
    unsigned r; asm("cvt.rna.tf32.f32 %0, %1;" : "=r"(r) : "f"(x)); return r;
}

__device__ __forceinline__ void mma8(float* c, const unsigned* a, const unsigned* b){
    asm volatile("mma.sync.aligned.m16n8k8.row.col.f32.tf32.tf32.f32 "
        "{%0,%1,%2,%3}, {%4,%5,%6,%7}, {%8,%9}, {%0,%1,%2,%3};"
        : "+f"(c[0]),"+f"(c[1]),"+f"(c[2]),"+f"(c[3])
        : "r"(a[0]),"r"(a[1]),"r"(a[2]),"r"(a[3]), "r"(b[0]),"r"(b[1]));
}

__device__ __forceinline__ void mma16(float* c, const unsigned* a, const unsigned* b){
    asm volatile("mma.sync.aligned.m16n8k16.row.col.f32.f16.f16.f32 "
        "{%0,%1,%2,%3}, {%4,%5,%6,%7}, {%8,%9}, {%0,%1,%2,%3};"
        : "+f"(c[0]),"+f"(c[1]),"+f"(c[2]),"+f"(c[3])
        : "r"(a[0]),"r"(a[1]),"r"(a[2]),"r"(a[3]), "r"(b[0]),"r"(b[1]));
}

__device__ __forceinline__ void ldsm4(unsigned &r0, unsigned &r1, unsigned &r2, unsigned &r3, uint32_t addr){
    asm volatile("ldmatrix.sync.aligned.m8n8.x4.shared.b16 {%0,%1,%2,%3}, [%4];"
        : "=r"(r0),"=r"(r1),"=r"(r2),"=r"(r3) : "r"(addr));
}

__device__ __forceinline__ void cpasyncF(float* dst, const float* src, bool pred){
    unsigned sa = (unsigned)__cvta_generic_to_shared(dst);
    int sz = pred ? 16 : 0;
    asm volatile("cp.async.cg.shared.global [%0], [%1], 16, %2;" :: "r"(sa), "l"(src), "r"(sz));
}
__device__ __forceinline__ void cpasyncH(__half* dst, const __half* src){
    unsigned sa = (unsigned)__cvta_generic_to_shared(dst);
    asm volatile("cp.async.cg.shared.global [%0], [%1], 16;" :: "r"(sa), "l"(src));
}
__device__ __forceinline__ void cp_commit(){ asm volatile("cp.async.commit_group;"); }
template<int N> __device__ __forceinline__ void cp_wait(){ asm volatile("cp.async.wait_group %0;"::"n"(N)); }

__device__ __forceinline__ unsigned packh2(float a, float b){
    __half2 h = __floats2half2_rn(a, b);
    return *reinterpret_cast<unsigned*>(&h);
}

// ---------------- fused preamble: RevIN + decompose + patch ----------------
__global__ void prep_k(const float* __restrict__ x){
    int n = blockIdx.x, b = n/7, m = n%7, tid = threadIdx.x;
    __shared__ float xs[LSEQ];
    __shared__ float valid[489];
    __shared__ float det[LSEQ];
    __shared__ float ph[24];
    __shared__ float red[256];
    if (n == 0 && tid == 0) g_rsim = 0.f;
    for (int l = tid; l < LSEQ; l += 256) xs[l] = x[((size_t)b*LSEQ + l)*7 + m];
    if (tid < 24) ph[tid] = 0.f;
    __syncthreads();
    float s = xs[tid] + xs[tid+256];
    red[tid] = s; __syncthreads();
    for (int o = 128; o; o >>= 1){ if (tid < o) red[tid] += red[tid+o]; __syncthreads(); }
    float mu = red[0] * (1.f/LSEQ);
    __syncthreads();
    float d0 = xs[tid]-mu, d1 = xs[tid+256]-mu;
    red[tid] = d0*d0 + d1*d1; __syncthreads();
    for (int o = 128; o; o >>= 1){ if (tid < o) red[tid] += red[tid+o]; __syncthreads(); }
    float sd = sqrtf(red[0]*(1.f/LSEQ) + 1e-5f);
    if (tid == 0){ g_mean[n] = mu; g_std[n] = sd; }
    float inv = 1.f/sd;
    xs[tid]       = d0*inv;
    xs[tid + 256] = d1*inv;
    __syncthreads();
    for (int i = tid; i < 489; i += 256){
        float ss = 0.f;
        #pragma unroll
        for (int k = 0; k < 24; k++) ss += xs[i+k];
        valid[i] = ss * (1.f/24.f);
    }
    __syncthreads();
    for (int l = tid; l < LSEQ; l += 256){
        int vi = l - 12; vi = vi < 0 ? 0 : (vi > 488 ? 488 : vi);
        float dt = xs[l] - valid[vi];
        det[l] = dt;
        atomicAdd(&ph[l % 24], dt);
    }
    __syncthreads();
    for (int e = tid; e < PNUM*48; e += 256){
        int p = e/48, rem = e%48, c = rem/16, j = rem%16;
        int l = p*8 + j; if (l > LSEQ-1) l = LSEQ-1;
        float v;
        if (c == 0){
            int vi = l - 12; vi = vi < 0 ? 0 : (vi > 488 ? 488 : vi);
            v = valid[vi];
        } else {
            int pp = l % 24;
            float cnt = (pp < 8) ? 22.f : 21.f;
            float se = ph[pp] / cnt;
            v = (c == 1) ? se : (det[l] - se);
        }
        g_tok[(size_t)n*PNUM*48 + e] = v;
    }
}

// ---------------- patch-mean ----------------
__global__ void meantok_k(){
    int n = blockIdx.x, tid = threadIdx.x;
    if (tid < 48){
        float s = 0.f;
        for (int p = 0; p < PNUM; p++) s += g_tok[(size_t)n*PNUM*48 + p*48 + tid];
        g_mtok[n*48 + tid] = s * (1.f/PNUM);
    }
}

// ---------------- l2-normalize xq rows in place ----------------
__global__ void xqn_k(){
    int n = blockIdx.x, tid = threadIdx.x;
    __shared__ float red[256];
    float v0 = g_xq[(size_t)n*DMOD + tid], v1 = g_xq[(size_t)n*DMOD + 256 + tid], v2 = g_xq[(size_t)n*DMOD + 512 + tid];
    red[tid] = v0*v0 + v1*v1 + v2*v2; __syncthreads();
    for (int o = 128; o; o >>= 1){ if (tid < o) red[tid] += red[tid+o]; __syncthreads(); }
    float inv = rsqrtf(fmaxf(red[0], 1e-12f));
    g_xq[(size_t)n*DMOD + tid]       = v0*inv;
    g_xq[(size_t)n*DMOD + 256 + tid] = v1*inv;
    g_xq[(size_t)n*DMOD + 512 + tid] = v2*inv;
}

// ---------------- weight transpose to half ----------------
__global__ void transp_k(const float* __restrict__ W, __half* __restrict__ WT, int K, int N){
    __shared__ float t[32][33];
    int bx = blockIdx.x*32, by = blockIdx.y*32;
    int x = threadIdx.x, y = threadIdx.y;
    #pragma unroll
    for (int i = 0; i < 4; i++){
        int r = by + y*4 + i;
        t[y*4+i][x] = W[(size_t)r*N + bx + x];
    }
    __syncthreads();
    #pragma unroll
    for (int i = 0; i < 4; i++){
        int rn = bx + y*4 + i;
        WT[(size_t)rn*K + by + x] = __float2half(t[x][y*4+i]);
    }
}

// ---------------- generic fp32 SIMT GEMM --------------------------------
template<bool TRANSB, int ACT, bool RESID, bool REMAP>
__global__ void gemm_k(const float* __restrict__ A, const float* __restrict__ B,
                       const float* __restrict__ bias, float* __restrict__ C,
                       int M, int N, int K, const float* __restrict__ wadd){
    __shared__ float As[16][68];
    __shared__ float Bs[16][68];
    int tid = threadIdx.x;
    int tx = tid & 15, ty = tid >> 4;
    int row0 = blockIdx.y * 64, col0 = blockIdx.x * 64;
    float acc[4][4] = {};
    for (int k0 = 0; k0 < K; k0 += 16){
        {
            int r  = tid >> 2;
            int c4 = (tid & 3) * 4;
            float4 v = *reinterpret_cast<const float4*>(&A[(size_t)(row0 + r)*K + k0 + c4]);
            As[c4+0][r] = v.x; As[c4+1][r] = v.y; As[c4+2][r] = v.z; As[c4+3][r] = v.w;
        }
        if (!TRANSB){
            int kk = tid >> 4;
            int c4 = (tid & 15) * 4;
            int col = col0 + c4;
            float4 v = make_float4(0.f,0.f,0.f,0.f);
            if (col < N) v = *reinterpret_cast<const float4*>(&B[(size_t)(k0+kk)*N + col]);
            Bs[kk][c4+0] = v.x; Bs[kk][c4+1] = v.y; Bs[kk][c4+2] = v.z; Bs[kk][c4+3] = v.w;
        } else {
            int nn = tid >> 2;
            int c4 = (tid & 3) * 4;
            int col = col0 + nn;
            float4 v = make_float4(0.f,0.f,0.f,0.f);
            if (col < N) v = *reinterpret_cast<const float4*>(&B[(size_t)col*K + k0 + c4]);
            Bs[c4+0][nn] = v.x; Bs[c4+1][nn] = v.y; Bs[c4+2][nn] = v.z; Bs[c4+3][nn] = v.w;
        }
        __syncthreads();
        #pragma unroll
        for (int kk = 0; kk < 16; kk++){
            float a[4], b[4];
            #pragma unroll
            for (int i = 0; i < 4; i++) a[i] = As[kk][ty*4+i];
            #pragma unroll
            for (int j = 0; j < 4; j++) b[j] = Bs[kk][tx*4+j];
            #pragma unroll
            for (int i = 0; i < 4; i++)
                #pragma unroll
                for (int j = 0; j < 4; j++) acc[i][j] = fmaf(a[i], b[j], acc[i][j]);
        }
        __syncthreads();
    }
    #pragma unroll
    for (int i = 0; i < 4; i++){
        int r = row0 + ty*4 + i;
        size_t orow = REMAP ? (size_t)((r >> 6)*TTOK + 4 + (r & 63)) : (size_t)r;
        int t = REMAP ? (4 + (r & 63)) : 0;
        #pragma unroll
        for (int j = 0; j < 4; j++){
            int col = col0 + tx*4 + j;
            if (col < N){
                float v = acc[i][j];
                if (bias) v += bias[col];
                if (ACT == 1) v = gelu_tanh(v);
                if (REMAP && wadd) v += wadd[(size_t)t*DMOD + col];
                size_t idx = orow*(size_t)N + col;
                if (RESID) C[idx] += v; else C[idx] = v;
            }
        }
    }
}

// ================= fp16 tensor-core GEMM (ldmatrix + PDL B-prefetch) ======
#define HST 40
#define H_STAGE (128*HST)
#define H_SMEMB (6*H_STAGE*2)

template<int ACT, bool RESID, bool HOUT>
__global__ __launch_bounds__(256, 2) void hgemm_k(
        const __half* __restrict__ A, const __half* __restrict__ BT,
        const float* __restrict__ bias, void* __restrict__ Cv,
        int M, int N, int K){
    extern __shared__ __half hsm[];
    __half* smA = hsm;
    __half* smB = hsm + 3*H_STAGE;
    int tid = threadIdx.x;
    int warp = tid >> 5, lane = tid & 31;
    int wm = warp >> 2, wn = warp & 3;
    int g = lane >> 2, tg = lane & 3;
    int row0 = blockIdx.y * 128, col0 = blockIdx.x * 128;

    float acc[4][4][4];
    #pragma unroll
    for (int i=0;i<4;i++) for (int j=0;j<4;j++) for (int q=0;q<4;q++) acc[i][j][q]=0.f;

    uint32_t smA_u = (uint32_t)__cvta_generic_to_shared(smA);
    uint32_t smB_u = (uint32_t)__cvta_generic_to_shared(smB);
    uint32_t aoff = (uint32_t)(((wm*64 + (lane & 15))*HST + ((lane >> 4)*8)) * 2);
    int brlo = lane & 7, b8 = ((lane >> 4) & 1)*8, bc8 = ((lane >> 3) & 1)*8;
    uint32_t boff0 = (uint32_t)(((wn*32 +  0 + b8 + brlo)*HST + bc8) * 2);
    uint32_t boff1 = (uint32_t)(((wn*32 + 16 + b8 + brlo)*HST + bc8) * 2);

    #define ISSUE_HB(T, S) { \
        __half* bs = smB + (S)*H_STAGE; \
        const __half* Bb = BT + (size_t)col0*K + (T)*32; \
        _Pragma("unroll") \
        for (int i=0;i<2;i++){ \
            int idx = tid + i*256; int r = idx>>2, ch = idx&3; \
            cpasyncH(&bs[r*HST + ch*8], &Bb[(size_t)r*K + ch*8]); \
        } \
        cp_commit(); }
    #define ISSUE_HA(T, S) { \
        __half* as = smA + (S)*H_STAGE; \
        const __half* Ab = A + (size_t)row0*K + (T)*32; \
        _Pragma("unroll") \
        for (int i=0;i<2;i++){ \
            int idx = tid + i*256; int r = idx>>2, ch = idx&3; \
            cpasyncH(&as[r*HST + ch*8], &Ab[(size_t)r*K + ch*8]); \
        } \
        cp_commit(); }
    #define ISSUE_H(T, S) { \
        __half* as = smA + (S)*H_STAGE; \
        __half* bs = smB + (S)*H_STAGE; \
        const __half* Ab = A + (size_t)row0*K + (T)*32; \
        const __half* Bb = BT + (size_t)col0*K + (T)*32; \
        _Pragma("unroll") \
        for (int i=0;i<2;i++){ \
            int idx = tid + i*256; int r = idx>>2, ch = idx&3; \
            cpasyncH(&as[r*HST + ch*8], &Ab[(size_t)r*K + ch*8]); \
        } \
        _Pragma("unroll") \
        for (int i=0;i<2;i++){ \
            int idx = tid + i*256; int r = idx>>2, ch = idx&3; \
            cpasyncH(&bs[r*HST + ch*8], &Bb[(size_t)r*K + ch*8]); \
        } \
        cp_commit(); }

    int nt = K >> 5;
    // B tiles are weights: independent of producer -> prefetch before griddepsync
    ISSUE_HB(0, 0);
    ISSUE_HB(1, 1);
    cudaGridDependencySynchronize();
    ISSUE_HA(0, 0);
    ISSUE_HA(1, 1);

    int stage = 0;
    for (int kt = 0; kt < nt; kt++){
        if (kt == nt-1) cp_wait<0>(); else cp_wait<1>();
        __syncthreads();
        if (kt + 2 < nt){
            int s2 = stage + 2; if (s2 >= 3) s2 -= 3;
            ISSUE_H(kt+2, s2);
        }
        uint32_t stb = (uint32_t)(stage*H_STAGE*2);
        #pragma unroll
        for (int ks = 0; ks < 32; ks += 16){
            unsigned af[4][4], bf[4][2];
            #pragma unroll
            for (int mt = 0; mt < 4; mt++)
                ldsm4(af[mt][0], af[mt][1], af[mt][2], af[mt][3],
                      smA_u + stb + aoff + (uint32_t)((mt*16*HST + ks)*2));
            ldsm4(bf[0][0], bf[0][1], bf[1][0], bf[1][1], smB_u + stb + boff0 + (uint32_t)(ks*2));
            ldsm4(bf[2][0], bf[2][1], bf[3][0], bf[3][1], smB_u + stb + boff1 + (uint32_t)(ks*2));
            #pragma unroll
            for (int mt = 0; mt < 4; mt++)
                #pragma unroll
                for (int nt2 = 0; nt2 < 4; nt2++)
                    mma16(acc[mt][nt2], af[mt], bf[nt2]);
        }
        stage++; if (stage >= 3) stage -= 3;
    }
    #undef ISSUE_H
    #undef ISSUE_HA
    #undef ISSUE_HB

    #pragma unroll
    for (int mt = 0; mt < 4; mt++){
        int rbase = row0 + wm*64 + mt*16;
        #pragma unroll
        for (int nt2 = 0; nt2 < 4; nt2++){
            int cbase = col0 + wn*32 + nt2*8 + tg*2;
            float b0 = bias[cbase], b1 = bias[cbase+1];
            #pragma unroll
            for (int hh = 0; hh < 2; hh++){
                int rr = rbase + g + hh*8;
                float v0 = acc[mt][nt2][hh*2]   + b0;
                float v1 = acc[mt][nt2][hh*2+1] + b1;
                if (ACT == 1){ v0 = gelu_tanh(v0); v1 = gelu_tanh(v1); }
                size_t gi = (size_t)rr*N + cbase;
                if (HOUT){
                    __half2* p = reinterpret_cast<__half2*>(reinterpret_cast<__half*>(Cv) + gi);
                    *p = __floats2half2_rn(v0, v1);
                } else {
                    float* C = reinterpret_cast<float*>(Cv);
                    if (RESID){
                        float2 c = *reinterpret_cast<float2*>(&C[gi]);
                        c.x += v0; c.y += v1;
                        *reinterpret_cast<float2*>(&C[gi]) = c;
                    } else {
                        *reinterpret_cast<float2*>(&C[gi]) = make_float2(v0, v1);
                    }
                }
            }
        }
    }
}

// ---------------- legacy tf32 tensor GEMM (output head, split-K) ----------
#define AS_ST 36
#define BS_ST 136
#define A_STAGE (128*AS_ST)
#define B_STAGE (32*BS_ST)
#define SM_FLOATS (3*(A_STAGE+B_STAGE))

__global__ __launch_bounds__(256, 2) void headgemm_k(
        const float* __restrict__ A, const float* __restrict__ B,
        float* __restrict__ C, int M, int N, int K){
    extern __shared__ float sm[];
    float* smA = sm;
    float* smB = sm + 3*A_STAGE;
    int tid = threadIdx.x;
    int warp = tid >> 5, lane = tid & 31;
    int wm = warp >> 2, wn = warp & 3;
    int g = lane >> 2, tg = lane & 3;
    int row0 = blockIdx.y * 128, col0 = blockIdx.x * 128;

    int Kc   = K / gridDim.z;
    int kbeg = blockIdx.z * Kc;
    int nt   = Kc >> 5;

    cudaGridDependencySynchronize();

    float acc[4][4][4];
    #pragma unroll
    for (int i=0;i<4;i++) for (int j=0;j<4;j++) for (int q=0;q<4;q++) acc[i][j][q]=0.f;

    #define ISSUE_T(T, S) { \
        int k0 = kbeg + (T)*32; \
        float* as = smA + (S)*A_STAGE; \
        float* bs = smB + (S)*B_STAGE; \
        _Pragma("unroll") \
        for (int i=0;i<4;i++){ \
            int idx = tid + i*256; int r = idx>>3; int ch=(idx&7)<<2; \
            int grow = row0 + r; bool p = grow < M; int gr = p ? grow : (M-1); \
            cpasyncF(&as[r*AS_ST + ch], &A[(size_t)gr*K + k0 + ch], p); \
        } \
        _Pragma("unroll") \
        for (int i=0;i<4;i++){ \
            int idx = tid + i*256; int kk = idx>>5; int c4=(idx&31)<<2; \
            int gcol = col0 + c4; bool p = gcol < N; int gc = p ? gcol : 0; \
            cpasyncF(&bs[kk*BS_ST + c4], &B[(size_t)(k0+kk)*N + gc], p); \
        } \
        cp_commit(); }

    ISSUE_T(0, 0);
    ISSUE_T(1, 1);

    int stage = 0;
    for (int kt = 0; kt < nt; kt++){
        if (kt == nt-1) cp_wait<0>(); else cp_wait<1>();
        __syncthreads();
        if (kt + 2 < nt){
            int s2 = stage + 2; if (s2 >= 3) s2 -= 3;
            ISSUE_T(kt+2, s2);
        }
        const float* as = smA + stage*A_STAGE;
        const float* bs = smB + stage*B_STAGE;
        #pragma unroll
        for (int ks = 0; ks < 32; ks += 8){
            unsigned af[4][4], bf[4][2];
            #pragma unroll
            for (int mt = 0; mt < 4; mt++){
                int r = wm*64 + mt*16 + g;
                af[mt][0] = f2tf(as[r*AS_ST + ks+tg]);
                af[mt][1] = f2tf(as[(r+8)*AS_ST + ks+tg]);
                af[mt][2] = f2tf(as[r*AS_ST + ks+tg+4]);
                af[mt][3] = f2tf(as[(r+8)*AS_ST + ks+tg+4]);
            }
            #pragma unroll
            for (int nt2 = 0; nt2 < 4; nt2++){
                int c = wn*32 + nt2*8 + g;
                bf[nt2][0] = f2tf(bs[(ks+tg)*BS_ST + c]);
                bf[nt2][1] = f2tf(bs[(ks+tg+4)*BS_ST + c]);
            }
            #pragma unroll
            for (int mt = 0; mt < 4; mt++)
                #pragma unroll
                for (int nt2 = 0; nt2 < 4; nt2++)
                    mma8(acc[mt][nt2], af[mt], bf[nt2]);
        }
        stage++; if (stage >= 3) stage -= 3;
        __syncthreads();
    }
    #undef ISSUE_T

    float* Cout = C + (size_t)blockIdx.z*M*N;
    #pragma unroll
    for (int mt = 0; mt < 4; mt++){
        int rbase = row0 + wm*64 + mt*16;
        #pragma unroll
        for (int nt2 = 0; nt2 < 4; nt2++){
            int cbase = col0 + wn*32 + nt2*8 + tg*2;
            #pragma unroll
            for (int half2_ = 0; half2_ < 2; half2_++){
                int rr = rbase + g + half2_*8;
                if (rr < M){
                    #pragma unroll
                    for (int jj = 0; jj < 2; jj++){
                        int cc = cbase + jj;
                        if (cc < N) Cout[(size_t)rr*N + cc] = acc[mt][nt2][half2_*2+jj];
                    }
                }
            }
        }
    }
}

// ---------------- l2-normalize prompt keys ----------------
__global__ void keynorm_k(const float* __restrict__ pk){
    int r = blockIdx.x, tid = threadIdx.x;
    __shared__ float red[256];
    float v0 = pk[(size_t)r*DMOD + tid], v1 = pk[(size_t)r*DMOD + 256 + tid], v2 = pk[(size_t)r*DMOD + 512 + tid];
    red[tid] = v0*v0 + v1*v1 + v2*v2; __syncthreads();
    for (int o = 128; o; o >>= 1){ if (tid < o) red[tid] += red[tid+o]; __syncthreads(); }
    float inv = rsqrtf(fmaxf(red[0], 1e-12f));
    g_keyn[(size_t)r*DMOD + tid]       = v0*inv;
    g_keyn[(size_t)r*DMOD + 256 + tid] = v1*inv;
    g_keyn[(size_t)r*DMOD + 512 + tid] = v2*inv;
}

// ---------------- top-k (writes prompts + wpe into h rows 0..3) -----------
__global__ void topk_k(const float* __restrict__ wpe){
    int n = blockIdx.x, tid = threadIdx.x;
    __shared__ float bv[256];
    __shared__ int   bi[256];
    __shared__ int   chosen[4];
    float rs = 0.f;
    for (int r = 0; r < 4; r++){
        float best = -1e30f; int besti = 1 << 30;
        for (int j = tid; j < POOLN; j += 256){
            bool skip = false;
            for (int c = 0; c < r; c++) if (chosen[c] == j) skip = true;
            float v = g_sim[(size_t)n*POOLN + j];
            if (!skip && (v > best || (v == best && j < besti))){ best = v; besti = j; }
        }
        bv[tid] = best; bi[tid] = besti; __syncthreads();
        for (int o = 128; o; o >>= 1){
            if (tid < o){
                if (bv[tid+o] > bv[tid] || (bv[tid+o] == bv[tid] && bi[tid+o] < bi[tid])){
                    bv[tid] = bv[tid+o]; bi[tid] = bi[tid+o];
                }
            }
            __syncthreads();
        }
        if (tid == 0){ chosen[r] = bi[0]; rs += bv[0]; }
        __syncthreads();
    }
    for (int e = tid; e < 4*DMOD; e += 256){
        int k = e / DMOD, d = e % DMOD;
        g_h[((size_t)n*TTOK + k)*DMOD + d] = g_keyn[(size_t)chosen[k]*DMOD + d] + wpe[(size_t)k*DMOD + d];
    }
    if (tid == 0) atomicAdd(&g_rsim, rs);
}

// ---------------- layernorm: warp per row; half or float out --------------
template<bool HOUT>
__global__ void ln_k(const float* __restrict__ x, const float* __restrict__ g,
                     const float* __restrict__ b, void* __restrict__ yv){
    int row  = blockIdx.x*8 + (threadIdx.x >> 5);
    int lane = threadIdx.x & 31;
    cudaGridDependencySynchronize();
    const float4* xr = reinterpret_cast<const float4*>(x + (size_t)row*DMOD);
    const float4* g4 = reinterpret_cast<const float4*>(g);
    const float4* b4 = reinterpret_cast<const float4*>(b);
    float4 v[6];
    float s = 0.f, sq = 0.f;
    #pragma unroll
    for (int i = 0; i < 6; i++){
        v[i] = xr[lane + i*32];
        s  += v[i].x + v[i].y + v[i].z + v[i].w;
        sq += v[i].x*v[i].x + v[i].y*v[i].y + v[i].z*v[i].z + v[i].w*v[i].w;
    }
    #pragma unroll
    for (int o = 16; o; o >>= 1){
        s  += __shfl_xor_sync(0xffffffffu, s,  o);
        sq += __shfl_xor_sync(0xffffffffu, sq, o);
    }
    float mu  = s * (1.f/DMOD);
    float var = sq * (1.f/DMOD) - mu*mu;
    float inv = rsqrtf(var + 1e-5f);
    #pragma unroll
    for (int i = 0; i < 6; i++){
        float4 gg = g4[lane + i*32], bb = b4[lane + i*32], o;
        o.x = (v[i].x-mu)*inv*gg.x + bb.x;
        o.y = (v[i].y-mu)*inv*gg.y + bb.y;
        o.z = (v[i].z-mu)*inv*gg.z + bb.z;
        o.w = (v[i].w-mu)*inv*gg.w + bb.w;
        if (HOUT){
            __half2* yr = reinterpret_cast<__half2*>(reinterpret_cast<__half*>(yv) + (size_t)row*DMOD);
            yr[2*(lane+i*32)]   = __floats2half2_rn(o.x, o.y);
            yr[2*(lane+i*32)+1] = __floats2half2_rn(o.z, o.w);
        } else {
            float4* yr = reinterpret_cast<float4*>(reinterpret_cast<float*>(yv) + (size_t)row*DMOD);
            yr[lane + i*32] = o;
        }
    }
}

// ---------------- attention: fp16 mma flash, block per (series, head) -----
#define QKS 72
#define VTS 88
__global__ __launch_bounds__(160) void attn_k(){
    int blk = blockIdx.x;
    int n = blk / 12, head = blk % 12;
    __shared__ __half qs[80*QKS];
    __shared__ __half ks[80*QKS];
    __shared__ __half vt[64*VTS];
    int tid = threadIdx.x, w = tid >> 5, lane = tid & 31;
    int g = lane >> 2, tg = lane & 3;

    for (int idx = tid; idx < 64*12; idx += 160){
        int d = idx / 12, t = 68 + idx % 12;
        vt[d*VTS + t] = __float2half(0.f);
    }
    cudaGridDependencySynchronize();
    const __half* qkv = g_qkvh + (size_t)n*TTOK*3*DMOD + head*64;
    for (int idx = tid; idx < TTOK*32; idx += 160){
        int t = idx >> 5, c = (idx & 31)*2;
        __half2 q2 = *reinterpret_cast<const __half2*>(qkv + (size_t)t*3*DMOD + c);
        __half2 k2 = *reinterpret_cast<const __half2*>(qkv + (size_t)t*3*DMOD + DMOD + c);
        __half2 v2 = *reinterpret_cast<const __half2*>(qkv + (size_t)t*3*DMOD + 2*DMOD + c);
        *reinterpret_cast<__half2*>(qs + t*QKS + c) = q2;
        *reinterpret_cast<__half2*>(ks + t*QKS + c) = k2;
        vt[c*VTS + t]     = __low2half(v2);
        vt[(c+1)*VTS + t] = __high2half(v2);
    }
    __syncthreads();

    int rb = w*16 + g;
    float sacc[10][4];
    #pragma unroll
    for (int i = 0; i < 10; i++) for (int j = 0; j < 4; j++) sacc[i][j] = 0.f;
    #pragma unroll
    for (int kc = 0; kc < 4; kc++){
        unsigned af[4];
        int base = rb*QKS + kc*16 + 2*tg;
        af[0] = *reinterpret_cast<const unsigned*>(&qs[base]);
        af[1] = *reinterpret_cast<const unsigned*>(&qs[base + 8*QKS]);
        af[2] = *reinterpret_cast<const unsigned*>(&qs[base + 8]);
        af[3] = *reinterpret_cast<const unsigned*>(&qs[base + 8*QKS + 8]);
        #pragma unroll
        for (int nt = 0; nt < 10; nt++){
            unsigned bf[2];
            int bb = (nt*8 + g)*QKS + kc*16 + 2*tg;
            bf[0] = *reinterpret_cast<const unsigned*>(&ks[bb]);
            bf[1] = *reinterpret_cast<const unsigned*>(&ks[bb + 8]);
            mma16(sacc[nt], af, bf);
        }
    }
    float inv_[2];
    #pragma unroll
    for (int hh = 0; hh < 2; hh++){
        int R = rb + hh*8;
        float mx = -1e30f;
        #pragma unroll
        for (int nt = 0; nt < 10; nt++)
            #pragma unroll
            for (int jj = 0; jj < 2; jj++){
                int Cn = nt*8 + 2*tg + jj;
                float sv = sacc[nt][hh*2+jj] * 0.125f;
                sv = (Cn <= R) ? sv : -1e9f;
                sacc[nt][hh*2+jj] = sv;
                mx = fmaxf(mx, sv);
            }
        mx = fmaxf(mx, __shfl_xor_sync(0xffffffffu, mx, 1));
        mx = fmaxf(mx, __shfl_xor_sync(0xffffffffu, mx, 2));
        float sm = 0.f;
        #pragma unroll
        for (int nt = 0; nt < 10; nt++)
            #pragma unroll
            for (int jj = 0; jj < 2; jj++){
                float p = expf(sacc[nt][hh*2+jj] - mx);
                sacc[nt][hh*2+jj] = p;
                sm += p;
            }
        sm += __shfl_xor_sync(0xffffffffu, sm, 1);
        sm += __shfl_xor_sync(0xffffffffu, sm, 2);
        inv_[hh] = 1.f/sm;
    }
    float oacc[8][4];
    #pragma unroll
    for (int i = 0; i < 8; i++) for (int j = 0; j < 4; j++) oacc[i][j] = 0.f;
    #pragma unroll
    for (int kc = 0; kc < 5; kc++){
        unsigned af[4];
        af[0] = packh2(sacc[2*kc][0],   sacc[2*kc][1]);
        af[1] = packh2(sacc[2*kc][2],   sacc[2*kc][3]);
        af[2] = packh2(sacc[2*kc+1][0], sacc[2*kc+1][1]);
        af[3] = packh2(sacc[2*kc+1][2], sacc[2*kc+1][3]);
        #pragma unroll
        for (int nt = 0; nt < 8; nt++){
            unsigned bf[2];
            int bb = (nt*8 + g)*VTS + kc*16 + 2*tg;
            bf[0] = *reinterpret_cast<const unsigned*>(&vt[bb]);
            bf[1] = *reinterpret_cast<const unsigned*>(&vt[bb + 8]);
            mma16(oacc[nt], af, bf);
        }
    }
    __half* ob = g_ob + (size_t)n*TTOK*DMOD + head*64;
    #pragma unroll
    for (int hh = 0; hh < 2; hh++){
        int R = rb + hh*8;
        if (R < TTOK){
            #pragma unroll
            for (int nt = 0; nt < 8; nt++){
                __half2 hv = __floats2half2_rn(oacc[nt][hh*2]*inv_[hh], oacc[nt][hh*2+1]*inv_[hh]);
                *reinterpret_cast<__half2*>(ob + (size_t)R*DMOD + nt*8 + 2*tg) = hv;
            }
        }
    }
}

// ---------------- final: sum split-K chunks + channels, denorm + rsim -----
__global__ void final_k(const float* __restrict__ outb, float* __restrict__ out, int out_size){
    int n = blockIdx.x, b = n/7, m = n%7;
    cudaGridDependencySynchronize();
    for (int t = threadIdx.x; t < PREDL; t += blockDim.x){
        float v = 3.f*outb[t];
        #pragma unroll
        for (int z = 0; z < SPLITZ; z++){
            const float* p = g_osp + (size_t)z*NSER*3*PREDL;
            v += p[(size_t)(n*3+0)*PREDL + t]
               + p[(size_t)(n*3+1)*PREDL + t]
               + p[(size_t)(n*3+2)*PREDL + t];
        }
        out[(size_t)b*PREDL*7 + (size_t)t*7 + m] = v*g_std[n] + g_mean[n];
    }
    if (n == 0 && threadIdx.x == 0 && out_size > 64*PREDL*7)
        out[64*PREDL*7] = g_rsim * (1.f/NSER);
}

// ---------------- host ----------------
template <typename T, size_t S>
static void* symaddr(T (&arr)[S]){ void* p = nullptr; cudaGetSymbolAddress(&p, arr); return p; }

template<typename F, typename... Args>
static void launch_pdl(F* k, dim3 gr, dim3 bl, size_t sm, cudaStream_t st, Args... args){
    cudaLaunchConfig_t cfg = {};
    cfg.gridDim = gr; cfg.blockDim = bl; cfg.dynamicSmemBytes = sm; cfg.stream = st;
    cudaLaunchAttribute at[1];
    at[0].id = cudaLaunchAttributeProgrammaticStreamSerialization;
    at[0].val.programmaticStreamSerializationAllowed = 1;
    cfg.attrs = at; cfg.numAttrs = 1;
    cudaLaunchKernelEx(&cfg, k, args...);
}

extern "C" void kernel_launch(void* const* d_in, const int* in_sizes, int n_in,
                              void* d_out, int out_size){
    int s = (n_in >= 2 && in_sizes[1] == 1) ? 1 : 0;
    const float* x    = (const float*)d_in[0];
    const float* in_w = (const float*)d_in[1+s];
    const float* in_b = (const float*)d_in[2+s];
    const float* pk   = (const float*)d_in[3+s];
    const float* wpe  = (const float*)d_in[4+s];
    const float* ln1g = (const float*)d_in[5+s];
    const float* ln1b = (const float*)d_in[6+s];
    const float* qkvw = (const float*)d_in[7+s];
    const float* qkvb = (const float*)d_in[8+s];
    const float* aw   = (const float*)d_in[9+s];
    const float* ab   = (const float*)d_in[10+s];
    const float* ln2g = (const float*)d_in[11+s];
    const float* ln2b = (const float*)d_in[12+s];
    const float* fcw  = (const float*)d_in[13+s];
    const float* fcb  = (const float*)d_in[14+s];
    const float* pw   = (const float*)d_in[15+s];
    const float* pbb  = (const float*)d_in[16+s];
    const float* lnfg = (const float*)d_in[17+s];
    const float* lnfb = (const float*)d_in[18+s];
    const float* outw = (const float*)d_in[19+s];
    const float* outb = (const float*)d_in[20+s];
    float* out = (float*)d_out;

    float*  p_h    = (float*) symaddr(g_h);
    __half* p_a    = (__half*)symaddr(g_a);
    float*  p_af   = (float*) symaddr(g_af);
    __half* p_qkv  = (__half*)symaddr(g_qkvh);
    __half* p_ob   = (__half*)symaddr(g_ob);
    __half* p_mlp  = (__half*)symaddr(g_mlp);
    float*  p_tok  = (float*) symaddr(g_tok);
    float*  p_mtok = (float*) symaddr(g_mtok);
    float*  p_xq   = (float*) symaddr(g_xq);
    float*  p_keyn = (float*) symaddr(g_keyn);
    float*  p_sim  = (float*) symaddr(g_sim);
    float*  p_osp  = (float*) symaddr(g_osp);
    __half* p_wT   = (__half*)symaddr(g_wT);

    const int SMB = SM_FLOATS*4;
    static cudaStream_t s2 = nullptr, s3 = nullptr;
    static cudaEvent_t evA = nullptr, evB = nullptr, evK = nullptr, evPre = nullptr, evP = nullptr;
    if (!s2){
        cudaFuncSetAttribute(headgemm_k, cudaFuncAttributeMaxDynamicSharedMemorySize, SMB);
        cudaFuncSetAttribute(hgemm_k<0,false,false>, cudaFuncAttributeMaxDynamicSharedMemorySize, H_SMEMB);
        cudaFuncSetAttribute(hgemm_k<0,true ,false>, cudaFuncAttributeMaxDynamicSharedMemorySize, H_SMEMB);
        cudaFuncSetAttribute(hgemm_k<1,false,true >, cudaFuncAttributeMaxDynamicSharedMemorySize, H_SMEMB);
        cudaFuncSetAttribute(hgemm_k<0,false,true >, cudaFuncAttributeMaxDynamicSharedMemorySize, H_SMEMB);
        cudaStreamCreateWithFlags(&s2, cudaStreamNonBlocking);
        cudaStreamCreateWithFlags(&s3, cudaStreamNonBlocking);
        cudaEventCreateWithFlags(&evA, cudaEventDisableTiming);
        cudaEventCreateWithFlags(&evB, cudaEventDisableTiming);
        cudaEventCreateWithFlags(&evK, cudaEventDisableTiming);
        cudaEventCreateWithFlags(&evPre, cudaEventDisableTiming);
        cudaEventCreateWithFlags(&evP, cudaEventDisableTiming);
    }

    // fork: keynorm + weight transposes on s2
    cudaEventRecord(evA, 0);
    cudaStreamWaitEvent(s2, evA, 0);
    keynorm_k<<<POOLN,256,0,s2>>>(pk);
    cudaEventRecord(evK, s2);
    for (int L = 0; L < NLAYER; L++){
        __half* qkvT = p_wT + (size_t)L*WL;
        __half* awT  = qkvT + 1769472;
        __half* fcT  = awT  + 589824;
        __half* pwT  = fcT  + 2359296;
        transp_k<<<dim3(2304/32, 768/32), dim3(32,8), 0, s2>>>(qkvw + (size_t)L*DMOD*3*DMOD, qkvT, 768, 2304);
        transp_k<<<dim3( 768/32, 768/32), dim3(32,8), 0, s2>>>(aw   + (size_t)L*DMOD*DMOD,   awT,  768, 768);
        transp_k<<<dim3(3072/32, 768/32), dim3(32,8), 0, s2>>>(fcw  + (size_t)L*DMOD*4*DMOD, fcT,  768, 3072);
        transp_k<<<dim3( 768/32,3072/32), dim3(32,8), 0, s2>>>(pw   + (size_t)L*4*DMOD*DMOD, pwT, 3072, 768);
    }
    cudaEventRecord(evB, s2);

    // main: prep; patch-embed GEMM forks to s3 (writes h rows 4..67 + wpe)
    prep_k<<<NSER,256>>>(x);
    cudaEventRecord(evPre, 0);
    cudaStreamWaitEvent(s3, evPre, 0);
    gemm_k<false,0,false,true><<<dim3(DMOD/64, NSER*PNUM/64),256,0,s3>>>(p_tok, in_w, in_b, p_h, NSER*PNUM, DMOD, 48, wpe);
    cudaEventRecord(evP, s3);

    meantok_k<<<NSER,64>>>();
    gemm_k<false,0,false,false><<<dim3(DMOD/64, NSER/64),256>>>(p_mtok, in_w, in_b, p_xq, NSER, DMOD, 48, nullptr);
    xqn_k<<<NSER,256>>>();
    cudaStreamWaitEvent(0, evK, 0);
    gemm_k<true,0,false,false><<<dim3((POOLN+63)/64, NSER/64),256>>>(p_xq, p_keyn, (const float*)nullptr, p_sim, NSER, POOLN, DMOD, nullptr);
    topk_k<<<NSER,256>>>(wpe);

    cudaStreamWaitEvent(0, evB, 0);
    cudaStreamWaitEvent(0, evP, 0);

    const int MB = NTOK/128;   // 238
    for (int L = 0; L < NLAYER; L++){
        __half* qkvT = p_wT + (size_t)L*WL;
        __half* awT  = qkvT + 1769472;
        __half* fcT  = awT  + 589824;
        __half* pwT  = fcT  + 2359296;
        launch_pdl(ln_k<true>, dim3(NTOK/8), dim3(256), 0, (cudaStream_t)0,
                   (const float*)p_h, (const float*)(ln1g + (size_t)L*DMOD), (const float*)(ln1b + (size_t)L*DMOD), (void*)p_a);
        launch_pdl(hgemm_k<0,false,true>, dim3(3*DMOD/128, MB), dim3(256), (size_t)H_SMEMB, (cudaStream_t)0,
                   (const __half*)p_a, (const __half*)qkvT, (const float*)(qkvb + (size_t)L*3*DMOD), (void*)p_qkv, NTOK, 3*DMOD, DMOD);
        launch_pdl(attn_k, dim3(NSER*12), dim3(160), 0, (cudaStream_t)0);
        launch_pdl(hgemm_k<0,true,false>, dim3(DMOD/128, MB), dim3(256), (size_t)H_SMEMB, (cudaStream_t)0,
                   (const __half*)p_ob, (const __half*)awT, (const float*)(ab + (size_t)L*DMOD), (void*)p_h, NTOK, DMOD, DMOD);
        launch_pdl(ln_k<true>, dim3(NTOK/8), dim3(256), 0, (cudaStream_t)0,
                   (const float*)p_h, (const float*)(ln2g + (size_t)L*DMOD), (const float*)(ln2b + (size_t)L*DMOD), (void*)p_a);
        launch_pdl(hgemm_k<1,false,true>, dim3(4*DMOD/128, MB), dim3(256), (size_t)H_SMEMB, (cudaStream_t)0,
                   (const __half*)p_a, (const __half*)fcT, (const float*)(fcb + (size_t)L*4*DMOD), (void*)p_mlp, NTOK, 4*DMOD, DMOD);
        launch_pdl(hgemm_k<0,true,false>, dim3(DMOD/128, MB), dim3(256), (size_t)H_SMEMB, (cudaStream_t)0,
                   (const __half*)p_mlp, (const __half*)pwT, (const float*)(pbb + (size_t)L*DMOD), (void*)p_h, NTOK, DMOD, 3072);
    }

    launch_pdl(ln_k<false>, dim3(NTOK/8), dim3(256), 0, (cudaStream_t)0,
               (const float*)p_h, (const float*)lnfg, (const float*)lnfb, (void*)p_af);
    launch_pdl(headgemm_k, dim3(1, (NSER*3+127)/128, SPLITZ), dim3(256), (size_t)SMB, (cudaStream_t)0,
               (const float*)p_af, (const float*)outw, (float*)p_osp, NSER*3, PREDL, TTOK*DMOD/3);
    launch_pdl(final_k, dim3(NSER), dim3(96), 0, (cudaStream_t)0,
               (const float*)outb, (float*)out, out_size);
}

// round 11
// speedup vs baseline: 7.0875x; 1.0005x over previous
#include <cuda_runtime.h>
#include <cuda_fp16.h>
#include <math.h>
#include <stdint.h>

#define NSER 448
#define LSEQ 512
#define TTOK 68
#define DMOD 768
#define NTOK (NSER*TTOK)       // 30464
#define PNUM 64
#define POOLN 1000
#define PREDL 96
#define NLAYER 6
#define SPLITZ 32

// ---------------- scratch (device globals; no allocations) ----------------
__device__ float  g_mean[NSER];
__device__ float  g_std [NSER];
__device__ float  g_tok [NSER*PNUM*48];
__device__ float  g_mtok[NSER*48];
__device__ float  g_h   [(size_t)NTOK*DMOD];
__device__ __half g_a   [(size_t)NTOK*DMOD];
__device__ float  g_af  [(size_t)NTOK*DMOD];
__device__ __half g_qkvh[(size_t)NTOK*3*DMOD];
__device__ __half g_ob  [(size_t)NTOK*DMOD];
__device__ __half g_mlp [(size_t)NTOK*4*DMOD];
__device__ float  g_xq  [NSER*DMOD];
__device__ float  g_keyn[POOLN*DMOD];
__device__ float  g_sim [NSER*POOLN];
__device__ float  g_osp [(size_t)SPLITZ*NSER*3*PREDL];
__device__ float  g_rsim;
#define WL 7077888u
__device__ __half g_wT  [(size_t)NLAYER*WL];

__device__ __forceinline__ float gelu_tanh(float x){
    float c = 0.7978845608028654f;
    float t = tanhf(c*(x + 0.044715f*x*x*x));
    return 0.5f*x*(1.f+t);
}

__device__ __forceinline__ unsigned f2tf(float x){
    unsigned r; asm("cvt.rna.tf32.f32 %0, %1;" : "=r"(r) : "f"(x)); return r;
}

__device__ __forceinline__ void mma8(float* c, const unsigned* a, const unsigned* b){
    asm volatile("mma.sync.aligned.m16n8k8.row.col.f32.tf32.tf32.f32 "
        "{%0,%1,%2,%3}, {%4,%5,%6,%7}, {%8,%9}, {%0,%1,%2,%3};"
        : "+f"(c[0]),"+f"(c[1]),"+f"(c[2]),"+f"(c[3])
        : "r"(a[0]),"r"(a[1]),"r"(a[2]),"r"(a[3]), "r"(b[0]),"r"(b[1]));
}

__device__ __forceinline__ void mma16(float* c, const unsigned* a, const unsigned* b){
    asm volatile("mma.sync.aligned.m16n8k16.row.col.f32.f16.f16.f32 "
        "{%0,%1,%2,%3}, {%4,%5,%6,%7}, {%8,%9}, {%0,%1,%2,%3};"
        : "+f"(c[0]),"+f"(c[1]),"+f"(c[2]),"+f"(c[3])
        : "r"(a[0]),"r"(a[1]),"r"(a[2]),"r"(a[3]), "r"(b[0]),"r"(b[1]));
}

__device__ __forceinline__ void ldsm4(unsigned &r0, unsigned &r1, unsigned &r2, unsigned &r3, uint32_t addr){
    asm volatile("ldmatrix.sync.aligned.m8n8.x4.shared.b16 {%0,%1,%2,%3}, [%4];"
        : "=r"(r0),"=r"(r1),"=r"(r2),"=r"(r3) : "r"(addr));
}

__device__ __forceinline__ void cpasyncF(float* dst, const float* src, bool pred){
    unsigned sa = (unsigned)__cvta_generic_to_shared(dst);
    int sz = pred ? 16 : 0;
    asm volatile("cp.async.cg.shared.global [%0], [%1], 16, %2;" :: "r"(sa), "l"(src), "r"(sz));
}
__device__ __forceinline__ void cpasyncH(__half* dst, const __half* src){
    unsigned sa = (unsigned)__cvta_generic_to_shared(dst);
    asm volatile("cp.async.cg.shared.global [%0], [%1], 16;" :: "r"(sa), "l"(src));
}
__device__ __forceinline__ void cp_commit(){ asm volatile("cp.async.commit_group;"); }
template<int N> __device__ __forceinline__ void cp_wait(){ asm volatile("cp.async.wait_group %0;"::"n"(N)); }

__device__ __forceinline__ unsigned packh2(float a, float b){
    __half2 h = __floats2half2_rn(a, b);
    return *reinterpret_cast<unsigned*>(&h);
}

// ---------------- fused preamble: RevIN + decompose + patch + patch-mean --
__global__ void prep_k(const float* __restrict__ x){
    int n = blockIdx.x, b = n/7, m = n%7, tid = threadIdx.x;
    __shared__ float xs[LSEQ];
    __shared__ float valid[489];
    __shared__ float det[LSEQ];
    __shared__ float ph[24];
    __shared__ float red[256];
    if (n == 0 && tid == 0) g_rsim = 0.f;
    for (int l = tid; l < LSEQ; l += 256) xs[l] = x[((size_t)b*LSEQ + l)*7 + m];
    if (tid < 24) ph[tid] = 0.f;
    __syncthreads();
    float s = xs[tid] + xs[tid+256];
    red[tid] = s; __syncthreads();
    for (int o = 128; o; o >>= 1){ if (tid < o) red[tid] += red[tid+o]; __syncthreads(); }
    float mu = red[0] * (1.f/LSEQ);
    __syncthreads();
    float d0 = xs[tid]-mu, d1 = xs[tid+256]-mu;
    red[tid] = d0*d0 + d1*d1; __syncthreads();
    for (int o = 128; o; o >>= 1){ if (tid < o) red[tid] += red[tid+o]; __syncthreads(); }
    float sd = sqrtf(red[0]*(1.f/LSEQ) + 1e-5f);
    if (tid == 0){ g_mean[n] = mu; g_std[n] = sd; }
    float inv = 1.f/sd;
    xs[tid]       = d0*inv;
    xs[tid + 256] = d1*inv;
    __syncthreads();
    for (int i = tid; i < 489; i += 256){
        float ss = 0.f;
        #pragma unroll
        for (int k = 0; k < 24; k++) ss += xs[i+k];
        valid[i] = ss * (1.f/24.f);
    }
    __syncthreads();
    for (int l = tid; l < LSEQ; l += 256){
        int vi = l - 12; vi = vi < 0 ? 0 : (vi > 488 ? 488 : vi);
        float dt = xs[l] - valid[vi];
        det[l] = dt;
        atomicAdd(&ph[l % 24], dt);
    }
    __syncthreads();
    for (int e = tid; e < PNUM*48; e += 256){
        int p = e/48, rem = e%48, c = rem/16, j = rem%16;
        int l = p*8 + j; if (l > LSEQ-1) l = LSEQ-1;
        float v;
        if (c == 0){
            int vi = l - 12; vi = vi < 0 ? 0 : (vi > 488 ? 488 : vi);
            v = valid[vi];
        } else {
            int pp = l % 24;
            float cnt = (pp < 8) ? 22.f : 21.f;
            float se = ph[pp] / cnt;
            v = (c == 1) ? se : (det[l] - se);
        }
        g_tok[(size_t)n*PNUM*48 + e] = v;
    }
    // patch-mean in smem (same p order as former meantok_k)
    if (tid < 48){
        int c = tid/16, j = tid%16;
        float sm = 0.f;
        for (int p = 0; p < PNUM; p++){
            int l = p*8 + j; if (l > LSEQ-1) l = LSEQ-1;
            float v;
            if (c == 0){
                int vi = l - 12; vi = vi < 0 ? 0 : (vi > 488 ? 488 : vi);
                v = valid[vi];
            } else {
                int pp = l % 24;
                float cnt = (pp < 8) ? 22.f : 21.f;
                float se = ph[pp] / cnt;
                v = (c == 1) ? se : (det[l] - se);
            }
            sm += v;
        }
        g_mtok[n*48 + tid] = sm * (1.f/PNUM);
    }
}

// ---------------- l2-normalize xq rows in place ----------------
__global__ void xqn_k(){
    int n = blockIdx.x, tid = threadIdx.x;
    __shared__ float red[256];
    float v0 = g_xq[(size_t)n*DMOD + tid], v1 = g_xq[(size_t)n*DMOD + 256 + tid], v2 = g_xq[(size_t)n*DMOD + 512 + tid];
    red[tid] = v0*v0 + v1*v1 + v2*v2; __syncthreads();
    for (int o = 128; o; o >>= 1){ if (tid < o) red[tid] += red[tid+o]; __syncthreads(); }
    float inv = rsqrtf(fmaxf(red[0], 1e-12f));
    g_xq[(size_t)n*DMOD + tid]       = v0*inv;
    g_xq[(size_t)n*DMOD + 256 + tid] = v1*inv;
    g_xq[(size_t)n*DMOD + 512 + tid] = v2*inv;
}

// ---------------- weight transpose to half ----------------
__global__ void transp_k(const float* __restrict__ W, __half* __restrict__ WT, int K, int N){
    __shared__ float t[32][33];
    int bx = blockIdx.x*32, by = blockIdx.y*32;
    int x = threadIdx.x, y = threadIdx.y;
    #pragma unroll
    for (int i = 0; i < 4; i++){
        int r = by + y*4 + i;
        t[y*4+i][x] = W[(size_t)r*N + bx + x];
    }
    __syncthreads();
    #pragma unroll
    for (int i = 0; i < 4; i++){
        int rn = bx + y*4 + i;
        WT[(size_t)rn*K + by + x] = __float2half(t[x][y*4+i]);
    }
}

// ---------------- generic fp32 SIMT GEMM --------------------------------
template<bool TRANSB, int ACT, bool RESID, bool REMAP>
__global__ void gemm_k(const float* __restrict__ A, const float* __restrict__ B,
                       const float* __restrict__ bias, float* __restrict__ C,
                       int M, int N, int K, const float* __restrict__ wadd){
    __shared__ float As[16][68];
    __shared__ float Bs[16][68];
    int tid = threadIdx.x;
    int tx = tid & 15, ty = tid >> 4;
    int row0 = blockIdx.y * 64, col0 = blockIdx.x * 64;
    float acc[4][4] = {};
    for (int k0 = 0; k0 < K; k0 += 16){
        {
            int r  = tid >> 2;
            int c4 = (tid & 3) * 4;
            float4 v = *reinterpret_cast<const float4*>(&A[(size_t)(row0 + r)*K + k0 + c4]);
            As[c4+0][r] = v.x; As[c4+1][r] = v.y; As[c4+2][r] = v.z; As[c4+3][r] = v.w;
        }
        if (!TRANSB){
            int kk = tid >> 4;
            int c4 = (tid & 15) * 4;
            int col = col0 + c4;
            float4 v = make_float4(0.f,0.f,0.f,0.f);
            if (col < N) v = *reinterpret_cast<const float4*>(&B[(size_t)(k0+kk)*N + col]);
            Bs[kk][c4+0] = v.x; Bs[kk][c4+1] = v.y; Bs[kk][c4+2] = v.z; Bs[kk][c4+3] = v.w;
        } else {
            int nn = tid >> 2;
            int c4 = (tid & 3) * 4;
            int col = col0 + nn;
            float4 v = make_float4(0.f,0.f,0.f,0.f);
            if (col < N) v = *reinterpret_cast<const float4*>(&B[(size_t)col*K + k0 + c4]);
            Bs[c4+0][nn] = v.x; Bs[c4+1][nn] = v.y; Bs[c4+2][nn] = v.z; Bs[c4+3][nn] = v.w;
        }
        __syncthreads();
        #pragma unroll
        for (int kk = 0; kk < 16; kk++){
            float a[4], b[4];
            #pragma unroll
            for (int i = 0; i < 4; i++) a[i] = As[kk][ty*4+i];
            #pragma unroll
            for (int j = 0; j < 4; j++) b[j] = Bs[kk][tx*4+j];
            #pragma unroll
            for (int i = 0; i < 4; i++)
                #pragma unroll
                for (int j = 0; j < 4; j++) acc[i][j] = fmaf(a[i], b[j], acc[i][j]);
        }
        __syncthreads();
    }
    #pragma unroll
    for (int i = 0; i < 4; i++){
        int r = row0 + ty*4 + i;
        size_t orow = REMAP ? (size_t)((r >> 6)*TTOK + 4 + (r & 63)) : (size_t)r;
        int t = REMAP ? (4 + (r & 63)) : 0;
        #pragma unroll
        for (int j = 0; j < 4; j++){
            int col = col0 + tx*4 + j;
            if (col < N){
                float v = acc[i][j];
                if (bias) v += bias[col];
                if (ACT == 1) v = gelu_tanh(v);
                if (REMAP && wadd) v += wadd[(size_t)t*DMOD + col];
                size_t idx = orow*(size_t)N + col;
                if (RESID) C[idx] += v; else C[idx] = v;
            }
        }
    }
}

// ================= fp16 tensor-core GEMM (ldmatrix + PDL B-prefetch) ======
#define HST 40
#define H_STAGE (128*HST)
#define H_SMEMB (6*H_STAGE*2)

template<int ACT, bool RESID, bool HOUT>
__global__ __launch_bounds__(256, 2) void hgemm_k(
        const __half* __restrict__ A, const __half* __restrict__ BT,
        const float* __restrict__ bias, void* __restrict__ Cv,
        int M, int N, int K){
    extern __shared__ __half hsm[];
    __half* smA = hsm;
    __half* smB = hsm + 3*H_STAGE;
    int tid = threadIdx.x;
    int warp = tid >> 5, lane = tid & 31;
    int wm = warp >> 2, wn = warp & 3;
    int g = lane >> 2, tg = lane & 3;
    int row0 = blockIdx.y * 128, col0 = blockIdx.x * 128;

    float acc[4][4][4];
    #pragma unroll
    for (int i=0;i<4;i++) for (int j=0;j<4;j++) for (int q=0;q<4;q++) acc[i][j][q]=0.f;

    uint32_t smA_u = (uint32_t)__cvta_generic_to_shared(smA);
    uint32_t smB_u = (uint32_t)__cvta_generic_to_shared(smB);
    uint32_t aoff = (uint32_t)(((wm*64 + (lane & 15))*HST + ((lane >> 4)*8)) * 2);
    int brlo = lane & 7, b8 = ((lane >> 4) & 1)*8, bc8 = ((lane >> 3) & 1)*8;
    uint32_t boff0 = (uint32_t)(((wn*32 +  0 + b8 + brlo)*HST + bc8) * 2);
    uint32_t boff1 = (uint32_t)(((wn*32 + 16 + b8 + brlo)*HST + bc8) * 2);

    #define ISSUE_HB(T, S) { \
        __half* bs = smB + (S)*H_STAGE; \
        const __half* Bb = BT + (size_t)col0*K + (T)*32; \
        _Pragma("unroll") \
        for (int i=0;i<2;i++){ \
            int idx = tid + i*256; int r = idx>>2, ch = idx&3; \
            cpasyncH(&bs[r*HST + ch*8], &Bb[(size_t)r*K + ch*8]); \
        } \
        cp_commit(); }
    #define ISSUE_HA(T, S) { \
        __half* as = smA + (S)*H_STAGE; \
        const __half* Ab = A + (size_t)row0*K + (T)*32; \
        _Pragma("unroll") \
        for (int i=0;i<2;i++){ \
            int idx = tid + i*256; int r = idx>>2, ch = idx&3; \
            cpasyncH(&as[r*HST + ch*8], &Ab[(size_t)r*K + ch*8]); \
        } \
        cp_commit(); }
    #define ISSUE_H(T, S) { \
        __half* as = smA + (S)*H_STAGE; \
        __half* bs = smB + (S)*H_STAGE; \
        const __half* Ab = A + (size_t)row0*K + (T)*32; \
        const __half* Bb = BT + (size_t)col0*K + (T)*32; \
        _Pragma("unroll") \
        for (int i=0;i<2;i++){ \
            int idx = tid + i*256; int r = idx>>2, ch = idx&3; \
            cpasyncH(&as[r*HST + ch*8], &Ab[(size_t)r*K + ch*8]); \
        } \
        _Pragma("unroll") \
        for (int i=0;i<2;i++){ \
            int idx = tid + i*256; int r = idx>>2, ch = idx&3; \
            cpasyncH(&bs[r*HST + ch*8], &Bb[(size_t)r*K + ch*8]); \
        } \
        cp_commit(); }

    int nt = K >> 5;
    ISSUE_HB(0, 0);
    ISSUE_HB(1, 1);
    cudaGridDependencySynchronize();
    ISSUE_HA(0, 0);
    ISSUE_HA(1, 1);

    int stage = 0;
    for (int kt = 0; kt < nt; kt++){
        if (kt == nt-1) cp_wait<0>(); else cp_wait<1>();
        __syncthreads();
        if (kt + 2 < nt){
            int s2 = stage + 2; if (s2 >= 3) s2 -= 3;
            ISSUE_H(kt+2, s2);
        }
        uint32_t stb = (uint32_t)(stage*H_STAGE*2);
        #pragma unroll
        for (int ks = 0; ks < 32; ks += 16){
            unsigned af[4][4], bf[4][2];
            #pragma unroll
            for (int mt = 0; mt < 4; mt++)
                ldsm4(af[mt][0], af[mt][1], af[mt][2], af[mt][3],
                      smA_u + stb + aoff + (uint32_t)((mt*16*HST + ks)*2));
            ldsm4(bf[0][0], bf[0][1], bf[1][0], bf[1][1], smB_u + stb + boff0 + (uint32_t)(ks*2));
            ldsm4(bf[2][0], bf[2][1], bf[3][0], bf[3][1], smB_u + stb + boff1 + (uint32_t)(ks*2));
            #pragma unroll
            for (int mt = 0; mt < 4; mt++)
                #pragma unroll
                for (int nt2 = 0; nt2 < 4; nt2++)
                    mma16(acc[mt][nt2], af[mt], bf[nt2]);
        }
        stage++; if (stage >= 3) stage -= 3;
    }
    #undef ISSUE_H
    #undef ISSUE_HA
    #undef ISSUE_HB

    #pragma unroll
    for (int mt = 0; mt < 4; mt++){
        int rbase = row0 + wm*64 + mt*16;
        #pragma unroll
        for (int nt2 = 0; nt2 < 4; nt2++){
            int cbase = col0 + wn*32 + nt2*8 + tg*2;
            float b0 = bias[cbase], b1 = bias[cbase+1];
            #pragma unroll
            for (int hh = 0; hh < 2; hh++){
                int rr = rbase + g + hh*8;
                float v0 = acc[mt][nt2][hh*2]   + b0;
                float v1 = acc[mt][nt2][hh*2+1] + b1;
                if (ACT == 1){ v0 = gelu_tanh(v0); v1 = gelu_tanh(v1); }
                size_t gi = (size_t)rr*N + cbase;
                if (HOUT){
                    __half2* p = reinterpret_cast<__half2*>(reinterpret_cast<__half*>(Cv) + gi);
                    *p = __floats2half2_rn(v0, v1);
                } else {
                    float* C = reinterpret_cast<float*>(Cv);
                    if (RESID){
                        float2 c = *reinterpret_cast<float2*>(&C[gi]);
                        c.x += v0; c.y += v1;
                        *reinterpret_cast<float2*>(&C[gi]) = c;
                    } else {
                        *reinterpret_cast<float2*>(&C[gi]) = make_float2(v0, v1);
                    }
                }
            }
        }
    }
    cudaTriggerProgrammaticLaunchCompletion();
}

// ---------------- legacy tf32 tensor GEMM (output head, split-K) ----------
#define AS_ST 36
#define BS_ST 136
#define A_STAGE (128*AS_ST)
#define B_STAGE (32*BS_ST)
#define SM_FLOATS (3*(A_STAGE+B_STAGE))

__global__ __launch_bounds__(256, 2) void headgemm_k(
        const float* __restrict__ A, const float* __restrict__ B,
        float* __restrict__ C, int M, int N, int K){
    extern __shared__ float sm[];
    float* smA = sm;
    float* smB = sm + 3*A_STAGE;
    int tid = threadIdx.x;
    int warp = tid >> 5, lane = tid & 31;
    int wm = warp >> 2, wn = warp & 3;
    int g = lane >> 2, tg = lane & 3;
    int row0 = blockIdx.y * 128, col0 = blockIdx.x * 128;

    int Kc   = K / gridDim.z;
    int kbeg = blockIdx.z * Kc;
    int nt   = Kc >> 5;

    float acc[4][4][4];
    #pragma unroll
    for (int i=0;i<4;i++) for (int j=0;j<4;j++) for (int q=0;q<4;q++) acc[i][j][q]=0.f;

    #define ISSUE_TB(T, S) { \
        int k0 = kbeg + (T)*32; \
        float* bs = smB + (S)*B_STAGE; \
        _Pragma("unroll") \
        for (int i=0;i<4;i++){ \
            int idx = tid + i*256; int kk = idx>>5; int c4=(idx&31)<<2; \
            int gcol = col0 + c4; bool p = gcol < N; int gc = p ? gcol : 0; \
            cpasyncF(&bs[kk*BS_ST + c4], &B[(size_t)(k0+kk)*N + gc], p); \
        } \
        cp_commit(); }
    #define ISSUE_TA(T, S) { \
        int k0 = kbeg + (T)*32; \
        float* as = smA + (S)*A_STAGE; \
        _Pragma("unroll") \
        for (int i=0;i<4;i++){ \
            int idx = tid + i*256; int r = idx>>3; int ch=(idx&7)<<2; \
            int grow = row0 + r; bool p = grow < M; int gr = p ? grow : (M-1); \
            cpasyncF(&as[r*AS_ST + ch], &A[(size_t)gr*K + k0 + ch], p); \
        } \
        cp_commit(); }
    #define ISSUE_T(T, S) { ISSUE_TA(T, S); ISSUE_TB(T, S); }

    // B (weights) prefetch before dependency sync
    ISSUE_TB(0, 0);
    ISSUE_TB(1, 1);
    cudaGridDependencySynchronize();
    ISSUE_TA(0, 0);
    ISSUE_TA(1, 1);

    int stage = 0;
    for (int kt = 0; kt < nt; kt++){
        if (kt == nt-1) cp_wait<0>(); else cp_wait<1>();
        __syncthreads();
        if (kt + 2 < nt){
            int s2 = stage + 2; if (s2 >= 3) s2 -= 3;
            ISSUE_T(kt+2, s2);
        }
        const float* as = smA + stage*A_STAGE;
        const float* bs = smB + stage*B_STAGE;
        #pragma unroll
        for (int ks = 0; ks < 32; ks += 8){
            unsigned af[4][4], bf[4][2];
            #pragma unroll
            for (int mt = 0; mt < 4; mt++){
                int r = wm*64 + mt*16 + g;
                af[mt][0] = f2tf(as[r*AS_ST + ks+tg]);
                af[mt][1] = f2tf(as[(r+8)*AS_ST + ks+tg]);
                af[mt][2] = f2tf(as[r*AS_ST + ks+tg+4]);
                af[mt][3] = f2tf(as[(r+8)*AS_ST + ks+tg+4]);
            }
            #pragma unroll
            for (int nt2 = 0; nt2 < 4; nt2++){
                int c = wn*32 + nt2*8 + g;
                bf[nt2][0] = f2tf(bs[(ks+tg)*BS_ST + c]);
                bf[nt2][1] = f2tf(bs[(ks+tg+4)*BS_ST + c]);
            }
            #pragma unroll
            for (int mt = 0; mt < 4; mt++)
                #pragma unroll
                for (int nt2 = 0; nt2 < 4; nt2++)
                    mma8(acc[mt][nt2], af[mt], bf[nt2]);
        }
        stage++; if (stage >= 3) stage -= 3;
        __syncthreads();
    }
    #undef ISSUE_T
    #undef ISSUE_TA
    #undef ISSUE_TB

    float* Cout = C + (size_t)blockIdx.z*M*N;
    #pragma unroll
    for (int mt = 0; mt < 4; mt++){
        int rbase = row0 + wm*64 + mt*16;
        #pragma unroll
        for (int nt2 = 0; nt2 < 4; nt2++){
            int cbase = col0 + wn*32 + nt2*8 + tg*2;
            #pragma unroll
            for (int half2_ = 0; half2_ < 2; half2_++){
                int rr = rbase + g + half2_*8;
                if (rr < M){
                    #pragma unroll
                    for (int jj = 0; jj < 2; jj++){
                        int cc = cbase + jj;
                        if (cc < N) Cout[(size_t)rr*N + cc] = acc[mt][nt2][half2_*2+jj];
                    }
                }
            }
        }
    }
    cudaTriggerProgrammaticLaunchCompletion();
}

// ---------------- l2-normalize prompt keys ----------------
__global__ void keynorm_k(const float* __restrict__ pk){
    int r = blockIdx.x, tid = threadIdx.x;
    __shared__ float red[256];
    float v0 = pk[(size_t)r*DMOD + tid], v1 = pk[(size_t)r*DMOD + 256 + tid], v2 = pk[(size_t)r*DMOD + 512 + tid];
    red[tid] = v0*v0 + v1*v1 + v2*v2; __syncthreads();
    for (int o = 128; o; o >>= 1){ if (tid < o) red[tid] += red[tid+o]; __syncthreads(); }
    float inv = rsqrtf(fmaxf(red[0], 1e-12f));
    g_keyn[(size_t)r*DMOD + tid]       = v0*inv;
    g_keyn[(size_t)r*DMOD + 256 + tid] = v1*inv;
    g_keyn[(size_t)r*DMOD + 512 + tid] = v2*inv;
}

// ---------------- top-k (writes prompts + wpe into h rows 0..3) -----------
__global__ void topk_k(const float* __restrict__ wpe){
    int n = blockIdx.x, tid = threadIdx.x;
    __shared__ float bv[256];
    __shared__ int   bi[256];
    __shared__ int   chosen[4];
    float rs = 0.f;
    for (int r = 0; r < 4; r++){
        float best = -1e30f; int besti = 1 << 30;
        for (int j = tid; j < POOLN; j += 256){
            bool skip = false;
            for (int c = 0; c < r; c++) if (chosen[c] == j) skip = true;
            float v = g_sim[(size_t)n*POOLN + j];
            if (!skip && (v > best || (v == best && j < besti))){ best = v; besti = j; }
        }
        bv[tid] = best; bi[tid] = besti; __syncthreads();
        for (int o = 128; o; o >>= 1){
            if (tid < o){
                if (bv[tid+o] > bv[tid] || (bv[tid+o] == bv[tid] && bi[tid+o] < bi[tid])){
                    bv[tid] = bv[tid+o]; bi[tid] = bi[tid+o];
                }
            }
            __syncthreads();
        }
        if (tid == 0){ chosen[r] = bi[0]; rs += bv[0]; }
        __syncthreads();
    }
    for (int e = tid; e < 4*DMOD; e += 256){
        int k = e / DMOD, d = e % DMOD;
        g_h[((size_t)n*TTOK + k)*DMOD + d] = g_keyn[(size_t)chosen[k]*DMOD + d] + wpe[(size_t)k*DMOD + d];
    }
    if (tid == 0) atomicAdd(&g_rsim, rs);
}

// ---------------- layernorm: warp per row; half or float out --------------
template<bool HOUT>
__global__ void ln_k(const float* __restrict__ x, const float* __restrict__ g,
                     const float* __restrict__ b, void* __restrict__ yv){
    int row  = blockIdx.x*8 + (threadIdx.x >> 5);
    int lane = threadIdx.x & 31;
    cudaGridDependencySynchronize();
    const float4* xr = reinterpret_cast<const float4*>(x + (size_t)row*DMOD);
    const float4* g4 = reinterpret_cast<const float4*>(g);
    const float4* b4 = reinterpret_cast<const float4*>(b);
    float4 v[6];
    float s = 0.f, sq = 0.f;
    #pragma unroll
    for (int i = 0; i < 6; i++){
        v[i] = xr[lane + i*32];
        s  += v[i].x + v[i].y + v[i].z + v[i].w;
        sq += v[i].x*v[i].x + v[i].y*v[i].y + v[i].z*v[i].z + v[i].w*v[i].w;
    }
    #pragma unroll
    for (int o = 16; o; o >>= 1){
        s  += __shfl_xor_sync(0xffffffffu, s,  o);
        sq += __shfl_xor_sync(0xffffffffu, sq, o);
    }
    float mu  = s * (1.f/DMOD);
    float var = sq * (1.f/DMOD) - mu*mu;
    float inv = rsqrtf(var + 1e-5f);
    #pragma unroll
    for (int i = 0; i < 6; i++){
        float4 gg = g4[lane + i*32], bb = b4[lane + i*32], o;
        o.x = (v[i].x-mu)*inv*gg.x + bb.x;
        o.y = (v[i].y-mu)*inv*gg.y + bb.y;
        o.z = (v[i].z-mu)*inv*gg.z + bb.z;
        o.w = (v[i].w-mu)*inv*gg.w + bb.w;
        if (HOUT){
            __half2* yr = reinterpret_cast<__half2*>(reinterpret_cast<__half*>(yv) + (size_t)row*DMOD);
            yr[2*(lane+i*32)]   = __floats2half2_rn(o.x, o.y);
            yr[2*(lane+i*32)+1] = __floats2half2_rn(o.z, o.w);
        } else {
            float4* yr = reinterpret_cast<float4*>(reinterpret_cast<float*>(yv) + (size_t)row*DMOD);
            yr[lane + i*32] = o;
        }
    }
    cudaTriggerProgrammaticLaunchCompletion();
}

// ---------------- attention: fp16 mma flash, block per (series, head) -----
#define QKS 72
#define VTS 88
__global__ __launch_bounds__(160) void attn_k(){
    int blk = blockIdx.x;
    int n = blk / 12, head = blk % 12;
    __shared__ __half qs[80*QKS];
    __shared__ __half ks[80*QKS];
    __shared__ __half vt[64*VTS];
    int tid = threadIdx.x, w = tid >> 5, lane = tid & 31;
    int g = lane >> 2, tg = lane & 3;

    for (int idx = tid; idx < 64*12; idx += 160){
        int d = idx / 12, t = 68 + idx % 12;
        vt[d*VTS + t] = __float2half(0.f);
    }
    cudaGridDependencySynchronize();
    const __half* qkv = g_qkvh + (size_t)n*TTOK*3*DMOD + head*64;
    for (int idx = tid; idx < TTOK*32; idx += 160){
        int t = idx >> 5, c = (idx & 31)*2;
        __half2 q2 = *reinterpret_cast<const __half2*>(qkv + (size_t)t*3*DMOD + c);
        __half2 k2 = *reinterpret_cast<const __half2*>(qkv + (size_t)t*3*DMOD + DMOD + c);
        __half2 v2 = *reinterpret_cast<const __half2*>(qkv + (size_t)t*3*DMOD + 2*DMOD + c);
        *reinterpret_cast<__half2*>(qs + t*QKS + c) = q2;
        *reinterpret_cast<__half2*>(ks + t*QKS + c) = k2;
        vt[c*VTS + t]     = __low2half(v2);
        vt[(c+1)*VTS + t] = __high2half(v2);
    }
    __syncthreads();

    int rb = w*16 + g;
    float sacc[10][4];
    #pragma unroll
    for (int i = 0; i < 10; i++) for (int j = 0; j < 4; j++) sacc[i][j] = 0.f;
    #pragma unroll
    for (int kc = 0; kc < 4; kc++){
        unsigned af[4];
        int base = rb*QKS + kc*16 + 2*tg;
        af[0] = *reinterpret_cast<const unsigned*>(&qs[base]);
        af[1] = *reinterpret_cast<const unsigned*>(&qs[base + 8*QKS]);
        af[2] = *reinterpret_cast<const unsigned*>(&qs[base + 8]);
        af[3] = *reinterpret_cast<const unsigned*>(&qs[base + 8*QKS + 8]);
        #pragma unroll
        for (int nt = 0; nt < 10; nt++){
            unsigned bf[2];
            int bb = (nt*8 + g)*QKS + kc*16 + 2*tg;
            bf[0] = *reinterpret_cast<const unsigned*>(&ks[bb]);
            bf[1] = *reinterpret_cast<const unsigned*>(&ks[bb + 8]);
            mma16(sacc[nt], af, bf);
        }
    }
    float inv_[2];
    #pragma unroll
    for (int hh = 0; hh < 2; hh++){
        int R = rb + hh*8;
        float mx = -1e30f;
        #pragma unroll
        for (int nt = 0; nt < 10; nt++)
            #pragma unroll
            for (int jj = 0; jj < 2; jj++){
                int Cn = nt*8 + 2*tg + jj;
                float sv = sacc[nt][hh*2+jj] * 0.125f;
                sv = (Cn <= R) ? sv : -1e9f;
                sacc[nt][hh*2+jj] = sv;
                mx = fmaxf(mx, sv);
            }
        mx = fmaxf(mx, __shfl_xor_sync(0xffffffffu, mx, 1));
        mx = fmaxf(mx, __shfl_xor_sync(0xffffffffu, mx, 2));
        float sm = 0.f;
        #pragma unroll
        for (int nt = 0; nt < 10; nt++)
            #pragma unroll
            for (int jj = 0; jj < 2; jj++){
                float p = expf(sacc[nt][hh*2+jj] - mx);
                sacc[nt][hh*2+jj] = p;
                sm += p;
            }
        sm += __shfl_xor_sync(0xffffffffu, sm, 1);
        sm += __shfl_xor_sync(0xffffffffu, sm, 2);
        inv_[hh] = 1.f/sm;
    }
    float oacc[8][4];
    #pragma unroll
    for (int i = 0; i < 8; i++) for (int j = 0; j < 4; j++) oacc[i][j] = 0.f;
    #pragma unroll
    for (int kc = 0; kc < 5; kc++){
        unsigned af[4];
        af[0] = packh2(sacc[2*kc][0],   sacc[2*kc][1]);
        af[1] = packh2(sacc[2*kc][2],   sacc[2*kc][3]);
        af[2] = packh2(sacc[2*kc+1][0], sacc[2*kc+1][1]);
        af[3] = packh2(sacc[2*kc+1][2], sacc[2*kc+1][3]);
        #pragma unroll
        for (int nt = 0; nt < 8; nt++){
            unsigned bf[2];
            int bb = (nt*8 + g)*VTS + kc*16 + 2*tg;
            bf[0] = *reinterpret_cast<const unsigned*>(&vt[bb]);
            bf[1] = *reinterpret_cast<const unsigned*>(&vt[bb + 8]);
            mma16(oacc[nt], af, bf);
        }
    }
    __half* ob = g_ob + (size_t)n*TTOK*DMOD + head*64;
    #pragma unroll
    for (int hh = 0; hh < 2; hh++){
        int R = rb + hh*8;
        if (R < TTOK){
            #pragma unroll
            for (int nt = 0; nt < 8; nt++){
                __half2 hv = __floats2half2_rn(oacc[nt][hh*2]*inv_[hh], oacc[nt][hh*2+1]*inv_[hh]);
                *reinterpret_cast<__half2*>(ob + (size_t)R*DMOD + nt*8 + 2*tg) = hv;
            }
        }
    }
    cudaTriggerProgrammaticLaunchCompletion();
}

// ---------------- final: sum split-K chunks + channels, denorm + rsim -----
__global__ void final_k(const float* __restrict__ outb, float* __restrict__ out, int out_size){
    int n = blockIdx.x, b = n/7, m = n%7;
    cudaGridDependencySynchronize();
    for (int t = threadIdx.x; t < PREDL; t += blockDim.x){
        float v = 3.f*outb[t];
        #pragma unroll
        for (int z = 0; z < SPLITZ; z++){
            const float* p = g_osp + (size_t)z*NSER*3*PREDL;
            v += p[(size_t)(n*3+0)*PREDL + t]
               + p[(size_t)(n*3+1)*PREDL + t]
               + p[(size_t)(n*3+2)*PREDL + t];
        }
        out[(size_t)b*PREDL*7 + (size_t)t*7 + m] = v*g_std[n] + g_mean[n];
    }
    if (n == 0 && threadIdx.x == 0 && out_size > 64*PREDL*7)
        out[64*PREDL*7] = g_rsim * (1.f/NSER);
}

// ---------------- host ----------------
template <typename T, size_t S>
static void* symaddr(T (&arr)[S]){ void* p = nullptr; cudaGetSymbolAddress(&p, arr); return p; }

template<typename F, typename... Args>
static void launch_pdl(F* k, dim3 gr, dim3 bl, size_t sm, cudaStream_t st, Args... args){
    cudaLaunchConfig_t cfg = {};
    cfg.gridDim = gr; cfg.blockDim = bl; cfg.dynamicSmemBytes = sm; cfg.stream = st;
    cudaLaunchAttribute at[1];
    at[0].id = cudaLaunchAttributeProgrammaticStreamSerialization;
    at[0].val.programmaticStreamSerializationAllowed = 1;
    cfg.attrs = at; cfg.numAttrs = 1;
    cudaLaunchKernelEx(&cfg, k, args...);
}

extern "C" void kernel_launch(void* const* d_in, const int* in_sizes, int n_in,
                              void* d_out, int out_size){
    int s = (n_in >= 2 && in_sizes[1] == 1) ? 1 : 0;
    const float* x    = (const float*)d_in[0];
    const float* in_w = (const float*)d_in[1+s];
    const float* in_b = (const float*)d_in[2+s];
    const float* pk   = (const float*)d_in[3+s];
    const float* wpe  = (const float*)d_in[4+s];
    const float* ln1g = (const float*)d_in[5+s];
    const float* ln1b = (const float*)d_in[6+s];
    const float* qkvw = (const float*)d_in[7+s];
    const float* qkvb = (const float*)d_in[8+s];
    const float* aw   = (const float*)d_in[9+s];
    const float* ab   = (const float*)d_in[10+s];
    const float* ln2g = (const float*)d_in[11+s];
    const float* ln2b = (const float*)d_in[12+s];
    const float* fcw  = (const float*)d_in[13+s];
    const float* fcb  = (const float*)d_in[14+s];
    const float* pw   = (const float*)d_in[15+s];
    const float* pbb  = (const float*)d_in[16+s];
    const float* lnfg = (const float*)d_in[17+s];
    const float* lnfb = (const float*)d_in[18+s];
    const float* outw = (const float*)d_in[19+s];
    const float* outb = (const float*)d_in[20+s];
    float* out = (float*)d_out;

    float*  p_h    = (float*) symaddr(g_h);
    __half* p_a    = (__half*)symaddr(g_a);
    float*  p_af   = (float*) symaddr(g_af);
    __half* p_qkv  = (__half*)symaddr(g_qkvh);
    __half* p_ob   = (__half*)symaddr(g_ob);
    __half* p_mlp  = (__half*)symaddr(g_mlp);
    float*  p_tok  = (float*) symaddr(g_tok);
    float*  p_mtok = (float*) symaddr(g_mtok);
    float*  p_xq   = (float*) symaddr(g_xq);
    float*  p_keyn = (float*) symaddr(g_keyn);
    float*  p_sim  = (float*) symaddr(g_sim);
    float*  p_osp  = (float*) symaddr(g_osp);
    __half* p_wT   = (__half*)symaddr(g_wT);

    const int SMB = SM_FLOATS*4;
    static cudaStream_t s2 = nullptr, s3 = nullptr;
    static cudaEvent_t evA = nullptr, evB = nullptr, evK = nullptr, evPre = nullptr, evP = nullptr;
    if (!s2){
        cudaFuncSetAttribute(headgemm_k, cudaFuncAttributeMaxDynamicSharedMemorySize, SMB);
        cudaFuncSetAttribute(hgemm_k<0,false,false>, cudaFuncAttributeMaxDynamicSharedMemorySize, H_SMEMB);
        cudaFuncSetAttribute(hgemm_k<0,true ,false>, cudaFuncAttributeMaxDynamicSharedMemorySize, H_SMEMB);
        cudaFuncSetAttribute(hgemm_k<1,false,true >, cudaFuncAttributeMaxDynamicSharedMemorySize, H_SMEMB);
        cudaFuncSetAttribute(hgemm_k<0,false,true >, cudaFuncAttributeMaxDynamicSharedMemorySize, H_SMEMB);
        cudaStreamCreateWithFlags(&s2, cudaStreamNonBlocking);
        cudaStreamCreateWithFlags(&s3, cudaStreamNonBlocking);
        cudaEventCreateWithFlags(&evA, cudaEventDisableTiming);
        cudaEventCreateWithFlags(&evB, cudaEventDisableTiming);
        cudaEventCreateWithFlags(&evK, cudaEventDisableTiming);
        cudaEventCreateWithFlags(&evPre, cudaEventDisableTiming);
        cudaEventCreateWithFlags(&evP, cudaEventDisableTiming);
    }

    // fork: keynorm + weight transposes on s2
    cudaEventRecord(evA, 0);
    cudaStreamWaitEvent(s2, evA, 0);
    keynorm_k<<<POOLN,256,0,s2>>>(pk);
    cudaEventRecord(evK, s2);
    for (int L = 0; L < NLAYER; L++){
        __half* qkvT = p_wT + (size_t)L*WL;
        __half* awT  = qkvT + 1769472;
        __half* fcT  = awT  + 589824;
        __half* pwT  = fcT  + 2359296;
        transp_k<<<dim3(2304/32, 768/32), dim3(32,8), 0, s2>>>(qkvw + (size_t)L*DMOD*3*DMOD, qkvT, 768, 2304);
        transp_k<<<dim3( 768/32, 768/32), dim3(32,8), 0, s2>>>(aw   + (size_t)L*DMOD*DMOD,   awT,  768, 768);
        transp_k<<<dim3(3072/32, 768/32), dim3(32,8), 0, s2>>>(fcw  + (size_t)L*DMOD*4*DMOD, fcT,  768, 3072);
        transp_k<<<dim3( 768/32,3072/32), dim3(32,8), 0, s2>>>(pw   + (size_t)L*4*DMOD*DMOD, pwT, 3072, 768);
    }
    cudaEventRecord(evB, s2);

    // main: prep (incl. patch-mean); patch-embed GEMM forks to s3
    prep_k<<<NSER,256>>>(x);
    cudaEventRecord(evPre, 0);
    cudaStreamWaitEvent(s3, evPre, 0);
    gemm_k<false,0,false,true><<<dim3(DMOD/64, NSER*PNUM/64),256,0,s3>>>(p_tok, in_w, in_b, p_h, NSER*PNUM, DMOD, 48, wpe);
    cudaEventRecord(evP, s3);

    gemm_k<false,0,false,false><<<dim3(DMOD/64, NSER/64),256>>>(p_mtok, in_w, in_b, p_xq, NSER, DMOD, 48, nullptr);
    xqn_k<<<NSER,256>>>();
    cudaStreamWaitEvent(0, evK, 0);
    gemm_k<true,0,false,false><<<dim3((POOLN+63)/64, NSER/64),256>>>(p_xq, p_keyn, (const float*)nullptr, p_sim, NSER, POOLN, DMOD, nullptr);
    topk_k<<<NSER,256>>>(wpe);

    cudaStreamWaitEvent(0, evB, 0);
    cudaStreamWaitEvent(0, evP, 0);

    const int MB = NTOK/128;   // 238
    for (int L = 0; L < NLAYER; L++){
        __half* qkvT = p_wT + (size_t)L*WL;
        __half* awT  = qkvT + 1769472;
        __half* fcT  = awT  + 589824;
        __half* pwT  = fcT  + 2359296;
        launch_pdl(ln_k<true>, dim3(NTOK/8), dim3(256), 0, (cudaStream_t)0,
                   (const float*)p_h, (const float*)(ln1g + (size_t)L*DMOD), (const float*)(ln1b + (size_t)L*DMOD), (void*)p_a);
        launch_pdl(hgemm_k<0,false,true>, dim3(3*DMOD/128, MB), dim3(256), (size_t)H_SMEMB, (cudaStream_t)0,
                   (const __half*)p_a, (const __half*)qkvT, (const float*)(qkvb + (size_t)L*3*DMOD), (void*)p_qkv, NTOK, 3*DMOD, DMOD);
        launch_pdl(attn_k, dim3(NSER*12), dim3(160), 0, (cudaStream_t)0);
        launch_pdl(hgemm_k<0,true,false>, dim3(DMOD/128, MB), dim3(256), (size_t)H_SMEMB, (cudaStream_t)0,
                   (const __half*)p_ob, (const __half*)awT, (const float*)(ab + (size_t)L*DMOD), (void*)p_h, NTOK, DMOD, DMOD);
        launch_pdl(ln_k<true>, dim3(NTOK/8), dim3(256), 0, (cudaStream_t)0,
                   (const float*)p_h, (const float*)(ln2g + (size_t)L*DMOD), (const float*)(ln2b + (size_t)L*DMOD), (void*)p_a);
        launch_pdl(hgemm_k<1,false,true>, dim3(4*DMOD/128, MB), dim3(256), (size_t)H_SMEMB, (cudaStream_t)0,
                   (const __half*)p_a, (const __half*)fcT, (const float*)(fcb + (size_t)L*4*DMOD), (void*)p_mlp, NTOK, 4*DMOD, DMOD);
        launch_pdl(hgemm_k<0,true,false>, dim3(DMOD/128, MB), dim3(256), (size_t)H_SMEMB, (cudaStream_t)0,
                   (const __half*)p_mlp, (const __half*)pwT, (const float*)(pbb + (size_t)L*DMOD), (void*)p_h, NTOK, DMOD, 3072);
    }

    launch_pdl(ln_k<false>, dim3(NTOK/8), dim3(256), 0, (cudaStream_t)0,
               (const float*)p_h, (const float*)lnfg, (const float*)lnfb, (void*)p_af);
    launch_pdl(headgemm_k, dim3(1, (NSER*3+127)/128, SPLITZ), dim3(256), (size_t)SMB, (cudaStream_t)0,
               (const float*)p_af, (const float*)outw, (float*)p_osp, NSER*3, PREDL, TTOK*DMOD/3);
    launch_pdl(final_k, dim3(NSER), dim3(96), 0, (cudaStream_t)0,
               (const float*)outb, (float*)out, out_size);
}

// round 12
// speedup vs baseline: 7.1571x; 1.0098x over previous
#include <cuda_runtime.h>
#include <cuda_fp16.h>
#include <math.h>
#include <stdint.h>

#define NSER 448
#define LSEQ 512
#define TTOK 68
#define DMOD 768
#define NTOK (NSER*TTOK)       // 30464
#define PNUM 64
#define POOLN 1000
#define PREDL 96
#define NLAYER 6
#define SPLITZ 32

// ---------------- scratch (device globals; no allocations) ----------------
__device__ float  g_mean[NSER];
__device__ float  g_std [NSER];
__device__ float  g_tok [NSER*PNUM*48];
__device__ float  g_mtok[NSER*48];
__device__ float  g_h   [(size_t)NTOK*DMOD];
__device__ __half g_a   [(size_t)NTOK*DMOD];
__device__ float  g_af  [(size_t)NTOK*DMOD];
__device__ __half g_qkvh[(size_t)NTOK*3*DMOD];
__device__ __half g_ob  [(size_t)NTOK*DMOD];
__device__ __half g_mlp [(size_t)NTOK*4*DMOD];
__device__ float  g_xq  [NSER*DMOD];
__device__ float  g_keyn[POOLN*DMOD];
__device__ float  g_sim [NSER*POOLN];
__device__ float  g_osp [(size_t)SPLITZ*NSER*3*PREDL];
__device__ float  g_rsim;
#define WL 7077888u
__device__ __half g_wT  [(size_t)NLAYER*WL];

__device__ __forceinline__ float gelu_tanh(float x){
    float c = 0.7978845608028654f;
    float t = tanhf(c*(x + 0.044715f*x*x*x));
    return 0.5f*x*(1.f+t);
}

__device__ __forceinline__ unsigned f2tf(float x){
    unsigned r; asm("cvt.rna.tf32.f32 %0, %1;" : "=r"(r) : "f"(x)); return r;
}

__device__ __forceinline__ void mma8(float* c, const unsigned* a, const unsigned* b){
    asm volatile("mma.sync.aligned.m16n8k8.row.col.f32.tf32.tf32.f32 "
        "{%0,%1,%2,%3}, {%4,%5,%6,%7}, {%8,%9}, {%0,%1,%2,%3};"
        : "+f"(c[0]),"+f"(c[1]),"+f"(c[2]),"+f"(c[3])
        : "r"(a[0]),"r"(a[1]),"r"(a[2]),"r"(a[3]), "r"(b[0]),"r"(b[1]));
}

__device__ __forceinline__ void mma16(float* c, const unsigned* a, const unsigned* b){
    asm volatile("mma.sync.aligned.m16n8k16.row.col.f32.f16.f16.f32 "
        "{%0,%1,%2,%3}, {%4,%5,%6,%7}, {%8,%9}, {%0,%1,%2,%3};"
        : "+f"(c[0]),"+f"(c[1]),"+f"(c[2]),"+f"(c[3])
        : "r"(a[0]),"r"(a[1]),"r"(a[2]),"r"(a[3]), "r"(b[0]),"r"(b[1]));
}

__device__ __forceinline__ void ldsm4(unsigned &r0, unsigned &r1, unsigned &r2, unsigned &r3, uint32_t addr){
    asm volatile("ldmatrix.sync.aligned.m8n8.x4.shared.b16 {%0,%1,%2,%3}, [%4];"
        : "=r"(r0),"=r"(r1),"=r"(r2),"=r"(r3) : "r"(addr));
}

__device__ __forceinline__ void cpasyncF(float* dst, const float* src, bool pred){
    unsigned sa = (unsigned)__cvta_generic_to_shared(dst);
    int sz = pred ? 16 : 0;
    asm volatile("cp.async.cg.shared.global [%0], [%1], 16, %2;" :: "r"(sa), "l"(src), "r"(sz));
}
__device__ __forceinline__ void cpasyncH(__half* dst, const __half* src){
    unsigned sa = (unsigned)__cvta_generic_to_shared(dst);
    asm volatile("cp.async.cg.shared.global [%0], [%1], 16;" :: "r"(sa), "l"(src));
}
__device__ __forceinline__ void cp_commit(){ asm volatile("cp.async.commit_group;"); }
template<int N> __device__ __forceinline__ void cp_wait(){ asm volatile("cp.async.wait_group %0;"::"n"(N)); }

__device__ __forceinline__ unsigned packh2(float a, float b){
    __half2 h = __floats2half2_rn(a, b);
    return *reinterpret_cast<unsigned*>(&h);
}

// ---------------- fused preamble: RevIN + decompose + patch + patch-mean --
__global__ void prep_k(const float* __restrict__ x){
    int n = blockIdx.x, b = n/7, m = n%7, tid = threadIdx.x;
    __shared__ float xs[LSEQ];
    __shared__ float valid[489];
    __shared__ float det[LSEQ];
    __shared__ float ph[24];
    __shared__ float red[256];
    if (n == 0 && tid == 0) g_rsim = 0.f;
    for (int l = tid; l < LSEQ; l += 256) xs[l] = x[((size_t)b*LSEQ + l)*7 + m];
    if (tid < 24) ph[tid] = 0.f;
    __syncthreads();
    float s = xs[tid] + xs[tid+256];
    red[tid] = s; __syncthreads();
    for (int o = 128; o; o >>= 1){ if (tid < o) red[tid] += red[tid+o]; __syncthreads(); }
    float mu = red[0] * (1.f/LSEQ);
    __syncthreads();
    float d0 = xs[tid]-mu, d1 = xs[tid+256]-mu;
    red[tid] = d0*d0 + d1*d1; __syncthreads();
    for (int o = 128; o; o >>= 1){ if (tid < o) red[tid] += red[tid+o]; __syncthreads(); }
    float sd = sqrtf(red[0]*(1.f/LSEQ) + 1e-5f);
    if (tid == 0){ g_mean[n] = mu; g_std[n] = sd; }
    float inv = 1.f/sd;
    xs[tid]       = d0*inv;
    xs[tid + 256] = d1*inv;
    __syncthreads();
    for (int i = tid; i < 489; i += 256){
        float ss = 0.f;
        #pragma unroll
        for (int k = 0; k < 24; k++) ss += xs[i+k];
        valid[i] = ss * (1.f/24.f);
    }
    __syncthreads();
    for (int l = tid; l < LSEQ; l += 256){
        int vi = l - 12; vi = vi < 0 ? 0 : (vi > 488 ? 488 : vi);
        float dt = xs[l] - valid[vi];
        det[l] = dt;
        atomicAdd(&ph[l % 24], dt);
    }
    __syncthreads();
    for (int e = tid; e < PNUM*48; e += 256){
        int p = e/48, rem = e%48, c = rem/16, j = rem%16;
        int l = p*8 + j; if (l > LSEQ-1) l = LSEQ-1;
        float v;
        if (c == 0){
            int vi = l - 12; vi = vi < 0 ? 0 : (vi > 488 ? 488 : vi);
            v = valid[vi];
        } else {
            int pp = l % 24;
            float cnt = (pp < 8) ? 22.f : 21.f;
            float se = ph[pp] / cnt;
            v = (c == 1) ? se : (det[l] - se);
        }
        g_tok[(size_t)n*PNUM*48 + e] = v;
    }
    if (tid < 48){
        int c = tid/16, j = tid%16;
        float sm = 0.f;
        for (int p = 0; p < PNUM; p++){
            int l = p*8 + j; if (l > LSEQ-1) l = LSEQ-1;
            float v;
            if (c == 0){
                int vi = l - 12; vi = vi < 0 ? 0 : (vi > 488 ? 488 : vi);
                v = valid[vi];
            } else {
                int pp = l % 24;
                float cnt = (pp < 8) ? 22.f : 21.f;
                float se = ph[pp] / cnt;
                v = (c == 1) ? se : (det[l] - se);
            }
            sm += v;
        }
        g_mtok[n*48 + tid] = sm * (1.f/PNUM);
    }
}

// ---------------- l2-normalize xq rows in place ----------------
__global__ void xqn_k(){
    int n = blockIdx.x, tid = threadIdx.x;
    __shared__ float red[256];
    float v0 = g_xq[(size_t)n*DMOD + tid], v1 = g_xq[(size_t)n*DMOD + 256 + tid], v2 = g_xq[(size_t)n*DMOD + 512 + tid];
    red[tid] = v0*v0 + v1*v1 + v2*v2; __syncthreads();
    for (int o = 128; o; o >>= 1){ if (tid < o) red[tid] += red[tid+o]; __syncthreads(); }
    float inv = rsqrtf(fmaxf(red[0], 1e-12f));
    g_xq[(size_t)n*DMOD + tid]       = v0*inv;
    g_xq[(size_t)n*DMOD + 256 + tid] = v1*inv;
    g_xq[(size_t)n*DMOD + 512 + tid] = v2*inv;
}

// ---------------- weight transpose to half ----------------
__global__ void transp_k(const float* __restrict__ W, __half* __restrict__ WT, int K, int N){
    __shared__ float t[32][33];
    int bx = blockIdx.x*32, by = blockIdx.y*32;
    int x = threadIdx.x, y = threadIdx.y;
    #pragma unroll
    for (int i = 0; i < 4; i++){
        int r = by + y*4 + i;
        t[y*4+i][x] = W[(size_t)r*N + bx + x];
    }
    __syncthreads();
    #pragma unroll
    for (int i = 0; i < 4; i++){
        int rn = bx + y*4 + i;
        WT[(size_t)rn*K + by + x] = __float2half(t[x][y*4+i]);
    }
}

// ---------------- generic fp32 SIMT GEMM --------------------------------
template<bool TRANSB, int ACT, bool RESID, bool REMAP>
__global__ void gemm_k(const float* __restrict__ A, const float* __restrict__ B,
                       const float* __restrict__ bias, float* __restrict__ C,
                       int M, int N, int K, const float* __restrict__ wadd){
    __shared__ float As[16][68];
    __shared__ float Bs[16][68];
    int tid = threadIdx.x;
    int tx = tid & 15, ty = tid >> 4;
    int row0 = blockIdx.y * 64, col0 = blockIdx.x * 64;
    float acc[4][4] = {};
    for (int k0 = 0; k0 < K; k0 += 16){
        {
            int r  = tid >> 2;
            int c4 = (tid & 3) * 4;
            float4 v = *reinterpret_cast<const float4*>(&A[(size_t)(row0 + r)*K + k0 + c4]);
            As[c4+0][r] = v.x; As[c4+1][r] = v.y; As[c4+2][r] = v.z; As[c4+3][r] = v.w;
        }
        if (!TRANSB){
            int kk = tid >> 4;
            int c4 = (tid & 15) * 4;
            int col = col0 + c4;
            float4 v = make_float4(0.f,0.f,0.f,0.f);
            if (col < N) v = *reinterpret_cast<const float4*>(&B[(size_t)(k0+kk)*N + col]);
            Bs[kk][c4+0] = v.x; Bs[kk][c4+1] = v.y; Bs[kk][c4+2] = v.z; Bs[kk][c4+3] = v.w;
        } else {
            int nn = tid >> 2;
            int c4 = (tid & 3) * 4;
            int col = col0 + nn;
            float4 v = make_float4(0.f,0.f,0.f,0.f);
            if (col < N) v = *reinterpret_cast<const float4*>(&B[(size_t)col*K + k0 + c4]);
            Bs[c4+0][nn] = v.x; Bs[c4+1][nn] = v.y; Bs[c4+2][nn] = v.z; Bs[c4+3][nn] = v.w;
        }
        __syncthreads();
        #pragma unroll
        for (int kk = 0; kk < 16; kk++){
            float a[4], b[4];
            #pragma unroll
            for (int i = 0; i < 4; i++) a[i] = As[kk][ty*4+i];
            #pragma unroll
            for (int j = 0; j < 4; j++) b[j] = Bs[kk][tx*4+j];
            #pragma unroll
            for (int i = 0; i < 4; i++)
                #pragma unroll
                for (int j = 0; j < 4; j++) acc[i][j] = fmaf(a[i], b[j], acc[i][j]);
        }
        __syncthreads();
    }
    #pragma unroll
    for (int i = 0; i < 4; i++){
        int r = row0 + ty*4 + i;
        size_t orow = REMAP ? (size_t)((r >> 6)*TTOK + 4 + (r & 63)) : (size_t)r;
        int t = REMAP ? (4 + (r & 63)) : 0;
        #pragma unroll
        for (int j = 0; j < 4; j++){
            int col = col0 + tx*4 + j;
            if (col < N){
                float v = acc[i][j];
                if (bias) v += bias[col];
                if (ACT == 1) v = gelu_tanh(v);
                if (REMAP && wadd) v += wadd[(size_t)t*DMOD + col];
                size_t idx = orow*(size_t)N + col;
                if (RESID) C[idx] += v; else C[idx] = v;
            }
        }
    }
}

// ================= fp16 tensor-core GEMM (ldmatrix, 4-stage, PDL) =========
#define HST 40
#define H_STAGE (128*HST)
#define H_SMEMB (8*H_STAGE*2)      // 4 stages A + 4 stages B = 81920 bytes

template<int ACT, bool RESID, bool HOUT>
__global__ __launch_bounds__(256, 2) void hgemm_k(
        const __half* __restrict__ A, const __half* __restrict__ BT,
        const float* __restrict__ bias, void* __restrict__ Cv,
        int M, int N, int K){
    extern __shared__ __half hsm[];
    __half* smA = hsm;
    __half* smB = hsm + 4*H_STAGE;
    int tid = threadIdx.x;
    int warp = tid >> 5, lane = tid & 31;
    int wm = warp >> 2, wn = warp & 3;
    int g = lane >> 2, tg = lane & 3;
    int row0 = blockIdx.y * 128, col0 = blockIdx.x * 128;

    float acc[4][4][4];
    #pragma unroll
    for (int i=0;i<4;i++) for (int j=0;j<4;j++) for (int q=0;q<4;q++) acc[i][j][q]=0.f;

    uint32_t smA_u = (uint32_t)__cvta_generic_to_shared(smA);
    uint32_t smB_u = (uint32_t)__cvta_generic_to_shared(smB);
    uint32_t aoff = (uint32_t)(((wm*64 + (lane & 15))*HST + ((lane >> 4)*8)) * 2);
    int brlo = lane & 7, b8 = ((lane >> 4) & 1)*8, bc8 = ((lane >> 3) & 1)*8;
    uint32_t boff0 = (uint32_t)(((wn*32 +  0 + b8 + brlo)*HST + bc8) * 2);
    uint32_t boff1 = (uint32_t)(((wn*32 + 16 + b8 + brlo)*HST + bc8) * 2);

    #define ISSUE_HB(T, S) { \
        __half* bs = smB + (S)*H_STAGE; \
        const __half* Bb = BT + (size_t)col0*K + (T)*32; \
        _Pragma("unroll") \
        for (int i=0;i<2;i++){ \
            int idx = tid + i*256; int r = idx>>2, ch = idx&3; \
            cpasyncH(&bs[r*HST + ch*8], &Bb[(size_t)r*K + ch*8]); \
        } \
        cp_commit(); }
    #define ISSUE_HA(T, S) { \
        __half* as = smA + (S)*H_STAGE; \
        const __half* Ab = A + (size_t)row0*K + (T)*32; \
        _Pragma("unroll") \
        for (int i=0;i<2;i++){ \
            int idx = tid + i*256; int r = idx>>2, ch = idx&3; \
            cpasyncH(&as[r*HST + ch*8], &Ab[(size_t)r*K + ch*8]); \
        } \
        cp_commit(); }
    #define ISSUE_H(T, S) { \
        __half* as = smA + (S)*H_STAGE; \
        __half* bs = smB + (S)*H_STAGE; \
        const __half* Ab = A + (size_t)row0*K + (T)*32; \
        const __half* Bb = BT + (size_t)col0*K + (T)*32; \
        _Pragma("unroll") \
        for (int i=0;i<2;i++){ \
            int idx = tid + i*256; int r = idx>>2, ch = idx&3; \
            cpasyncH(&as[r*HST + ch*8], &Ab[(size_t)r*K + ch*8]); \
        } \
        _Pragma("unroll") \
        for (int i=0;i<2;i++){ \
            int idx = tid + i*256; int r = idx>>2, ch = idx&3; \
            cpasyncH(&bs[r*HST + ch*8], &Bb[(size_t)r*K + ch*8]); \
        } \
        cp_commit(); }

    int nt = K >> 5;                 // nt >= 24 for all uses
    // weights independent of producer -> prefetch before dependency sync
    ISSUE_HB(0, 0);
    ISSUE_HB(1, 1);
    cudaGridDependencySynchronize();
    ISSUE_HA(0, 0);
    ISSUE_HA(1, 1);
    ISSUE_H(2, 2);
    // groups pending: B0,B1,A0,A1,T2

    for (int kt = 0; kt < nt; kt++){
        int rem = nt - 1 - kt;       // tiles after this one
        if      (rem >= 2) cp_wait<2>();
        else if (rem == 1) cp_wait<1>();
        else               cp_wait<0>();
        __syncthreads();
        if (kt + 3 < nt){
            int s3 = (kt+3) & 3;
            ISSUE_H(kt+3, s3);
        }
        uint32_t stb = (uint32_t)((kt & 3)*H_STAGE*2);
        #pragma unroll
        for (int ks = 0; ks < 32; ks += 16){
            unsigned af[4][4], bf[4][2];
            #pragma unroll
            for (int mt = 0; mt < 4; mt++)
                ldsm4(af[mt][0], af[mt][1], af[mt][2], af[mt][3],
                      smA_u + stb + aoff + (uint32_t)((mt*16*HST + ks)*2));
            ldsm4(bf[0][0], bf[0][1], bf[1][0], bf[1][1], smB_u + stb + boff0 + (uint32_t)(ks*2));
            ldsm4(bf[2][0], bf[2][1], bf[3][0], bf[3][1], smB_u + stb + boff1 + (uint32_t)(ks*2));
            #pragma unroll
            for (int mt = 0; mt < 4; mt++)
                #pragma unroll
                for (int nt2 = 0; nt2 < 4; nt2++)
                    mma16(acc[mt][nt2], af[mt], bf[nt2]);
        }
    }
    #undef ISSUE_H
    #undef ISSUE_HA
    #undef ISSUE_HB

    #pragma unroll
    for (int mt = 0; mt < 4; mt++){
        int rbase = row0 + wm*64 + mt*16;
        #pragma unroll
        for (int nt2 = 0; nt2 < 4; nt2++){
            int cbase = col0 + wn*32 + nt2*8 + tg*2;
            float b0 = bias[cbase], b1 = bias[cbase+1];
            #pragma unroll
            for (int hh = 0; hh < 2; hh++){
                int rr = rbase + g + hh*8;
                float v0 = acc[mt][nt2][hh*2]   + b0;
                float v1 = acc[mt][nt2][hh*2+1] + b1;
                if (ACT == 1){ v0 = gelu_tanh(v0); v1 = gelu_tanh(v1); }
                size_t gi = (size_t)rr*N + cbase;
                if (HOUT){
                    __half2* p = reinterpret_cast<__half2*>(reinterpret_cast<__half*>(Cv) + gi);
                    *p = __floats2half2_rn(v0, v1);
                } else {
                    float* C = reinterpret_cast<float*>(Cv);
                    if (RESID){
                        float2 c = *reinterpret_cast<float2*>(&C[gi]);
                        c.x += v0; c.y += v1;
                        *reinterpret_cast<float2*>(&C[gi]) = c;
                    } else {
                        *reinterpret_cast<float2*>(&C[gi]) = make_float2(v0, v1);
                    }
                }
            }
        }
    }
    cudaTriggerProgrammaticLaunchCompletion();
}

// ---------------- legacy tf32 tensor GEMM (output head, split-K) ----------
#define AS_ST 36
#define BS_ST 136
#define A_STAGE (128*AS_ST)
#define B_STAGE (32*BS_ST)
#define SM_FLOATS (3*(A_STAGE+B_STAGE))

__global__ __launch_bounds__(256, 2) void headgemm_k(
        const float* __restrict__ A, const float* __restrict__ B,
        float* __restrict__ C, int M, int N, int K){
    extern __shared__ float sm[];
    float* smA = sm;
    float* smB = sm + 3*A_STAGE;
    int tid = threadIdx.x;
    int warp = tid >> 5, lane = tid & 31;
    int wm = warp >> 2, wn = warp & 3;
    int g = lane >> 2, tg = lane & 3;
    int row0 = blockIdx.y * 128, col0 = blockIdx.x * 128;

    int Kc   = K / gridDim.z;
    int kbeg = blockIdx.z * Kc;
    int nt   = Kc >> 5;

    float acc[4][4][4];
    #pragma unroll
    for (int i=0;i<4;i++) for (int j=0;j<4;j++) for (int q=0;q<4;q++) acc[i][j][q]=0.f;

    #define ISSUE_TB(T, S) { \
        int k0 = kbeg + (T)*32; \
        float* bs = smB + (S)*B_STAGE; \
        _Pragma("unroll") \
        for (int i=0;i<4;i++){ \
            int idx = tid + i*256; int kk = idx>>5; int c4=(idx&31)<<2; \
            int gcol = col0 + c4; bool p = gcol < N; int gc = p ? gcol : 0; \
            cpasyncF(&bs[kk*BS_ST + c4], &B[(size_t)(k0+kk)*N + gc], p); \
        } \
        cp_commit(); }
    #define ISSUE_TA(T, S) { \
        int k0 = kbeg + (T)*32; \
        float* as = smA + (S)*A_STAGE; \
        _Pragma("unroll") \
        for (int i=0;i<4;i++){ \
            int idx = tid + i*256; int r = idx>>3; int ch=(idx&7)<<2; \
            int grow = row0 + r; bool p = grow < M; int gr = p ? grow : (M-1); \
            cpasyncF(&as[r*AS_ST + ch], &A[(size_t)gr*K + k0 + ch], p); \
        } \
        cp_commit(); }
    #define ISSUE_T(T, S) { ISSUE_TA(T, S); ISSUE_TB(T, S); }

    ISSUE_TB(0, 0);
    ISSUE_TB(1, 1);
    cudaGridDependencySynchronize();
    ISSUE_TA(0, 0);
    ISSUE_TA(1, 1);

    int stage = 0;
    for (int kt = 0; kt < nt; kt++){
        if (kt == nt-1) cp_wait<0>(); else cp_wait<1>();
        __syncthreads();
        if (kt + 2 < nt){
            int s2 = stage + 2; if (s2 >= 3) s2 -= 3;
            ISSUE_T(kt+2, s2);
        }
        const float* as = smA + stage*A_STAGE;
        const float* bs = smB + stage*B_STAGE;
        #pragma unroll
        for (int ks = 0; ks < 32; ks += 8){
            unsigned af[4][4], bf[4][2];
            #pragma unroll
            for (int mt = 0; mt < 4; mt++){
                int r = wm*64 + mt*16 + g;
                af[mt][0] = f2tf(as[r*AS_ST + ks+tg]);
                af[mt][1] = f2tf(as[(r+8)*AS_ST + ks+tg]);
                af[mt][2] = f2tf(as[r*AS_ST + ks+tg+4]);
                af[mt][3] = f2tf(as[(r+8)*AS_ST + ks+tg+4]);
            }
            #pragma unroll
            for (int nt2 = 0; nt2 < 4; nt2++){
                int c = wn*32 + nt2*8 + g;
                bf[nt2][0] = f2tf(bs[(ks+tg)*BS_ST + c]);
                bf[nt2][1] = f2tf(bs[(ks+tg+4)*BS_ST + c]);
            }
            #pragma unroll
            for (int mt = 0; mt < 4; mt++)
                #pragma unroll
                for (int nt2 = 0; nt2 < 4; nt2++)
                    mma8(acc[mt][nt2], af[mt], bf[nt2]);
        }
        stage++; if (stage >= 3) stage -= 3;
        __syncthreads();
    }
    #undef ISSUE_T
    #undef ISSUE_TA
    #undef ISSUE_TB

    float* Cout = C + (size_t)blockIdx.z*M*N;
    #pragma unroll
    for (int mt = 0; mt < 4; mt++){
        int rbase = row0 + wm*64 + mt*16;
        #pragma unroll
        for (int nt2 = 0; nt2 < 4; nt2++){
            int cbase = col0 + wn*32 + nt2*8 + tg*2;
            #pragma unroll
            for (int half2_ = 0; half2_ < 2; half2_++){
                int rr = rbase + g + half2_*8;
                if (rr < M){
                    #pragma unroll
                    for (int jj = 0; jj < 2; jj++){
                        int cc = cbase + jj;
                        if (cc < N) Cout[(size_t)rr*N + cc] = acc[mt][nt2][half2_*2+jj];
                    }
                }
            }
        }
    }
    cudaTriggerProgrammaticLaunchCompletion();
}

// ---------------- l2-normalize prompt keys ----------------
__global__ void keynorm_k(const float* __restrict__ pk){
    int r = blockIdx.x, tid = threadIdx.x;
    __shared__ float red[256];
    float v0 = pk[(size_t)r*DMOD + tid], v1 = pk[(size_t)r*DMOD + 256 + tid], v2 = pk[(size_t)r*DMOD + 512 + tid];
    red[tid] = v0*v0 + v1*v1 + v2*v2; __syncthreads();
    for (int o = 128; o; o >>= 1){ if (tid < o) red[tid] += red[tid+o]; __syncthreads(); }
    float inv = rsqrtf(fmaxf(red[0], 1e-12f));
    g_keyn[(size_t)r*DMOD + tid]       = v0*inv;
    g_keyn[(size_t)r*DMOD + 256 + tid] = v1*inv;
    g_keyn[(size_t)r*DMOD + 512 + tid] = v2*inv;
}

// ---------------- top-k (writes prompts + wpe into h rows 0..3) -----------
__global__ void topk_k(const float* __restrict__ wpe){
    int n = blockIdx.x, tid = threadIdx.x;
    __shared__ float bv[256];
    __shared__ int   bi[256];
    __shared__ int   chosen[4];
    float rs = 0.f;
    for (int r = 0; r < 4; r++){
        float best = -1e30f; int besti = 1 << 30;
        for (int j = tid; j < POOLN; j += 256){
            bool skip = false;
            for (int c = 0; c < r; c++) if (chosen[c] == j) skip = true;
            float v = g_sim[(size_t)n*POOLN + j];
            if (!skip && (v > best || (v == best && j < besti))){ best = v; besti = j; }
        }
        bv[tid] = best; bi[tid] = besti; __syncthreads();
        for (int o = 128; o; o >>= 1){
            if (tid < o){
                if (bv[tid+o] > bv[tid] || (bv[tid+o] == bv[tid] && bi[tid+o] < bi[tid])){
                    bv[tid] = bv[tid+o]; bi[tid] = bi[tid+o];
                }
            }
            __syncthreads();
        }
        if (tid == 0){ chosen[r] = bi[0]; rs += bv[0]; }
        __syncthreads();
    }
    for (int e = tid; e < 4*DMOD; e += 256){
        int k = e / DMOD, d = e % DMOD;
        g_h[((size_t)n*TTOK + k)*DMOD + d] = g_keyn[(size_t)chosen[k]*DMOD + d] + wpe[(size_t)k*DMOD + d];
    }
    if (tid == 0) atomicAdd(&g_rsim, rs);
}

// ---------------- layernorm: warp per row; half or float out --------------
template<bool HOUT>
__global__ void ln_k(const float* __restrict__ x, const float* __restrict__ g,
                     const float* __restrict__ b, void* __restrict__ yv){
    int row  = blockIdx.x*8 + (threadIdx.x >> 5);
    int lane = threadIdx.x & 31;
    cudaGridDependencySynchronize();
    const float4* xr = reinterpret_cast<const float4*>(x + (size_t)row*DMOD);
    const float4* g4 = reinterpret_cast<const float4*>(g);
    const float4* b4 = reinterpret_cast<const float4*>(b);
    float4 v[6];
    float s = 0.f, sq = 0.f;
    #pragma unroll
    for (int i = 0; i < 6; i++){
        v[i] = xr[lane + i*32];
        s  += v[i].x + v[i].y + v[i].z + v[i].w;
        sq += v[i].x*v[i].x + v[i].y*v[i].y + v[i].z*v[i].z + v[i].w*v[i].w;
    }
    #pragma unroll
    for (int o = 16; o; o >>= 1){
        s  += __shfl_xor_sync(0xffffffffu, s,  o);
        sq += __shfl_xor_sync(0xffffffffu, sq, o);
    }
    float mu  = s * (1.f/DMOD);
    float var = sq * (1.f/DMOD) - mu*mu;
    float inv = rsqrtf(var + 1e-5f);
    #pragma unroll
    for (int i = 0; i < 6; i++){
        float4 gg = g4[lane + i*32], bb = b4[lane + i*32], o;
        o.x = (v[i].x-mu)*inv*gg.x + bb.x;
        o.y = (v[i].y-mu)*inv*gg.y + bb.y;
        o.z = (v[i].z-mu)*inv*gg.z + bb.z;
        o.w = (v[i].w-mu)*inv*gg.w + bb.w;
        if (HOUT){
            __half2* yr = reinterpret_cast<__half2*>(reinterpret_cast<__half*>(yv) + (size_t)row*DMOD);
            yr[2*(lane+i*32)]   = __floats2half2_rn(o.x, o.y);
            yr[2*(lane+i*32)+1] = __floats2half2_rn(o.z, o.w);
        } else {
            float4* yr = reinterpret_cast<float4*>(reinterpret_cast<float*>(yv) + (size_t)row*DMOD);
            yr[lane + i*32] = o;
        }
    }
    cudaTriggerProgrammaticLaunchCompletion();
}

// ---------------- attention: fp16 mma flash, block per (series, head) -----
#define QKS 72
#define VTS 88
__global__ __launch_bounds__(160) void attn_k(){
    int blk = blockIdx.x;
    int n = blk / 12, head = blk % 12;
    __shared__ __half qs[80*QKS];
    __shared__ __half ks[80*QKS];
    __shared__ __half vt[64*VTS];
    int tid = threadIdx.x, w = tid >> 5, lane = tid & 31;
    int g = lane >> 2, tg = lane & 3;

    for (int idx = tid; idx < 64*12; idx += 160){
        int d = idx / 12, t = 68 + idx % 12;
        vt[d*VTS + t] = __float2half(0.f);
    }
    cudaGridDependencySynchronize();
    const __half* qkv = g_qkvh + (size_t)n*TTOK*3*DMOD + head*64;
    for (int idx = tid; idx < TTOK*32; idx += 160){
        int t = idx >> 5, c = (idx & 31)*2;
        __half2 q2 = *reinterpret_cast<const __half2*>(qkv + (size_t)t*3*DMOD + c);
        __half2 k2 = *reinterpret_cast<const __half2*>(qkv + (size_t)t*3*DMOD + DMOD + c);
        __half2 v2 = *reinterpret_cast<const __half2*>(qkv + (size_t)t*3*DMOD + 2*DMOD + c);
        *reinterpret_cast<__half2*>(qs + t*QKS + c) = q2;
        *reinterpret_cast<__half2*>(ks + t*QKS + c) = k2;
        vt[c*VTS + t]     = __low2half(v2);
        vt[(c+1)*VTS + t] = __high2half(v2);
    }
    __syncthreads();

    int rb = w*16 + g;
    float sacc[10][4];
    #pragma unroll
    for (int i = 0; i < 10; i++) for (int j = 0; j < 4; j++) sacc[i][j] = 0.f;
    #pragma unroll
    for (int kc = 0; kc < 4; kc++){
        unsigned af[4];
        int base = rb*QKS + kc*16 + 2*tg;
        af[0] = *reinterpret_cast<const unsigned*>(&qs[base]);
        af[1] = *reinterpret_cast<const unsigned*>(&qs[base + 8*QKS]);
        af[2] = *reinterpret_cast<const unsigned*>(&qs[base + 8]);
        af[3] = *reinterpret_cast<const unsigned*>(&qs[base + 8*QKS + 8]);
        #pragma unroll
        for (int nt = 0; nt < 10; nt++){
            unsigned bf[2];
            int bb = (nt*8 + g)*QKS + kc*16 + 2*tg;
            bf[0] = *reinterpret_cast<const unsigned*>(&ks[bb]);
            bf[1] = *reinterpret_cast<const unsigned*>(&ks[bb + 8]);
            mma16(sacc[nt], af, bf);
        }
    }
    float inv_[2];
    #pragma unroll
    for (int hh = 0; hh < 2; hh++){
        int R = rb + hh*8;
        float mx = -1e30f;
        #pragma unroll
        for (int nt = 0; nt < 10; nt++)
            #pragma unroll
            for (int jj = 0; jj < 2; jj++){
                int Cn = nt*8 + 2*tg + jj;
                float sv = sacc[nt][hh*2+jj] * 0.125f;
                sv = (Cn <= R) ? sv : -1e9f;
                sacc[nt][hh*2+jj] = sv;
                mx = fmaxf(mx, sv);
            }
        mx = fmaxf(mx, __shfl_xor_sync(0xffffffffu, mx, 1));
        mx = fmaxf(mx, __shfl_xor_sync(0xffffffffu, mx, 2));
        float sm = 0.f;
        #pragma unroll
        for (int nt = 0; nt < 10; nt++)
            #pragma unroll
            for (int jj = 0; jj < 2; jj++){
                float p = expf(sacc[nt][hh*2+jj] - mx);
                sacc[nt][hh*2+jj] = p;
                sm += p;
            }
        sm += __shfl_xor_sync(0xffffffffu, sm, 1);
        sm += __shfl_xor_sync(0xffffffffu, sm, 2);
        inv_[hh] = 1.f/sm;
    }
    float oacc[8][4];
    #pragma unroll
    for (int i = 0; i < 8; i++) for (int j = 0; j < 4; j++) oacc[i][j] = 0.f;
    #pragma unroll
    for (int kc = 0; kc < 5; kc++){
        unsigned af[4];
        af[0] = packh2(sacc[2*kc][0],   sacc[2*kc][1]);
        af[1] = packh2(sacc[2*kc][2],   sacc[2*kc][3]);
        af[2] = packh2(sacc[2*kc+1][0], sacc[2*kc+1][1]);
        af[3] = packh2(sacc[2*kc+1][2], sacc[2*kc+1][3]);
        #pragma unroll
        for (int nt = 0; nt < 8; nt++){
            unsigned bf[2];
            int bb = (nt*8 + g)*VTS + kc*16 + 2*tg;
            bf[0] = *reinterpret_cast<const unsigned*>(&vt[bb]);
            bf[1] = *reinterpret_cast<const unsigned*>(&vt[bb + 8]);
            mma16(oacc[nt], af, bf);
        }
    }
    __half* ob = g_ob + (size_t)n*TTOK*DMOD + head*64;
    #pragma unroll
    for (int hh = 0; hh < 2; hh++){
        int R = rb + hh*8;
        if (R < TTOK){
            #pragma unroll
            for (int nt = 0; nt < 8; nt++){
                __half2 hv = __floats2half2_rn(oacc[nt][hh*2]*inv_[hh], oacc[nt][hh*2+1]*inv_[hh]);
                *reinterpret_cast<__half2*>(ob + (size_t)R*DMOD + nt*8 + 2*tg) = hv;
            }
        }
    }
    cudaTriggerProgrammaticLaunchCompletion();
}

// ---------------- final: sum split-K chunks + channels, denorm + rsim -----
__global__ void final_k(const float* __restrict__ outb, float* __restrict__ out, int out_size){
    int n = blockIdx.x, b = n/7, m = n%7;
    cudaGridDependencySynchronize();
    for (int t = threadIdx.x; t < PREDL; t += blockDim.x){
        float v = 3.f*outb[t];
        #pragma unroll
        for (int z = 0; z < SPLITZ; z++){
            const float* p = g_osp + (size_t)z*NSER*3*PREDL;
            v += p[(size_t)(n*3+0)*PREDL + t]
               + p[(size_t)(n*3+1)*PREDL + t]
               + p[(size_t)(n*3+2)*PREDL + t];
        }
        out[(size_t)b*PREDL*7 + (size_t)t*7 + m] = v*g_std[n] + g_mean[n];
    }
    if (n == 0 && threadIdx.x == 0 && out_size > 64*PREDL*7)
        out[64*PREDL*7] = g_rsim * (1.f/NSER);
}

// ---------------- host ----------------
template <typename T, size_t S>
static void* symaddr(T (&arr)[S]){ void* p = nullptr; cudaGetSymbolAddress(&p, arr); return p; }

template<typename F, typename... Args>
static void launch_pdl(F* k, dim3 gr, dim3 bl, size_t sm, cudaStream_t st, Args... args){
    cudaLaunchConfig_t cfg = {};
    cfg.gridDim = gr; cfg.blockDim = bl; cfg.dynamicSmemBytes = sm; cfg.stream = st;
    cudaLaunchAttribute at[1];
    at[0].id = cudaLaunchAttributeProgrammaticStreamSerialization;
    at[0].val.programmaticStreamSerializationAllowed = 1;
    cfg.attrs = at; cfg.numAttrs = 1;
    cudaLaunchKernelEx(&cfg, k, args...);
}

extern "C" void kernel_launch(void* const* d_in, const int* in_sizes, int n_in,
                              void* d_out, int out_size){
    int s = (n_in >= 2 && in_sizes[1] == 1) ? 1 : 0;
    const float* x    = (const float*)d_in[0];
    const float* in_w = (const float*)d_in[1+s];
    const float* in_b = (const float*)d_in[2+s];
    const float* pk   = (const float*)d_in[3+s];
    const float* wpe  = (const float*)d_in[4+s];
    const float* ln1g = (const float*)d_in[5+s];
    const float* ln1b = (const float*)d_in[6+s];
    const float* qkvw = (const float*)d_in[7+s];
    const float* qkvb = (const float*)d_in[8+s];
    const float* aw   = (const float*)d_in[9+s];
    const float* ab   = (const float*)d_in[10+s];
    const float* ln2g = (const float*)d_in[11+s];
    const float* ln2b = (const float*)d_in[12+s];
    const float* fcw  = (const float*)d_in[13+s];
    const float* fcb  = (const float*)d_in[14+s];
    const float* pw   = (const float*)d_in[15+s];
    const float* pbb  = (const float*)d_in[16+s];
    const float* lnfg = (const float*)d_in[17+s];
    const float* lnfb = (const float*)d_in[18+s];
    const float* outw = (const float*)d_in[19+s];
    const float* outb = (const float*)d_in[20+s];
    float* out = (float*)d_out;

    float*  p_h    = (float*) symaddr(g_h);
    __half* p_a    = (__half*)symaddr(g_a);
    float*  p_af   = (float*) symaddr(g_af);
    __half* p_qkv  = (__half*)symaddr(g_qkvh);
    __half* p_ob   = (__half*)symaddr(g_ob);
    __half* p_mlp  = (__half*)symaddr(g_mlp);
    float*  p_tok  = (float*) symaddr(g_tok);
    float*  p_mtok = (float*) symaddr(g_mtok);
    float*  p_xq   = (float*) symaddr(g_xq);
    float*  p_keyn = (float*) symaddr(g_keyn);
    float*  p_sim  = (float*) symaddr(g_sim);
    float*  p_osp  = (float*) symaddr(g_osp);
    __half* p_wT   = (__half*)symaddr(g_wT);

    const int SMB = SM_FLOATS*4;
    static cudaStream_t s2 = nullptr, s3 = nullptr;
    static cudaEvent_t evA = nullptr, evB = nullptr, evK = nullptr, evPre = nullptr, evP = nullptr;
    if (!s2){
        cudaFuncSetAttribute(headgemm_k, cudaFuncAttributeMaxDynamicSharedMemorySize, SMB);
        cudaFuncSetAttribute(hgemm_k<0,false,false>, cudaFuncAttributeMaxDynamicSharedMemorySize, H_SMEMB);
        cudaFuncSetAttribute(hgemm_k<0,true ,false>, cudaFuncAttributeMaxDynamicSharedMemorySize, H_SMEMB);
        cudaFuncSetAttribute(hgemm_k<1,false,true >, cudaFuncAttributeMaxDynamicSharedMemorySize, H_SMEMB);
        cudaFuncSetAttribute(hgemm_k<0,false,true >, cudaFuncAttributeMaxDynamicSharedMemorySize, H_SMEMB);
        cudaStreamCreateWithFlags(&s2, cudaStreamNonBlocking);
        cudaStreamCreateWithFlags(&s3, cudaStreamNonBlocking);
        cudaEventCreateWithFlags(&evA, cudaEventDisableTiming);
        cudaEventCreateWithFlags(&evB, cudaEventDisableTiming);
        cudaEventCreateWithFlags(&evK, cudaEventDisableTiming);
        cudaEventCreateWithFlags(&evPre, cudaEventDisableTiming);
        cudaEventCreateWithFlags(&evP, cudaEventDisableTiming);
    }

    // fork: keynorm + weight transposes on s2
    cudaEventRecord(evA, 0);
    cudaStreamWaitEvent(s2, evA, 0);
    keynorm_k<<<POOLN,256,0,s2>>>(pk);
    cudaEventRecord(evK, s2);
    for (int L = 0; L < NLAYER; L++){
        __half* qkvT = p_wT + (size_t)L*WL;
        __half* awT  = qkvT + 1769472;
        __half* fcT  = awT  + 589824;
        __half* pwT  = fcT  + 2359296;
        transp_k<<<dim3(2304/32, 768/32), dim3(32,8), 0, s2>>>(qkvw + (size_t)L*DMOD*3*DMOD, qkvT, 768, 2304);
        transp_k<<<dim3( 768/32, 768/32), dim3(32,8), 0, s2>>>(aw   + (size_t)L*DMOD*DMOD,   awT,  768, 768);
        transp_k<<<dim3(3072/32, 768/32), dim3(32,8), 0, s2>>>(fcw  + (size_t)L*DMOD*4*DMOD, fcT,  768, 3072);
        transp_k<<<dim3( 768/32,3072/32), dim3(32,8), 0, s2>>>(pw   + (size_t)L*4*DMOD*DMOD, pwT, 3072, 768);
    }
    cudaEventRecord(evB, s2);

    // main: prep (incl. patch-mean); patch-embed GEMM forks to s3
    prep_k<<<NSER,256>>>(x);
    cudaEventRecord(evPre, 0);
    cudaStreamWaitEvent(s3, evPre, 0);
    gemm_k<false,0,false,true><<<dim3(DMOD/64, NSER*PNUM/64),256,0,s3>>>(p_tok, in_w, in_b, p_h, NSER*PNUM, DMOD, 48, wpe);
    cudaEventRecord(evP, s3);

    gemm_k<false,0,false,false><<<dim3(DMOD/64, NSER/64),256>>>(p_mtok, in_w, in_b, p_xq, NSER, DMOD, 48, nullptr);
    xqn_k<<<NSER,256>>>();
    cudaStreamWaitEvent(0, evK, 0);
    gemm_k<true,0,false,false><<<dim3((POOLN+63)/64, NSER/64),256>>>(p_xq, p_keyn, (const float*)nullptr, p_sim, NSER, POOLN, DMOD, nullptr);
    topk_k<<<NSER,256>>>(wpe);

    cudaStreamWaitEvent(0, evB, 0);
    cudaStreamWaitEvent(0, evP, 0);

    const int MB = NTOK/128;   // 238
    for (int L = 0; L < NLAYER; L++){
        __half* qkvT = p_wT + (size_t)L*WL;
        __half* awT  = qkvT + 1769472;
        __half* fcT  = awT  + 589824;
        __half* pwT  = fcT  + 2359296;
        launch_pdl(ln_k<true>, dim3(NTOK/8), dim3(256), 0, (cudaStream_t)0,
                   (const float*)p_h, (const float*)(ln1g + (size_t)L*DMOD), (const float*)(ln1b + (size_t)L*DMOD), (void*)p_a);
        launch_pdl(hgemm_k<0,false,true>, dim3(3*DMOD/128, MB), dim3(256), (size_t)H_SMEMB, (cudaStream_t)0,
                   (const __half*)p_a, (const __half*)qkvT, (const float*)(qkvb + (size_t)L*3*DMOD), (void*)p_qkv, NTOK, 3*DMOD, DMOD);
        launch_pdl(attn_k, dim3(NSER*12), dim3(160), 0, (cudaStream_t)0);
        launch_pdl(hgemm_k<0,true,false>, dim3(DMOD/128, MB), dim3(256), (size_t)H_SMEMB, (cudaStream_t)0,
                   (const __half*)p_ob, (const __half*)awT, (const float*)(ab + (size_t)L*DMOD), (void*)p_h, NTOK, DMOD, DMOD);
        launch_pdl(ln_k<true>, dim3(NTOK/8), dim3(256), 0, (cudaStream_t)0,
                   (const float*)p_h, (const float*)(ln2g + (size_t)L*DMOD), (const float*)(ln2b + (size_t)L*DMOD), (void*)p_a);
        launch_pdl(hgemm_k<1,false,true>, dim3(4*DMOD/128, MB), dim3(256), (size_t)H_SMEMB, (cudaStream_t)0,
                   (const __half*)p_a, (const __half*)fcT, (const float*)(fcb + (size_t)L*4*DMOD), (void*)p_mlp, NTOK, 4*DMOD, DMOD);
        launch_pdl(hgemm_k<0,true,false>, dim3(DMOD/128, MB), dim3(256), (size_t)H_SMEMB, (cudaStream_t)0,
                   (const __half*)p_mlp, (const __half*)pwT, (const float*)(pbb + (size_t)L*DMOD), (void*)p_h, NTOK, DMOD, 3072);
    }

    launch_pdl(ln_k<false>, dim3(NTOK/8), dim3(256), 0, (cudaStream_t)0,
               (const float*)p_h, (const float*)lnfg, (const float*)lnfb, (void*)p_af);
    launch_pdl(headgemm_k, dim3(1, (NSER*3+127)/128, SPLITZ), dim3(256), (size_t)SMB, (cudaStream_t)0,
               (const float*)p_af, (const float*)outw, (float*)p_osp, NSER*3, PREDL, TTOK*DMOD/3);
    launch_pdl(final_k, dim3(NSER), dim3(96), 0, (cudaStream_t)0,
               (const float*)outb, (float*)out, out_size);
}